// round 2
// baseline (speedup 1.0000x reference)
#include <cuda_runtime.h>
#include <math.h>

#define Bc 4
#define Lc 1024
#define Dc 1024
#define Hc 16
#define Tc 64
#define dc 64
#define BHLD (Bc*Hc*Lc*dc)   /* 4,194,304 */

// ---------------- scratch (device globals; no allocs allowed) ----------------
__device__ float g_QKV[3 * BHLD];      // Q | K | V in (B,H,L,d) layout, 48 MB
__device__ float g_O[Bc * Lc * Dc];    // attention output in (B,L,D) layout, 16 MB
__device__ float g_coords[Bc * Lc];
__device__ float g_qsca[Bc * Lc];
__device__ float g_psum[Lc];
__device__ float g_rsum[Lc];

// ---------------- kernel 0: column sums of p_mat / r_mat ----------------
__global__ void colsum_kernel(const float* __restrict__ p_mat,
                              const float* __restrict__ r_mat) {
    int l = blockIdx.x * blockDim.x + threadIdx.x;
    if (l >= Lc) return;
    const float* src = blockIdx.y ? r_mat : p_mat;
    float s = 0.f;
#pragma unroll 8
    for (int dd = 0; dd < Dc; dd++) s += src[dd * Lc + l];
    if (blockIdx.y) g_rsum[l] = s; else g_psum[l] = s;
}

// ---------------- kernel 1: tau -> coords -> cubic q_sca ----------------
__global__ void coords_kernel(const float* __restrict__ t_enc,
                              const float* __restrict__ Wt,
                              const float* __restrict__ bt) {
    int n = blockIdx.x * blockDim.x + threadIdx.x;
    if (n >= Bc * Lc) return;
    float z = bt[0];
    const float* te = t_enc + (size_t)n * Tc;
#pragma unroll
    for (int k = 0; k < Tc; k++) z += te[k] * Wt[k];
    float tau = 1.f / (1.f + expf(-z));
    float c = tau * (float)(Lc - 1);
    g_coords[n] = c;
    int i = (int)floorf(c);
    float t = c - (float)i;
    int im1 = min(max(i - 1, 0), Lc - 1);
    int ii0 = min(max(i,     0), Lc - 1);
    int ii1 = min(max(i + 1, 0), Lc - 1);
    int ii2 = min(max(i + 2, 0), Lc - 1);
    float p0 = g_psum[im1], p1 = g_psum[ii0], p2 = g_psum[ii1], p3 = g_psum[ii2];
    float t2 = t * t, t3 = t2 * t;
    g_qsca[n] = 0.5f * (2.f * p1 + (-p0 + p2) * t
              + (2.f * p0 - 5.f * p1 + 4.f * p2 - p3) * t2
              + (-p0 + 3.f * p1 - 3.f * p2 + p3) * t3);
}

// ---------------- shared GEMM tile core: C[64x64] = A[64xK] * W[64xK]^T ----------------
// A, W row-major with leading dim Dc. 256 threads, 4x4 per thread, BK=16.
__device__ __forceinline__ void gemm_tile(const float* __restrict__ A,
                                          const float* __restrict__ W,
                                          int n0, int o0,
                                          float acc[4][4],
                                          float* As, float* Bs) {
    int t  = threadIdx.x;
    int ty = t >> 4, tx = t & 15;
    int rr = t >> 2;             // 0..63 tile row
    int sg = (t & 3) * 4;        // k-segment within 16-wide chunk
    const float* Ap = A + (size_t)(n0 + rr) * Dc + sg;
    const float* Wp = W + (size_t)(o0 + rr) * Dc + sg;
    for (int k0 = 0; k0 < Dc; k0 += 16) {
        float4 av = *(const float4*)(Ap + k0);
        float4 wv = *(const float4*)(Wp + k0);
        __syncthreads();
        As[(sg + 0) * 64 + rr] = av.x;  As[(sg + 1) * 64 + rr] = av.y;
        As[(sg + 2) * 64 + rr] = av.z;  As[(sg + 3) * 64 + rr] = av.w;
        Bs[(sg + 0) * 64 + rr] = wv.x;  Bs[(sg + 1) * 64 + rr] = wv.y;
        Bs[(sg + 2) * 64 + rr] = wv.z;  Bs[(sg + 3) * 64 + rr] = wv.w;
        __syncthreads();
#pragma unroll
        for (int kk = 0; kk < 16; kk++) {
            float4 a4 = *(const float4*)(As + kk * 64 + 4 * ty);
            float4 b4 = *(const float4*)(Bs + kk * 64 + 4 * tx);
            float a[4] = {a4.x, a4.y, a4.z, a4.w};
            float b[4] = {b4.x, b4.y, b4.z, b4.w};
#pragma unroll
            for (int i = 0; i < 4; i++)
#pragma unroll
                for (int j = 0; j < 4; j++)
                    acc[i][j] += a[i] * b[j];
        }
    }
}

// ---------------- kernel 2: QKV projection, output in (B,H,L,d) ----------------
__global__ void __launch_bounds__(256) qkv_gemm(const float* __restrict__ x,
                                                const float* __restrict__ WQ,
                                                const float* __restrict__ WK,
                                                const float* __restrict__ WV) {
    __shared__ float As[16 * 64];
    __shared__ float Bs[16 * 64];
    const float* W = (blockIdx.z == 0) ? WQ : ((blockIdx.z == 1) ? WK : WV);
    float* outp = g_QKV + (size_t)blockIdx.z * BHLD;
    int n0 = blockIdx.y * 64;
    int h  = blockIdx.x;          // o-tile == head (tile width 64 == d)
    float acc[4][4] = {};
    gemm_tile(x, W, n0, h * 64, acc, As, Bs);
    int ty = threadIdx.x >> 4, tx = threadIdx.x & 15;
    int b = n0 >> 10;
#pragma unroll
    for (int i = 0; i < 4; i++) {
        int n = n0 + 4 * ty + i;
        int l = n & (Lc - 1);
        float4 v = make_float4(acc[i][0], acc[i][1], acc[i][2], acc[i][3]);
        *(float4*)(outp + ((size_t)(b * Hc + h) * Lc + l) * dc + 4 * tx) = v;
    }
}

// ---------------- kernel 4: output projection + bias ----------------
__global__ void __launch_bounds__(256) out_gemm(const float* __restrict__ WO,
                                                const float* __restrict__ bO,
                                                float* __restrict__ out) {
    __shared__ float As[16 * 64];
    __shared__ float Bs[16 * 64];
    int n0 = blockIdx.y * 64;
    int o0 = blockIdx.x * 64;
    float acc[4][4] = {};
    gemm_tile(g_O, WO, n0, o0, acc, As, Bs);
    int ty = threadIdx.x >> 4, tx = threadIdx.x & 15;
    float4 bv = *(const float4*)(bO + o0 + 4 * tx);
#pragma unroll
    for (int i = 0; i < 4; i++) {
        int n = n0 + 4 * ty + i;
        float4 v = make_float4(acc[i][0] + bv.x, acc[i][1] + bv.y,
                               acc[i][2] + bv.z, acc[i][3] + bv.w);
        *(float4*)(out + (size_t)n * Dc + o0 + 4 * tx) = v;
    }
}

// ---------------- kernel 3: flash attention with interpolated bias ----------------
// smem floats: 5*4096 (Q,Pi,K,Pj,V) + 64*65 (S) + 1024 (rsum) + 4*64 = 25920
#define ATTN_SMEM_FLOATS (5 * 4096 + 64 * 65 + 1024 + 4 * 64)
#define ATTN_SMEM_BYTES  (ATTN_SMEM_FLOATS * 4)

// load a 64x16 column slab of a row-major tile, store transposed s[k][r]
__device__ __forceinline__ void load_T(const float* __restrict__ g, float* __restrict__ s,
                                       int rr, int sg) {
#pragma unroll
    for (int q = 0; q < 4; q++) {
        float4 v = *(const float4*)(g + q * 4);
        s[(sg + q * 4 + 0) * 64 + rr] = v.x;
        s[(sg + q * 4 + 1) * 64 + rr] = v.y;
        s[(sg + q * 4 + 2) * 64 + rr] = v.z;
        s[(sg + q * 4 + 3) * 64 + rr] = v.w;
    }
}

__global__ void __launch_bounds__(256, 2) attn_kernel(const float* __restrict__ x,
                                                      const float* __restrict__ alpha,
                                                      const float* __restrict__ beta,
                                                      const float* __restrict__ gamma) {
    extern __shared__ float sm[];
    float* sQ  = sm;                // [dd][r]
    float* sPi = sQ  + 4096;        // [dd][r]
    float* sK  = sPi + 4096;        // [dd][c]
    float* sPj = sK  + 4096;        // [dd][c]
    float* sV  = sPj + 4096;        // [c][dd] natural
    float* sS  = sV  + 4096;        // [r][c] stride 65
    float* sR  = sS  + 64 * 65;     // r_sum (L floats)
    float* sCi = sR  + Lc;
    float* sQi = sCi + 64;
    float* sCj = sQi + 64;
    float* sQj = sCj + 64;

    int t  = threadIdx.x;
    int ty = t >> 4, tx = t & 15;
    int bh = blockIdx.y;
    int b  = bh >> 4, h = bh & 15;
    int i0 = blockIdx.x * 64;

    float a_h = alpha[h], b_h = beta[h], c_h = gamma[h];

    for (int idx = t; idx < Lc; idx += 256) sR[idx] = g_rsum[idx];
    if (t < 64) {
        sCi[t] = g_coords[b * Lc + i0 + t];
        sQi[t] = g_qsca [b * Lc + i0 + t];
    }

    int rr = t >> 2;
    int sg = (t & 3) * 16;
    load_T(g_QKV + ((size_t)(b * Hc + h) * Lc + i0 + rr) * dc + sg, sQ,  rr, sg);
    load_T(x      + ((size_t)(b * Lc)      + i0 + rr) * Dc + h * dc + sg, sPi, rr, sg);

    float m_run[4], l_run[4], oacc[4][4] = {};
#pragma unroll
    for (int i = 0; i < 4; i++) { m_run[i] = -INFINITY; l_run[i] = 0.f; }
    float ci[4], qi[4];

    for (int jt = 0; jt < 16; jt++) {
        int j0 = jt * 64;
        __syncthreads();   // prior-iter PV reads complete; iter 0: nothing pending
        // K lives at g_QKV + BHLD (fixed: was reading the Q region)
        load_T(g_QKV + BHLD + ((size_t)(b * Hc + h) * Lc + j0 + rr) * dc + sg, sK,  rr, sg);
        load_T(x            + ((size_t)(b * Lc)      + j0 + rr) * Dc + h * dc + sg, sPj, rr, sg);
        {
            const float* gv = g_QKV + 2 * BHLD + ((size_t)(b * Hc + h) * Lc + j0 + rr) * dc + sg;
#pragma unroll
            for (int q = 0; q < 4; q++)
                *(float4*)(sV + rr * 64 + sg + q * 4) = *(const float4*)(gv + q * 4);
        }
        if (t < 64) {
            sCj[t] = g_coords[b * Lc + j0 + t];
            sQj[t] = g_qsca [b * Lc + j0 + t];
        }
        __syncthreads();

        if (jt == 0) {
#pragma unroll
            for (int i = 0; i < 4; i++) { ci[i] = sCi[4 * ty + i]; qi[i] = sQi[4 * ty + i]; }
        }

        // --- QK^T and PP^T 64x64 tiles ---
        float sc[4][4] = {}, pp[4][4] = {};
#pragma unroll 4
        for (int kk = 0; kk < 64; kk++) {
            float4 qa = *(const float4*)(sQ  + kk * 64 + 4 * ty);
            float4 ka = *(const float4*)(sK  + kk * 64 + 4 * tx);
            float4 pa = *(const float4*)(sPi + kk * 64 + 4 * ty);
            float4 pb = *(const float4*)(sPj + kk * 64 + 4 * tx);
            float aq[4] = {qa.x, qa.y, qa.z, qa.w};
            float bk[4] = {ka.x, ka.y, ka.z, ka.w};
            float ap[4] = {pa.x, pa.y, pa.z, pa.w};
            float bp[4] = {pb.x, pb.y, pb.z, pb.w};
#pragma unroll
            for (int i = 0; i < 4; i++)
#pragma unroll
                for (int j = 0; j < 4; j++) {
                    sc[i][j] += aq[i] * bk[j];
                    pp[i][j] += ap[i] * bp[j];
                }
        }

        // --- combine with interpolated bias term ---
        float cj[4], qj[4];
#pragma unroll
        for (int j = 0; j < 4; j++) { cj[j] = sCj[4 * tx + j]; qj[j] = sQj[4 * tx + j]; }
#pragma unroll
        for (int i = 0; i < 4; i++)
#pragma unroll
            for (int j = 0; j < 4; j++) {
                float delta = fabsf(ci[i] - cj[j]);
                int   di = (int)floorf(delta);
                float tt = delta - (float)di;
                int d0 = min(di,     Lc - 1);
                int d1 = min(di + 1, Lc - 1);
                float r = sR[d0] * (1.f - tt) + sR[d1] * tt;
                float S = a_h * (qi[i] + qj[j]) + b_h * r + c_h;
                sc[i][j] = sc[i][j] * 0.125f + S * pp[i][j];
            }

        // --- online softmax (row groups of 16 lanes) ---
#pragma unroll
        for (int i = 0; i < 4; i++) {
            float rmax = fmaxf(fmaxf(sc[i][0], sc[i][1]), fmaxf(sc[i][2], sc[i][3]));
#pragma unroll
            for (int off = 1; off < 16; off <<= 1)
                rmax = fmaxf(rmax, __shfl_xor_sync(0xffffffffu, rmax, off, 16));
            float m_new = fmaxf(m_run[i], rmax);
            float rsum = 0.f;
#pragma unroll
            for (int j = 0; j < 4; j++) { sc[i][j] = __expf(sc[i][j] - m_new); rsum += sc[i][j]; }
#pragma unroll
            for (int off = 1; off < 16; off <<= 1)
                rsum += __shfl_xor_sync(0xffffffffu, rsum, off, 16);
            float scale = __expf(m_run[i] - m_new);
            l_run[i] = l_run[i] * scale + rsum;
            m_run[i] = m_new;
#pragma unroll
            for (int j = 0; j < 4; j++) oacc[i][j] *= scale;
#pragma unroll
            for (int j = 0; j < 4; j++) sS[(4 * ty + i) * 65 + 4 * tx + j] = sc[i][j];
        }
        __syncthreads();

        // --- O += P_soft * V ---
#pragma unroll 4
        for (int c = 0; c < 64; c++) {
            float a0 = sS[(4 * ty + 0) * 65 + c];
            float a1 = sS[(4 * ty + 1) * 65 + c];
            float a2 = sS[(4 * ty + 2) * 65 + c];
            float a3 = sS[(4 * ty + 3) * 65 + c];
            float4 vb = *(const float4*)(sV + c * 64 + 4 * tx);
            float av[4] = {a0, a1, a2, a3};
            float bv2[4] = {vb.x, vb.y, vb.z, vb.w};
#pragma unroll
            for (int i = 0; i < 4; i++)
#pragma unroll
                for (int j = 0; j < 4; j++)
                    oacc[i][j] += av[i] * bv2[j];
        }
    }

    // epilogue: normalize, write (B,L,D)
#pragma unroll
    for (int i = 0; i < 4; i++) {
        float inv = 1.f / l_run[i];
        int l = i0 + 4 * ty + i;
        float4 v = make_float4(oacc[i][0] * inv, oacc[i][1] * inv,
                               oacc[i][2] * inv, oacc[i][3] * inv);
        *(float4*)(g_O + ((size_t)(b * Lc) + l) * Dc + h * dc + 4 * tx) = v;
    }
}

// ---------------- launch ----------------
extern "C" void kernel_launch(void* const* d_in, const int* in_sizes, int n_in,
                              void* d_out, int out_size) {
    const float* x     = (const float*)d_in[0];
    const float* t_enc = (const float*)d_in[1];
    const float* WQ    = (const float*)d_in[2];
    const float* WK    = (const float*)d_in[3];
    const float* WV    = (const float*)d_in[4];
    const float* WO    = (const float*)d_in[5];
    const float* bO    = (const float*)d_in[6];
    const float* Wt    = (const float*)d_in[7];
    const float* bt    = (const float*)d_in[8];
    const float* p_mat = (const float*)d_in[9];
    const float* r_mat = (const float*)d_in[10];
    const float* alpha = (const float*)d_in[11];
    const float* beta  = (const float*)d_in[12];
    const float* gamma = (const float*)d_in[13];
    float* out = (float*)d_out;

    cudaFuncSetAttribute(attn_kernel, cudaFuncAttributeMaxDynamicSharedMemorySize,
                         ATTN_SMEM_BYTES);

    colsum_kernel<<<dim3(Lc / 256, 2), 256>>>(p_mat, r_mat);
    coords_kernel<<<(Bc * Lc) / 128, 128>>>(t_enc, Wt, bt);
    qkv_gemm<<<dim3(Dc / 64, (Bc * Lc) / 64, 3), 256>>>(x, WQ, WK, WV);
    attn_kernel<<<dim3(Lc / 64, Bc * Hc), 256, ATTN_SMEM_BYTES>>>(x, alpha, beta, gamma);
    out_gemm<<<dim3(Dc / 64, (Bc * Lc) / 64), 256>>>(WO, bO, out);
}

// round 3
// speedup vs baseline: 1.1227x; 1.1227x over previous
#include <cuda_runtime.h>
#include <math.h>

#define Bc 4
#define Lc 1024
#define Dc 1024
#define Hc 16
#define Tc 64
#define dc 64
#define BHLD (Bc*Hc*Lc*dc)   /* 4,194,304 */

// ---------------- scratch ----------------
__device__ float g_QKV[3 * BHLD];      // Q | K | V in (B,H,L,d)
__device__ float g_O[Bc * Lc * Dc];    // attention output (B,L,D)
__device__ float g_coords[Bc * Lc];
__device__ float g_qsca[Bc * Lc];
__device__ float g_psum[Lc];
__device__ float g_rsum[Lc];

// ---------------- kernel 0: column sums ----------------
__global__ void colsum_kernel(const float* __restrict__ p_mat,
                              const float* __restrict__ r_mat) {
    int l = blockIdx.x * blockDim.x + threadIdx.x;
    if (l >= Lc) return;
    const float* src = blockIdx.y ? r_mat : p_mat;
    float s = 0.f;
#pragma unroll 8
    for (int dd = 0; dd < Dc; dd++) s += src[dd * Lc + l];
    if (blockIdx.y) g_rsum[l] = s; else g_psum[l] = s;
}

// ---------------- kernel 1: coords + cubic q_sca ----------------
__global__ void coords_kernel(const float* __restrict__ t_enc,
                              const float* __restrict__ Wt,
                              const float* __restrict__ bt) {
    int n = blockIdx.x * blockDim.x + threadIdx.x;
    if (n >= Bc * Lc) return;
    float z = bt[0];
    const float* te = t_enc + (size_t)n * Tc;
#pragma unroll
    for (int k = 0; k < Tc; k++) z += te[k] * Wt[k];
    float tau = 1.f / (1.f + expf(-z));
    float c = tau * (float)(Lc - 1);
    g_coords[n] = c;
    int i = (int)floorf(c);
    float t = c - (float)i;
    int im1 = min(max(i - 1, 0), Lc - 1);
    int ii0 = min(max(i,     0), Lc - 1);
    int ii1 = min(max(i + 1, 0), Lc - 1);
    int ii2 = min(max(i + 2, 0), Lc - 1);
    float p0 = g_psum[im1], p1 = g_psum[ii0], p2 = g_psum[ii1], p3 = g_psum[ii2];
    float t2 = t * t, t3 = t2 * t;
    g_qsca[n] = 0.5f * (2.f * p1 + (-p0 + p2) * t
              + (2.f * p0 - 5.f * p1 + 4.f * p2 - p3) * t2
              + (-p0 + 3.f * p1 - 3.f * p2 + p3) * t3);
}

// ================= SGEMM core: C[128x128] = A[128xK] * B[128xK]^T =================
// 256 threads, 8x8 microtile, BK=16, double-buffered smem, reg prefetch.
// As/Bs: [2][16][128] each.
struct Frag8 { float4 a0, a1, b0, b1; };

__device__ __forceinline__ void g_ld(const float* __restrict__ A,
                                     const float* __restrict__ B,
                                     int M0, int N0, int k0, int t, Frag8& f) {
    int r  = t >> 1;
    int kb = (t & 1) * 8;
    const float* ap = A + (size_t)(M0 + r) * Dc + k0 + kb;
    const float* bp = B + (size_t)(N0 + r) * Dc + k0 + kb;
    f.a0 = *(const float4*)(ap);     f.a1 = *(const float4*)(ap + 4);
    f.b0 = *(const float4*)(bp);     f.b1 = *(const float4*)(bp + 4);
}
__device__ __forceinline__ void s_st(float* As, float* Bs, int t, const Frag8& f) {
    int r  = t >> 1;
    int kb = (t & 1) * 8;
    As[(kb+0)*128+r]=f.a0.x; As[(kb+1)*128+r]=f.a0.y; As[(kb+2)*128+r]=f.a0.z; As[(kb+3)*128+r]=f.a0.w;
    As[(kb+4)*128+r]=f.a1.x; As[(kb+5)*128+r]=f.a1.y; As[(kb+6)*128+r]=f.a1.z; As[(kb+7)*128+r]=f.a1.w;
    Bs[(kb+0)*128+r]=f.b0.x; Bs[(kb+1)*128+r]=f.b0.y; Bs[(kb+2)*128+r]=f.b0.z; Bs[(kb+3)*128+r]=f.b0.w;
    Bs[(kb+4)*128+r]=f.b1.x; Bs[(kb+5)*128+r]=f.b1.y; Bs[(kb+6)*128+r]=f.b1.z; Bs[(kb+7)*128+r]=f.b1.w;
}

__device__ __forceinline__ void sgemm_core(const float* __restrict__ A,
                                           const float* __restrict__ B,
                                           int M0, int N0,
                                           float acc[8][8],
                                           float* As, float* Bs) {
    int t  = threadIdx.x;
    int ty = t >> 4, tx = t & 15;
    Frag8 f;
    g_ld(A, B, M0, N0, 0, t, f);
    s_st(As, Bs, t, f);
    __syncthreads();
    g_ld(A, B, M0, N0, 16, t, f);
    const int NS = Dc / 16;  // 64
    for (int s = 0; s < NS; s++) {
        int cur = s & 1;
        const float* Ab = As + cur * 2048;
        const float* Bb = Bs + cur * 2048;
#pragma unroll
        for (int kk = 0; kk < 16; kk++) {
            float4 a0 = *(const float4*)(Ab + kk * 128 + ty * 8);
            float4 a1 = *(const float4*)(Ab + kk * 128 + ty * 8 + 4);
            float4 b0 = *(const float4*)(Bb + kk * 128 + tx * 8);
            float4 b1 = *(const float4*)(Bb + kk * 128 + tx * 8 + 4);
            float av[8] = {a0.x,a0.y,a0.z,a0.w,a1.x,a1.y,a1.z,a1.w};
            float bv[8] = {b0.x,b0.y,b0.z,b0.w,b1.x,b1.y,b1.z,b1.w};
#pragma unroll
            for (int i = 0; i < 8; i++)
#pragma unroll
                for (int j = 0; j < 8; j++)
                    acc[i][j] += av[i] * bv[j];
        }
        if (s < NS - 1) s_st(As + (cur^1)*2048, Bs + (cur^1)*2048, t, f);
        __syncthreads();
        if (s < NS - 2) g_ld(A, B, M0, N0, (s + 2) * 16, t, f);
    }
}

// ---------------- kernel 2: QKV projection -> (B,H,L,d) ----------------
__global__ void __launch_bounds__(256, 2) qkv_gemm(const float* __restrict__ x,
                                                   const float* __restrict__ WQ,
                                                   const float* __restrict__ WK,
                                                   const float* __restrict__ WV) {
    __shared__ float As[2 * 16 * 128];
    __shared__ float Bs[2 * 16 * 128];
    const float* W = (blockIdx.z == 0) ? WQ : ((blockIdx.z == 1) ? WK : WV);
    float* outp = g_QKV + (size_t)blockIdx.z * BHLD;
    int M0 = blockIdx.y * 128;
    int N0 = blockIdx.x * 128;
    float acc[8][8] = {};
    sgemm_core(x, W, M0, N0, acc, As, Bs);
    int ty = threadIdx.x >> 4, tx = threadIdx.x & 15;
    int b = M0 >> 10;
#pragma unroll
    for (int i = 0; i < 8; i++) {
        int n = M0 + ty * 8 + i;
        int l = n & (Lc - 1);
#pragma unroll
        for (int jb = 0; jb < 8; jb += 4) {
            int col = N0 + tx * 8 + jb;
            int h = col >> 6, dd = col & 63;
            float4 v = make_float4(acc[i][jb], acc[i][jb+1], acc[i][jb+2], acc[i][jb+3]);
            *(float4*)(outp + ((size_t)(b * Hc + h) * Lc + l) * dc + dd) = v;
        }
    }
}

// ---------------- kernel 4: output projection + bias ----------------
__global__ void __launch_bounds__(256, 2) out_gemm(const float* __restrict__ WO,
                                                   const float* __restrict__ bO,
                                                   float* __restrict__ out) {
    __shared__ float As[2 * 16 * 128];
    __shared__ float Bs[2 * 16 * 128];
    int M0 = blockIdx.y * 128;
    int N0 = blockIdx.x * 128;
    float acc[8][8] = {};
    sgemm_core(g_O, WO, M0, N0, acc, As, Bs);
    int ty = threadIdx.x >> 4, tx = threadIdx.x & 15;
#pragma unroll
    for (int i = 0; i < 8; i++) {
        int n = M0 + ty * 8 + i;
#pragma unroll
        for (int jb = 0; jb < 8; jb += 4) {
            int col = N0 + tx * 8 + jb;
            float4 bv = *(const float4*)(bO + col);
            float4 v = make_float4(acc[i][jb] + bv.x, acc[i][jb+1] + bv.y,
                                   acc[i][jb+2] + bv.z, acc[i][jb+3] + bv.w);
            *(float4*)(out + (size_t)n * Dc + col) = v;
        }
    }
}

// ---------------- kernel 3: flash attention with interpolated bias ----------------
// 128 threads, 64x64 tile, 8x4 microtile.
// smem floats: sQ 4096 | sPi 4096 | sKV 4096 (K, then V) | sPjS 4096 (Pj, then S) |
//              sR 1024 | sCi/sQi/sCj/sQj 256  == 17664 floats = 70656 B
#define ATTN_SMEM_FLOATS (4 * 4096 + Lc + 4 * 64)
#define ATTN_SMEM_BYTES  (ATTN_SMEM_FLOATS * 4)

// load a 64x32 half of a row-major [64 x 64] tile, store transposed s[k][r]
__device__ __forceinline__ void load_T64(const float* __restrict__ g,
                                         float* __restrict__ s, int rr, int sg) {
#pragma unroll
    for (int q = 0; q < 8; q++) {
        float4 v = *(const float4*)(g + 4 * q);
        s[(sg + 4*q + 0) * 64 + rr] = v.x;
        s[(sg + 4*q + 1) * 64 + rr] = v.y;
        s[(sg + 4*q + 2) * 64 + rr] = v.z;
        s[(sg + 4*q + 3) * 64 + rr] = v.w;
    }
}

__global__ void __launch_bounds__(128, 3) attn_kernel(const float* __restrict__ x,
                                                      const float* __restrict__ alpha,
                                                      const float* __restrict__ beta,
                                                      const float* __restrict__ gamma) {
    extern __shared__ float sm[];
    float* sQ   = sm;               // [dd][r]
    float* sPi  = sQ   + 4096;      // [dd][r]
    float* sKV  = sPi  + 4096;      // K: [dd][c]  then V: [c][dd]
    float* sPjS = sKV  + 4096;      // Pj: [dd][c] then S: [r][c] stride 64
    float* sR   = sPjS + 4096;
    float* sCi  = sR   + Lc;
    float* sQi  = sCi  + 64;
    float* sCj  = sQi  + 64;
    float* sQj  = sCj  + 64;

    int t  = threadIdx.x;
    int ty = t >> 4, tx = t & 15;      // ty 0..7 (8 rows each), tx 0..15 (4 cols each)
    int rr = t >> 1;                   // 0..63 for tile loads
    int sg = (t & 1) * 32;
    int bh = blockIdx.y;
    int b  = bh >> 4, h = bh & 15;
    int i0 = blockIdx.x * 64;

    float a_h = alpha[h], b_h = beta[h], c_h = gamma[h];

    for (int idx = t; idx < Lc; idx += 128) sR[idx] = g_rsum[idx];
    if (t < 64) {
        sCi[t] = g_coords[b * Lc + i0 + t];
        sQi[t] = g_qsca [b * Lc + i0 + t];
    }
    const float* qkv_bh = g_QKV + ((size_t)(b * Hc + h) * Lc) * dc;
    const float* x_bh   = x + ((size_t)(b * Lc)) * Dc + h * dc;
    load_T64(qkv_bh + (size_t)(i0 + rr) * dc + sg, sQ,  rr, sg);
    load_T64(x_bh   + (size_t)(i0 + rr) * Dc + sg, sPi, rr, sg);

    float m_run[8], l_run[8], oacc[8][4] = {};
#pragma unroll
    for (int i = 0; i < 8; i++) { m_run[i] = -INFINITY; l_run[i] = 0.f; }

    for (int jt = 0; jt < 16; jt++) {
        int j0 = jt * 64;
        __syncthreads();   // prior PV done reading sKV/sPjS
        load_T64(qkv_bh + BHLD + (size_t)(j0 + rr) * dc + sg, sKV,  rr, sg);
        load_T64(x_bh          + (size_t)(j0 + rr) * Dc + sg, sPjS, rr, sg);
        if (t < 64) {
            sCj[t] = g_coords[b * Lc + j0 + t];
            sQj[t] = g_qsca [b * Lc + j0 + t];
        }
        __syncthreads();

        // --- dual GEMM: sc = Q K^T, pp = Pi Pj^T (8x4 per thread) ---
        float sc[8][4] = {}, pp[8][4] = {};
#pragma unroll 4
        for (int kk = 0; kk < 64; kk++) {
            float4 q0 = *(const float4*)(sQ   + kk * 64 + ty * 8);
            float4 q1 = *(const float4*)(sQ   + kk * 64 + ty * 8 + 4);
            float4 p0 = *(const float4*)(sPi  + kk * 64 + ty * 8);
            float4 p1 = *(const float4*)(sPi  + kk * 64 + ty * 8 + 4);
            float4 kb = *(const float4*)(sKV  + kk * 64 + tx * 4);
            float4 pb = *(const float4*)(sPjS + kk * 64 + tx * 4);
            float aq[8] = {q0.x,q0.y,q0.z,q0.w,q1.x,q1.y,q1.z,q1.w};
            float ap[8] = {p0.x,p0.y,p0.z,p0.w,p1.x,p1.y,p1.z,p1.w};
            float bk[4] = {kb.x,kb.y,kb.z,kb.w};
            float bp[4] = {pb.x,pb.y,pb.z,pb.w};
#pragma unroll
            for (int i = 0; i < 8; i++)
#pragma unroll
                for (int j = 0; j < 4; j++) {
                    sc[i][j] += aq[i] * bk[j];
                    pp[i][j] += ap[i] * bp[j];
                }
        }
        __syncthreads();   // done reading K / Pj (buffers reused for V / S)

        // --- combine with interpolated bias (pp dies here) ---
        float cj[4], qj[4];
#pragma unroll
        for (int j = 0; j < 4; j++) { cj[j] = sCj[4 * tx + j]; qj[j] = sQj[4 * tx + j]; }
#pragma unroll
        for (int i = 0; i < 8; i++) {
            float ci = sCi[8 * ty + i];
            float qi = sQi[8 * ty + i];
#pragma unroll
            for (int j = 0; j < 4; j++) {
                float delta = fabsf(ci - cj[j]);
                int   di = (int)delta;
                float tt = delta - (float)di;
                int d0 = min(di,     Lc - 1);
                int d1 = min(di + 1, Lc - 1);
                float r = sR[d0] * (1.f - tt) + sR[d1] * tt;
                float S = a_h * (qi + qj[j]) + b_h * r + c_h;
                sc[i][j] = sc[i][j] * 0.125f + S * pp[i][j];
            }
        }

        // --- prefetch V tile into regs (overlaps with softmax math) ---
        float4 vreg[8];
        {
            const float* gv = qkv_bh + 2 * (size_t)BHLD + (size_t)(j0 + rr) * dc + sg;
#pragma unroll
            for (int q = 0; q < 8; q++) vreg[q] = *(const float4*)(gv + 4 * q);
        }

        // --- online softmax (16-lane row groups) ---
#pragma unroll
        for (int i = 0; i < 8; i++) {
            float rmax = fmaxf(fmaxf(sc[i][0], sc[i][1]), fmaxf(sc[i][2], sc[i][3]));
#pragma unroll
            for (int off = 1; off < 16; off <<= 1)
                rmax = fmaxf(rmax, __shfl_xor_sync(0xffffffffu, rmax, off, 16));
            float m_new = fmaxf(m_run[i], rmax);
            float rsum = 0.f;
#pragma unroll
            for (int j = 0; j < 4; j++) { sc[i][j] = __expf(sc[i][j] - m_new); rsum += sc[i][j]; }
#pragma unroll
            for (int off = 1; off < 16; off <<= 1)
                rsum += __shfl_xor_sync(0xffffffffu, rsum, off, 16);
            float scale = __expf(m_run[i] - m_new);
            l_run[i] = l_run[i] * scale + rsum;
            m_run[i] = m_new;
#pragma unroll
            for (int j = 0; j < 4; j++) oacc[i][j] *= scale;
            *(float4*)(sPjS + (8 * ty + i) * 64 + 4 * tx) =
                make_float4(sc[i][0], sc[i][1], sc[i][2], sc[i][3]);
        }
        // store V (natural [c][dd]) into sKV
#pragma unroll
        for (int q = 0; q < 8; q++)
            *(float4*)(sKV + rr * 64 + sg + 4 * q) = vreg[q];
        __syncthreads();

        // --- O += softmax(S) * V ---
#pragma unroll 4
        for (int cb = 0; cb < 64; cb += 4) {
            float4 vb0 = *(const float4*)(sKV + (cb + 0) * 64 + 4 * tx);
            float4 vb1 = *(const float4*)(sKV + (cb + 1) * 64 + 4 * tx);
            float4 vb2 = *(const float4*)(sKV + (cb + 2) * 64 + 4 * tx);
            float4 vb3 = *(const float4*)(sKV + (cb + 3) * 64 + 4 * tx);
#pragma unroll
            for (int i = 0; i < 8; i++) {
                float4 s4 = *(const float4*)(sPjS + (8 * ty + i) * 64 + cb);
                oacc[i][0] += s4.x * vb0.x + s4.y * vb1.x + s4.z * vb2.x + s4.w * vb3.x;
                oacc[i][1] += s4.x * vb0.y + s4.y * vb1.y + s4.z * vb2.y + s4.w * vb3.y;
                oacc[i][2] += s4.x * vb0.z + s4.y * vb1.z + s4.z * vb2.z + s4.w * vb3.z;
                oacc[i][3] += s4.x * vb0.w + s4.y * vb1.w + s4.z * vb2.w + s4.w * vb3.w;
            }
        }
    }

    // epilogue: normalize, write (B,L,D)
#pragma unroll
    for (int i = 0; i < 8; i++) {
        float inv = 1.f / l_run[i];
        int l = i0 + 8 * ty + i;
        float4 v = make_float4(oacc[i][0] * inv, oacc[i][1] * inv,
                               oacc[i][2] * inv, oacc[i][3] * inv);
        *(float4*)(g_O + ((size_t)(b * Lc) + l) * Dc + h * dc + 4 * tx) = v;
    }
}

// ---------------- launch ----------------
extern "C" void kernel_launch(void* const* d_in, const int* in_sizes, int n_in,
                              void* d_out, int out_size) {
    const float* x     = (const float*)d_in[0];
    const float* t_enc = (const float*)d_in[1];
    const float* WQ    = (const float*)d_in[2];
    const float* WK    = (const float*)d_in[3];
    const float* WV    = (const float*)d_in[4];
    const float* WO    = (const float*)d_in[5];
    const float* bO    = (const float*)d_in[6];
    const float* Wt    = (const float*)d_in[7];
    const float* bt    = (const float*)d_in[8];
    const float* p_mat = (const float*)d_in[9];
    const float* r_mat = (const float*)d_in[10];
    const float* alpha = (const float*)d_in[11];
    const float* beta  = (const float*)d_in[12];
    const float* gamma = (const float*)d_in[13];
    float* out = (float*)d_out;

    cudaFuncSetAttribute(attn_kernel, cudaFuncAttributeMaxDynamicSharedMemorySize,
                         ATTN_SMEM_BYTES);

    colsum_kernel<<<dim3(Lc / 256, 2), 256>>>(p_mat, r_mat);
    coords_kernel<<<(Bc * Lc) / 128, 128>>>(t_enc, Wt, bt);
    qkv_gemm<<<dim3(Dc / 128, (Bc * Lc) / 128, 3), 256>>>(x, WQ, WK, WV);
    attn_kernel<<<dim3(Lc / 64, Bc * Hc), 128, ATTN_SMEM_BYTES>>>(x, alpha, beta, gamma);
    out_gemm<<<dim3(Dc / 128, (Bc * Lc) / 128), 256>>>(WO, bO, out);
}

// round 5
// speedup vs baseline: 1.3250x; 1.1802x over previous
#include <cuda_runtime.h>
#include <cuda_bf16.h>
#include <math.h>
#include <stdint.h>

#define Bc 4
#define Lc 1024
#define Dc 1024
#define Hc 16
#define Tc 64
#define dc 64
#define BHLD (Bc*Hc*Lc*dc)   /* 4,194,304 */

// ---------------- scratch ----------------
__device__ float g_QKV[3 * BHLD];        // Q | K | V in (B,H,L,d)
__device__ float g_O[Bc * Lc * Dc];      // attention output (B,L,D)
__device__ float g_coords[Bc * Lc];
__device__ float g_qsca[Bc * Lc];
__device__ float g_psum[Lc];
__device__ float g_rsum[Lc];
// bf16 hi/lo splits
__device__ __nv_bfloat16 g_xh[Bc*Lc*Dc], g_xl[Bc*Lc*Dc];     // x
__device__ __nv_bfloat16 g_wh[4*Dc*Dc],  g_wl[4*Dc*Dc];      // WQ|WK|WV|WO
__device__ __nv_bfloat16 g_oh[Bc*Lc*Dc], g_ol[Bc*Lc*Dc];     // attn out

// ---------------- fast exp: FFMA-pipe polynomial (frees MUFU) ----------------
__device__ __forceinline__ float fexp(float x) {
    float t = fmaxf(x * 1.4426950408889634f, -126.0f);   // log2(e), clamp
    float n = floorf(t);
    float f = t - n;
    float p =              1.5403530393381609e-4f;       // ~ln2^6/720
    p = fmaf(p, f, 1.3333558146428443e-3f);
    p = fmaf(p, f, 9.6181291076284772e-3f);
    p = fmaf(p, f, 5.5504108664821580e-2f);
    p = fmaf(p, f, 2.4022650695910072e-1f);
    p = fmaf(p, f, 6.9314718055994531e-1f);
    p = fmaf(p, f, 1.0f);
    int ni = (int)n;
    float s = __int_as_float((ni + 127) << 23);
    return p * s;
}

// ---------------- kernel 0: column sums ----------------
__global__ void colsum_kernel(const float* __restrict__ p_mat,
                              const float* __restrict__ r_mat) {
    int l = blockIdx.x * blockDim.x + threadIdx.x;
    if (l >= Lc) return;
    const float* src = blockIdx.y ? r_mat : p_mat;
    float s = 0.f;
#pragma unroll 8
    for (int dd = 0; dd < Dc; dd++) s += src[dd * Lc + l];
    if (blockIdx.y) g_rsum[l] = s; else g_psum[l] = s;
}

// ---------------- kernel 1: coords + cubic q_sca ----------------
__global__ void coords_kernel(const float* __restrict__ t_enc,
                              const float* __restrict__ Wt,
                              const float* __restrict__ bt) {
    int n = blockIdx.x * blockDim.x + threadIdx.x;
    if (n >= Bc * Lc) return;
    float z = bt[0];
    const float* te = t_enc + (size_t)n * Tc;
#pragma unroll
    for (int k = 0; k < Tc; k++) z += te[k] * Wt[k];
    float tau = 1.f / (1.f + expf(-z));
    float c = tau * (float)(Lc - 1);
    g_coords[n] = c;
    int i = (int)floorf(c);
    float t = c - (float)i;
    int im1 = min(max(i - 1, 0), Lc - 1);
    int ii0 = min(max(i,     0), Lc - 1);
    int ii1 = min(max(i + 1, 0), Lc - 1);
    int ii2 = min(max(i + 2, 0), Lc - 1);
    float p0 = g_psum[im1], p1 = g_psum[ii0], p2 = g_psum[ii1], p3 = g_psum[ii2];
    float t2 = t * t, t3 = t2 * t;
    g_qsca[n] = 0.5f * (2.f * p1 + (-p0 + p2) * t
              + (2.f * p0 - 5.f * p1 + 4.f * p2 - p3) * t2
              + (-p0 + 3.f * p1 - 3.f * p2 + p3) * t3);
}

// ---------------- split fp32 -> bf16 hi + bf16 lo ----------------
__device__ __forceinline__ void split1(float v, __nv_bfloat16* h, __nv_bfloat16* l) {
    __nv_bfloat16 hh = __float2bfloat16(v);
    *h = hh;
    *l = __float2bfloat16(v - __bfloat162float(hh));
}
__global__ void split_kernel(const float* __restrict__ s,
                             __nv_bfloat16* __restrict__ h,
                             __nv_bfloat16* __restrict__ l) {
    int i = (blockIdx.x * blockDim.x + threadIdx.x) * 4;
    float4 v = *(const float4*)(s + i);
    split1(v.x, h + i + 0, l + i + 0);
    split1(v.y, h + i + 1, l + i + 1);
    split1(v.z, h + i + 2, l + i + 2);
    split1(v.w, h + i + 3, l + i + 3);
}
__global__ void split_w_kernel(const float* __restrict__ WQ, const float* __restrict__ WK,
                               const float* __restrict__ WV, const float* __restrict__ WO) {
    const float* src = (blockIdx.y == 0) ? WQ : (blockIdx.y == 1) ? WK
                     : (blockIdx.y == 2) ? WV : WO;
    size_t off = (size_t)blockIdx.y << 20;
    int i = (blockIdx.x * blockDim.x + threadIdx.x) * 4;
    float4 v = *(const float4*)(src + i);
    split1(v.x, g_wh + off + i + 0, g_wl + off + i + 0);
    split1(v.y, g_wh + off + i + 1, g_wl + off + i + 1);
    split1(v.z, g_wh + off + i + 2, g_wl + off + i + 2);
    split1(v.w, g_wh + off + i + 3, g_wl + off + i + 3);
}

// ================= mma.sync bf16x3 GEMM: C[128x128] = A[128x1024]*B[128x1024]^T =================
// 512 threads = 16 warps (4m x 4n), warp tile 32x32 (2 x 4 mma m16n8k16), BK=32.
// Both A and B stored K-major -> row.col mma fragments are contiguous bf16 pairs (plain LDS.32).
#define KP 40   // smem k-pitch in bf16 elems (80B rows: 16B-aligned, conflict-light)

__device__ __forceinline__ void hmma(float c[4], uint32_t a0, uint32_t a1, uint32_t a2,
                                     uint32_t a3, uint32_t b0, uint32_t b1) {
    asm volatile(
        "mma.sync.aligned.m16n8k16.row.col.f32.bf16.bf16.f32 "
        "{%0,%1,%2,%3}, {%4,%5,%6,%7}, {%8,%9}, {%0,%1,%2,%3};"
        : "+f"(c[0]), "+f"(c[1]), "+f"(c[2]), "+f"(c[3])
        : "r"(a0), "r"(a1), "r"(a2), "r"(a3), "r"(b0), "r"(b1));
}

struct GPf { uint4 ah, al, bh, bl; };

__device__ __forceinline__ void mma_gload(const __nv_bfloat16* Ah, const __nv_bfloat16* Al,
                                          const __nv_bfloat16* Bh, const __nv_bfloat16* Bl,
                                          int k0, GPf& f) {
    int v = threadIdx.x;
    int row = v >> 2, seg = v & 3;
    size_t gs = (size_t)row * Dc + k0 + seg * 8;
    f.ah = *(const uint4*)(Ah + gs);
    f.al = *(const uint4*)(Al + gs);
    f.bh = *(const uint4*)(Bh + gs);
    f.bl = *(const uint4*)(Bl + gs);
}
__device__ __forceinline__ void mma_sstore(__nv_bfloat16* sAh, __nv_bfloat16* sAl,
                                           __nv_bfloat16* sBh, __nv_bfloat16* sBl,
                                           const GPf& f) {
    int v = threadIdx.x;
    int row = v >> 2, seg = v & 3;
    int si = row * KP + seg * 8;
    *(uint4*)(sAh + si) = f.ah;
    *(uint4*)(sAl + si) = f.al;
    *(uint4*)(sBh + si) = f.bh;
    *(uint4*)(sBl + si) = f.bl;
}

// core mainloop: accumulate c[2][4][4]
__device__ __forceinline__ void mma_core(const __nv_bfloat16* Ah, const __nv_bfloat16* Al,
                                         const __nv_bfloat16* Bh, const __nv_bfloat16* Bl,
                                         __nv_bfloat16* sAh, __nv_bfloat16* sAl,
                                         __nv_bfloat16* sBh, __nv_bfloat16* sBl,
                                         float c[2][4][4]) {
    int lane = threadIdx.x & 31, w = threadIdx.x >> 5;
    int wm = w >> 2, wn = w & 3;
    int g = lane >> 2, t2 = (lane & 3) * 2;
    GPf f;
    mma_gload(Ah, Al, Bh, Bl, 0, f);
    mma_sstore(sAh, sAl, sBh, sBl, f);
    __syncthreads();
    const int NCH = Dc / 32;   // 32
    for (int ch = 0; ch < NCH; ch++) {
        if (ch + 1 < NCH) mma_gload(Ah, Al, Bh, Bl, (ch + 1) * 32, f);
#pragma unroll
        for (int ks = 0; ks < 32; ks += 16) {
            uint32_t ah[2][4], al[2][4];
#pragma unroll
            for (int mi = 0; mi < 2; mi++) {
                int r0 = (wm * 32 + mi * 16 + g) * KP + ks + t2;
                int r8 = r0 + 8 * KP;
                ah[mi][0] = *(const uint32_t*)(sAh + r0);
                ah[mi][1] = *(const uint32_t*)(sAh + r8);
                ah[mi][2] = *(const uint32_t*)(sAh + r0 + 8);
                ah[mi][3] = *(const uint32_t*)(sAh + r8 + 8);
                al[mi][0] = *(const uint32_t*)(sAl + r0);
                al[mi][1] = *(const uint32_t*)(sAl + r8);
                al[mi][2] = *(const uint32_t*)(sAl + r0 + 8);
                al[mi][3] = *(const uint32_t*)(sAl + r8 + 8);
            }
            uint32_t bh[4][2], bl[4][2];
#pragma unroll
            for (int ni = 0; ni < 4; ni++) {
                int c0 = (wn * 32 + ni * 8 + g) * KP + ks + t2;
                bh[ni][0] = *(const uint32_t*)(sBh + c0);
                bh[ni][1] = *(const uint32_t*)(sBh + c0 + 8);
                bl[ni][0] = *(const uint32_t*)(sBl + c0);
                bl[ni][1] = *(const uint32_t*)(sBl + c0 + 8);
            }
#pragma unroll
            for (int mi = 0; mi < 2; mi++)
#pragma unroll
                for (int ni = 0; ni < 4; ni++) {
                    hmma(c[mi][ni], ah[mi][0], ah[mi][1], ah[mi][2], ah[mi][3],
                         bh[ni][0], bh[ni][1]);
                    hmma(c[mi][ni], ah[mi][0], ah[mi][1], ah[mi][2], ah[mi][3],
                         bl[ni][0], bl[ni][1]);
                    hmma(c[mi][ni], al[mi][0], al[mi][1], al[mi][2], al[mi][3],
                         bh[ni][0], bh[ni][1]);
                }
        }
        __syncthreads();
        if (ch + 1 < NCH) {
            mma_sstore(sAh, sAl, sBh, sBl, f);
            __syncthreads();
        }
    }
}

// ---------------- kernel 2: QKV projection via mma -> (B,H,L,d) ----------------
__global__ void __launch_bounds__(512, 2) qkv_mma() {
    __shared__ __nv_bfloat16 sAh[128 * KP], sAl[128 * KP], sBh[128 * KP], sBl[128 * KP];
    int z = blockIdx.z;
    int M0 = blockIdx.y * 128, N0 = blockIdx.x * 128;
    const __nv_bfloat16* Ah = g_xh + (size_t)M0 * Dc;
    const __nv_bfloat16* Al = g_xl + (size_t)M0 * Dc;
    const __nv_bfloat16* Bh = g_wh + ((size_t)z << 20) + (size_t)N0 * Dc;
    const __nv_bfloat16* Bl = g_wl + ((size_t)z << 20) + (size_t)N0 * Dc;
    float c[2][4][4] = {};
    mma_core(Ah, Al, Bh, Bl, sAh, sAl, sBh, sBl, c);

    int lane = threadIdx.x & 31, w = threadIdx.x >> 5;
    int wm = w >> 2, wn = w & 3;
    int g = lane >> 2, t2 = (lane & 3) * 2;
    float* base = g_QKV + (size_t)z * BHLD;
#pragma unroll
    for (int mi = 0; mi < 2; mi++) {
#pragma unroll
        for (int ni = 0; ni < 4; ni++) {
            int col = N0 + wn * 32 + ni * 8 + t2;
            int h = col >> 6, dd = col & 63;
#pragma unroll
            for (int rh = 0; rh < 2; rh++) {
                int row = M0 + wm * 32 + mi * 16 + g + rh * 8;
                int b = row >> 10, l = row & (Lc - 1);
                float2 v = make_float2(c[mi][ni][rh * 2], c[mi][ni][rh * 2 + 1]);
                *(float2*)(base + (((size_t)(b * Hc + h)) * Lc + l) * dc + dd) = v;
            }
        }
    }
}

// ---------------- kernel 4: output projection + bias via mma ----------------
__global__ void __launch_bounds__(512, 2) out_mma(const float* __restrict__ bO,
                                                  float* __restrict__ out) {
    __shared__ __nv_bfloat16 sAh[128 * KP], sAl[128 * KP], sBh[128 * KP], sBl[128 * KP];
    int M0 = blockIdx.y * 128, N0 = blockIdx.x * 128;
    const __nv_bfloat16* Ah = g_oh + (size_t)M0 * Dc;
    const __nv_bfloat16* Al = g_ol + (size_t)M0 * Dc;
    const __nv_bfloat16* Bh = g_wh + ((size_t)3 << 20) + (size_t)N0 * Dc;
    const __nv_bfloat16* Bl = g_wl + ((size_t)3 << 20) + (size_t)N0 * Dc;
    float c[2][4][4] = {};
    mma_core(Ah, Al, Bh, Bl, sAh, sAl, sBh, sBl, c);

    int lane = threadIdx.x & 31, w = threadIdx.x >> 5;
    int wm = w >> 2, wn = w & 3;
    int g = lane >> 2, t2 = (lane & 3) * 2;
#pragma unroll
    for (int mi = 0; mi < 2; mi++) {
#pragma unroll
        for (int ni = 0; ni < 4; ni++) {
            int col = N0 + wn * 32 + ni * 8 + t2;
            float2 bv = *(const float2*)(bO + col);
#pragma unroll
            for (int rh = 0; rh < 2; rh++) {
                int row = M0 + wm * 32 + mi * 16 + g + rh * 8;
                float2 v = make_float2(c[mi][ni][rh * 2] + bv.x,
                                       c[mi][ni][rh * 2 + 1] + bv.y);
                *(float2*)(out + (size_t)row * Dc + col) = v;
            }
        }
    }
}

// ---------------- kernel 3: flash attention (poly-exp; structure unchanged) ----------------
#define ATTN_SMEM_FLOATS (4 * 4096 + Lc + 4 * 64)
#define ATTN_SMEM_BYTES  (ATTN_SMEM_FLOATS * 4)

__device__ __forceinline__ void load_T64(const float* __restrict__ g,
                                         float* __restrict__ s, int rr, int sg) {
#pragma unroll
    for (int q = 0; q < 8; q++) {
        float4 v = *(const float4*)(g + 4 * q);
        s[(sg + 4*q + 0) * 64 + rr] = v.x;
        s[(sg + 4*q + 1) * 64 + rr] = v.y;
        s[(sg + 4*q + 2) * 64 + rr] = v.z;
        s[(sg + 4*q + 3) * 64 + rr] = v.w;
    }
}

__global__ void __launch_bounds__(128, 3) attn_kernel(const float* __restrict__ x,
                                                      const float* __restrict__ alpha,
                                                      const float* __restrict__ beta,
                                                      const float* __restrict__ gamma) {
    extern __shared__ float sm[];
    float* sQ   = sm;
    float* sPi  = sQ   + 4096;
    float* sKV  = sPi  + 4096;
    float* sPjS = sKV  + 4096;
    float* sR   = sPjS + 4096;
    float* sCi  = sR   + Lc;
    float* sQi  = sCi  + 64;
    float* sCj  = sQi  + 64;
    float* sQj  = sCj  + 64;

    int t  = threadIdx.x;
    int ty = t >> 4, tx = t & 15;
    int rr = t >> 1;
    int sg = (t & 1) * 32;
    int bh = blockIdx.y;
    int b  = bh >> 4, h = bh & 15;
    int i0 = blockIdx.x * 64;

    float a_h = alpha[h], b_h = beta[h], c_h = gamma[h];

    for (int idx = t; idx < Lc; idx += 128) sR[idx] = g_rsum[idx];
    if (t < 64) {
        sCi[t] = g_coords[b * Lc + i0 + t];
        sQi[t] = g_qsca [b * Lc + i0 + t];
    }
    const float* qkv_bh = g_QKV + ((size_t)(b * Hc + h) * Lc) * dc;
    const float* x_bh   = x + ((size_t)(b * Lc)) * Dc + h * dc;
    load_T64(qkv_bh + (size_t)(i0 + rr) * dc + sg, sQ,  rr, sg);
    load_T64(x_bh   + (size_t)(i0 + rr) * Dc + sg, sPi, rr, sg);

    float m_run[8], l_run[8], oacc[8][4] = {};
#pragma unroll
    for (int i = 0; i < 8; i++) { m_run[i] = -INFINITY; l_run[i] = 0.f; }

    for (int jt = 0; jt < 16; jt++) {
        int j0 = jt * 64;
        __syncthreads();
        load_T64(qkv_bh + BHLD + (size_t)(j0 + rr) * dc + sg, sKV,  rr, sg);
        load_T64(x_bh          + (size_t)(j0 + rr) * Dc + sg, sPjS, rr, sg);
        if (t < 64) {
            sCj[t] = g_coords[b * Lc + j0 + t];
            sQj[t] = g_qsca [b * Lc + j0 + t];
        }
        __syncthreads();

        float sc[8][4] = {}, pp[8][4] = {};
#pragma unroll 4
        for (int kk = 0; kk < 64; kk++) {
            float4 q0 = *(const float4*)(sQ   + kk * 64 + ty * 8);
            float4 q1 = *(const float4*)(sQ   + kk * 64 + ty * 8 + 4);
            float4 p0 = *(const float4*)(sPi  + kk * 64 + ty * 8);
            float4 p1 = *(const float4*)(sPi  + kk * 64 + ty * 8 + 4);
            float4 kb = *(const float4*)(sKV  + kk * 64 + tx * 4);
            float4 pb = *(const float4*)(sPjS + kk * 64 + tx * 4);
            float aq[8] = {q0.x,q0.y,q0.z,q0.w,q1.x,q1.y,q1.z,q1.w};
            float ap[8] = {p0.x,p0.y,p0.z,p0.w,p1.x,p1.y,p1.z,p1.w};
            float bk[4] = {kb.x,kb.y,kb.z,kb.w};
            float bp[4] = {pb.x,pb.y,pb.z,pb.w};
#pragma unroll
            for (int i = 0; i < 8; i++)
#pragma unroll
                for (int j = 0; j < 4; j++) {
                    sc[i][j] += aq[i] * bk[j];
                    pp[i][j] += ap[i] * bp[j];
                }
        }
        __syncthreads();

        float cj[4], qj[4];
#pragma unroll
        for (int j = 0; j < 4; j++) { cj[j] = sCj[4 * tx + j]; qj[j] = sQj[4 * tx + j]; }
#pragma unroll
        for (int i = 0; i < 8; i++) {
            float ci = sCi[8 * ty + i];
            float qi = sQi[8 * ty + i];
#pragma unroll
            for (int j = 0; j < 4; j++) {
                float delta = fabsf(ci - cj[j]);
                int   di = (int)delta;
                float tt = delta - (float)di;
                int d0 = min(di,     Lc - 1);
                int d1 = min(di + 1, Lc - 1);
                float r = sR[d0] * (1.f - tt) + sR[d1] * tt;
                float S = a_h * (qi + qj[j]) + b_h * r + c_h;
                sc[i][j] = sc[i][j] * 0.125f + S * pp[i][j];
            }
        }

        float4 vreg[8];
        {
            const float* gv = qkv_bh + 2 * (size_t)BHLD + (size_t)(j0 + rr) * dc + sg;
#pragma unroll
            for (int q = 0; q < 8; q++) vreg[q] = *(const float4*)(gv + 4 * q);
        }

#pragma unroll
        for (int i = 0; i < 8; i++) {
            float rmax = fmaxf(fmaxf(sc[i][0], sc[i][1]), fmaxf(sc[i][2], sc[i][3]));
#pragma unroll
            for (int off = 1; off < 16; off <<= 1)
                rmax = fmaxf(rmax, __shfl_xor_sync(0xffffffffu, rmax, off, 16));
            float m_new = fmaxf(m_run[i], rmax);
            float rsum = 0.f;
#pragma unroll
            for (int j = 0; j < 4; j++) { sc[i][j] = fexp(sc[i][j] - m_new); rsum += sc[i][j]; }
#pragma unroll
            for (int off = 1; off < 16; off <<= 1)
                rsum += __shfl_xor_sync(0xffffffffu, rsum, off, 16);
            float scale = fexp(m_run[i] - m_new);
            l_run[i] = l_run[i] * scale + rsum;
            m_run[i] = m_new;
#pragma unroll
            for (int j = 0; j < 4; j++) oacc[i][j] *= scale;
            *(float4*)(sPjS + (8 * ty + i) * 64 + 4 * tx) =
                make_float4(sc[i][0], sc[i][1], sc[i][2], sc[i][3]);
        }
#pragma unroll
        for (int q = 0; q < 8; q++)
            *(float4*)(sKV + rr * 64 + sg + 4 * q) = vreg[q];
        __syncthreads();

#pragma unroll 4
        for (int cb = 0; cb < 64; cb += 4) {
            float4 vb0 = *(const float4*)(sKV + (cb + 0) * 64 + 4 * tx);
            float4 vb1 = *(const float4*)(sKV + (cb + 1) * 64 + 4 * tx);
            float4 vb2 = *(const float4*)(sKV + (cb + 2) * 64 + 4 * tx);
            float4 vb3 = *(const float4*)(sKV + (cb + 3) * 64 + 4 * tx);
#pragma unroll
            for (int i = 0; i < 8; i++) {
                float4 s4 = *(const float4*)(sPjS + (8 * ty + i) * 64 + cb);
                oacc[i][0] += s4.x * vb0.x + s4.y * vb1.x + s4.z * vb2.x + s4.w * vb3.x;
                oacc[i][1] += s4.x * vb0.y + s4.y * vb1.y + s4.z * vb2.y + s4.w * vb3.y;
                oacc[i][2] += s4.x * vb0.z + s4.y * vb1.z + s4.z * vb2.z + s4.w * vb3.z;
                oacc[i][3] += s4.x * vb0.w + s4.y * vb1.w + s4.z * vb2.w + s4.w * vb3.w;
            }
        }
    }

#pragma unroll
    for (int i = 0; i < 8; i++) {
        float inv = 1.f / l_run[i];
        int l = i0 + 8 * ty + i;
        float4 v = make_float4(oacc[i][0] * inv, oacc[i][1] * inv,
                               oacc[i][2] * inv, oacc[i][3] * inv);
        *(float4*)(g_O + ((size_t)(b * Lc) + l) * Dc + h * dc + 4 * tx) = v;
    }
}

// ---------------- launch ----------------
extern "C" void kernel_launch(void* const* d_in, const int* in_sizes, int n_in,
                              void* d_out, int out_size) {
    const float* x     = (const float*)d_in[0];
    const float* t_enc = (const float*)d_in[1];
    const float* WQ    = (const float*)d_in[2];
    const float* WK    = (const float*)d_in[3];
    const float* WV    = (const float*)d_in[4];
    const float* WO    = (const float*)d_in[5];
    const float* bO    = (const float*)d_in[6];
    const float* Wt    = (const float*)d_in[7];
    const float* bt    = (const float*)d_in[8];
    const float* p_mat = (const float*)d_in[9];
    const float* r_mat = (const float*)d_in[10];
    const float* alpha = (const float*)d_in[11];
    const float* beta  = (const float*)d_in[12];
    const float* gamma = (const float*)d_in[13];
    float* out = (float*)d_out;

    cudaFuncSetAttribute(attn_kernel, cudaFuncAttributeMaxDynamicSharedMemorySize,
                         ATTN_SMEM_BYTES);

    __nv_bfloat16 *xh, *xl, *oh, *ol;
    cudaGetSymbolAddress((void**)&xh, g_xh);
    cudaGetSymbolAddress((void**)&xl, g_xl);
    cudaGetSymbolAddress((void**)&oh, g_oh);
    cudaGetSymbolAddress((void**)&ol, g_ol);
    float* gO;
    cudaGetSymbolAddress((void**)&gO, g_O);

    colsum_kernel<<<dim3(Lc / 256, 2), 256>>>(p_mat, r_mat);
    coords_kernel<<<(Bc * Lc) / 128, 128>>>(t_enc, Wt, bt);
    split_kernel<<<(Bc * Lc * Dc) / (256 * 4), 256>>>(x, xh, xl);
    split_w_kernel<<<dim3((Dc * Dc) / (256 * 4), 4), 256>>>(WQ, WK, WV, WO);
    qkv_mma<<<dim3(Dc / 128, (Bc * Lc) / 128, 3), 512>>>();
    attn_kernel<<<dim3(Lc / 64, Bc * Hc), 128, ATTN_SMEM_BYTES>>>(x, alpha, beta, gamma);
    split_kernel<<<(Bc * Lc * Dc) / (256 * 4), 256>>>(gO, oh, ol);
    out_mma<<<dim3(Dc / 128, (Bc * Lc) / 128), 512>>>(bO, out);
}

// round 6
// speedup vs baseline: 1.7595x; 1.3279x over previous
#include <cuda_runtime.h>
#include <cuda_bf16.h>
#include <math.h>
#include <stdint.h>

#define Bc 4
#define Lc 1024
#define Dc 1024
#define Hc 16
#define Tc 64
#define dc 64
#define BHLD (Bc*Hc*Lc*dc)   /* 4,194,304 */

// ---------------- scratch ----------------
__device__ float g_coords[Bc * Lc];
__device__ float g_qsca[Bc * Lc];
__device__ float g_psum[Lc];
__device__ float g_rsum[Lc];
// bf16 hi/lo splits
__device__ __nv_bfloat16 g_xh[Bc*Lc*Dc], g_xl[Bc*Lc*Dc];     // x
__device__ __nv_bfloat16 g_wh[4*Dc*Dc],  g_wl[4*Dc*Dc];      // WQ|WK|WV|WO
__device__ __nv_bfloat16 g_qh[BHLD], g_ql[BHLD];             // Q (b,h,l,d)
__device__ __nv_bfloat16 g_kh[BHLD], g_kl[BHLD];             // K (b,h,l,d)
__device__ __nv_bfloat16 g_vth[BHLD], g_vtl[BHLD];           // V^T (b,h,d,l)
__device__ __nv_bfloat16 g_oh[Bc*Lc*Dc], g_ol[Bc*Lc*Dc];     // attn out (b,l,D)

// ---------------- fast exp (FFMA pipe) ----------------
__device__ __forceinline__ float fexp(float x) {
    float t = fmaxf(x * 1.4426950408889634f, -126.0f);
    float n = floorf(t);
    float f = t - n;
    float p =              1.5403530393381609e-4f;
    p = fmaf(p, f, 1.3333558146428443e-3f);
    p = fmaf(p, f, 9.6181291076284772e-3f);
    p = fmaf(p, f, 5.5504108664821580e-2f);
    p = fmaf(p, f, 2.4022650695910072e-1f);
    p = fmaf(p, f, 6.9314718055994531e-1f);
    p = fmaf(p, f, 1.0f);
    float s = __int_as_float(((int)n + 127) << 23);
    return p * s;
}

__device__ __forceinline__ uint32_t pack_bf16(float lo, float hi) {
    __nv_bfloat162 r = __floats2bfloat162_rn(lo, hi);
    return *(uint32_t*)&r;
}
__device__ __forceinline__ float bf_hi(float v) {
    return __bfloat162float(__float2bfloat16(v));
}

// ---------------- kernel 0: column sums ----------------
__global__ void colsum_kernel(const float* __restrict__ p_mat,
                              const float* __restrict__ r_mat) {
    int l = blockIdx.x * blockDim.x + threadIdx.x;
    if (l >= Lc) return;
    const float* src = blockIdx.y ? r_mat : p_mat;
    float s = 0.f;
#pragma unroll 8
    for (int dd = 0; dd < Dc; dd++) s += src[dd * Lc + l];
    if (blockIdx.y) g_rsum[l] = s; else g_psum[l] = s;
}

// ---------------- kernel 1: coords + cubic q_sca ----------------
__global__ void coords_kernel(const float* __restrict__ t_enc,
                              const float* __restrict__ Wt,
                              const float* __restrict__ bt) {
    int n = blockIdx.x * blockDim.x + threadIdx.x;
    if (n >= Bc * Lc) return;
    float z = bt[0];
    const float* te = t_enc + (size_t)n * Tc;
#pragma unroll
    for (int k = 0; k < Tc; k++) z += te[k] * Wt[k];
    float tau = 1.f / (1.f + expf(-z));
    float c = tau * (float)(Lc - 1);
    g_coords[n] = c;
    int i = (int)floorf(c);
    float t = c - (float)i;
    int im1 = min(max(i - 1, 0), Lc - 1);
    int ii0 = min(max(i,     0), Lc - 1);
    int ii1 = min(max(i + 1, 0), Lc - 1);
    int ii2 = min(max(i + 2, 0), Lc - 1);
    float p0 = g_psum[im1], p1 = g_psum[ii0], p2 = g_psum[ii1], p3 = g_psum[ii2];
    float t2 = t * t, t3 = t2 * t;
    g_qsca[n] = 0.5f * (2.f * p1 + (-p0 + p2) * t
              + (2.f * p0 - 5.f * p1 + 4.f * p2 - p3) * t2
              + (-p0 + 3.f * p1 - 3.f * p2 + p3) * t3);
}

// ---------------- split fp32 -> bf16 hi + lo ----------------
__device__ __forceinline__ void split1(float v, __nv_bfloat16* h, __nv_bfloat16* l) {
    __nv_bfloat16 hh = __float2bfloat16(v);
    *h = hh;
    *l = __float2bfloat16(v - __bfloat162float(hh));
}
__global__ void split_kernel(const float* __restrict__ s,
                             __nv_bfloat16* __restrict__ h,
                             __nv_bfloat16* __restrict__ l) {
    int i = (blockIdx.x * blockDim.x + threadIdx.x) * 4;
    float4 v = *(const float4*)(s + i);
    split1(v.x, h + i + 0, l + i + 0);
    split1(v.y, h + i + 1, l + i + 1);
    split1(v.z, h + i + 2, l + i + 2);
    split1(v.w, h + i + 3, l + i + 3);
}
__global__ void split_w_kernel(const float* __restrict__ WQ, const float* __restrict__ WK,
                               const float* __restrict__ WV, const float* __restrict__ WO) {
    const float* src = (blockIdx.y == 0) ? WQ : (blockIdx.y == 1) ? WK
                     : (blockIdx.y == 2) ? WV : WO;
    size_t off = (size_t)blockIdx.y << 20;
    int i = (blockIdx.x * blockDim.x + threadIdx.x) * 4;
    float4 v = *(const float4*)(src + i);
    split1(v.x, g_wh + off + i + 0, g_wl + off + i + 0);
    split1(v.y, g_wh + off + i + 1, g_wl + off + i + 1);
    split1(v.z, g_wh + off + i + 2, g_wl + off + i + 2);
    split1(v.w, g_wh + off + i + 3, g_wl + off + i + 3);
}

// ================= mma.sync bf16x3 GEMM core =================
#define KP 40

__device__ __forceinline__ void hmma(float c[4], uint32_t a0, uint32_t a1, uint32_t a2,
                                     uint32_t a3, uint32_t b0, uint32_t b1) {
    asm volatile(
        "mma.sync.aligned.m16n8k16.row.col.f32.bf16.bf16.f32 "
        "{%0,%1,%2,%3}, {%4,%5,%6,%7}, {%8,%9}, {%0,%1,%2,%3};"
        : "+f"(c[0]), "+f"(c[1]), "+f"(c[2]), "+f"(c[3])
        : "r"(a0), "r"(a1), "r"(a2), "r"(a3), "r"(b0), "r"(b1));
}

struct GPf { uint4 ah, al, bh, bl; };

__device__ __forceinline__ void mma_gload(const __nv_bfloat16* Ah, const __nv_bfloat16* Al,
                                          const __nv_bfloat16* Bh, const __nv_bfloat16* Bl,
                                          int k0, GPf& f) {
    int v = threadIdx.x;
    int row = v >> 2, seg = v & 3;
    size_t gs = (size_t)row * Dc + k0 + seg * 8;
    f.ah = *(const uint4*)(Ah + gs);
    f.al = *(const uint4*)(Al + gs);
    f.bh = *(const uint4*)(Bh + gs);
    f.bl = *(const uint4*)(Bl + gs);
}
__device__ __forceinline__ void mma_sstore(__nv_bfloat16* sAh, __nv_bfloat16* sAl,
                                           __nv_bfloat16* sBh, __nv_bfloat16* sBl,
                                           const GPf& f) {
    int v = threadIdx.x;
    int row = v >> 2, seg = v & 3;
    int si = row * KP + seg * 8;
    *(uint4*)(sAh + si) = f.ah;
    *(uint4*)(sAl + si) = f.al;
    *(uint4*)(sBh + si) = f.bh;
    *(uint4*)(sBl + si) = f.bl;
}

__device__ __forceinline__ void mma_core(const __nv_bfloat16* Ah, const __nv_bfloat16* Al,
                                         const __nv_bfloat16* Bh, const __nv_bfloat16* Bl,
                                         __nv_bfloat16* sAh, __nv_bfloat16* sAl,
                                         __nv_bfloat16* sBh, __nv_bfloat16* sBl,
                                         float c[2][4][4]) {
    int lane = threadIdx.x & 31, w = threadIdx.x >> 5;
    int wm = w >> 2, wn = w & 3;
    int g = lane >> 2, t2 = (lane & 3) * 2;
    GPf f;
    mma_gload(Ah, Al, Bh, Bl, 0, f);
    mma_sstore(sAh, sAl, sBh, sBl, f);
    __syncthreads();
    const int NCH = Dc / 32;
    for (int ch = 0; ch < NCH; ch++) {
        if (ch + 1 < NCH) mma_gload(Ah, Al, Bh, Bl, (ch + 1) * 32, f);
#pragma unroll
        for (int ks = 0; ks < 32; ks += 16) {
            uint32_t ah[2][4], al[2][4];
#pragma unroll
            for (int mi = 0; mi < 2; mi++) {
                int r0 = (wm * 32 + mi * 16 + g) * KP + ks + t2;
                int r8 = r0 + 8 * KP;
                ah[mi][0] = *(const uint32_t*)(sAh + r0);
                ah[mi][1] = *(const uint32_t*)(sAh + r8);
                ah[mi][2] = *(const uint32_t*)(sAh + r0 + 8);
                ah[mi][3] = *(const uint32_t*)(sAh + r8 + 8);
                al[mi][0] = *(const uint32_t*)(sAl + r0);
                al[mi][1] = *(const uint32_t*)(sAl + r8);
                al[mi][2] = *(const uint32_t*)(sAl + r0 + 8);
                al[mi][3] = *(const uint32_t*)(sAl + r8 + 8);
            }
            uint32_t bh[4][2], bl[4][2];
#pragma unroll
            for (int ni = 0; ni < 4; ni++) {
                int c0 = (wn * 32 + ni * 8 + g) * KP + ks + t2;
                bh[ni][0] = *(const uint32_t*)(sBh + c0);
                bh[ni][1] = *(const uint32_t*)(sBh + c0 + 8);
                bl[ni][0] = *(const uint32_t*)(sBl + c0);
                bl[ni][1] = *(const uint32_t*)(sBl + c0 + 8);
            }
#pragma unroll
            for (int mi = 0; mi < 2; mi++)
#pragma unroll
                for (int ni = 0; ni < 4; ni++) {
                    hmma(c[mi][ni], ah[mi][0], ah[mi][1], ah[mi][2], ah[mi][3],
                         bh[ni][0], bh[ni][1]);
                    hmma(c[mi][ni], ah[mi][0], ah[mi][1], ah[mi][2], ah[mi][3],
                         bl[ni][0], bl[ni][1]);
                    hmma(c[mi][ni], al[mi][0], al[mi][1], al[mi][2], al[mi][3],
                         bh[ni][0], bh[ni][1]);
                }
        }
        __syncthreads();
        if (ch + 1 < NCH) {
            mma_sstore(sAh, sAl, sBh, sBl, f);
            __syncthreads();
        }
    }
}

// ---------------- kernel 2: QKV projection -> bf16 Q,K (b,h,l,d) and V^T (b,h,d,l) ----------------
__global__ void __launch_bounds__(512, 2) qkv_mma() {
    __shared__ __nv_bfloat16 sAh[128 * KP], sAl[128 * KP], sBh[128 * KP], sBl[128 * KP];
    int z = blockIdx.z;
    int M0 = blockIdx.y * 128, N0 = blockIdx.x * 128;
    const __nv_bfloat16* Ah = g_xh + (size_t)M0 * Dc;
    const __nv_bfloat16* Al = g_xl + (size_t)M0 * Dc;
    const __nv_bfloat16* Bh = g_wh + ((size_t)z << 20) + (size_t)N0 * Dc;
    const __nv_bfloat16* Bl = g_wl + ((size_t)z << 20) + (size_t)N0 * Dc;
    float c[2][4][4] = {};
    mma_core(Ah, Al, Bh, Bl, sAh, sAl, sBh, sBl, c);

    int lane = threadIdx.x & 31, w = threadIdx.x >> 5;
    int wm = w >> 2, wn = w & 3;
    int g = lane >> 2, t2 = (lane & 3) * 2;
    if (z < 2) {
        __nv_bfloat16* dh = z ? g_kh : g_qh;
        __nv_bfloat16* dl = z ? g_kl : g_ql;
#pragma unroll
        for (int mi = 0; mi < 2; mi++)
#pragma unroll
            for (int ni = 0; ni < 4; ni++) {
                int col = N0 + wn * 32 + ni * 8 + t2;
                int h = col >> 6, dd = col & 63;
#pragma unroll
                for (int rh = 0; rh < 2; rh++) {
                    int row = M0 + wm * 32 + mi * 16 + g + rh * 8;
                    int b = row >> 10, l = row & (Lc - 1);
                    float v0 = c[mi][ni][rh * 2], v1 = c[mi][ni][rh * 2 + 1];
                    float h0 = bf_hi(v0), h1 = bf_hi(v1);
                    size_t idx = (((size_t)(b * Hc + h)) * Lc + l) * dc + dd;
                    *(uint32_t*)(dh + idx) = pack_bf16(h0, h1);
                    *(uint32_t*)(dl + idx) = pack_bf16(v0 - h0, v1 - h1);
                }
            }
    } else {
        // V^T scatter: (b,h,dd,l)
#pragma unroll
        for (int mi = 0; mi < 2; mi++)
#pragma unroll
            for (int ni = 0; ni < 4; ni++) {
                int col = N0 + wn * 32 + ni * 8 + t2;
                int h = col >> 6, dd = col & 63;
#pragma unroll
                for (int rh = 0; rh < 2; rh++) {
                    int row = M0 + wm * 32 + mi * 16 + g + rh * 8;
                    int b = row >> 10, l = row & (Lc - 1);
                    size_t base = ((size_t)(b * Hc + h)) * dc;
#pragma unroll
                    for (int cc = 0; cc < 2; cc++) {
                        float v = c[mi][ni][rh * 2 + cc];
                        float vh = bf_hi(v);
                        size_t idx = (base + dd + cc) * Lc + l;
                        g_vth[idx] = __float2bfloat16(vh);
                        g_vtl[idx] = __float2bfloat16(v - vh);
                    }
                }
            }
    }
}

// ---------------- kernel 4: output projection + bias ----------------
__global__ void __launch_bounds__(512, 2) out_mma(const float* __restrict__ bO,
                                                  float* __restrict__ out) {
    __shared__ __nv_bfloat16 sAh[128 * KP], sAl[128 * KP], sBh[128 * KP], sBl[128 * KP];
    int M0 = blockIdx.y * 128, N0 = blockIdx.x * 128;
    const __nv_bfloat16* Ah = g_oh + (size_t)M0 * Dc;
    const __nv_bfloat16* Al = g_ol + (size_t)M0 * Dc;
    const __nv_bfloat16* Bh = g_wh + ((size_t)3 << 20) + (size_t)N0 * Dc;
    const __nv_bfloat16* Bl = g_wl + ((size_t)3 << 20) + (size_t)N0 * Dc;
    float c[2][4][4] = {};
    mma_core(Ah, Al, Bh, Bl, sAh, sAl, sBh, sBl, c);

    int lane = threadIdx.x & 31, w = threadIdx.x >> 5;
    int wm = w >> 2, wn = w & 3;
    int g = lane >> 2, t2 = (lane & 3) * 2;
#pragma unroll
    for (int mi = 0; mi < 2; mi++)
#pragma unroll
        for (int ni = 0; ni < 4; ni++) {
            int col = N0 + wn * 32 + ni * 8 + t2;
            float2 bv = *(const float2*)(bO + col);
#pragma unroll
            for (int rh = 0; rh < 2; rh++) {
                int row = M0 + wm * 32 + mi * 16 + g + rh * 8;
                float2 v = make_float2(c[mi][ni][rh * 2] + bv.x,
                                       c[mi][ni][rh * 2 + 1] + bv.y);
                *(float2*)(out + (size_t)row * Dc + col) = v;
            }
        }
}

// ---------------- kernel 3: flash attention, all GEMMs on mma.sync ----------------
// 128 threads = 4 warps; each warp owns 16 rows of the 64-row i-tile, all 64 cols.
#define PT 80   // smem pitch (bf16 elems) = 160B, 16B-aligned; 2-way LDS conflict max
#define ABUF (64 * PT)
#define ATTN_SMEM_BYTES (10 * ABUF * 2 + (Lc + 4 * 64) * 4)

__global__ void __launch_bounds__(128, 2) attn_mma(const float* __restrict__ alpha,
                                                   const float* __restrict__ beta,
                                                   const float* __restrict__ gamma) {
    extern __shared__ char smraw[];
    __nv_bfloat16* sQh  = (__nv_bfloat16*)smraw;
    __nv_bfloat16* sQl  = sQh  + ABUF;
    __nv_bfloat16* sPih = sQl  + ABUF;
    __nv_bfloat16* sPil = sPih + ABUF;
    __nv_bfloat16* sKh  = sPil + ABUF;
    __nv_bfloat16* sKl  = sKh  + ABUF;
    __nv_bfloat16* sPjh = sKl  + ABUF;
    __nv_bfloat16* sPjl = sPjh + ABUF;
    __nv_bfloat16* sVh  = sPjl + ABUF;
    __nv_bfloat16* sVl  = sVh  + ABUF;
    float* sR  = (float*)(sVl + ABUF);
    float* sCi = sR  + Lc;
    float* sQi = sCi + 64;
    float* sCj = sQi + 64;
    float* sQj = sCj + 64;

    int t = threadIdx.x;
    int w = t >> 5, lane = t & 31;
    int g = lane >> 2, t2 = (lane & 3) * 2;
    int bh = blockIdx.y;
    int b = bh >> 4, h = bh & 15;
    int i0 = blockIdx.x * 64;

    float a_h = alpha[h], b_h = beta[h], c_h = gamma[h];

    for (int idx = t; idx < Lc; idx += 128) sR[idx] = g_rsum[idx];
    if (t < 64) {
        sCi[t] = g_coords[b * Lc + i0 + t];
        sQi[t] = g_qsca [b * Lc + i0 + t];
    }

    // ---- i-tile loads: Q hi/lo, Pi hi/lo (4 uint4 per thread per buffer) ----
    const size_t qoff = ((size_t)bh * Lc) * dc;
    const size_t xoff = ((size_t)b * Lc) * Dc + h * dc;
#pragma unroll
    for (int q = 0; q < 4; q++) {
        int v = t * 4 + q;
        int row = v >> 3, seg = v & 7;
        int d = row * PT + seg * 8;
        size_t gq = qoff + (size_t)(i0 + row) * dc + seg * 8;
        size_t gx = xoff + (size_t)(i0 + row) * Dc + seg * 8;
        *(uint4*)(sQh  + d) = *(const uint4*)(g_qh + gq);
        *(uint4*)(sQl  + d) = *(const uint4*)(g_ql + gq);
        *(uint4*)(sPih + d) = *(const uint4*)(g_xh + gx);
        *(uint4*)(sPil + d) = *(const uint4*)(g_xl + gx);
    }

    float oacc[8][4] = {};
    float m_run[2] = {-INFINITY, -INFINITY}, l_run[2] = {0.f, 0.f};
    float ci_r[2], qi_r[2];
    __syncthreads();
    ci_r[0] = sCi[16 * w + g];     qi_r[0] = sQi[16 * w + g];
    ci_r[1] = sCi[16 * w + g + 8]; qi_r[1] = sQi[16 * w + g + 8];

    for (int jt = 0; jt < 16; jt++) {
        int j0 = jt * 64;
        __syncthreads();   // prior PV done reading j-buffers
#pragma unroll
        for (int q = 0; q < 4; q++) {
            int v = t * 4 + q;
            int row = v >> 3, seg = v & 7;
            int d = row * PT + seg * 8;
            size_t gk = qoff + (size_t)(j0 + row) * dc + seg * 8;
            size_t gx = xoff + (size_t)(j0 + row) * Dc + seg * 8;
            size_t gv = ((size_t)bh * dc + row) * Lc + j0 + seg * 8;
            *(uint4*)(sKh  + d) = *(const uint4*)(g_kh  + gk);
            *(uint4*)(sKl  + d) = *(const uint4*)(g_kl  + gk);
            *(uint4*)(sPjh + d) = *(const uint4*)(g_xh  + gx);
            *(uint4*)(sPjl + d) = *(const uint4*)(g_xl  + gx);
            *(uint4*)(sVh  + d) = *(const uint4*)(g_vth + gv);
            *(uint4*)(sVl  + d) = *(const uint4*)(g_vtl + gv);
        }
        if (t < 64) {
            sCj[t] = g_coords[b * Lc + j0 + t];
            sQj[t] = g_qsca [b * Lc + j0 + t];
        }
        __syncthreads();

        // ---- QK^T and PP^T via mma ----
        float cS[8][4] = {}, cP[8][4] = {};
#pragma unroll
        for (int ks = 0; ks < 64; ks += 16) {
            int ra = (16 * w + g) * PT + ks + t2;
            uint32_t qh0 = *(const uint32_t*)(sQh + ra);
            uint32_t qh1 = *(const uint32_t*)(sQh + ra + 8 * PT);
            uint32_t qh2 = *(const uint32_t*)(sQh + ra + 8);
            uint32_t qh3 = *(const uint32_t*)(sQh + ra + 8 * PT + 8);
            uint32_t ql0 = *(const uint32_t*)(sQl + ra);
            uint32_t ql1 = *(const uint32_t*)(sQl + ra + 8 * PT);
            uint32_t ql2 = *(const uint32_t*)(sQl + ra + 8);
            uint32_t ql3 = *(const uint32_t*)(sQl + ra + 8 * PT + 8);
            uint32_t ph0 = *(const uint32_t*)(sPih + ra);
            uint32_t ph1 = *(const uint32_t*)(sPih + ra + 8 * PT);
            uint32_t ph2 = *(const uint32_t*)(sPih + ra + 8);
            uint32_t ph3 = *(const uint32_t*)(sPih + ra + 8 * PT + 8);
            uint32_t pl0 = *(const uint32_t*)(sPil + ra);
            uint32_t pl1 = *(const uint32_t*)(sPil + ra + 8 * PT);
            uint32_t pl2 = *(const uint32_t*)(sPil + ra + 8);
            uint32_t pl3 = *(const uint32_t*)(sPil + ra + 8 * PT + 8);
#pragma unroll
            for (int ni = 0; ni < 8; ni++) {
                int rb = (ni * 8 + g) * PT + ks + t2;
                uint32_t kh0 = *(const uint32_t*)(sKh + rb);
                uint32_t kh1 = *(const uint32_t*)(sKh + rb + 8);
                uint32_t kl0 = *(const uint32_t*)(sKl + rb);
                uint32_t kl1 = *(const uint32_t*)(sKl + rb + 8);
                uint32_t jh0 = *(const uint32_t*)(sPjh + rb);
                uint32_t jh1 = *(const uint32_t*)(sPjh + rb + 8);
                uint32_t jl0 = *(const uint32_t*)(sPjl + rb);
                uint32_t jl1 = *(const uint32_t*)(sPjl + rb + 8);
                hmma(cS[ni], qh0, qh1, qh2, qh3, kh0, kh1);
                hmma(cS[ni], qh0, qh1, qh2, qh3, kl0, kl1);
                hmma(cS[ni], ql0, ql1, ql2, ql3, kh0, kh1);
                hmma(cP[ni], ph0, ph1, ph2, ph3, jh0, jh1);
                hmma(cP[ni], ph0, ph1, ph2, ph3, jl0, jl1);
                hmma(cP[ni], pl0, pl1, pl2, pl3, jh0, jh1);
            }
        }

        // ---- bias + online softmax in fragment layout ----
        float m_new[2], scale[2];
#pragma unroll
        for (int rh = 0; rh < 2; rh++) {
            float ci = ci_r[rh], qi = qi_r[rh];
            float rmax = -INFINITY;
#pragma unroll
            for (int ni = 0; ni < 8; ni++)
#pragma unroll
                for (int cc = 0; cc < 2; cc++) {
                    int col = ni * 8 + t2 + cc;
                    float cj = sCj[col], qj = sQj[col];
                    float delta = fabsf(ci - cj);
                    int   di = (int)delta;
                    float tt = delta - (float)di;
                    int d0 = min(di,     Lc - 1);
                    int d1 = min(di + 1, Lc - 1);
                    float r = sR[d0] * (1.f - tt) + sR[d1] * tt;
                    float S = a_h * (qi + qj) + b_h * r + c_h;
                    float v = cS[ni][rh * 2 + cc] * 0.125f + S * cP[ni][rh * 2 + cc];
                    cS[ni][rh * 2 + cc] = v;
                    rmax = fmaxf(rmax, v);
                }
            rmax = fmaxf(rmax, __shfl_xor_sync(0xffffffffu, rmax, 1));
            rmax = fmaxf(rmax, __shfl_xor_sync(0xffffffffu, rmax, 2));
            float mn = fmaxf(m_run[rh], rmax);
            float rsum = 0.f;
#pragma unroll
            for (int ni = 0; ni < 8; ni++)
#pragma unroll
                for (int cc = 0; cc < 2; cc++) {
                    float e = fexp(cS[ni][rh * 2 + cc] - mn);
                    cS[ni][rh * 2 + cc] = e;
                    rsum += e;
                }
            rsum += __shfl_xor_sync(0xffffffffu, rsum, 1);
            rsum += __shfl_xor_sync(0xffffffffu, rsum, 2);
            scale[rh] = fexp(m_run[rh] - mn);
            l_run[rh] = l_run[rh] * scale[rh] + rsum;
            m_run[rh] = mn;
            m_new[rh] = mn;
        }
#pragma unroll
        for (int ni = 0; ni < 8; ni++) {
            oacc[ni][0] *= scale[0]; oacc[ni][1] *= scale[0];
            oacc[ni][2] *= scale[1]; oacc[ni][3] *= scale[1];
        }

        // ---- PV: P fragments (C->A identity), bf16x3 ----
#pragma unroll
        for (int kc = 0; kc < 4; kc++) {
            float v00 = cS[2*kc][0],   v01 = cS[2*kc][1];
            float v10 = cS[2*kc][2],   v11 = cS[2*kc][3];
            float v20 = cS[2*kc+1][0], v21 = cS[2*kc+1][1];
            float v30 = cS[2*kc+1][2], v31 = cS[2*kc+1][3];
            float h00 = bf_hi(v00), h01 = bf_hi(v01), h10 = bf_hi(v10), h11 = bf_hi(v11);
            float h20 = bf_hi(v20), h21 = bf_hi(v21), h30 = bf_hi(v30), h31 = bf_hi(v31);
            uint32_t aph0 = pack_bf16(h00, h01), aph1 = pack_bf16(h10, h11);
            uint32_t aph2 = pack_bf16(h20, h21), aph3 = pack_bf16(h30, h31);
            uint32_t apl0 = pack_bf16(v00 - h00, v01 - h01), apl1 = pack_bf16(v10 - h10, v11 - h11);
            uint32_t apl2 = pack_bf16(v20 - h20, v21 - h21), apl3 = pack_bf16(v30 - h30, v31 - h31);
#pragma unroll
            for (int ni = 0; ni < 8; ni++) {
                int rb = (ni * 8 + g) * PT + kc * 16 + t2;
                uint32_t vh0 = *(const uint32_t*)(sVh + rb);
                uint32_t vh1 = *(const uint32_t*)(sVh + rb + 8);
                uint32_t vl0 = *(const uint32_t*)(sVl + rb);
                uint32_t vl1 = *(const uint32_t*)(sVl + rb + 8);
                hmma(oacc[ni], aph0, aph1, aph2, aph3, vh0, vh1);
                hmma(oacc[ni], apl0, apl1, apl2, apl3, vh0, vh1);
                hmma(oacc[ni], aph0, aph1, aph2, aph3, vl0, vl1);
            }
        }
    }

    // ---- epilogue: normalize, split to bf16 hi/lo, write (b,l,D) ----
    float inv0 = 1.f / l_run[0], inv1 = 1.f / l_run[1];
#pragma unroll
    for (int rh = 0; rh < 2; rh++) {
        int row = i0 + 16 * w + g + rh * 8;
        float inv = rh ? inv1 : inv0;
        size_t base = ((size_t)(b * Lc) + row) * Dc + h * dc;
#pragma unroll
        for (int ni = 0; ni < 8; ni++) {
            float v0 = oacc[ni][rh * 2]     * inv;
            float v1 = oacc[ni][rh * 2 + 1] * inv;
            float h0 = bf_hi(v0), h1 = bf_hi(v1);
            size_t idx = base + ni * 8 + t2;
            *(uint32_t*)(g_oh + idx) = pack_bf16(h0, h1);
            *(uint32_t*)(g_ol + idx) = pack_bf16(v0 - h0, v1 - h1);
        }
    }
}

// ---------------- launch ----------------
extern "C" void kernel_launch(void* const* d_in, const int* in_sizes, int n_in,
                              void* d_out, int out_size) {
    const float* x     = (const float*)d_in[0];
    const float* t_enc = (const float*)d_in[1];
    const float* WQ    = (const float*)d_in[2];
    const float* WK    = (const float*)d_in[3];
    const float* WV    = (const float*)d_in[4];
    const float* WO    = (const float*)d_in[5];
    const float* bO    = (const float*)d_in[6];
    const float* Wt    = (const float*)d_in[7];
    const float* bt    = (const float*)d_in[8];
    const float* p_mat = (const float*)d_in[9];
    const float* r_mat = (const float*)d_in[10];
    const float* alpha = (const float*)d_in[11];
    const float* beta  = (const float*)d_in[12];
    const float* gamma = (const float*)d_in[13];
    float* out = (float*)d_out;

    cudaFuncSetAttribute(attn_mma, cudaFuncAttributeMaxDynamicSharedMemorySize,
                         ATTN_SMEM_BYTES);

    __nv_bfloat16 *xh, *xl;
    cudaGetSymbolAddress((void**)&xh, g_xh);
    cudaGetSymbolAddress((void**)&xl, g_xl);

    colsum_kernel<<<dim3(Lc / 256, 2), 256>>>(p_mat, r_mat);
    coords_kernel<<<(Bc * Lc) / 128, 128>>>(t_enc, Wt, bt);
    split_kernel<<<(Bc * Lc * Dc) / (256 * 4), 256>>>(x, xh, xl);
    split_w_kernel<<<dim3((Dc * Dc) / (256 * 4), 4), 256>>>(WQ, WK, WV, WO);
    qkv_mma<<<dim3(Dc / 128, (Bc * Lc) / 128, 3), 512>>>();
    attn_mma<<<dim3(Lc / 64, Bc * Hc), 128, ATTN_SMEM_BYTES>>>(alpha, beta, gamma);
    out_mma<<<dim3(Dc / 128, (Bc * Lc) / 128), 512>>>(bO, out);
}

// round 7
// speedup vs baseline: 1.9132x; 1.0874x over previous
#include <cuda_runtime.h>
#include <cuda_bf16.h>
#include <math.h>
#include <stdint.h>

#define Bc 4
#define Lc 1024
#define Dc 1024
#define Hc 16
#define Tc 64
#define dc 64
#define BHLD (Bc*Hc*Lc*dc)   /* 4,194,304 */

// ---------------- scratch ----------------
__device__ float g_coords[Bc * Lc];
__device__ float g_qsca[Bc * Lc];
__device__ float g_psum[Lc];
__device__ float g_rsum[Lc];
__device__ __nv_bfloat16 g_xh[Bc*Lc*Dc], g_xl[Bc*Lc*Dc];     // x
__device__ __nv_bfloat16 g_wh[4*Dc*Dc],  g_wl[4*Dc*Dc];      // WQ|WK|WV|WO
__device__ __nv_bfloat16 g_qh[BHLD], g_ql[BHLD];             // Q (b,h,l,d)
__device__ __nv_bfloat16 g_kh[BHLD], g_kl[BHLD];             // K (b,h,l,d)
__device__ __nv_bfloat16 g_vh[BHLD], g_vl[BHLD];             // V (b,h,l,d) coalesced
__device__ __nv_bfloat16 g_vth[BHLD], g_vtl[BHLD];           // V^T (b,h,d,l)
__device__ __nv_bfloat16 g_oh[Bc*Lc*Dc], g_ol[Bc*Lc*Dc];     // attn out (b,l,D)

// ---------------- fast exp (FFMA pipe) ----------------
__device__ __forceinline__ float fexp(float x) {
    float t = fmaxf(x * 1.4426950408889634f, -126.0f);
    float n = floorf(t);
    float f = t - n;
    float p =              1.5403530393381609e-4f;
    p = fmaf(p, f, 1.3333558146428443e-3f);
    p = fmaf(p, f, 9.6181291076284772e-3f);
    p = fmaf(p, f, 5.5504108664821580e-2f);
    p = fmaf(p, f, 2.4022650695910072e-1f);
    p = fmaf(p, f, 6.9314718055994531e-1f);
    p = fmaf(p, f, 1.0f);
    float s = __int_as_float(((int)n + 127) << 23);
    return p * s;
}

__device__ __forceinline__ uint32_t pack_bf16(float lo, float hi) {
    __nv_bfloat162 r = __floats2bfloat162_rn(lo, hi);
    return *(uint32_t*)&r;
}
__device__ __forceinline__ float bf_hi(float v) {
    return __bfloat162float(__float2bfloat16(v));
}
__device__ __forceinline__ uint32_t smem_u32(const void* p) {
    uint32_t a;
    asm("{ .reg .u64 t; cvta.to.shared.u64 t, %1; cvt.u32.u64 %0, t; }" : "=r"(a) : "l"(p));
    return a;
}
__device__ __forceinline__ void cp16(uint32_t dst, const void* src) {
    asm volatile("cp.async.cg.shared.global [%0], [%1], 16;" :: "r"(dst), "l"(src));
}
#define CP_COMMIT() asm volatile("cp.async.commit_group;" ::: "memory")
#define CP_WAIT0()  asm volatile("cp.async.wait_group 0;"  ::: "memory")

// ---------------- kernel 0: column sums ----------------
__global__ void colsum_kernel(const float* __restrict__ p_mat,
                              const float* __restrict__ r_mat) {
    int l = blockIdx.x * blockDim.x + threadIdx.x;
    if (l >= Lc) return;
    const float* src = blockIdx.y ? r_mat : p_mat;
    float s = 0.f;
#pragma unroll 8
    for (int dd = 0; dd < Dc; dd++) s += src[dd * Lc + l];
    if (blockIdx.y) g_rsum[l] = s; else g_psum[l] = s;
}

// ---------------- kernel 1: coords + cubic q_sca ----------------
__global__ void coords_kernel(const float* __restrict__ t_enc,
                              const float* __restrict__ Wt,
                              const float* __restrict__ bt) {
    int n = blockIdx.x * blockDim.x + threadIdx.x;
    if (n >= Bc * Lc) return;
    float z = bt[0];
    const float* te = t_enc + (size_t)n * Tc;
#pragma unroll
    for (int k = 0; k < Tc; k++) z += te[k] * Wt[k];
    float tau = 1.f / (1.f + expf(-z));
    float c = tau * (float)(Lc - 1);
    g_coords[n] = c;
    int i = (int)floorf(c);
    float t = c - (float)i;
    int im1 = min(max(i - 1, 0), Lc - 1);
    int ii0 = min(max(i,     0), Lc - 1);
    int ii1 = min(max(i + 1, 0), Lc - 1);
    int ii2 = min(max(i + 2, 0), Lc - 1);
    float p0 = g_psum[im1], p1 = g_psum[ii0], p2 = g_psum[ii1], p3 = g_psum[ii2];
    float t2 = t * t, t3 = t2 * t;
    g_qsca[n] = 0.5f * (2.f * p1 + (-p0 + p2) * t
              + (2.f * p0 - 5.f * p1 + 4.f * p2 - p3) * t2
              + (-p0 + 3.f * p1 - 3.f * p2 + p3) * t3);
}

// ---------------- split fp32 -> bf16 hi + lo ----------------
__device__ __forceinline__ void split1(float v, __nv_bfloat16* h, __nv_bfloat16* l) {
    __nv_bfloat16 hh = __float2bfloat16(v);
    *h = hh;
    *l = __float2bfloat16(v - __bfloat162float(hh));
}
__global__ void split_kernel(const float* __restrict__ s,
                             __nv_bfloat16* __restrict__ h,
                             __nv_bfloat16* __restrict__ l) {
    int i = (blockIdx.x * blockDim.x + threadIdx.x) * 4;
    float4 v = *(const float4*)(s + i);
    split1(v.x, h + i + 0, l + i + 0);
    split1(v.y, h + i + 1, l + i + 1);
    split1(v.z, h + i + 2, l + i + 2);
    split1(v.w, h + i + 3, l + i + 3);
}
__global__ void split_w_kernel(const float* __restrict__ WQ, const float* __restrict__ WK,
                               const float* __restrict__ WV, const float* __restrict__ WO) {
    const float* src = (blockIdx.y == 0) ? WQ : (blockIdx.y == 1) ? WK
                     : (blockIdx.y == 2) ? WV : WO;
    size_t off = (size_t)blockIdx.y << 20;
    int i = (blockIdx.x * blockDim.x + threadIdx.x) * 4;
    float4 v = *(const float4*)(src + i);
    split1(v.x, g_wh + off + i + 0, g_wl + off + i + 0);
    split1(v.y, g_wh + off + i + 1, g_wl + off + i + 1);
    split1(v.z, g_wh + off + i + 2, g_wl + off + i + 2);
    split1(v.w, g_wh + off + i + 3, g_wl + off + i + 3);
}

// ================= mma.sync bf16x3 GEMM core (double-buffered) =================
#define KP 40
#define SB (128 * KP)            // elems per buffer
#define STG (4 * SB)             // elems per stage (Ah,Al,Bh,Bl)
#define GEMM_SMEM_BYTES (2 * STG * 2)

__device__ __forceinline__ void hmma(float c[4], uint32_t a0, uint32_t a1, uint32_t a2,
                                     uint32_t a3, uint32_t b0, uint32_t b1) {
    asm volatile(
        "mma.sync.aligned.m16n8k16.row.col.f32.bf16.bf16.f32 "
        "{%0,%1,%2,%3}, {%4,%5,%6,%7}, {%8,%9}, {%0,%1,%2,%3};"
        : "+f"(c[0]), "+f"(c[1]), "+f"(c[2]), "+f"(c[3])
        : "r"(a0), "r"(a1), "r"(a2), "r"(a3), "r"(b0), "r"(b1));
}

struct GPf { uint4 ah, al, bh, bl; };

__device__ __forceinline__ void mma_gload(const __nv_bfloat16* Ah, const __nv_bfloat16* Al,
                                          const __nv_bfloat16* Bh, const __nv_bfloat16* Bl,
                                          int k0, GPf& f) {
    int v = threadIdx.x;
    int row = v >> 2, seg = v & 3;
    size_t gs = (size_t)row * Dc + k0 + seg * 8;
    f.ah = *(const uint4*)(Ah + gs);
    f.al = *(const uint4*)(Al + gs);
    f.bh = *(const uint4*)(Bh + gs);
    f.bl = *(const uint4*)(Bl + gs);
}
__device__ __forceinline__ void mma_sstore(__nv_bfloat16* S, const GPf& f) {
    int v = threadIdx.x;
    int row = v >> 2, seg = v & 3;
    int si = row * KP + seg * 8;
    *(uint4*)(S + si)          = f.ah;
    *(uint4*)(S + SB + si)     = f.al;
    *(uint4*)(S + 2 * SB + si) = f.bh;
    *(uint4*)(S + 3 * SB + si) = f.bl;
}

__device__ __forceinline__ void mma_core(const __nv_bfloat16* Ah, const __nv_bfloat16* Al,
                                         const __nv_bfloat16* Bh, const __nv_bfloat16* Bl,
                                         __nv_bfloat16* S, float c[2][4][4]) {
    int lane = threadIdx.x & 31, w = threadIdx.x >> 5;
    int wm = w >> 2, wn = w & 3;
    int g = lane >> 2, t2 = (lane & 3) * 2;
    GPf f;
    mma_gload(Ah, Al, Bh, Bl, 0, f);
    mma_sstore(S, f);
    mma_gload(Ah, Al, Bh, Bl, 32, f);
    __syncthreads();
    const int NCH = Dc / 32;
    for (int ch = 0; ch < NCH; ch++) {
        __nv_bfloat16* st = S + (ch & 1) * STG;
        const __nv_bfloat16* sAh = st;
        const __nv_bfloat16* sAl = st + SB;
        const __nv_bfloat16* sBh = st + 2 * SB;
        const __nv_bfloat16* sBl = st + 3 * SB;
        if (ch + 1 < NCH) mma_sstore(S + ((ch + 1) & 1) * STG, f);
        if (ch + 2 < NCH) mma_gload(Ah, Al, Bh, Bl, (ch + 2) * 32, f);
#pragma unroll
        for (int ks = 0; ks < 32; ks += 16) {
            uint32_t ah[2][4], al[2][4];
#pragma unroll
            for (int mi = 0; mi < 2; mi++) {
                int r0 = (wm * 32 + mi * 16 + g) * KP + ks + t2;
                int r8 = r0 + 8 * KP;
                ah[mi][0] = *(const uint32_t*)(sAh + r0);
                ah[mi][1] = *(const uint32_t*)(sAh + r8);
                ah[mi][2] = *(const uint32_t*)(sAh + r0 + 8);
                ah[mi][3] = *(const uint32_t*)(sAh + r8 + 8);
                al[mi][0] = *(const uint32_t*)(sAl + r0);
                al[mi][1] = *(const uint32_t*)(sAl + r8);
                al[mi][2] = *(const uint32_t*)(sAl + r0 + 8);
                al[mi][3] = *(const uint32_t*)(sAl + r8 + 8);
            }
            uint32_t bh[4][2], bl[4][2];
#pragma unroll
            for (int ni = 0; ni < 4; ni++) {
                int c0 = (wn * 32 + ni * 8 + g) * KP + ks + t2;
                bh[ni][0] = *(const uint32_t*)(sBh + c0);
                bh[ni][1] = *(const uint32_t*)(sBh + c0 + 8);
                bl[ni][0] = *(const uint32_t*)(sBl + c0);
                bl[ni][1] = *(const uint32_t*)(sBl + c0 + 8);
            }
#pragma unroll
            for (int mi = 0; mi < 2; mi++)
#pragma unroll
                for (int ni = 0; ni < 4; ni++) {
                    hmma(c[mi][ni], ah[mi][0], ah[mi][1], ah[mi][2], ah[mi][3],
                         bh[ni][0], bh[ni][1]);
                    hmma(c[mi][ni], ah[mi][0], ah[mi][1], ah[mi][2], ah[mi][3],
                         bl[ni][0], bl[ni][1]);
                    hmma(c[mi][ni], al[mi][0], al[mi][1], al[mi][2], al[mi][3],
                         bh[ni][0], bh[ni][1]);
                }
        }
        __syncthreads();
    }
}

// ---------------- kernel 2: QKV projection -> bf16 Q,K,V (b,h,l,d) ----------------
__global__ void __launch_bounds__(512, 2) qkv_mma() {
    extern __shared__ __nv_bfloat16 Sdyn[];
    int z = blockIdx.z;
    int M0 = blockIdx.y * 128, N0 = blockIdx.x * 128;
    const __nv_bfloat16* Ah = g_xh + (size_t)M0 * Dc;
    const __nv_bfloat16* Al = g_xl + (size_t)M0 * Dc;
    const __nv_bfloat16* Bh = g_wh + ((size_t)z << 20) + (size_t)N0 * Dc;
    const __nv_bfloat16* Bl = g_wl + ((size_t)z << 20) + (size_t)N0 * Dc;
    float c[2][4][4] = {};
    mma_core(Ah, Al, Bh, Bl, Sdyn, c);

    int lane = threadIdx.x & 31, w = threadIdx.x >> 5;
    int wm = w >> 2, wn = w & 3;
    int g = lane >> 2, t2 = (lane & 3) * 2;
    __nv_bfloat16* dh = (z == 0) ? g_qh : (z == 1) ? g_kh : g_vh;
    __nv_bfloat16* dl = (z == 0) ? g_ql : (z == 1) ? g_kl : g_vl;
#pragma unroll
    for (int mi = 0; mi < 2; mi++)
#pragma unroll
        for (int ni = 0; ni < 4; ni++) {
            int col = N0 + wn * 32 + ni * 8 + t2;
            int h = col >> 6, dd = col & 63;
#pragma unroll
            for (int rh = 0; rh < 2; rh++) {
                int row = M0 + wm * 32 + mi * 16 + g + rh * 8;
                int b = row >> 10, l = row & (Lc - 1);
                float v0 = c[mi][ni][rh * 2], v1 = c[mi][ni][rh * 2 + 1];
                float h0 = bf_hi(v0), h1 = bf_hi(v1);
                size_t idx = (((size_t)(b * Hc + h)) * Lc + l) * dc + dd;
                *(uint32_t*)(dh + idx) = pack_bf16(h0, h1);
                *(uint32_t*)(dl + idx) = pack_bf16(v0 - h0, v1 - h1);
            }
        }
}

// ---------------- V transpose: (b,h,l,d) -> (b,h,d,l) ----------------
__global__ void __launch_bounds__(256) vtrans_kernel() {
    __shared__ uint16_t sH[64 * 72], sL[64 * 72];
    int t = threadIdx.x;
    int bh = blockIdx.y;
    int l0 = blockIdx.x * 64;
    size_t src = ((size_t)bh * Lc + l0) * dc;
#pragma unroll
    for (int q = 0; q < 2; q++) {
        int v = t * 2 + q;
        int row = v >> 3, seg = v & 7;
        uint4 hv = *(const uint4*)(g_vh + src + (size_t)row * dc + seg * 8);
        uint4 lv = *(const uint4*)(g_vl + src + (size_t)row * dc + seg * 8);
        const uint16_t* hp = (const uint16_t*)&hv;
        const uint16_t* lp = (const uint16_t*)&lv;
#pragma unroll
        for (int e = 0; e < 8; e++) {
            sH[(seg * 8 + e) * 72 + row] = hp[e];
            sL[(seg * 8 + e) * 72 + row] = lp[e];
        }
    }
    __syncthreads();
    size_t dst = (size_t)bh * dc * Lc;
#pragma unroll
    for (int q = 0; q < 2; q++) {
        int v = t * 2 + q;
        int d = v >> 3, seg = v & 7;
        *(uint4*)(g_vth + dst + (size_t)d * Lc + l0 + seg * 8) = *(const uint4*)(sH + d * 72 + seg * 8);
        *(uint4*)(g_vtl + dst + (size_t)d * Lc + l0 + seg * 8) = *(const uint4*)(sL + d * 72 + seg * 8);
    }
}

// ---------------- kernel 4: output projection + bias ----------------
__global__ void __launch_bounds__(512, 2) out_mma(const float* __restrict__ bO,
                                                  float* __restrict__ out) {
    extern __shared__ __nv_bfloat16 Sdyn[];
    int M0 = blockIdx.y * 128, N0 = blockIdx.x * 128;
    const __nv_bfloat16* Ah = g_oh + (size_t)M0 * Dc;
    const __nv_bfloat16* Al = g_ol + (size_t)M0 * Dc;
    const __nv_bfloat16* Bh = g_wh + ((size_t)3 << 20) + (size_t)N0 * Dc;
    const __nv_bfloat16* Bl = g_wl + ((size_t)3 << 20) + (size_t)N0 * Dc;
    float c[2][4][4] = {};
    mma_core(Ah, Al, Bh, Bl, Sdyn, c);

    int lane = threadIdx.x & 31, w = threadIdx.x >> 5;
    int wm = w >> 2, wn = w & 3;
    int g = lane >> 2, t2 = (lane & 3) * 2;
#pragma unroll
    for (int mi = 0; mi < 2; mi++)
#pragma unroll
        for (int ni = 0; ni < 4; ni++) {
            int col = N0 + wn * 32 + ni * 8 + t2;
            float2 bv = *(const float2*)(bO + col);
#pragma unroll
            for (int rh = 0; rh < 2; rh++) {
                int row = M0 + wm * 32 + mi * 16 + g + rh * 8;
                float2 v = make_float2(c[mi][ni][rh * 2] + bv.x,
                                       c[mi][ni][rh * 2 + 1] + bv.y);
                *(float2*)(out + (size_t)row * Dc + col) = v;
            }
        }
}

// ---------------- kernel 3: flash attention (128-row i-tile, cp.async j pipeline) ----------------
#define PT 80
#define IB (128 * PT)            // i-buffer elems
#define JBe (64 * PT)            // j-buffer elems
#define JBB (JBe * 2)            // j-buffer bytes
#define JSTG (6 * JBe)           // j-stage elems
#define ATTN_SMEM_BYTES ((4 * IB + 2 * JSTG) * 2 + (Lc + 128 + 128 + 2 * 64 + 2 * 64) * 4)

__global__ void __launch_bounds__(256, 1) attn_mma(const float* __restrict__ alpha,
                                                   const float* __restrict__ beta,
                                                   const float* __restrict__ gamma) {
    extern __shared__ __nv_bfloat16 smb[];
    __nv_bfloat16* sQh  = smb;
    __nv_bfloat16* sQl  = sQh + IB;
    __nv_bfloat16* sPih = sQl + IB;
    __nv_bfloat16* sPil = sPih + IB;
    __nv_bfloat16* jbase = sPil + IB;           // 2 stages x (Kh,Kl,Pjh,Pjl,Vh,Vl)
    float* sR  = (float*)(jbase + 2 * JSTG);
    float* sCi = sR  + Lc;
    float* sQi = sCi + 128;
    float* sCj = sQi + 128;                     // [2][64]
    float* sQj = sCj + 2 * 64;                  // [2][64]

    uint32_t jb32 = smem_u32(jbase);

    int t = threadIdx.x;
    int w = t >> 5, lane = t & 31;
    int g = lane >> 2, t2 = (lane & 3) * 2;
    int bh = blockIdx.y;
    int b = bh >> 4, h = bh & 15;
    int i0 = blockIdx.x * 128;

    float a_h = alpha[h], b_h = beta[h], c_h = gamma[h];

    const size_t qoff = ((size_t)bh * Lc) * dc;
    const size_t xoff = ((size_t)b * Lc) * Dc + h * dc;
    const size_t voff = (size_t)bh * dc * Lc;

    for (int idx = t; idx < Lc; idx += 256) sR[idx] = g_rsum[idx];
    if (t < 128) {
        sCi[t] = g_coords[b * Lc + i0 + t];
        sQi[t] = g_qsca [b * Lc + i0 + t];
    }
    if (t < 64) {
        sCj[t] = g_coords[b * Lc + t];   // jt = 0
        sQj[t] = g_qsca [b * Lc + t];
    }
    // i-tile loads (regular)
#pragma unroll
    for (int q = 0; q < 4; q++) {
        int v = t * 4 + q;
        int row = v >> 3, seg = v & 7;
        int d = row * PT + seg * 8;
        size_t gq = qoff + (size_t)(i0 + row) * dc + seg * 8;
        size_t gx = xoff + (size_t)(i0 + row) * Dc + seg * 8;
        *(uint4*)(sQh  + d) = *(const uint4*)(g_qh + gq);
        *(uint4*)(sQl  + d) = *(const uint4*)(g_ql + gq);
        *(uint4*)(sPih + d) = *(const uint4*)(g_xh + gx);
        *(uint4*)(sPil + d) = *(const uint4*)(g_xl + gx);
    }
    // j-tile 0 via cp.async into stage 0
#pragma unroll
    for (int q = 0; q < 2; q++) {
        int v = t * 2 + q;
        int row = v >> 3, seg = v & 7;
        uint32_t boff = (uint32_t)((row * PT + seg * 8) * 2);
        size_t gk = qoff + (size_t)row * dc + seg * 8;
        size_t gx = xoff + (size_t)row * Dc + seg * 8;
        size_t gv = voff + (size_t)row * Lc + seg * 8;
        cp16(jb32 + 0 * JBB + boff, g_kh  + gk);
        cp16(jb32 + 1 * JBB + boff, g_kl  + gk);
        cp16(jb32 + 2 * JBB + boff, g_xh  + gx);
        cp16(jb32 + 3 * JBB + boff, g_xl  + gx);
        cp16(jb32 + 4 * JBB + boff, g_vth + gv);
        cp16(jb32 + 5 * JBB + boff, g_vtl + gv);
    }
    CP_COMMIT();
    __syncthreads();

    float ci_r[2], qi_r[2];
    ci_r[0] = sCi[16 * w + g];     qi_r[0] = sQi[16 * w + g];
    ci_r[1] = sCi[16 * w + g + 8]; qi_r[1] = sQi[16 * w + g + 8];

    float oacc[8][4] = {};
    float m_run[2] = {-INFINITY, -INFINITY}, l_run[2] = {0.f, 0.f};

    for (int jt = 0; jt < 16; jt++) {
        int cur = jt & 1;
        CP_WAIT0();
        __syncthreads();
        if (jt < 15) {
            int j1 = (jt + 1) * 64;
            uint32_t st32 = jb32 + (cur ^ 1) * (JSTG * 2);
#pragma unroll
            for (int q = 0; q < 2; q++) {
                int v = t * 2 + q;
                int row = v >> 3, seg = v & 7;
                uint32_t boff = (uint32_t)((row * PT + seg * 8) * 2);
                size_t gk = qoff + (size_t)(j1 + row) * dc + seg * 8;
                size_t gx = xoff + (size_t)(j1 + row) * Dc + seg * 8;
                size_t gv = voff + (size_t)row * Lc + j1 + seg * 8;
                cp16(st32 + 0 * JBB + boff, g_kh  + gk);
                cp16(st32 + 1 * JBB + boff, g_kl  + gk);
                cp16(st32 + 2 * JBB + boff, g_xh  + gx);
                cp16(st32 + 3 * JBB + boff, g_xl  + gx);
                cp16(st32 + 4 * JBB + boff, g_vth + gv);
                cp16(st32 + 5 * JBB + boff, g_vtl + gv);
            }
            CP_COMMIT();
            if (t < 64) {
                sCj[(cur ^ 1) * 64 + t] = g_coords[b * Lc + j1 + t];
                sQj[(cur ^ 1) * 64 + t] = g_qsca [b * Lc + j1 + t];
            }
        }
        __nv_bfloat16* js = jbase + cur * JSTG;
        const __nv_bfloat16* sKh  = js;
        const __nv_bfloat16* sKl  = js + JBe;
        const __nv_bfloat16* sPjh = js + 2 * JBe;
        const __nv_bfloat16* sPjl = js + 3 * JBe;
        const __nv_bfloat16* sVh  = js + 4 * JBe;
        const __nv_bfloat16* sVl  = js + 5 * JBe;
        const float* cjp = sCj + cur * 64;
        const float* qjp = sQj + cur * 64;

        // ---- QK^T and PP^T via mma ----
        float cS[8][4] = {}, cP[8][4] = {};
#pragma unroll
        for (int ks = 0; ks < 64; ks += 16) {
            int ra = (16 * w + g) * PT + ks + t2;
            uint32_t qh0 = *(const uint32_t*)(sQh + ra);
            uint32_t qh1 = *(const uint32_t*)(sQh + ra + 8 * PT);
            uint32_t qh2 = *(const uint32_t*)(sQh + ra + 8);
            uint32_t qh3 = *(const uint32_t*)(sQh + ra + 8 * PT + 8);
            uint32_t ql0 = *(const uint32_t*)(sQl + ra);
            uint32_t ql1 = *(const uint32_t*)(sQl + ra + 8 * PT);
            uint32_t ql2 = *(const uint32_t*)(sQl + ra + 8);
            uint32_t ql3 = *(const uint32_t*)(sQl + ra + 8 * PT + 8);
            uint32_t ph0 = *(const uint32_t*)(sPih + ra);
            uint32_t ph1 = *(const uint32_t*)(sPih + ra + 8 * PT);
            uint32_t ph2 = *(const uint32_t*)(sPih + ra + 8);
            uint32_t ph3 = *(const uint32_t*)(sPih + ra + 8 * PT + 8);
            uint32_t pl0 = *(const uint32_t*)(sPil + ra);
            uint32_t pl1 = *(const uint32_t*)(sPil + ra + 8 * PT);
            uint32_t pl2 = *(const uint32_t*)(sPil + ra + 8);
            uint32_t pl3 = *(const uint32_t*)(sPil + ra + 8 * PT + 8);
#pragma unroll
            for (int ni = 0; ni < 8; ni++) {
                int rb = (ni * 8 + g) * PT + ks + t2;
                uint32_t kh0 = *(const uint32_t*)(sKh + rb);
                uint32_t kh1 = *(const uint32_t*)(sKh + rb + 8);
                uint32_t kl0 = *(const uint32_t*)(sKl + rb);
                uint32_t kl1 = *(const uint32_t*)(sKl + rb + 8);
                uint32_t jh0 = *(const uint32_t*)(sPjh + rb);
                uint32_t jh1 = *(const uint32_t*)(sPjh + rb + 8);
                uint32_t jl0 = *(const uint32_t*)(sPjl + rb);
                uint32_t jl1 = *(const uint32_t*)(sPjl + rb + 8);
                hmma(cS[ni], qh0, qh1, qh2, qh3, kh0, kh1);
                hmma(cS[ni], qh0, qh1, qh2, qh3, kl0, kl1);
                hmma(cS[ni], ql0, ql1, ql2, ql3, kh0, kh1);
                hmma(cP[ni], ph0, ph1, ph2, ph3, jh0, jh1);
                hmma(cP[ni], ph0, ph1, ph2, ph3, jl0, jl1);
                hmma(cP[ni], pl0, pl1, pl2, pl3, jh0, jh1);
            }
        }

        // ---- bias + online softmax in fragment layout ----
        float scale[2];
#pragma unroll
        for (int rh = 0; rh < 2; rh++) {
            float ci = ci_r[rh], qi = qi_r[rh];
            float rmax = -INFINITY;
#pragma unroll
            for (int ni = 0; ni < 8; ni++)
#pragma unroll
                for (int cc = 0; cc < 2; cc++) {
                    int col = ni * 8 + t2 + cc;
                    float cj = cjp[col], qj = qjp[col];
                    float delta = fabsf(ci - cj);
                    int   di = (int)delta;
                    float tt = delta - (float)di;
                    int d0 = min(di,     Lc - 1);
                    int d1 = min(di + 1, Lc - 1);
                    float r = sR[d0] * (1.f - tt) + sR[d1] * tt;
                    float S = a_h * (qi + qj) + b_h * r + c_h;
                    float v = cS[ni][rh * 2 + cc] * 0.125f + S * cP[ni][rh * 2 + cc];
                    cS[ni][rh * 2 + cc] = v;
                    rmax = fmaxf(rmax, v);
                }
            rmax = fmaxf(rmax, __shfl_xor_sync(0xffffffffu, rmax, 1));
            rmax = fmaxf(rmax, __shfl_xor_sync(0xffffffffu, rmax, 2));
            float mn = fmaxf(m_run[rh], rmax);
            float rsum = 0.f;
#pragma unroll
            for (int ni = 0; ni < 8; ni++)
#pragma unroll
                for (int cc = 0; cc < 2; cc++) {
                    float e = fexp(cS[ni][rh * 2 + cc] - mn);
                    cS[ni][rh * 2 + cc] = e;
                    rsum += e;
                }
            rsum += __shfl_xor_sync(0xffffffffu, rsum, 1);
            rsum += __shfl_xor_sync(0xffffffffu, rsum, 2);
            scale[rh] = fexp(m_run[rh] - mn);
            l_run[rh] = l_run[rh] * scale[rh] + rsum;
            m_run[rh] = mn;
        }
#pragma unroll
        for (int ni = 0; ni < 8; ni++) {
            oacc[ni][0] *= scale[0]; oacc[ni][1] *= scale[0];
            oacc[ni][2] *= scale[1]; oacc[ni][3] *= scale[1];
        }

        // ---- PV (C->A fragment identity), bf16x3 ----
#pragma unroll
        for (int kc = 0; kc < 4; kc++) {
            float v00 = cS[2*kc][0],   v01 = cS[2*kc][1];
            float v10 = cS[2*kc][2],   v11 = cS[2*kc][3];
            float v20 = cS[2*kc+1][0], v21 = cS[2*kc+1][1];
            float v30 = cS[2*kc+1][2], v31 = cS[2*kc+1][3];
            float h00 = bf_hi(v00), h01 = bf_hi(v01), h10 = bf_hi(v10), h11 = bf_hi(v11);
            float h20 = bf_hi(v20), h21 = bf_hi(v21), h30 = bf_hi(v30), h31 = bf_hi(v31);
            uint32_t aph0 = pack_bf16(h00, h01), aph1 = pack_bf16(h10, h11);
            uint32_t aph2 = pack_bf16(h20, h21), aph3 = pack_bf16(h30, h31);
            uint32_t apl0 = pack_bf16(v00 - h00, v01 - h01), apl1 = pack_bf16(v10 - h10, v11 - h11);
            uint32_t apl2 = pack_bf16(v20 - h20, v21 - h21), apl3 = pack_bf16(v30 - h30, v31 - h31);
#pragma unroll
            for (int ni = 0; ni < 8; ni++) {
                int rb = (ni * 8 + g) * PT + kc * 16 + t2;
                uint32_t vh0 = *(const uint32_t*)(sVh + rb);
                uint32_t vh1 = *(const uint32_t*)(sVh + rb + 8);
                uint32_t vl0 = *(const uint32_t*)(sVl + rb);
                uint32_t vl1 = *(const uint32_t*)(sVl + rb + 8);
                hmma(oacc[ni], aph0, aph1, aph2, aph3, vh0, vh1);
                hmma(oacc[ni], apl0, apl1, apl2, apl3, vh0, vh1);
                hmma(oacc[ni], aph0, aph1, aph2, aph3, vl0, vl1);
            }
        }
    }

    // ---- epilogue ----
    float inv0 = 1.f / l_run[0], inv1 = 1.f / l_run[1];
#pragma unroll
    for (int rh = 0; rh < 2; rh++) {
        int row = i0 + 16 * w + g + rh * 8;
        float inv = rh ? inv1 : inv0;
        size_t base = ((size_t)(b * Lc) + row) * Dc + h * dc;
#pragma unroll
        for (int ni = 0; ni < 8; ni++) {
            float v0 = oacc[ni][rh * 2]     * inv;
            float v1 = oacc[ni][rh * 2 + 1] * inv;
            float h0 = bf_hi(v0), h1 = bf_hi(v1);
            size_t idx = base + ni * 8 + t2;
            *(uint32_t*)(g_oh + idx) = pack_bf16(h0, h1);
            *(uint32_t*)(g_ol + idx) = pack_bf16(v0 - h0, v1 - h1);
        }
    }
}

// ---------------- launch ----------------
extern "C" void kernel_launch(void* const* d_in, const int* in_sizes, int n_in,
                              void* d_out, int out_size) {
    const float* x     = (const float*)d_in[0];
    const float* t_enc = (const float*)d_in[1];
    const float* WQ    = (const float*)d_in[2];
    const float* WK    = (const float*)d_in[3];
    const float* WV    = (const float*)d_in[4];
    const float* WO    = (const float*)d_in[5];
    const float* bO    = (const float*)d_in[6];
    const float* Wt    = (const float*)d_in[7];
    const float* bt    = (const float*)d_in[8];
    const float* p_mat = (const float*)d_in[9];
    const float* r_mat = (const float*)d_in[10];
    const float* alpha = (const float*)d_in[11];
    const float* beta  = (const float*)d_in[12];
    const float* gamma = (const float*)d_in[13];
    float* out = (float*)d_out;

    cudaFuncSetAttribute(attn_mma, cudaFuncAttributeMaxDynamicSharedMemorySize,
                         ATTN_SMEM_BYTES);
    cudaFuncSetAttribute(qkv_mma, cudaFuncAttributeMaxDynamicSharedMemorySize,
                         GEMM_SMEM_BYTES);
    cudaFuncSetAttribute(out_mma, cudaFuncAttributeMaxDynamicSharedMemorySize,
                         GEMM_SMEM_BYTES);

    __nv_bfloat16 *xh, *xl;
    cudaGetSymbolAddress((void**)&xh, g_xh);
    cudaGetSymbolAddress((void**)&xl, g_xl);

    colsum_kernel<<<dim3(Lc / 256, 2), 256>>>(p_mat, r_mat);
    coords_kernel<<<(Bc * Lc) / 128, 128>>>(t_enc, Wt, bt);
    split_kernel<<<(Bc * Lc * Dc) / (256 * 4), 256>>>(x, xh, xl);
    split_w_kernel<<<dim3((Dc * Dc) / (256 * 4), 4), 256>>>(WQ, WK, WV, WO);
    qkv_mma<<<dim3(Dc / 128, (Bc * Lc) / 128, 3), 512, GEMM_SMEM_BYTES>>>();
    vtrans_kernel<<<dim3(Lc / 64, Bc * Hc), 256>>>();
    attn_mma<<<dim3(Lc / 128, Bc * Hc), 256, ATTN_SMEM_BYTES>>>(alpha, beta, gamma);
    out_mma<<<dim3(Dc / 128, (Bc * Lc) / 128), 512, GEMM_SMEM_BYTES>>>(bO, out);
}

// round 8
// speedup vs baseline: 2.5026x; 1.3080x over previous
#include <cuda_runtime.h>
#include <cuda_bf16.h>
#include <math.h>
#include <stdint.h>

#define Bc 4
#define Lc 1024
#define Dc 1024
#define Hc 16
#define Tc 64
#define dc 64
#define BHLD (Bc*Hc*Lc*dc)   /* 4,194,304 */

// ---------------- scratch ----------------
__device__ float g_coords[Bc * Lc];
__device__ float g_qsca[Bc * Lc];
__device__ float g_psum[Lc];
__device__ float g_rsum[Lc];
__device__ __nv_bfloat16 g_xh[Bc*Lc*Dc], g_xl[Bc*Lc*Dc];     // x
__device__ __nv_bfloat16 g_wh[4*Dc*Dc],  g_wl[4*Dc*Dc];      // WQ|WK|WV|WO
__device__ __nv_bfloat16 g_qh[BHLD], g_ql[BHLD];             // Q (b,h,l,d)
__device__ __nv_bfloat16 g_kh[BHLD], g_kl[BHLD];             // K (b,h,l,d)
__device__ __nv_bfloat16 g_vth[BHLD], g_vtl[BHLD];           // V^T (b,h,d,l)
__device__ __nv_bfloat16 g_oh[Bc*Lc*Dc], g_ol[Bc*Lc*Dc];     // attn out (b,l,D)

__device__ __forceinline__ uint32_t pack_bf16(float lo, float hi) {
    __nv_bfloat162 r = __floats2bfloat162_rn(lo, hi);
    return *(uint32_t*)&r;
}
__device__ __forceinline__ float bf_hi(float v) {
    return __bfloat162float(__float2bfloat16(v));
}
__device__ __forceinline__ uint32_t smem_u32(const void* p) {
    uint32_t a;
    asm("{ .reg .u64 t; cvta.to.shared.u64 t, %1; cvt.u32.u64 %0, t; }" : "=r"(a) : "l"(p));
    return a;
}
__device__ __forceinline__ void cp16(uint32_t dst, const void* src) {
    asm volatile("cp.async.cg.shared.global [%0], [%1], 16;" :: "r"(dst), "l"(src));
}
#define CP_COMMIT() asm volatile("cp.async.commit_group;" ::: "memory")
#define CP_WAIT0()  asm volatile("cp.async.wait_group 0;"  ::: "memory")
#define CP_WAIT1()  asm volatile("cp.async.wait_group 1;"  ::: "memory")

// ---------------- kernel 0: column sums ----------------
__global__ void colsum_kernel(const float* __restrict__ p_mat,
                              const float* __restrict__ r_mat) {
    int l = blockIdx.x * blockDim.x + threadIdx.x;
    if (l >= Lc) return;
    const float* src = blockIdx.y ? r_mat : p_mat;
    float s = 0.f;
#pragma unroll 8
    for (int dd = 0; dd < Dc; dd++) s += src[dd * Lc + l];
    if (blockIdx.y) g_rsum[l] = s; else g_psum[l] = s;
}

// ---------------- kernel 1: coords + cubic q_sca ----------------
__global__ void coords_kernel(const float* __restrict__ t_enc,
                              const float* __restrict__ Wt,
                              const float* __restrict__ bt) {
    int n = blockIdx.x * blockDim.x + threadIdx.x;
    if (n >= Bc * Lc) return;
    float z = bt[0];
    const float* te = t_enc + (size_t)n * Tc;
#pragma unroll
    for (int k = 0; k < Tc; k++) z += te[k] * Wt[k];
    float tau = 1.f / (1.f + expf(-z));
    float c = tau * (float)(Lc - 1);
    g_coords[n] = c;
    int i = (int)floorf(c);
    float t = c - (float)i;
    int im1 = min(max(i - 1, 0), Lc - 1);
    int ii0 = min(max(i,     0), Lc - 1);
    int ii1 = min(max(i + 1, 0), Lc - 1);
    int ii2 = min(max(i + 2, 0), Lc - 1);
    float p0 = g_psum[im1], p1 = g_psum[ii0], p2 = g_psum[ii1], p3 = g_psum[ii2];
    float t2 = t * t, t3 = t2 * t;
    g_qsca[n] = 0.5f * (2.f * p1 + (-p0 + p2) * t
              + (2.f * p0 - 5.f * p1 + 4.f * p2 - p3) * t2
              + (-p0 + 3.f * p1 - 3.f * p2 + p3) * t3);
}

// ---------------- split fp32 -> bf16 hi + lo ----------------
__device__ __forceinline__ void split1(float v, __nv_bfloat16* h, __nv_bfloat16* l) {
    __nv_bfloat16 hh = __float2bfloat16(v);
    *h = hh;
    *l = __float2bfloat16(v - __bfloat162float(hh));
}
__global__ void split_kernel(const float* __restrict__ s,
                             __nv_bfloat16* __restrict__ h,
                             __nv_bfloat16* __restrict__ l) {
    int i = (blockIdx.x * blockDim.x + threadIdx.x) * 4;
    float4 v = *(const float4*)(s + i);
    split1(v.x, h + i + 0, l + i + 0);
    split1(v.y, h + i + 1, l + i + 1);
    split1(v.z, h + i + 2, l + i + 2);
    split1(v.w, h + i + 3, l + i + 3);
}
__global__ void split_w_kernel(const float* __restrict__ WQ, const float* __restrict__ WK,
                               const float* __restrict__ WV, const float* __restrict__ WO) {
    const float* src = (blockIdx.y == 0) ? WQ : (blockIdx.y == 1) ? WK
                     : (blockIdx.y == 2) ? WV : WO;
    size_t off = (size_t)blockIdx.y << 20;
    int i = (blockIdx.x * blockDim.x + threadIdx.x) * 4;
    float4 v = *(const float4*)(src + i);
    split1(v.x, g_wh + off + i + 0, g_wl + off + i + 0);
    split1(v.y, g_wh + off + i + 1, g_wl + off + i + 1);
    split1(v.z, g_wh + off + i + 2, g_wl + off + i + 2);
    split1(v.w, g_wh + off + i + 3, g_wl + off + i + 3);
}

// ================= mma.sync bf16x3 GEMM core =================
// 256 threads = 8 warps (4m x 2n), warp tile 32x64, BK=32, cp.async double-buffer.
#define KP 40
#define SB (128 * KP)            // elems per buffer (5120)
#define STG (4 * SB)             // elems per stage (Ah,Al,Bh,Bl)
#define GEMM_SMEM_BYTES (2 * STG * 2)   // 81920

__device__ __forceinline__ void hmma(float c[4], uint32_t a0, uint32_t a1, uint32_t a2,
                                     uint32_t a3, uint32_t b0, uint32_t b1) {
    asm volatile(
        "mma.sync.aligned.m16n8k16.row.col.f32.bf16.bf16.f32 "
        "{%0,%1,%2,%3}, {%4,%5,%6,%7}, {%8,%9}, {%0,%1,%2,%3};"
        : "+f"(c[0]), "+f"(c[1]), "+f"(c[2]), "+f"(c[3])
        : "r"(a0), "r"(a1), "r"(a2), "r"(a3), "r"(b0), "r"(b1));
}

__device__ __forceinline__ void gemm_gissue(uint32_t st32,
                                            const __nv_bfloat16* Ah, const __nv_bfloat16* Al,
                                            const __nv_bfloat16* Bh, const __nv_bfloat16* Bl,
                                            int k0) {
    int tid = threadIdx.x;
#pragma unroll
    for (int i = 0; i < 2; i++) {
        int v = tid + i * 256;
        int row = v >> 2, seg = v & 3;
        size_t gs = (size_t)row * Dc + k0 + seg * 8;
        uint32_t so = (uint32_t)((row * KP + seg * 8) * 2);
        cp16(st32 + so,              Ah + gs);
        cp16(st32 + SB * 2 + so,     Al + gs);
        cp16(st32 + 2 * SB * 2 + so, Bh + gs);
        cp16(st32 + 3 * SB * 2 + so, Bl + gs);
    }
}

__device__ __forceinline__ void mma_core(const __nv_bfloat16* Ah, const __nv_bfloat16* Al,
                                         const __nv_bfloat16* Bh, const __nv_bfloat16* Bl,
                                         __nv_bfloat16* S, float c[2][8][4]) {
    int lane = threadIdx.x & 31, w = threadIdx.x >> 5;
    int wm = w >> 1, wn = w & 1;
    int g = lane >> 2, t2 = (lane & 3) * 2;
    uint32_t s32 = smem_u32(S);
    gemm_gissue(s32, Ah, Al, Bh, Bl, 0);
    CP_COMMIT();
    gemm_gissue(s32 + STG * 2, Ah, Al, Bh, Bl, 32);
    CP_COMMIT();
    const int NCH = Dc / 32;
    for (int ch = 0; ch < NCH; ch++) {
        CP_WAIT1();
        __syncthreads();
        const __nv_bfloat16* st  = S + (ch & 1) * STG;
        const __nv_bfloat16* sAh = st;
        const __nv_bfloat16* sAl = st + SB;
        const __nv_bfloat16* sBh = st + 2 * SB;
        const __nv_bfloat16* sBl = st + 3 * SB;
#pragma unroll
        for (int ks = 0; ks < 32; ks += 16) {
            uint32_t ah[2][4], al[2][4];
#pragma unroll
            for (int mi = 0; mi < 2; mi++) {
                int r0 = (wm * 32 + mi * 16 + g) * KP + ks + t2;
                int r8 = r0 + 8 * KP;
                ah[mi][0] = *(const uint32_t*)(sAh + r0);
                ah[mi][1] = *(const uint32_t*)(sAh + r8);
                ah[mi][2] = *(const uint32_t*)(sAh + r0 + 8);
                ah[mi][3] = *(const uint32_t*)(sAh + r8 + 8);
                al[mi][0] = *(const uint32_t*)(sAl + r0);
                al[mi][1] = *(const uint32_t*)(sAl + r8);
                al[mi][2] = *(const uint32_t*)(sAl + r0 + 8);
                al[mi][3] = *(const uint32_t*)(sAl + r8 + 8);
            }
#pragma unroll
            for (int ni = 0; ni < 8; ni++) {
                int c0 = (wn * 64 + ni * 8 + g) * KP + ks + t2;
                uint32_t bh0 = *(const uint32_t*)(sBh + c0);
                uint32_t bh1 = *(const uint32_t*)(sBh + c0 + 8);
                uint32_t bl0 = *(const uint32_t*)(sBl + c0);
                uint32_t bl1 = *(const uint32_t*)(sBl + c0 + 8);
#pragma unroll
                for (int mi = 0; mi < 2; mi++) {
                    hmma(c[mi][ni], ah[mi][0], ah[mi][1], ah[mi][2], ah[mi][3], bh0, bh1);
                    hmma(c[mi][ni], ah[mi][0], ah[mi][1], ah[mi][2], ah[mi][3], bl0, bl1);
                    hmma(c[mi][ni], al[mi][0], al[mi][1], al[mi][2], al[mi][3], bh0, bh1);
                }
            }
        }
        __syncthreads();
        if (ch + 2 < NCH) {
            gemm_gissue(s32 + (ch & 1) * STG * 2, Ah, Al, Bh, Bl, (ch + 2) * 32);
            CP_COMMIT();
        }
    }
}

// ---------------- kernel 2: QKV projection -> Q,K (b,h,l,d), V^T (b,h,d,l) ----------------
__global__ void __launch_bounds__(256, 2) qkv_mma() {
    extern __shared__ __nv_bfloat16 Sdyn[];
    int z = blockIdx.z;
    int M0 = blockIdx.y * 128, N0 = blockIdx.x * 128;
    const __nv_bfloat16* Ah = g_xh + (size_t)M0 * Dc;
    const __nv_bfloat16* Al = g_xl + (size_t)M0 * Dc;
    const __nv_bfloat16* Bh = g_wh + ((size_t)z << 20) + (size_t)N0 * Dc;
    const __nv_bfloat16* Bl = g_wl + ((size_t)z << 20) + (size_t)N0 * Dc;
    float c[2][8][4] = {};
    mma_core(Ah, Al, Bh, Bl, Sdyn, c);

    int lane = threadIdx.x & 31, w = threadIdx.x >> 5;
    int wm = w >> 1, wn = w & 1;
    int g = lane >> 2, t2 = (lane & 3) * 2;
    if (z < 2) {
        __nv_bfloat16* dh = z ? g_kh : g_qh;
        __nv_bfloat16* dl = z ? g_kl : g_ql;
#pragma unroll
        for (int mi = 0; mi < 2; mi++)
#pragma unroll
            for (int ni = 0; ni < 8; ni++) {
                int col = N0 + wn * 64 + ni * 8 + t2;
                int h = col >> 6, dd = col & 63;
#pragma unroll
                for (int rh = 0; rh < 2; rh++) {
                    int row = M0 + wm * 32 + mi * 16 + g + rh * 8;
                    int bb = row >> 10, l = row & (Lc - 1);
                    float v0 = c[mi][ni][rh * 2], v1 = c[mi][ni][rh * 2 + 1];
                    float h0 = bf_hi(v0), h1 = bf_hi(v1);
                    size_t idx = (((size_t)(bb * Hc + h)) * Lc + l) * dc + dd;
                    *(uint32_t*)(dh + idx) = pack_bf16(h0, h1);
                    *(uint32_t*)(dl + idx) = pack_bf16(v0 - h0, v1 - h1);
                }
            }
    } else {
        // V: transpose via smem (mma_core ended with __syncthreads; Sdyn free)
        uint16_t* sT = (uint16_t*)Sdyn;            // hi at 0, lo at 128*136
#pragma unroll
        for (int mi = 0; mi < 2; mi++)
#pragma unroll
            for (int ni = 0; ni < 8; ni++) {
                int col_l = wn * 64 + ni * 8 + t2;
#pragma unroll
                for (int rh = 0; rh < 2; rh++) {
                    int row_l = wm * 32 + mi * 16 + g + rh * 8;
#pragma unroll
                    for (int cc = 0; cc < 2; cc++) {
                        float v = c[mi][ni][rh * 2 + cc];
                        __nv_bfloat16 vh = __float2bfloat16(v);
                        __nv_bfloat16 vl = __float2bfloat16(v - __bfloat162float(vh));
                        sT[(col_l + cc) * 136 + row_l]             = *(uint16_t*)&vh;
                        sT[128 * 136 + (col_l + cc) * 136 + row_l] = *(uint16_t*)&vl;
                    }
                }
            }
        __syncthreads();
        int bb = M0 >> 10, l0 = M0 & (Lc - 1);
#pragma unroll
        for (int q = 0; q < 8; q++) {
            int v = threadIdx.x + q * 256;
            int d = v >> 4, seg = v & 15;
            int col = N0 + d;
            int h = col >> 6, dd = col & 63;
            size_t dst = (((size_t)(bb * Hc + h)) * dc + dd) * Lc + l0 + seg * 8;
            *(uint4*)(g_vth + dst) = *(const uint4*)(sT + d * 136 + seg * 8);
            *(uint4*)(g_vtl + dst) = *(const uint4*)(sT + 128 * 136 + d * 136 + seg * 8);
        }
    }
}

// ---------------- kernel 4: output projection + bias ----------------
__global__ void __launch_bounds__(256, 2) out_mma(const float* __restrict__ bO,
                                                  float* __restrict__ out) {
    extern __shared__ __nv_bfloat16 Sdyn[];
    int M0 = blockIdx.y * 128, N0 = blockIdx.x * 128;
    const __nv_bfloat16* Ah = g_oh + (size_t)M0 * Dc;
    const __nv_bfloat16* Al = g_ol + (size_t)M0 * Dc;
    const __nv_bfloat16* Bh = g_wh + ((size_t)3 << 20) + (size_t)N0 * Dc;
    const __nv_bfloat16* Bl = g_wl + ((size_t)3 << 20) + (size_t)N0 * Dc;
    float c[2][8][4] = {};
    mma_core(Ah, Al, Bh, Bl, Sdyn, c);

    int lane = threadIdx.x & 31, w = threadIdx.x >> 5;
    int wm = w >> 1, wn = w & 1;
    int g = lane >> 2, t2 = (lane & 3) * 2;
#pragma unroll
    for (int mi = 0; mi < 2; mi++)
#pragma unroll
        for (int ni = 0; ni < 8; ni++) {
            int col = N0 + wn * 64 + ni * 8 + t2;
            float2 bv = *(const float2*)(bO + col);
#pragma unroll
            for (int rh = 0; rh < 2; rh++) {
                int row = M0 + wm * 32 + mi * 16 + g + rh * 8;
                float2 v = make_float2(c[mi][ni][rh * 2] + bv.x,
                                       c[mi][ni][rh * 2 + 1] + bv.y);
                *(float2*)(out + (size_t)row * Dc + col) = v;
            }
        }
}

// ---------------- kernel 3: flash attention (mma, cp.async, hoisted i-frags) ----------------
#define PT 80
#define IB (128 * PT)
#define JBe (64 * PT)
#define JBB (JBe * 2)
#define JSTG (6 * JBe)
#define ATTN_SMEM_BYTES ((4 * IB + 2 * JSTG) * 2 + (Lc + 128 + 128 + 2 * 64 + 2 * 64) * 4)

__global__ void __launch_bounds__(256, 1) attn_mma(const float* __restrict__ alpha,
                                                   const float* __restrict__ beta,
                                                   const float* __restrict__ gamma) {
    extern __shared__ __nv_bfloat16 smb[];
    __nv_bfloat16* sQh  = smb;
    __nv_bfloat16* sQl  = sQh + IB;
    __nv_bfloat16* sPih = sQl + IB;
    __nv_bfloat16* sPil = sPih + IB;
    __nv_bfloat16* jbase = sPil + IB;
    float* sR  = (float*)(jbase + 2 * JSTG);
    float* sCi = sR  + Lc;
    float* sQi = sCi + 128;
    float* sCj = sQi + 128;
    float* sQj = sCj + 2 * 64;

    uint32_t jb32 = smem_u32(jbase);

    int t = threadIdx.x;
    int w = t >> 5, lane = t & 31;
    int g = lane >> 2, t2 = (lane & 3) * 2;
    int bh = blockIdx.y;
    int b = bh >> 4, h = bh & 15;
    int i0 = blockIdx.x * 128;

    float a_h = alpha[h], b_h = beta[h], c_h = gamma[h];

    const size_t qoff = ((size_t)bh * Lc) * dc;
    const size_t xoff = ((size_t)b * Lc) * Dc + h * dc;
    const size_t voff = (size_t)bh * dc * Lc;

    for (int idx = t; idx < Lc; idx += 256) sR[idx] = g_rsum[idx];
    if (t < 128) {
        sCi[t] = g_coords[b * Lc + i0 + t];
        sQi[t] = fmaf(a_h, g_qsca[b * Lc + i0 + t], c_h);   // a*qi + c folded
    }
    if (t < 64) {
        sCj[t] = g_coords[b * Lc + t];
        sQj[t] = a_h * g_qsca[b * Lc + t];                  // a*qj folded
    }
#pragma unroll
    for (int q = 0; q < 4; q++) {
        int v = t * 4 + q;
        int row = v >> 3, seg = v & 7;
        int d = row * PT + seg * 8;
        size_t gq = qoff + (size_t)(i0 + row) * dc + seg * 8;
        size_t gx = xoff + (size_t)(i0 + row) * Dc + seg * 8;
        *(uint4*)(sQh  + d) = *(const uint4*)(g_qh + gq);
        *(uint4*)(sQl  + d) = *(const uint4*)(g_ql + gq);
        *(uint4*)(sPih + d) = *(const uint4*)(g_xh + gx);
        *(uint4*)(sPil + d) = *(const uint4*)(g_xl + gx);
    }
#pragma unroll
    for (int q = 0; q < 2; q++) {
        int v = t * 2 + q;
        int row = v >> 3, seg = v & 7;
        uint32_t boff = (uint32_t)((row * PT + seg * 8) * 2);
        size_t gk = qoff + (size_t)row * dc + seg * 8;
        size_t gx = xoff + (size_t)row * Dc + seg * 8;
        size_t gv = voff + (size_t)row * Lc + seg * 8;
        cp16(jb32 + 0 * JBB + boff, g_kh  + gk);
        cp16(jb32 + 1 * JBB + boff, g_kl  + gk);
        cp16(jb32 + 2 * JBB + boff, g_xh  + gx);
        cp16(jb32 + 3 * JBB + boff, g_xl  + gx);
        cp16(jb32 + 4 * JBB + boff, g_vth + gv);
        cp16(jb32 + 5 * JBB + boff, g_vtl + gv);
    }
    CP_COMMIT();
    __syncthreads();

    // hoist loop-invariant i-side fragments to registers
    uint32_t fqh[16], fql[16], fph[16], fpl[16];
#pragma unroll
    for (int ks4 = 0; ks4 < 4; ks4++) {
        int ra = (16 * w + g) * PT + ks4 * 16 + t2;
        fqh[ks4*4+0] = *(const uint32_t*)(sQh + ra);
        fqh[ks4*4+1] = *(const uint32_t*)(sQh + ra + 8 * PT);
        fqh[ks4*4+2] = *(const uint32_t*)(sQh + ra + 8);
        fqh[ks4*4+3] = *(const uint32_t*)(sQh + ra + 8 * PT + 8);
        fql[ks4*4+0] = *(const uint32_t*)(sQl + ra);
        fql[ks4*4+1] = *(const uint32_t*)(sQl + ra + 8 * PT);
        fql[ks4*4+2] = *(const uint32_t*)(sQl + ra + 8);
        fql[ks4*4+3] = *(const uint32_t*)(sQl + ra + 8 * PT + 8);
        fph[ks4*4+0] = *(const uint32_t*)(sPih + ra);
        fph[ks4*4+1] = *(const uint32_t*)(sPih + ra + 8 * PT);
        fph[ks4*4+2] = *(const uint32_t*)(sPih + ra + 8);
        fph[ks4*4+3] = *(const uint32_t*)(sPih + ra + 8 * PT + 8);
        fpl[ks4*4+0] = *(const uint32_t*)(sPil + ra);
        fpl[ks4*4+1] = *(const uint32_t*)(sPil + ra + 8 * PT);
        fpl[ks4*4+2] = *(const uint32_t*)(sPil + ra + 8);
        fpl[ks4*4+3] = *(const uint32_t*)(sPil + ra + 8 * PT + 8);
    }

    float ci_r[2], qi_r[2];
    ci_r[0] = sCi[16 * w + g];     qi_r[0] = sQi[16 * w + g];
    ci_r[1] = sCi[16 * w + g + 8]; qi_r[1] = sQi[16 * w + g + 8];

    float oacc[8][4] = {};
    float m_run[2] = {-INFINITY, -INFINITY}, l_run[2] = {0.f, 0.f};

    for (int jt = 0; jt < 16; jt++) {
        int cur = jt & 1;
        CP_WAIT0();
        __syncthreads();
        if (jt < 15) {
            int j1 = (jt + 1) * 64;
            uint32_t st32 = jb32 + (cur ^ 1) * (JSTG * 2);
#pragma unroll
            for (int q = 0; q < 2; q++) {
                int v = t * 2 + q;
                int row = v >> 3, seg = v & 7;
                uint32_t boff = (uint32_t)((row * PT + seg * 8) * 2);
                size_t gk = qoff + (size_t)(j1 + row) * dc + seg * 8;
                size_t gx = xoff + (size_t)(j1 + row) * Dc + seg * 8;
                size_t gv = voff + (size_t)row * Lc + j1 + seg * 8;
                cp16(st32 + 0 * JBB + boff, g_kh  + gk);
                cp16(st32 + 1 * JBB + boff, g_kl  + gk);
                cp16(st32 + 2 * JBB + boff, g_xh  + gx);
                cp16(st32 + 3 * JBB + boff, g_xl  + gx);
                cp16(st32 + 4 * JBB + boff, g_vth + gv);
                cp16(st32 + 5 * JBB + boff, g_vtl + gv);
            }
            CP_COMMIT();
            if (t < 64) {
                sCj[(cur ^ 1) * 64 + t] = g_coords[b * Lc + j1 + t];
                sQj[(cur ^ 1) * 64 + t] = a_h * g_qsca[b * Lc + j1 + t];
            }
        }
        __nv_bfloat16* js = jbase + cur * JSTG;
        const __nv_bfloat16* sKh  = js;
        const __nv_bfloat16* sKl  = js + JBe;
        const __nv_bfloat16* sPjh = js + 2 * JBe;
        const __nv_bfloat16* sPjl = js + 3 * JBe;
        const __nv_bfloat16* sVh  = js + 4 * JBe;
        const __nv_bfloat16* sVl  = js + 5 * JBe;
        const float* cjp = sCj + cur * 64;
        const float* qjp = sQj + cur * 64;

        // ---- QK^T and PP^T ----
        float cS[8][4] = {}, cP[8][4] = {};
#pragma unroll
        for (int ks4 = 0; ks4 < 4; ks4++) {
            int ks = ks4 * 16;
#pragma unroll
            for (int ni = 0; ni < 8; ni++) {
                int rb = (ni * 8 + g) * PT + ks + t2;
                uint32_t kh0 = *(const uint32_t*)(sKh + rb);
                uint32_t kh1 = *(const uint32_t*)(sKh + rb + 8);
                uint32_t kl0 = *(const uint32_t*)(sKl + rb);
                uint32_t kl1 = *(const uint32_t*)(sKl + rb + 8);
                uint32_t jh0 = *(const uint32_t*)(sPjh + rb);
                uint32_t jh1 = *(const uint32_t*)(sPjh + rb + 8);
                uint32_t jl0 = *(const uint32_t*)(sPjl + rb);
                uint32_t jl1 = *(const uint32_t*)(sPjl + rb + 8);
                hmma(cS[ni], fqh[ks4*4+0], fqh[ks4*4+1], fqh[ks4*4+2], fqh[ks4*4+3], kh0, kh1);
                hmma(cS[ni], fqh[ks4*4+0], fqh[ks4*4+1], fqh[ks4*4+2], fqh[ks4*4+3], kl0, kl1);
                hmma(cS[ni], fql[ks4*4+0], fql[ks4*4+1], fql[ks4*4+2], fql[ks4*4+3], kh0, kh1);
                hmma(cP[ni], fph[ks4*4+0], fph[ks4*4+1], fph[ks4*4+2], fph[ks4*4+3], jh0, jh1);
                hmma(cP[ni], fph[ks4*4+0], fph[ks4*4+1], fph[ks4*4+2], fph[ks4*4+3], jl0, jl1);
                hmma(cP[ni], fpl[ks4*4+0], fpl[ks4*4+1], fpl[ks4*4+2], fpl[ks4*4+3], jh0, jh1);
            }
        }

        // ---- bias + online softmax ----
        float scale[2];
#pragma unroll
        for (int rh = 0; rh < 2; rh++) {
            float ci = ci_r[rh], base_i = qi_r[rh];
            float rmax = -INFINITY;
#pragma unroll
            for (int ni = 0; ni < 8; ni++)
#pragma unroll
                for (int cc = 0; cc < 2; cc++) {
                    int col = ni * 8 + t2 + cc;
                    float delta = fabsf(ci - cjp[col]);
                    int   di = (int)delta;
                    float tt = delta - (float)di;
                    int d0 = min(di,     Lc - 1);
                    int d1 = min(di + 1, Lc - 1);
                    float r0 = sR[d0];
                    float r = fmaf(tt, sR[d1] - r0, r0);
                    float S = fmaf(b_h, r, base_i + qjp[col]);
                    float v = fmaf(S, cP[ni][rh * 2 + cc], cS[ni][rh * 2 + cc] * 0.125f);
                    cS[ni][rh * 2 + cc] = v;
                    rmax = fmaxf(rmax, v);
                }
            rmax = fmaxf(rmax, __shfl_xor_sync(0xffffffffu, rmax, 1));
            rmax = fmaxf(rmax, __shfl_xor_sync(0xffffffffu, rmax, 2));
            float mn = fmaxf(m_run[rh], rmax);
            float rsum = 0.f;
#pragma unroll
            for (int ni = 0; ni < 8; ni++)
#pragma unroll
                for (int cc = 0; cc < 2; cc++) {
                    float e = __expf(cS[ni][rh * 2 + cc] - mn);
                    cS[ni][rh * 2 + cc] = e;
                    rsum += e;
                }
            rsum += __shfl_xor_sync(0xffffffffu, rsum, 1);
            rsum += __shfl_xor_sync(0xffffffffu, rsum, 2);
            scale[rh] = __expf(m_run[rh] - mn);
            l_run[rh] = l_run[rh] * scale[rh] + rsum;
            m_run[rh] = mn;
        }
#pragma unroll
        for (int ni = 0; ni < 8; ni++) {
            oacc[ni][0] *= scale[0]; oacc[ni][1] *= scale[0];
            oacc[ni][2] *= scale[1]; oacc[ni][3] *= scale[1];
        }

        // ---- PV (C->A fragment identity), bf16x3 ----
#pragma unroll
        for (int kc = 0; kc < 4; kc++) {
            float v00 = cS[2*kc][0],   v01 = cS[2*kc][1];
            float v10 = cS[2*kc][2],   v11 = cS[2*kc][3];
            float v20 = cS[2*kc+1][0], v21 = cS[2*kc+1][1];
            float v30 = cS[2*kc+1][2], v31 = cS[2*kc+1][3];
            float h00 = bf_hi(v00), h01 = bf_hi(v01), h10 = bf_hi(v10), h11 = bf_hi(v11);
            float h20 = bf_hi(v20), h21 = bf_hi(v21), h30 = bf_hi(v30), h31 = bf_hi(v31);
            uint32_t aph0 = pack_bf16(h00, h01), aph1 = pack_bf16(h10, h11);
            uint32_t aph2 = pack_bf16(h20, h21), aph3 = pack_bf16(h30, h31);
            uint32_t apl0 = pack_bf16(v00 - h00, v01 - h01), apl1 = pack_bf16(v10 - h10, v11 - h11);
            uint32_t apl2 = pack_bf16(v20 - h20, v21 - h21), apl3 = pack_bf16(v30 - h30, v31 - h31);
#pragma unroll
            for (int ni = 0; ni < 8; ni++) {
                int rb = (ni * 8 + g) * PT + kc * 16 + t2;
                uint32_t vh0 = *(const uint32_t*)(sVh + rb);
                uint32_t vh1 = *(const uint32_t*)(sVh + rb + 8);
                uint32_t vl0 = *(const uint32_t*)(sVl + rb);
                uint32_t vl1 = *(const uint32_t*)(sVl + rb + 8);
                hmma(oacc[ni], aph0, aph1, aph2, aph3, vh0, vh1);
                hmma(oacc[ni], apl0, apl1, apl2, apl3, vh0, vh1);
                hmma(oacc[ni], aph0, aph1, aph2, aph3, vl0, vl1);
            }
        }
    }

    // ---- epilogue ----
    float inv0 = 1.f / l_run[0], inv1 = 1.f / l_run[1];
#pragma unroll
    for (int rh = 0; rh < 2; rh++) {
        int row = i0 + 16 * w + g + rh * 8;
        float inv = rh ? inv1 : inv0;
        size_t base = ((size_t)(b * Lc) + row) * Dc + h * dc;
#pragma unroll
        for (int ni = 0; ni < 8; ni++) {
            float v0 = oacc[ni][rh * 2]     * inv;
            float v1 = oacc[ni][rh * 2 + 1] * inv;
            float h0 = bf_hi(v0), h1 = bf_hi(v1);
            size_t idx = base + ni * 8 + t2;
            *(uint32_t*)(g_oh + idx) = pack_bf16(h0, h1);
            *(uint32_t*)(g_ol + idx) = pack_bf16(v0 - h0, v1 - h1);
        }
    }
}

// ---------------- launch ----------------
extern "C" void kernel_launch(void* const* d_in, const int* in_sizes, int n_in,
                              void* d_out, int out_size) {
    const float* x     = (const float*)d_in[0];
    const float* t_enc = (const float*)d_in[1];
    const float* WQ    = (const float*)d_in[2];
    const float* WK    = (const float*)d_in[3];
    const float* WV    = (const float*)d_in[4];
    const float* WO    = (const float*)d_in[5];
    const float* bO    = (const float*)d_in[6];
    const float* Wt    = (const float*)d_in[7];
    const float* bt    = (const float*)d_in[8];
    const float* p_mat = (const float*)d_in[9];
    const float* r_mat = (const float*)d_in[10];
    const float* alpha = (const float*)d_in[11];
    const float* beta  = (const float*)d_in[12];
    const float* gamma = (const float*)d_in[13];
    float* out = (float*)d_out;

    cudaFuncSetAttribute(attn_mma, cudaFuncAttributeMaxDynamicSharedMemorySize,
                         ATTN_SMEM_BYTES);
    cudaFuncSetAttribute(qkv_mma, cudaFuncAttributeMaxDynamicSharedMemorySize,
                         GEMM_SMEM_BYTES);
    cudaFuncSetAttribute(out_mma, cudaFuncAttributeMaxDynamicSharedMemorySize,
                         GEMM_SMEM_BYTES);

    __nv_bfloat16 *xh, *xl;
    cudaGetSymbolAddress((void**)&xh, g_xh);
    cudaGetSymbolAddress((void**)&xl, g_xl);

    colsum_kernel<<<dim3(Lc / 256, 2), 256>>>(p_mat, r_mat);
    coords_kernel<<<(Bc * Lc) / 128, 128>>>(t_enc, Wt, bt);
    split_kernel<<<(Bc * Lc * Dc) / (256 * 4), 256>>>(x, xh, xl);
    split_w_kernel<<<dim3((Dc * Dc) / (256 * 4), 4), 256>>>(WQ, WK, WV, WO);
    qkv_mma<<<dim3(Dc / 128, (Bc * Lc) / 128, 3), 256, GEMM_SMEM_BYTES>>>();
    attn_mma<<<dim3(Lc / 128, Bc * Hc), 256, ATTN_SMEM_BYTES>>>(alpha, beta, gamma);
    out_mma<<<dim3(Dc / 128, (Bc * Lc) / 128), 256, GEMM_SMEM_BYTES>>>(bO, out);
}

// round 9
// speedup vs baseline: 2.5558x; 1.0213x over previous
#include <cuda_runtime.h>
#include <cuda_bf16.h>
#include <math.h>
#include <stdint.h>

#define Bc 4
#define Lc 1024
#define Dc 1024
#define Hc 16
#define Tc 64
#define dc 64
#define BHLD (Bc*Hc*Lc*dc)   /* 4,194,304 */

// ---------------- scratch ----------------
__device__ float g_coords[Bc * Lc];
__device__ float g_qsca[Bc * Lc];
__device__ float g_psum[Lc];
__device__ float g_rsum[Lc];
__device__ __nv_bfloat16 g_xh[Bc*Lc*Dc], g_xl[Bc*Lc*Dc];     // x
__device__ __nv_bfloat16 g_wh[4*Dc*Dc],  g_wl[4*Dc*Dc];      // WQ|WK|WV|WO
__device__ __nv_bfloat16 g_qh[BHLD], g_ql[BHLD];             // Q*0.125 (b,h,l,d)
__device__ __nv_bfloat16 g_kh[BHLD], g_kl[BHLD];             // K (b,h,l,d)
__device__ __nv_bfloat16 g_vth[BHLD], g_vtl[BHLD];           // V^T (b,h,d,l)
__device__ __nv_bfloat16 g_oh[Bc*Lc*Dc], g_ol[Bc*Lc*Dc];     // attn out (b,l,D)

__device__ __forceinline__ uint32_t pack_bf16(float lo, float hi) {
    __nv_bfloat162 r = __floats2bfloat162_rn(lo, hi);
    return *(uint32_t*)&r;
}
__device__ __forceinline__ float bf_hi(float v) {
    return __bfloat162float(__float2bfloat16(v));
}
__device__ __forceinline__ uint32_t smem_u32(const void* p) {
    uint32_t a;
    asm("{ .reg .u64 t; cvta.to.shared.u64 t, %1; cvt.u32.u64 %0, t; }" : "=r"(a) : "l"(p));
    return a;
}
__device__ __forceinline__ void cp16(uint32_t dst, const void* src) {
    asm volatile("cp.async.cg.shared.global [%0], [%1], 16;" :: "r"(dst), "l"(src));
}
#define CP_COMMIT() asm volatile("cp.async.commit_group;" ::: "memory")
#define CP_WAIT0()  asm volatile("cp.async.wait_group 0;"  ::: "memory")
#define CP_WAIT1()  asm volatile("cp.async.wait_group 1;"  ::: "memory")

// ---------------- kernel 0: column sums ----------------
__global__ void colsum_kernel(const float* __restrict__ p_mat,
                              const float* __restrict__ r_mat) {
    int l = blockIdx.x * blockDim.x + threadIdx.x;
    if (l >= Lc) return;
    const float* src = blockIdx.y ? r_mat : p_mat;
    float s = 0.f;
#pragma unroll 8
    for (int dd = 0; dd < Dc; dd++) s += src[dd * Lc + l];
    if (blockIdx.y) g_rsum[l] = s; else g_psum[l] = s;
}

// ---------------- kernel 1: coords + cubic q_sca ----------------
__global__ void coords_kernel(const float* __restrict__ t_enc,
                              const float* __restrict__ Wt,
                              const float* __restrict__ bt) {
    int n = blockIdx.x * blockDim.x + threadIdx.x;
    if (n >= Bc * Lc) return;
    float z = bt[0];
    const float* te = t_enc + (size_t)n * Tc;
#pragma unroll
    for (int k = 0; k < Tc; k++) z += te[k] * Wt[k];
    float tau = 1.f / (1.f + expf(-z));
    float c = tau * (float)(Lc - 1);
    g_coords[n] = c;
    int i = (int)floorf(c);
    float t = c - (float)i;
    int im1 = min(max(i - 1, 0), Lc - 1);
    int ii0 = min(max(i,     0), Lc - 1);
    int ii1 = min(max(i + 1, 0), Lc - 1);
    int ii2 = min(max(i + 2, 0), Lc - 1);
    float p0 = g_psum[im1], p1 = g_psum[ii0], p2 = g_psum[ii1], p3 = g_psum[ii2];
    float t2 = t * t, t3 = t2 * t;
    g_qsca[n] = 0.5f * (2.f * p1 + (-p0 + p2) * t
              + (2.f * p0 - 5.f * p1 + 4.f * p2 - p3) * t2
              + (-p0 + 3.f * p1 - 3.f * p2 + p3) * t3);
}

// ---------------- split fp32 -> bf16 hi + lo (packed 8B stores) ----------------
__global__ void split_kernel(const float* __restrict__ s,
                             __nv_bfloat16* __restrict__ h,
                             __nv_bfloat16* __restrict__ l) {
    int i = (blockIdx.x * blockDim.x + threadIdx.x) * 4;
    float4 v = *(const float4*)(s + i);
    float h0 = bf_hi(v.x), h1 = bf_hi(v.y), h2 = bf_hi(v.z), h3 = bf_hi(v.w);
    uint2 H = make_uint2(pack_bf16(h0, h1), pack_bf16(h2, h3));
    uint2 L = make_uint2(pack_bf16(v.x - h0, v.y - h1), pack_bf16(v.z - h2, v.w - h3));
    *(uint2*)(h + i) = H;
    *(uint2*)(l + i) = L;
}
__global__ void split_w_kernel(const float* __restrict__ WQ, const float* __restrict__ WK,
                               const float* __restrict__ WV, const float* __restrict__ WO) {
    const float* src = (blockIdx.y == 0) ? WQ : (blockIdx.y == 1) ? WK
                     : (blockIdx.y == 2) ? WV : WO;
    size_t off = (size_t)blockIdx.y << 20;
    int i = (blockIdx.x * blockDim.x + threadIdx.x) * 4;
    float4 v = *(const float4*)(src + i);
    float h0 = bf_hi(v.x), h1 = bf_hi(v.y), h2 = bf_hi(v.z), h3 = bf_hi(v.w);
    uint2 H = make_uint2(pack_bf16(h0, h1), pack_bf16(h2, h3));
    uint2 L = make_uint2(pack_bf16(v.x - h0, v.y - h1), pack_bf16(v.z - h2, v.w - h3));
    *(uint2*)(g_wh + off + i) = H;
    *(uint2*)(g_wl + off + i) = L;
}

// ================= mma.sync bf16x3 GEMM core =================
// 128 threads = 4 warps (2m x 2n), warp tile 64x64, BK=32, cp.async double-buffer.
#define KP 40
#define SB (128 * KP)
#define STG (4 * SB)
#define GEMM_SMEM_BYTES (2 * STG * 2)   // 81920

__device__ __forceinline__ void hmma(float c[4], uint32_t a0, uint32_t a1, uint32_t a2,
                                     uint32_t a3, uint32_t b0, uint32_t b1) {
    asm volatile(
        "mma.sync.aligned.m16n8k16.row.col.f32.bf16.bf16.f32 "
        "{%0,%1,%2,%3}, {%4,%5,%6,%7}, {%8,%9}, {%0,%1,%2,%3};"
        : "+f"(c[0]), "+f"(c[1]), "+f"(c[2]), "+f"(c[3])
        : "r"(a0), "r"(a1), "r"(a2), "r"(a3), "r"(b0), "r"(b1));
}

__device__ __forceinline__ void gemm_gissue(uint32_t st32,
                                            const __nv_bfloat16* Ah, const __nv_bfloat16* Al,
                                            const __nv_bfloat16* Bh, const __nv_bfloat16* Bl,
                                            int k0) {
    int tid = threadIdx.x;
#pragma unroll
    for (int i = 0; i < 4; i++) {
        int v = tid + i * 128;
        int row = v >> 2, seg = v & 3;
        size_t gs = (size_t)row * Dc + k0 + seg * 8;
        uint32_t so = (uint32_t)((row * KP + seg * 8) * 2);
        cp16(st32 + so,              Ah + gs);
        cp16(st32 + SB * 2 + so,     Al + gs);
        cp16(st32 + 2 * SB * 2 + so, Bh + gs);
        cp16(st32 + 3 * SB * 2 + so, Bl + gs);
    }
}

__device__ __forceinline__ void mma_core(const __nv_bfloat16* Ah, const __nv_bfloat16* Al,
                                         const __nv_bfloat16* Bh, const __nv_bfloat16* Bl,
                                         __nv_bfloat16* S, float c[4][8][4]) {
    int lane = threadIdx.x & 31, w = threadIdx.x >> 5;
    int wm = w >> 1, wn = w & 1;
    int g = lane >> 2, t2 = (lane & 3) * 2;
    uint32_t s32 = smem_u32(S);
    gemm_gissue(s32, Ah, Al, Bh, Bl, 0);
    CP_COMMIT();
    gemm_gissue(s32 + STG * 2, Ah, Al, Bh, Bl, 32);
    CP_COMMIT();
    const int NCH = Dc / 32;
    for (int ch = 0; ch < NCH; ch++) {
        CP_WAIT1();
        __syncthreads();
        const __nv_bfloat16* st  = S + (ch & 1) * STG;
        const __nv_bfloat16* sAh = st;
        const __nv_bfloat16* sAl = st + SB;
        const __nv_bfloat16* sBh = st + 2 * SB;
        const __nv_bfloat16* sBl = st + 3 * SB;
#pragma unroll
        for (int ks = 0; ks < 32; ks += 16) {
            uint32_t ah[4][4], al[4][4];
#pragma unroll
            for (int mi = 0; mi < 4; mi++) {
                int r0 = (wm * 64 + mi * 16 + g) * KP + ks + t2;
                int r8 = r0 + 8 * KP;
                ah[mi][0] = *(const uint32_t*)(sAh + r0);
                ah[mi][1] = *(const uint32_t*)(sAh + r8);
                ah[mi][2] = *(const uint32_t*)(sAh + r0 + 8);
                ah[mi][3] = *(const uint32_t*)(sAh + r8 + 8);
                al[mi][0] = *(const uint32_t*)(sAl + r0);
                al[mi][1] = *(const uint32_t*)(sAl + r8);
                al[mi][2] = *(const uint32_t*)(sAl + r0 + 8);
                al[mi][3] = *(const uint32_t*)(sAl + r8 + 8);
            }
#pragma unroll
            for (int ni = 0; ni < 8; ni++) {
                int c0 = (wn * 64 + ni * 8 + g) * KP + ks + t2;
                uint32_t bh0 = *(const uint32_t*)(sBh + c0);
                uint32_t bh1 = *(const uint32_t*)(sBh + c0 + 8);
                uint32_t bl0 = *(const uint32_t*)(sBl + c0);
                uint32_t bl1 = *(const uint32_t*)(sBl + c0 + 8);
#pragma unroll
                for (int mi = 0; mi < 4; mi++) {
                    hmma(c[mi][ni], ah[mi][0], ah[mi][1], ah[mi][2], ah[mi][3], bh0, bh1);
                    hmma(c[mi][ni], ah[mi][0], ah[mi][1], ah[mi][2], ah[mi][3], bl0, bl1);
                    hmma(c[mi][ni], al[mi][0], al[mi][1], al[mi][2], al[mi][3], bh0, bh1);
                }
            }
        }
        __syncthreads();
        if (ch + 2 < NCH) {
            gemm_gissue(s32 + (ch & 1) * STG * 2, Ah, Al, Bh, Bl, (ch + 2) * 32);
            CP_COMMIT();
        }
    }
}

// ---------------- kernel 2: QKV projection -> Q*0.125,K (b,h,l,d), V^T (b,h,d,l) ----------------
__global__ void __launch_bounds__(128, 2) qkv_mma() {
    extern __shared__ __nv_bfloat16 Sdyn[];
    int z = blockIdx.z;
    int M0 = blockIdx.y * 128, N0 = blockIdx.x * 128;
    const __nv_bfloat16* Ah = g_xh + (size_t)M0 * Dc;
    const __nv_bfloat16* Al = g_xl + (size_t)M0 * Dc;
    const __nv_bfloat16* Bh = g_wh + ((size_t)z << 20) + (size_t)N0 * Dc;
    const __nv_bfloat16* Bl = g_wl + ((size_t)z << 20) + (size_t)N0 * Dc;
    float c[4][8][4] = {};
    mma_core(Ah, Al, Bh, Bl, Sdyn, c);

    int lane = threadIdx.x & 31, w = threadIdx.x >> 5;
    int wm = w >> 1, wn = w & 1;
    int g = lane >> 2, t2 = (lane & 3) * 2;
    if (z < 2) {
        __nv_bfloat16* dh = z ? g_kh : g_qh;
        __nv_bfloat16* dl = z ? g_kl : g_ql;
        float qs = z ? 1.0f : 0.125f;   // fold 1/sqrt(d) into Q (exact pow2)
#pragma unroll
        for (int mi = 0; mi < 4; mi++)
#pragma unroll
            for (int ni = 0; ni < 8; ni++) {
                int col = N0 + wn * 64 + ni * 8 + t2;
                int h = col >> 6, dd = col & 63;
#pragma unroll
                for (int rh = 0; rh < 2; rh++) {
                    int row = M0 + wm * 64 + mi * 16 + g + rh * 8;
                    int bb = row >> 10, l = row & (Lc - 1);
                    float v0 = c[mi][ni][rh * 2] * qs, v1 = c[mi][ni][rh * 2 + 1] * qs;
                    float h0 = bf_hi(v0), h1 = bf_hi(v1);
                    size_t idx = (((size_t)(bb * Hc + h)) * Lc + l) * dc + dd;
                    *(uint32_t*)(dh + idx) = pack_bf16(h0, h1);
                    *(uint32_t*)(dl + idx) = pack_bf16(v0 - h0, v1 - h1);
                }
            }
    } else {
        // V: transpose via smem (mma_core ended with __syncthreads; Sdyn free)
        uint16_t* sT = (uint16_t*)Sdyn;            // hi at 0, lo at 128*136
#pragma unroll
        for (int mi = 0; mi < 4; mi++)
#pragma unroll
            for (int ni = 0; ni < 8; ni++) {
                int col_l = wn * 64 + ni * 8 + t2;
#pragma unroll
                for (int rh = 0; rh < 2; rh++) {
                    int row_l = wm * 64 + mi * 16 + g + rh * 8;
#pragma unroll
                    for (int cc = 0; cc < 2; cc++) {
                        float v = c[mi][ni][rh * 2 + cc];
                        __nv_bfloat16 vh = __float2bfloat16(v);
                        __nv_bfloat16 vl = __float2bfloat16(v - __bfloat162float(vh));
                        sT[(col_l + cc) * 136 + row_l]             = *(uint16_t*)&vh;
                        sT[128 * 136 + (col_l + cc) * 136 + row_l] = *(uint16_t*)&vl;
                    }
                }
            }
        __syncthreads();
        int bb = M0 >> 10, l0 = M0 & (Lc - 1);
#pragma unroll
        for (int q = 0; q < 16; q++) {
            int v = threadIdx.x + q * 128;
            int d = v >> 4, seg = v & 15;
            int col = N0 + d;
            int h = col >> 6, dd = col & 63;
            size_t dst = (((size_t)(bb * Hc + h)) * dc + dd) * Lc + l0 + seg * 8;
            *(uint4*)(g_vth + dst) = *(const uint4*)(sT + d * 136 + seg * 8);
            *(uint4*)(g_vtl + dst) = *(const uint4*)(sT + 128 * 136 + d * 136 + seg * 8);
        }
    }
}

// ---------------- kernel 4: output projection + bias ----------------
__global__ void __launch_bounds__(128, 2) out_mma(const float* __restrict__ bO,
                                                  float* __restrict__ out) {
    extern __shared__ __nv_bfloat16 Sdyn[];
    int M0 = blockIdx.y * 128, N0 = blockIdx.x * 128;
    const __nv_bfloat16* Ah = g_oh + (size_t)M0 * Dc;
    const __nv_bfloat16* Al = g_ol + (size_t)M0 * Dc;
    const __nv_bfloat16* Bh = g_wh + ((size_t)3 << 20) + (size_t)N0 * Dc;
    const __nv_bfloat16* Bl = g_wl + ((size_t)3 << 20) + (size_t)N0 * Dc;
    float c[4][8][4] = {};
    mma_core(Ah, Al, Bh, Bl, Sdyn, c);

    int lane = threadIdx.x & 31, w = threadIdx.x >> 5;
    int wm = w >> 1, wn = w & 1;
    int g = lane >> 2, t2 = (lane & 3) * 2;
#pragma unroll
    for (int mi = 0; mi < 4; mi++)
#pragma unroll
        for (int ni = 0; ni < 8; ni++) {
            int col = N0 + wn * 64 + ni * 8 + t2;
            float2 bv = *(const float2*)(bO + col);
#pragma unroll
            for (int rh = 0; rh < 2; rh++) {
                int row = M0 + wm * 64 + mi * 16 + g + rh * 8;
                float2 v = make_float2(c[mi][ni][rh * 2] + bv.x,
                                       c[mi][ni][rh * 2 + 1] + bv.y);
                *(float2*)(out + (size_t)row * Dc + col) = v;
            }
        }
}

// ---------------- kernel 3: flash attention (mma, cp.async, hoisted i-frags) ----------------
#define PT 80
#define IB (128 * PT)
#define JBe (64 * PT)
#define JBB (JBe * 2)
#define JSTG (6 * JBe)
#define ATTN_SMEM_BYTES ((4 * IB + 2 * JSTG) * 2 + (Lc + 128 + 128 + 2 * 64 + 2 * 64) * 4)

__global__ void __launch_bounds__(256, 1) attn_mma(const float* __restrict__ alpha,
                                                   const float* __restrict__ beta,
                                                   const float* __restrict__ gamma) {
    extern __shared__ __nv_bfloat16 smb[];
    __nv_bfloat16* sQh  = smb;
    __nv_bfloat16* sQl  = sQh + IB;
    __nv_bfloat16* sPih = sQl + IB;
    __nv_bfloat16* sPil = sPih + IB;
    __nv_bfloat16* jbase = sPil + IB;
    float* sR  = (float*)(jbase + 2 * JSTG);
    float* sCi = sR  + Lc;
    float* sQi = sCi + 128;
    float* sCj = sQi + 128;
    float* sQj = sCj + 2 * 64;

    uint32_t jb32 = smem_u32(jbase);

    int t = threadIdx.x;
    int w = t >> 5, lane = t & 31;
    int g = lane >> 2, t2 = (lane & 3) * 2;
    int bh = blockIdx.y;
    int b = bh >> 4, h = bh & 15;
    int i0 = blockIdx.x * 128;

    float a_h = alpha[h], b_h = beta[h], c_h = gamma[h];

    const size_t qoff = ((size_t)bh * Lc) * dc;
    const size_t xoff = ((size_t)b * Lc) * Dc + h * dc;
    const size_t voff = (size_t)bh * dc * Lc;

    for (int idx = t; idx < Lc; idx += 256) sR[idx] = g_rsum[idx];
    if (t < 128) {
        sCi[t] = g_coords[b * Lc + i0 + t];
        sQi[t] = fmaf(a_h, g_qsca[b * Lc + i0 + t], c_h);
    }
    if (t < 64) {
        sCj[t] = g_coords[b * Lc + t];
        sQj[t] = a_h * g_qsca[b * Lc + t];
    }
#pragma unroll
    for (int q = 0; q < 4; q++) {
        int v = t * 4 + q;
        int row = v >> 3, seg = v & 7;
        int d = row * PT + seg * 8;
        size_t gq = qoff + (size_t)(i0 + row) * dc + seg * 8;
        size_t gx = xoff + (size_t)(i0 + row) * Dc + seg * 8;
        *(uint4*)(sQh  + d) = *(const uint4*)(g_qh + gq);
        *(uint4*)(sQl  + d) = *(const uint4*)(g_ql + gq);
        *(uint4*)(sPih + d) = *(const uint4*)(g_xh + gx);
        *(uint4*)(sPil + d) = *(const uint4*)(g_xl + gx);
    }
#pragma unroll
    for (int q = 0; q < 2; q++) {
        int v = t * 2 + q;
        int row = v >> 3, seg = v & 7;
        uint32_t boff = (uint32_t)((row * PT + seg * 8) * 2);
        size_t gk = qoff + (size_t)row * dc + seg * 8;
        size_t gx = xoff + (size_t)row * Dc + seg * 8;
        size_t gv = voff + (size_t)row * Lc + seg * 8;
        cp16(jb32 + 0 * JBB + boff, g_kh  + gk);
        cp16(jb32 + 1 * JBB + boff, g_kl  + gk);
        cp16(jb32 + 2 * JBB + boff, g_xh  + gx);
        cp16(jb32 + 3 * JBB + boff, g_xl  + gx);
        cp16(jb32 + 4 * JBB + boff, g_vth + gv);
        cp16(jb32 + 5 * JBB + boff, g_vtl + gv);
    }
    CP_COMMIT();
    __syncthreads();

    uint32_t fqh[16], fql[16], fph[16], fpl[16];
#pragma unroll
    for (int ks4 = 0; ks4 < 4; ks4++) {
        int ra = (16 * w + g) * PT + ks4 * 16 + t2;
        fqh[ks4*4+0] = *(const uint32_t*)(sQh + ra);
        fqh[ks4*4+1] = *(const uint32_t*)(sQh + ra + 8 * PT);
        fqh[ks4*4+2] = *(const uint32_t*)(sQh + ra + 8);
        fqh[ks4*4+3] = *(const uint32_t*)(sQh + ra + 8 * PT + 8);
        fql[ks4*4+0] = *(const uint32_t*)(sQl + ra);
        fql[ks4*4+1] = *(const uint32_t*)(sQl + ra + 8 * PT);
        fql[ks4*4+2] = *(const uint32_t*)(sQl + ra + 8);
        fql[ks4*4+3] = *(const uint32_t*)(sQl + ra + 8 * PT + 8);
        fph[ks4*4+0] = *(const uint32_t*)(sPih + ra);
        fph[ks4*4+1] = *(const uint32_t*)(sPih + ra + 8 * PT);
        fph[ks4*4+2] = *(const uint32_t*)(sPih + ra + 8);
        fph[ks4*4+3] = *(const uint32_t*)(sPih + ra + 8 * PT + 8);
        fpl[ks4*4+0] = *(const uint32_t*)(sPil + ra);
        fpl[ks4*4+1] = *(const uint32_t*)(sPil + ra + 8 * PT);
        fpl[ks4*4+2] = *(const uint32_t*)(sPil + ra + 8);
        fpl[ks4*4+3] = *(const uint32_t*)(sPil + ra + 8 * PT + 8);
    }

    float ci_r[2], qi_r[2];
    ci_r[0] = sCi[16 * w + g];     qi_r[0] = sQi[16 * w + g];
    ci_r[1] = sCi[16 * w + g + 8]; qi_r[1] = sQi[16 * w + g + 8];

    float oacc[8][4] = {};
    float m_run[2] = {-INFINITY, -INFINITY}, l_run[2] = {0.f, 0.f};

    for (int jt = 0; jt < 16; jt++) {
        int cur = jt & 1;
        CP_WAIT0();
        __syncthreads();
        if (jt < 15) {
            int j1 = (jt + 1) * 64;
            uint32_t st32 = jb32 + (cur ^ 1) * (JSTG * 2);
#pragma unroll
            for (int q = 0; q < 2; q++) {
                int v = t * 2 + q;
                int row = v >> 3, seg = v & 7;
                uint32_t boff = (uint32_t)((row * PT + seg * 8) * 2);
                size_t gk = qoff + (size_t)(j1 + row) * dc + seg * 8;
                size_t gx = xoff + (size_t)(j1 + row) * Dc + seg * 8;
                size_t gv = voff + (size_t)row * Lc + j1 + seg * 8;
                cp16(st32 + 0 * JBB + boff, g_kh  + gk);
                cp16(st32 + 1 * JBB + boff, g_kl  + gk);
                cp16(st32 + 2 * JBB + boff, g_xh  + gx);
                cp16(st32 + 3 * JBB + boff, g_xl  + gx);
                cp16(st32 + 4 * JBB + boff, g_vth + gv);
                cp16(st32 + 5 * JBB + boff, g_vtl + gv);
            }
            CP_COMMIT();
            if (t < 64) {
                sCj[(cur ^ 1) * 64 + t] = g_coords[b * Lc + j1 + t];
                sQj[(cur ^ 1) * 64 + t] = a_h * g_qsca[b * Lc + j1 + t];
            }
        }
        __nv_bfloat16* js = jbase + cur * JSTG;
        const __nv_bfloat16* sKh  = js;
        const __nv_bfloat16* sKl  = js + JBe;
        const __nv_bfloat16* sPjh = js + 2 * JBe;
        const __nv_bfloat16* sPjl = js + 3 * JBe;
        const __nv_bfloat16* sVh  = js + 4 * JBe;
        const __nv_bfloat16* sVl  = js + 5 * JBe;
        const float* cjp = sCj + cur * 64;
        const float* qjp = sQj + cur * 64;

        float cS[8][4] = {}, cP[8][4] = {};
#pragma unroll
        for (int ks4 = 0; ks4 < 4; ks4++) {
            int ks = ks4 * 16;
#pragma unroll
            for (int ni = 0; ni < 8; ni++) {
                int rb = (ni * 8 + g) * PT + ks + t2;
                uint32_t kh0 = *(const uint32_t*)(sKh + rb);
                uint32_t kh1 = *(const uint32_t*)(sKh + rb + 8);
                uint32_t kl0 = *(const uint32_t*)(sKl + rb);
                uint32_t kl1 = *(const uint32_t*)(sKl + rb + 8);
                uint32_t jh0 = *(const uint32_t*)(sPjh + rb);
                uint32_t jh1 = *(const uint32_t*)(sPjh + rb + 8);
                uint32_t jl0 = *(const uint32_t*)(sPjl + rb);
                uint32_t jl1 = *(const uint32_t*)(sPjl + rb + 8);
                hmma(cS[ni], fqh[ks4*4+0], fqh[ks4*4+1], fqh[ks4*4+2], fqh[ks4*4+3], kh0, kh1);
                hmma(cS[ni], fqh[ks4*4+0], fqh[ks4*4+1], fqh[ks4*4+2], fqh[ks4*4+3], kl0, kl1);
                hmma(cS[ni], fql[ks4*4+0], fql[ks4*4+1], fql[ks4*4+2], fql[ks4*4+3], kh0, kh1);
                hmma(cP[ni], fph[ks4*4+0], fph[ks4*4+1], fph[ks4*4+2], fph[ks4*4+3], jh0, jh1);
                hmma(cP[ni], fph[ks4*4+0], fph[ks4*4+1], fph[ks4*4+2], fph[ks4*4+3], jl0, jl1);
                hmma(cP[ni], fpl[ks4*4+0], fpl[ks4*4+1], fpl[ks4*4+2], fpl[ks4*4+3], jh0, jh1);
            }
        }

        float scale[2];
#pragma unroll
        for (int rh = 0; rh < 2; rh++) {
            float ci = ci_r[rh], base_i = qi_r[rh];
            float rmax = -INFINITY;
#pragma unroll
            for (int ni = 0; ni < 8; ni++)
#pragma unroll
                for (int cc = 0; cc < 2; cc++) {
                    int col = ni * 8 + t2 + cc;
                    float delta = fabsf(ci - cjp[col]);
                    int   di = (int)delta;
                    float tt = delta - (float)di;
                    int d0 = min(di,     Lc - 1);
                    int d1 = min(di + 1, Lc - 1);
                    float r0 = sR[d0];
                    float r = fmaf(tt, sR[d1] - r0, r0);
                    float S = fmaf(b_h, r, base_i + qjp[col]);
                    float v = fmaf(S, cP[ni][rh * 2 + cc], cS[ni][rh * 2 + cc]);
                    cS[ni][rh * 2 + cc] = v;
                    rmax = fmaxf(rmax, v);
                }
            rmax = fmaxf(rmax, __shfl_xor_sync(0xffffffffu, rmax, 1));
            rmax = fmaxf(rmax, __shfl_xor_sync(0xffffffffu, rmax, 2));
            float mn = fmaxf(m_run[rh], rmax);
            float rsum = 0.f;
#pragma unroll
            for (int ni = 0; ni < 8; ni++)
#pragma unroll
                for (int cc = 0; cc < 2; cc++) {
                    float e = __expf(cS[ni][rh * 2 + cc] - mn);
                    cS[ni][rh * 2 + cc] = e;
                    rsum += e;
                }
            rsum += __shfl_xor_sync(0xffffffffu, rsum, 1);
            rsum += __shfl_xor_sync(0xffffffffu, rsum, 2);
            scale[rh] = __expf(m_run[rh] - mn);
            l_run[rh] = l_run[rh] * scale[rh] + rsum;
            m_run[rh] = mn;
        }
#pragma unroll
        for (int ni = 0; ni < 8; ni++) {
            oacc[ni][0] *= scale[0]; oacc[ni][1] *= scale[0];
            oacc[ni][2] *= scale[1]; oacc[ni][3] *= scale[1];
        }

#pragma unroll
        for (int kc = 0; kc < 4; kc++) {
            float v00 = cS[2*kc][0],   v01 = cS[2*kc][1];
            float v10 = cS[2*kc][2],   v11 = cS[2*kc][3];
            float v20 = cS[2*kc+1][0], v21 = cS[2*kc+1][1];
            float v30 = cS[2*kc+1][2], v31 = cS[2*kc+1][3];
            float h00 = bf_hi(v00), h01 = bf_hi(v01), h10 = bf_hi(v10), h11 = bf_hi(v11);
            float h20 = bf_hi(v20), h21 = bf_hi(v21), h30 = bf_hi(v30), h31 = bf_hi(v31);
            uint32_t aph0 = pack_bf16(h00, h01), aph1 = pack_bf16(h10, h11);
            uint32_t aph2 = pack_bf16(h20, h21), aph3 = pack_bf16(h30, h31);
            uint32_t apl0 = pack_bf16(v00 - h00, v01 - h01), apl1 = pack_bf16(v10 - h10, v11 - h11);
            uint32_t apl2 = pack_bf16(v20 - h20, v21 - h21), apl3 = pack_bf16(v30 - h30, v31 - h31);
#pragma unroll
            for (int ni = 0; ni < 8; ni++) {
                int rb = (ni * 8 + g) * PT + kc * 16 + t2;
                uint32_t vh0 = *(const uint32_t*)(sVh + rb);
                uint32_t vh1 = *(const uint32_t*)(sVh + rb + 8);
                uint32_t vl0 = *(const uint32_t*)(sVl + rb);
                uint32_t vl1 = *(const uint32_t*)(sVl + rb + 8);
                hmma(oacc[ni], aph0, aph1, aph2, aph3, vh0, vh1);
                hmma(oacc[ni], apl0, apl1, apl2, apl3, vh0, vh1);
                hmma(oacc[ni], aph0, aph1, aph2, aph3, vl0, vl1);
            }
        }
    }

    float inv0 = 1.f / l_run[0], inv1 = 1.f / l_run[1];
#pragma unroll
    for (int rh = 0; rh < 2; rh++) {
        int row = i0 + 16 * w + g + rh * 8;
        float inv = rh ? inv1 : inv0;
        size_t base = ((size_t)(b * Lc) + row) * Dc + h * dc;
#pragma unroll
        for (int ni = 0; ni < 8; ni++) {
            float v0 = oacc[ni][rh * 2]     * inv;
            float v1 = oacc[ni][rh * 2 + 1] * inv;
            float h0 = bf_hi(v0), h1 = bf_hi(v1);
            size_t idx = base + ni * 8 + t2;
            *(uint32_t*)(g_oh + idx) = pack_bf16(h0, h1);
            *(uint32_t*)(g_ol + idx) = pack_bf16(v0 - h0, v1 - h1);
        }
    }
}

// ---------------- launch ----------------
extern "C" void kernel_launch(void* const* d_in, const int* in_sizes, int n_in,
                              void* d_out, int out_size) {
    const float* x     = (const float*)d_in[0];
    const float* t_enc = (const float*)d_in[1];
    const float* WQ    = (const float*)d_in[2];
    const float* WK    = (const float*)d_in[3];
    const float* WV    = (const float*)d_in[4];
    const float* WO    = (const float*)d_in[5];
    const float* bO    = (const float*)d_in[6];
    const float* Wt    = (const float*)d_in[7];
    const float* bt    = (const float*)d_in[8];
    const float* p_mat = (const float*)d_in[9];
    const float* r_mat = (const float*)d_in[10];
    const float* alpha = (const float*)d_in[11];
    const float* beta  = (const float*)d_in[12];
    const float* gamma = (const float*)d_in[13];
    float* out = (float*)d_out;

    cudaFuncSetAttribute(attn_mma, cudaFuncAttributeMaxDynamicSharedMemorySize,
                         ATTN_SMEM_BYTES);
    cudaFuncSetAttribute(qkv_mma, cudaFuncAttributeMaxDynamicSharedMemorySize,
                         GEMM_SMEM_BYTES);
    cudaFuncSetAttribute(out_mma, cudaFuncAttributeMaxDynamicSharedMemorySize,
                         GEMM_SMEM_BYTES);

    __nv_bfloat16 *xh, *xl;
    cudaGetSymbolAddress((void**)&xh, g_xh);
    cudaGetSymbolAddress((void**)&xl, g_xl);

    colsum_kernel<<<dim3(Lc / 256, 2), 256>>>(p_mat, r_mat);
    coords_kernel<<<(Bc * Lc) / 128, 128>>>(t_enc, Wt, bt);
    split_kernel<<<(Bc * Lc * Dc) / (256 * 4), 256>>>(x, xh, xl);
    split_w_kernel<<<dim3((Dc * Dc) / (256 * 4), 4), 256>>>(WQ, WK, WV, WO);
    qkv_mma<<<dim3(Dc / 128, (Bc * Lc) / 128, 3), 128, GEMM_SMEM_BYTES>>>();
    attn_mma<<<dim3(Lc / 128, Bc * Hc), 256, ATTN_SMEM_BYTES>>>(alpha, beta, gamma);
    out_mma<<<dim3(Dc / 128, (Bc * Lc) / 128), 128, GEMM_SMEM_BYTES>>>(bO, out);
}

// round 10
// speedup vs baseline: 2.6894x; 1.0523x over previous
#include <cuda_runtime.h>
#include <cuda_bf16.h>
#include <math.h>
#include <stdint.h>

#define Bc 4
#define Lc 1024
#define Dc 1024
#define Hc 16
#define Tc 64
#define dc 64
#define BHLD (Bc*Hc*Lc*dc)   /* 4,194,304 */

// ---------------- scratch ----------------
__device__ float g_coords[Bc * Lc];
__device__ float g_qsca[Bc * Lc];
__device__ float g_psum[Lc];
__device__ float g_rsum[Lc];
__device__ __nv_bfloat16 g_xh[Bc*Lc*Dc], g_xl[Bc*Lc*Dc];     // x
__device__ __nv_bfloat16 g_wh[4*Dc*Dc],  g_wl[4*Dc*Dc];      // WQ|WK|WV|WO
__device__ __nv_bfloat16 g_qh[BHLD], g_ql[BHLD];             // Q*0.125 (b,h,l,d)
__device__ __nv_bfloat16 g_kh[BHLD], g_kl[BHLD];             // K (b,h,l,d)
__device__ __nv_bfloat16 g_vth[BHLD], g_vtl[BHLD];           // V^T (b,h,d,l)
__device__ __nv_bfloat16 g_oh[Bc*Lc*Dc], g_ol[Bc*Lc*Dc];     // attn out (b,l,D)

__device__ __forceinline__ uint32_t pack_bf16(float lo, float hi) {
    __nv_bfloat162 r = __floats2bfloat162_rn(lo, hi);
    return *(uint32_t*)&r;
}
__device__ __forceinline__ float bf_hi(float v) {
    return __bfloat162float(__float2bfloat16(v));
}
__device__ __forceinline__ uint32_t smem_u32(const void* p) {
    uint32_t a;
    asm("{ .reg .u64 t; cvta.to.shared.u64 t, %1; cvt.u32.u64 %0, t; }" : "=r"(a) : "l"(p));
    return a;
}
__device__ __forceinline__ void cp16(uint32_t dst, const void* src) {
    asm volatile("cp.async.cg.shared.global [%0], [%1], 16;" :: "r"(dst), "l"(src));
}
#define CP_COMMIT() asm volatile("cp.async.commit_group;" ::: "memory")
#define CP_WAIT0()  asm volatile("cp.async.wait_group 0;"  ::: "memory")
#define CP_WAIT1()  asm volatile("cp.async.wait_group 1;"  ::: "memory")
#define CP_WAIT2()  asm volatile("cp.async.wait_group 2;"  ::: "memory")

// ---------------- kernel 0: column sums ----------------
__global__ void colsum_kernel(const float* __restrict__ p_mat,
                              const float* __restrict__ r_mat) {
    int l = blockIdx.x * blockDim.x + threadIdx.x;
    if (l >= Lc) return;
    const float* src = blockIdx.y ? r_mat : p_mat;
    float s = 0.f;
#pragma unroll 8
    for (int dd = 0; dd < Dc; dd++) s += src[dd * Lc + l];
    if (blockIdx.y) g_rsum[l] = s; else g_psum[l] = s;
}

// ---------------- kernel 1: coords + cubic q_sca ----------------
__global__ void coords_kernel(const float* __restrict__ t_enc,
                              const float* __restrict__ Wt,
                              const float* __restrict__ bt) {
    int n = blockIdx.x * blockDim.x + threadIdx.x;
    if (n >= Bc * Lc) return;
    float z = bt[0];
    const float* te = t_enc + (size_t)n * Tc;
#pragma unroll
    for (int k = 0; k < Tc; k++) z += te[k] * Wt[k];
    float tau = 1.f / (1.f + expf(-z));
    float c = tau * (float)(Lc - 1);
    g_coords[n] = c;
    int i = (int)floorf(c);
    float t = c - (float)i;
    int im1 = min(max(i - 1, 0), Lc - 1);
    int ii0 = min(max(i,     0), Lc - 1);
    int ii1 = min(max(i + 1, 0), Lc - 1);
    int ii2 = min(max(i + 2, 0), Lc - 1);
    float p0 = g_psum[im1], p1 = g_psum[ii0], p2 = g_psum[ii1], p3 = g_psum[ii2];
    float t2 = t * t, t3 = t2 * t;
    g_qsca[n] = 0.5f * (2.f * p1 + (-p0 + p2) * t
              + (2.f * p0 - 5.f * p1 + 4.f * p2 - p3) * t2
              + (-p0 + 3.f * p1 - 3.f * p2 + p3) * t3);
}

// ---------------- split fp32 -> bf16 hi + lo ----------------
__global__ void split_kernel(const float* __restrict__ s,
                             __nv_bfloat16* __restrict__ h,
                             __nv_bfloat16* __restrict__ l) {
    int i = (blockIdx.x * blockDim.x + threadIdx.x) * 4;
    float4 v = *(const float4*)(s + i);
    float h0 = bf_hi(v.x), h1 = bf_hi(v.y), h2 = bf_hi(v.z), h3 = bf_hi(v.w);
    uint2 H = make_uint2(pack_bf16(h0, h1), pack_bf16(h2, h3));
    uint2 L = make_uint2(pack_bf16(v.x - h0, v.y - h1), pack_bf16(v.z - h2, v.w - h3));
    *(uint2*)(h + i) = H;
    *(uint2*)(l + i) = L;
}
__global__ void split_w_kernel(const float* __restrict__ WQ, const float* __restrict__ WK,
                               const float* __restrict__ WV, const float* __restrict__ WO) {
    const float* src = (blockIdx.y == 0) ? WQ : (blockIdx.y == 1) ? WK
                     : (blockIdx.y == 2) ? WV : WO;
    size_t off = (size_t)blockIdx.y << 20;
    int i = (blockIdx.x * blockDim.x + threadIdx.x) * 4;
    float4 v = *(const float4*)(src + i);
    float h0 = bf_hi(v.x), h1 = bf_hi(v.y), h2 = bf_hi(v.z), h3 = bf_hi(v.w);
    uint2 H = make_uint2(pack_bf16(h0, h1), pack_bf16(h2, h3));
    uint2 L = make_uint2(pack_bf16(v.x - h0, v.y - h1), pack_bf16(v.z - h2, v.w - h3));
    *(uint2*)(g_wh + off + i) = H;
    *(uint2*)(g_wl + off + i) = L;
}

// ================= mma.sync bf16x3 GEMM core (unchanged from R9) =================
#define KP 40
#define SB (128 * KP)
#define STG (4 * SB)
#define GEMM_SMEM_BYTES (2 * STG * 2)   // 81920

__device__ __forceinline__ void hmma(float c[4], uint32_t a0, uint32_t a1, uint32_t a2,
                                     uint32_t a3, uint32_t b0, uint32_t b1) {
    asm volatile(
        "mma.sync.aligned.m16n8k16.row.col.f32.bf16.bf16.f32 "
        "{%0,%1,%2,%3}, {%4,%5,%6,%7}, {%8,%9}, {%0,%1,%2,%3};"
        : "+f"(c[0]), "+f"(c[1]), "+f"(c[2]), "+f"(c[3])
        : "r"(a0), "r"(a1), "r"(a2), "r"(a3), "r"(b0), "r"(b1));
}

__device__ __forceinline__ void gemm_gissue(uint32_t st32,
                                            const __nv_bfloat16* Ah, const __nv_bfloat16* Al,
                                            const __nv_bfloat16* Bh, const __nv_bfloat16* Bl,
                                            int k0) {
    int tid = threadIdx.x;
#pragma unroll
    for (int i = 0; i < 4; i++) {
        int v = tid + i * 128;
        int row = v >> 2, seg = v & 3;
        size_t gs = (size_t)row * Dc + k0 + seg * 8;
        uint32_t so = (uint32_t)((row * KP + seg * 8) * 2);
        cp16(st32 + so,              Ah + gs);
        cp16(st32 + SB * 2 + so,     Al + gs);
        cp16(st32 + 2 * SB * 2 + so, Bh + gs);
        cp16(st32 + 3 * SB * 2 + so, Bl + gs);
    }
}

__device__ __forceinline__ void mma_core(const __nv_bfloat16* Ah, const __nv_bfloat16* Al,
                                         const __nv_bfloat16* Bh, const __nv_bfloat16* Bl,
                                         __nv_bfloat16* S, float c[4][8][4]) {
    int lane = threadIdx.x & 31, w = threadIdx.x >> 5;
    int wm = w >> 1, wn = w & 1;
    int g = lane >> 2, t2 = (lane & 3) * 2;
    uint32_t s32 = smem_u32(S);
    gemm_gissue(s32, Ah, Al, Bh, Bl, 0);
    CP_COMMIT();
    gemm_gissue(s32 + STG * 2, Ah, Al, Bh, Bl, 32);
    CP_COMMIT();
    const int NCH = Dc / 32;
    for (int ch = 0; ch < NCH; ch++) {
        CP_WAIT1();
        __syncthreads();
        const __nv_bfloat16* st  = S + (ch & 1) * STG;
        const __nv_bfloat16* sAh = st;
        const __nv_bfloat16* sAl = st + SB;
        const __nv_bfloat16* sBh = st + 2 * SB;
        const __nv_bfloat16* sBl = st + 3 * SB;
#pragma unroll
        for (int ks = 0; ks < 32; ks += 16) {
            uint32_t ah[4][4], al[4][4];
#pragma unroll
            for (int mi = 0; mi < 4; mi++) {
                int r0 = (wm * 64 + mi * 16 + g) * KP + ks + t2;
                int r8 = r0 + 8 * KP;
                ah[mi][0] = *(const uint32_t*)(sAh + r0);
                ah[mi][1] = *(const uint32_t*)(sAh + r8);
                ah[mi][2] = *(const uint32_t*)(sAh + r0 + 8);
                ah[mi][3] = *(const uint32_t*)(sAh + r8 + 8);
                al[mi][0] = *(const uint32_t*)(sAl + r0);
                al[mi][1] = *(const uint32_t*)(sAl + r8);
                al[mi][2] = *(const uint32_t*)(sAl + r0 + 8);
                al[mi][3] = *(const uint32_t*)(sAl + r8 + 8);
            }
#pragma unroll
            for (int ni = 0; ni < 8; ni++) {
                int c0 = (wn * 64 + ni * 8 + g) * KP + ks + t2;
                uint32_t bh0 = *(const uint32_t*)(sBh + c0);
                uint32_t bh1 = *(const uint32_t*)(sBh + c0 + 8);
                uint32_t bl0 = *(const uint32_t*)(sBl + c0);
                uint32_t bl1 = *(const uint32_t*)(sBl + c0 + 8);
#pragma unroll
                for (int mi = 0; mi < 4; mi++) {
                    hmma(c[mi][ni], ah[mi][0], ah[mi][1], ah[mi][2], ah[mi][3], bh0, bh1);
                    hmma(c[mi][ni], ah[mi][0], ah[mi][1], ah[mi][2], ah[mi][3], bl0, bl1);
                    hmma(c[mi][ni], al[mi][0], al[mi][1], al[mi][2], al[mi][3], bh0, bh1);
                }
            }
        }
        __syncthreads();
        if (ch + 2 < NCH) {
            gemm_gissue(s32 + (ch & 1) * STG * 2, Ah, Al, Bh, Bl, (ch + 2) * 32);
            CP_COMMIT();
        }
    }
}

// ---------------- kernel 2: QKV projection ----------------
__global__ void __launch_bounds__(128, 2) qkv_mma() {
    extern __shared__ __nv_bfloat16 Sdyn[];
    int z = blockIdx.z;
    int M0 = blockIdx.y * 128, N0 = blockIdx.x * 128;
    const __nv_bfloat16* Ah = g_xh + (size_t)M0 * Dc;
    const __nv_bfloat16* Al = g_xl + (size_t)M0 * Dc;
    const __nv_bfloat16* Bh = g_wh + ((size_t)z << 20) + (size_t)N0 * Dc;
    const __nv_bfloat16* Bl = g_wl + ((size_t)z << 20) + (size_t)N0 * Dc;
    float c[4][8][4] = {};
    mma_core(Ah, Al, Bh, Bl, Sdyn, c);

    int lane = threadIdx.x & 31, w = threadIdx.x >> 5;
    int wm = w >> 1, wn = w & 1;
    int g = lane >> 2, t2 = (lane & 3) * 2;
    if (z < 2) {
        __nv_bfloat16* dh = z ? g_kh : g_qh;
        __nv_bfloat16* dl = z ? g_kl : g_ql;
        float qs = z ? 1.0f : 0.125f;
#pragma unroll
        for (int mi = 0; mi < 4; mi++)
#pragma unroll
            for (int ni = 0; ni < 8; ni++) {
                int col = N0 + wn * 64 + ni * 8 + t2;
                int h = col >> 6, dd = col & 63;
#pragma unroll
                for (int rh = 0; rh < 2; rh++) {
                    int row = M0 + wm * 64 + mi * 16 + g + rh * 8;
                    int bb = row >> 10, l = row & (Lc - 1);
                    float v0 = c[mi][ni][rh * 2] * qs, v1 = c[mi][ni][rh * 2 + 1] * qs;
                    float h0 = bf_hi(v0), h1 = bf_hi(v1);
                    size_t idx = (((size_t)(bb * Hc + h)) * Lc + l) * dc + dd;
                    *(uint32_t*)(dh + idx) = pack_bf16(h0, h1);
                    *(uint32_t*)(dl + idx) = pack_bf16(v0 - h0, v1 - h1);
                }
            }
    } else {
        uint16_t* sT = (uint16_t*)Sdyn;
#pragma unroll
        for (int mi = 0; mi < 4; mi++)
#pragma unroll
            for (int ni = 0; ni < 8; ni++) {
                int col_l = wn * 64 + ni * 8 + t2;
#pragma unroll
                for (int rh = 0; rh < 2; rh++) {
                    int row_l = wm * 64 + mi * 16 + g + rh * 8;
#pragma unroll
                    for (int cc = 0; cc < 2; cc++) {
                        float v = c[mi][ni][rh * 2 + cc];
                        __nv_bfloat16 vh = __float2bfloat16(v);
                        __nv_bfloat16 vl = __float2bfloat16(v - __bfloat162float(vh));
                        sT[(col_l + cc) * 136 + row_l]             = *(uint16_t*)&vh;
                        sT[128 * 136 + (col_l + cc) * 136 + row_l] = *(uint16_t*)&vl;
                    }
                }
            }
        __syncthreads();
        int bb = M0 >> 10, l0 = M0 & (Lc - 1);
#pragma unroll
        for (int q = 0; q < 16; q++) {
            int v = threadIdx.x + q * 128;
            int d = v >> 4, seg = v & 15;
            int col = N0 + d;
            int h = col >> 6, dd = col & 63;
            size_t dst = (((size_t)(bb * Hc + h)) * dc + dd) * Lc + l0 + seg * 8;
            *(uint4*)(g_vth + dst) = *(const uint4*)(sT + d * 136 + seg * 8);
            *(uint4*)(g_vtl + dst) = *(const uint4*)(sT + 128 * 136 + d * 136 + seg * 8);
        }
    }
}

// ---------------- kernel 4: output projection + bias ----------------
__global__ void __launch_bounds__(128, 2) out_mma(const float* __restrict__ bO,
                                                  float* __restrict__ out) {
    extern __shared__ __nv_bfloat16 Sdyn[];
    int M0 = blockIdx.y * 128, N0 = blockIdx.x * 128;
    const __nv_bfloat16* Ah = g_oh + (size_t)M0 * Dc;
    const __nv_bfloat16* Al = g_ol + (size_t)M0 * Dc;
    const __nv_bfloat16* Bh = g_wh + ((size_t)3 << 20) + (size_t)N0 * Dc;
    const __nv_bfloat16* Bl = g_wl + ((size_t)3 << 20) + (size_t)N0 * Dc;
    float c[4][8][4] = {};
    mma_core(Ah, Al, Bh, Bl, Sdyn, c);

    int lane = threadIdx.x & 31, w = threadIdx.x >> 5;
    int wm = w >> 1, wn = w & 1;
    int g = lane >> 2, t2 = (lane & 3) * 2;
#pragma unroll
    for (int mi = 0; mi < 4; mi++)
#pragma unroll
        for (int ni = 0; ni < 8; ni++) {
            int col = N0 + wn * 64 + ni * 8 + t2;
            float2 bv = *(const float2*)(bO + col);
#pragma unroll
            for (int rh = 0; rh < 2; rh++) {
                int row = M0 + wm * 64 + mi * 16 + g + rh * 8;
                float2 v = make_float2(c[mi][ni][rh * 2] + bv.x,
                                       c[mi][ni][rh * 2 + 1] + bv.y);
                *(float2*)(out + (size_t)row * Dc + col) = v;
            }
        }
}

// ---------------- kernel 3: flash attention ----------------
// 256 thr / 8 warps. NO i-tile smem (frags loaded direct from global).
// 4-stage swizzled j-ring: 6 buffers x 64x64 bf16 (pitch 64, XOR (row&7)<<4 on 16B units).
#define JROWB 128                       // bytes per j-buffer row
#define JBUFB (64 * JROWB)              // 8192 B per buffer
#define JSTGB (6 * JBUFB)               // 49152 B per stage
#define NSTG 4
#define ATTN_SMEM_BYTES (NSTG * JSTGB + (Lc + NSTG * 64 * 2) * 4)

__device__ __forceinline__ uint32_t jswz(int row, int byte_in_row) {
    return (uint32_t)(row * JROWB + (byte_in_row ^ ((row & 7) << 4)));
}

__global__ void __launch_bounds__(256, 1) attn_mma(const float* __restrict__ alpha,
                                                   const float* __restrict__ beta,
                                                   const float* __restrict__ gamma) {
    extern __shared__ __nv_bfloat16 smb[];
    __nv_bfloat16* jbase = smb;
    float* sR  = (float*)((char*)smb + NSTG * JSTGB);
    float* sCj = sR + Lc;                 // [NSTG][64]
    float* sQj = sCj + NSTG * 64;         // [NSTG][64]

    uint32_t jb32 = smem_u32(jbase);

    int t = threadIdx.x;
    int w = t >> 5, lane = t & 31;
    int g = lane >> 2, t2 = (lane & 3) * 2;
    int bh = blockIdx.y;
    int b = bh >> 4, h = bh & 15;
    int i0 = blockIdx.x * 128;

    float a_h = alpha[h], b_h = beta[h], c_h = gamma[h];

    const size_t qoff = ((size_t)bh * Lc) * dc;
    const size_t xoff = ((size_t)b * Lc) * Dc + h * dc;
    const size_t voff = (size_t)bh * dc * Lc;

    for (int idx = t; idx < Lc; idx += 256) sR[idx] = g_rsum[idx];

    // issue j-stage st for tile jt (row = j-local 0..63)
    auto issue_stage = [&](int jt, int st) {
        uint32_t s32 = jb32 + (uint32_t)st * JSTGB;
        int j0 = jt * 64;
#pragma unroll
        for (int q = 0; q < 2; q++) {
            int v = t * 2 + q;
            int row = v >> 3, seg = v & 7;
            uint32_t boff = jswz(row, seg * 16);
            size_t gk = qoff + (size_t)(j0 + row) * dc + seg * 8;
            size_t gx = xoff + (size_t)(j0 + row) * Dc + seg * 8;
            size_t gv = voff + (size_t)row * Lc + j0 + seg * 8;
            cp16(s32 + 0 * JBUFB + boff, g_kh  + gk);
            cp16(s32 + 1 * JBUFB + boff, g_kl  + gk);
            cp16(s32 + 2 * JBUFB + boff, g_xh  + gx);
            cp16(s32 + 3 * JBUFB + boff, g_xl  + gx);
            cp16(s32 + 4 * JBUFB + boff, g_vth + gv);
            cp16(s32 + 5 * JBUFB + boff, g_vtl + gv);
        }
        CP_COMMIT();
        if (t < 64) {
            sCj[st * 64 + t] = g_coords[b * Lc + j0 + t];
            sQj[st * 64 + t] = a_h * g_qsca[b * Lc + j0 + t];
        }
    };
    issue_stage(0, 0);
    issue_stage(1, 1);
    issue_stage(2, 2);

    // i-side fragments direct from global (loop-invariant)
    uint32_t fqh[16], fql[16], fph[16], fpl[16];
    {
        int r0 = i0 + 16 * w + g;
#pragma unroll
        for (int ks4 = 0; ks4 < 4; ks4++) {
            int cc0 = ks4 * 16 + t2;
            size_t q0 = qoff + (size_t)r0 * dc + cc0;
            size_t q8 = qoff + (size_t)(r0 + 8) * dc + cc0;
            size_t x0 = xoff + (size_t)r0 * Dc + cc0;
            size_t x8 = xoff + (size_t)(r0 + 8) * Dc + cc0;
            fqh[ks4*4+0] = *(const uint32_t*)(g_qh + q0);
            fqh[ks4*4+1] = *(const uint32_t*)(g_qh + q8);
            fqh[ks4*4+2] = *(const uint32_t*)(g_qh + q0 + 8);
            fqh[ks4*4+3] = *(const uint32_t*)(g_qh + q8 + 8);
            fql[ks4*4+0] = *(const uint32_t*)(g_ql + q0);
            fql[ks4*4+1] = *(const uint32_t*)(g_ql + q8);
            fql[ks4*4+2] = *(const uint32_t*)(g_ql + q0 + 8);
            fql[ks4*4+3] = *(const uint32_t*)(g_ql + q8 + 8);
            fph[ks4*4+0] = *(const uint32_t*)(g_xh + x0);
            fph[ks4*4+1] = *(const uint32_t*)(g_xh + x8);
            fph[ks4*4+2] = *(const uint32_t*)(g_xh + x0 + 8);
            fph[ks4*4+3] = *(const uint32_t*)(g_xh + x8 + 8);
            fpl[ks4*4+0] = *(const uint32_t*)(g_xl + x0);
            fpl[ks4*4+1] = *(const uint32_t*)(g_xl + x8);
            fpl[ks4*4+2] = *(const uint32_t*)(g_xl + x0 + 8);
            fpl[ks4*4+3] = *(const uint32_t*)(g_xl + x8 + 8);
        }
    }
    float ci_r[2], qi_r[2];
    {
        int r0 = i0 + 16 * w + g;
        ci_r[0] = g_coords[b * Lc + r0];
        ci_r[1] = g_coords[b * Lc + r0 + 8];
        qi_r[0] = fmaf(a_h, g_qsca[b * Lc + r0], c_h);
        qi_r[1] = fmaf(a_h, g_qsca[b * Lc + r0 + 8], c_h);
    }

    float oacc[8][4] = {};
    float m_run[2] = {-INFINITY, -INFINITY}, l_run[2] = {0.f, 0.f};

    for (int jt = 0; jt < 16; jt++) {
        int st = jt & (NSTG - 1);
        if (jt <= 13) CP_WAIT2();
        else if (jt == 14) CP_WAIT1();
        else CP_WAIT0();
        __syncthreads();

        const __nv_bfloat16* js = jbase + (size_t)st * (JSTGB / 2);
        const char* cKh = (const char*)js;
        const char* cKl = cKh + JBUFB;
        const char* cJh = cKl + JBUFB;
        const char* cJl = cJh + JBUFB;
        const char* cVh = cJl + JBUFB;
        const char* cVl = cVh + JBUFB;
        const float* cjp = sCj + st * 64;
        const float* qjp = sQj + st * 64;

        // ---- QK^T and PP^T ----
        float cS[8][4] = {}, cP[8][4] = {};
#pragma unroll
        for (int ks4 = 0; ks4 < 4; ks4++) {
            int ks = ks4 * 16;
#pragma unroll
            for (int ni = 0; ni < 8; ni++) {
                int row = ni * 8 + g;
                uint32_t o0 = jswz(row, (ks + t2) * 2);
                uint32_t o1 = jswz(row, (ks + t2 + 8) * 2);
                uint32_t kh0 = *(const uint32_t*)(cKh + o0);
                uint32_t kh1 = *(const uint32_t*)(cKh + o1);
                uint32_t kl0 = *(const uint32_t*)(cKl + o0);
                uint32_t kl1 = *(const uint32_t*)(cKl + o1);
                uint32_t jh0 = *(const uint32_t*)(cJh + o0);
                uint32_t jh1 = *(const uint32_t*)(cJh + o1);
                uint32_t jl0 = *(const uint32_t*)(cJl + o0);
                uint32_t jl1 = *(const uint32_t*)(cJl + o1);
                hmma(cS[ni], fqh[ks4*4+0], fqh[ks4*4+1], fqh[ks4*4+2], fqh[ks4*4+3], kh0, kh1);
                hmma(cS[ni], fqh[ks4*4+0], fqh[ks4*4+1], fqh[ks4*4+2], fqh[ks4*4+3], kl0, kl1);
                hmma(cS[ni], fql[ks4*4+0], fql[ks4*4+1], fql[ks4*4+2], fql[ks4*4+3], kh0, kh1);
                hmma(cP[ni], fph[ks4*4+0], fph[ks4*4+1], fph[ks4*4+2], fph[ks4*4+3], jh0, jh1);
                hmma(cP[ni], fph[ks4*4+0], fph[ks4*4+1], fph[ks4*4+2], fph[ks4*4+3], jl0, jl1);
                hmma(cP[ni], fpl[ks4*4+0], fpl[ks4*4+1], fpl[ks4*4+2], fpl[ks4*4+3], jh0, jh1);
            }
        }

        // ---- bias + online softmax ----
        float scale[2];
#pragma unroll
        for (int rh = 0; rh < 2; rh++) {
            float ci = ci_r[rh], base_i = qi_r[rh];
            float rmax = -INFINITY;
#pragma unroll
            for (int ni = 0; ni < 8; ni++)
#pragma unroll
                for (int cc = 0; cc < 2; cc++) {
                    int col = ni * 8 + t2 + cc;
                    float delta = fabsf(ci - cjp[col]);
                    int   di = (int)delta;
                    float tt = delta - (float)di;
                    int d0 = min(di,     Lc - 1);
                    int d1 = min(di + 1, Lc - 1);
                    float r0 = sR[d0];
                    float r = fmaf(tt, sR[d1] - r0, r0);
                    float S = fmaf(b_h, r, base_i + qjp[col]);
                    float v = fmaf(S, cP[ni][rh * 2 + cc], cS[ni][rh * 2 + cc]);
                    cS[ni][rh * 2 + cc] = v;
                    rmax = fmaxf(rmax, v);
                }
            rmax = fmaxf(rmax, __shfl_xor_sync(0xffffffffu, rmax, 1));
            rmax = fmaxf(rmax, __shfl_xor_sync(0xffffffffu, rmax, 2));
            float mn = fmaxf(m_run[rh], rmax);
            float rsum = 0.f;
#pragma unroll
            for (int ni = 0; ni < 8; ni++)
#pragma unroll
                for (int cc = 0; cc < 2; cc++) {
                    float e = __expf(cS[ni][rh * 2 + cc] - mn);
                    cS[ni][rh * 2 + cc] = e;
                    rsum += e;
                }
            rsum += __shfl_xor_sync(0xffffffffu, rsum, 1);
            rsum += __shfl_xor_sync(0xffffffffu, rsum, 2);
            scale[rh] = __expf(m_run[rh] - mn);
            l_run[rh] = l_run[rh] * scale[rh] + rsum;
            m_run[rh] = mn;
        }
#pragma unroll
        for (int ni = 0; ni < 8; ni++) {
            oacc[ni][0] *= scale[0]; oacc[ni][1] *= scale[0];
            oacc[ni][2] *= scale[1]; oacc[ni][3] *= scale[1];
        }

        // ---- PV (C->A fragment identity), bf16x3 ----
#pragma unroll
        for (int kc = 0; kc < 4; kc++) {
            float v00 = cS[2*kc][0],   v01 = cS[2*kc][1];
            float v10 = cS[2*kc][2],   v11 = cS[2*kc][3];
            float v20 = cS[2*kc+1][0], v21 = cS[2*kc+1][1];
            float v30 = cS[2*kc+1][2], v31 = cS[2*kc+1][3];
            float h00 = bf_hi(v00), h01 = bf_hi(v01), h10 = bf_hi(v10), h11 = bf_hi(v11);
            float h20 = bf_hi(v20), h21 = bf_hi(v21), h30 = bf_hi(v30), h31 = bf_hi(v31);
            uint32_t aph0 = pack_bf16(h00, h01), aph1 = pack_bf16(h10, h11);
            uint32_t aph2 = pack_bf16(h20, h21), aph3 = pack_bf16(h30, h31);
            uint32_t apl0 = pack_bf16(v00 - h00, v01 - h01), apl1 = pack_bf16(v10 - h10, v11 - h11);
            uint32_t apl2 = pack_bf16(v20 - h20, v21 - h21), apl3 = pack_bf16(v30 - h30, v31 - h31);
#pragma unroll
            for (int ni = 0; ni < 8; ni++) {
                int row = ni * 8 + g;
                uint32_t o0 = jswz(row, (kc * 16 + t2) * 2);
                uint32_t o1 = jswz(row, (kc * 16 + t2 + 8) * 2);
                uint32_t vh0 = *(const uint32_t*)(cVh + o0);
                uint32_t vh1 = *(const uint32_t*)(cVh + o1);
                uint32_t vl0 = *(const uint32_t*)(cVl + o0);
                uint32_t vl1 = *(const uint32_t*)(cVl + o1);
                hmma(oacc[ni], aph0, aph1, aph2, aph3, vh0, vh1);
                hmma(oacc[ni], apl0, apl1, apl2, apl3, vh0, vh1);
                hmma(oacc[ni], aph0, aph1, aph2, aph3, vl0, vl1);
            }
        }

        // refill this ring slot (stage (jt+3)&3 == slot last read at jt-1; all warps
        // passed this iteration's top syncthreads after that, so safe)
        __syncthreads();
        if (jt + 3 < 16) issue_stage(jt + 3, (jt + 3) & (NSTG - 1));
    }

    // ---- epilogue ----
    float inv0 = 1.f / l_run[0], inv1 = 1.f / l_run[1];
#pragma unroll
    for (int rh = 0; rh < 2; rh++) {
        int row = i0 + 16 * w + g + rh * 8;
        float inv = rh ? inv1 : inv0;
        size_t base = ((size_t)(b * Lc) + row) * Dc + h * dc;
#pragma unroll
        for (int ni = 0; ni < 8; ni++) {
            float v0 = oacc[ni][rh * 2]     * inv;
            float v1 = oacc[ni][rh * 2 + 1] * inv;
            float h0 = bf_hi(v0), h1 = bf_hi(v1);
            size_t idx = base + ni * 8 + t2;
            *(uint32_t*)(g_oh + idx) = pack_bf16(h0, h1);
            *(uint32_t*)(g_ol + idx) = pack_bf16(v0 - h0, v1 - h1);
        }
    }
}

// ---------------- launch ----------------
extern "C" void kernel_launch(void* const* d_in, const int* in_sizes, int n_in,
                              void* d_out, int out_size) {
    const float* x     = (const float*)d_in[0];
    const float* t_enc = (const float*)d_in[1];
    const float* WQ    = (const float*)d_in[2];
    const float* WK    = (const float*)d_in[3];
    const float* WV    = (const float*)d_in[4];
    const float* WO    = (const float*)d_in[5];
    const float* bO    = (const float*)d_in[6];
    const float* Wt    = (const float*)d_in[7];
    const float* bt    = (const float*)d_in[8];
    const float* p_mat = (const float*)d_in[9];
    const float* r_mat = (const float*)d_in[10];
    const float* alpha = (const float*)d_in[11];
    const float* beta  = (const float*)d_in[12];
    const float* gamma = (const float*)d_in[13];
    float* out = (float*)d_out;

    cudaFuncSetAttribute(attn_mma, cudaFuncAttributeMaxDynamicSharedMemorySize,
                         ATTN_SMEM_BYTES);
    cudaFuncSetAttribute(qkv_mma, cudaFuncAttributeMaxDynamicSharedMemorySize,
                         GEMM_SMEM_BYTES);
    cudaFuncSetAttribute(out_mma, cudaFuncAttributeMaxDynamicSharedMemorySize,
                         GEMM_SMEM_BYTES);

    __nv_bfloat16 *xh, *xl;
    cudaGetSymbolAddress((void**)&xh, g_xh);
    cudaGetSymbolAddress((void**)&xl, g_xl);

    colsum_kernel<<<dim3(Lc / 256, 2), 256>>>(p_mat, r_mat);
    coords_kernel<<<(Bc * Lc) / 128, 128>>>(t_enc, Wt, bt);
    split_kernel<<<(Bc * Lc * Dc) / (256 * 4), 256>>>(x, xh, xl);
    split_w_kernel<<<dim3((Dc * Dc) / (256 * 4), 4), 256>>>(WQ, WK, WV, WO);
    qkv_mma<<<dim3(Dc / 128, (Bc * Lc) / 128, 3), 128, GEMM_SMEM_BYTES>>>();
    attn_mma<<<dim3(Lc / 128, Bc * Hc), 256, ATTN_SMEM_BYTES>>>(alpha, beta, gamma);
    out_mma<<<dim3(Dc / 128, (Bc * Lc) / 128), 128, GEMM_SMEM_BYTES>>>(bO, out);
}

// round 11
// speedup vs baseline: 2.7431x; 1.0200x over previous
#include <cuda_runtime.h>
#include <cuda_bf16.h>
#include <math.h>
#include <stdint.h>

#define Bc 4
#define Lc 1024
#define Dc 1024
#define Hc 16
#define Tc 64
#define dc 64
#define BHLD (Bc*Hc*Lc*dc)   /* 4,194,304 */

// ---------------- scratch ----------------
__device__ float g_coords[Bc * Lc];
__device__ float g_qsca[Bc * Lc];
__device__ float g_psum[Lc];
__device__ float g_rsum[Lc];
__device__ __nv_bfloat16 g_xh[Bc*Lc*Dc], g_xl[Bc*Lc*Dc];     // x
__device__ __nv_bfloat16 g_wh[4*Dc*Dc],  g_wl[4*Dc*Dc];      // WQ|WK|WV|WO
__device__ __nv_bfloat16 g_qh[BHLD], g_ql[BHLD];             // Q*0.125 (b,h,l,d)
__device__ __nv_bfloat16 g_kh[BHLD], g_kl[BHLD];             // K (b,h,l,d)
__device__ __nv_bfloat16 g_vth[BHLD], g_vtl[BHLD];           // V^T (b,h,d,l)
__device__ __nv_bfloat16 g_oh[Bc*Lc*Dc], g_ol[Bc*Lc*Dc];     // attn out (b,l,D)

__device__ __forceinline__ uint32_t pack_bf16(float lo, float hi) {
    __nv_bfloat162 r = __floats2bfloat162_rn(lo, hi);
    return *(uint32_t*)&r;
}
__device__ __forceinline__ float bf_hi(float v) {
    return __bfloat162float(__float2bfloat16(v));
}
__device__ __forceinline__ uint32_t smem_u32(const void* p) {
    uint32_t a;
    asm("{ .reg .u64 t; cvta.to.shared.u64 t, %1; cvt.u32.u64 %0, t; }" : "=r"(a) : "l"(p));
    return a;
}
__device__ __forceinline__ void cp16(uint32_t dst, const void* src) {
    asm volatile("cp.async.cg.shared.global [%0], [%1], 16;" :: "r"(dst), "l"(src));
}
#define CP_COMMIT() asm volatile("cp.async.commit_group;" ::: "memory")
#define CP_WAIT0()  asm volatile("cp.async.wait_group 0;"  ::: "memory")
#define CP_WAIT1()  asm volatile("cp.async.wait_group 1;"  ::: "memory")
#define CP_WAIT2()  asm volatile("cp.async.wait_group 2;"  ::: "memory")

__device__ __forceinline__ void ldsm4(uint32_t& r0, uint32_t& r1, uint32_t& r2,
                                      uint32_t& r3, uint32_t addr) {
    asm volatile("ldmatrix.sync.aligned.m8n8.x4.shared.b16 {%0,%1,%2,%3}, [%4];"
                 : "=r"(r0), "=r"(r1), "=r"(r2), "=r"(r3) : "r"(addr));
}

// ---------------- kernel 0: column sums ----------------
__global__ void colsum_kernel(const float* __restrict__ p_mat,
                              const float* __restrict__ r_mat) {
    int l = blockIdx.x * blockDim.x + threadIdx.x;
    if (l >= Lc) return;
    const float* src = blockIdx.y ? r_mat : p_mat;
    float s = 0.f;
#pragma unroll 8
    for (int dd = 0; dd < Dc; dd++) s += src[dd * Lc + l];
    if (blockIdx.y) g_rsum[l] = s; else g_psum[l] = s;
}

// ---------------- kernel 1: coords + cubic q_sca ----------------
__global__ void coords_kernel(const float* __restrict__ t_enc,
                              const float* __restrict__ Wt,
                              const float* __restrict__ bt) {
    int n = blockIdx.x * blockDim.x + threadIdx.x;
    if (n >= Bc * Lc) return;
    float z = bt[0];
    const float* te = t_enc + (size_t)n * Tc;
#pragma unroll
    for (int k = 0; k < Tc; k++) z += te[k] * Wt[k];
    float tau = 1.f / (1.f + expf(-z));
    float c = tau * (float)(Lc - 1);
    g_coords[n] = c;
    int i = (int)floorf(c);
    float t = c - (float)i;
    int im1 = min(max(i - 1, 0), Lc - 1);
    int ii0 = min(max(i,     0), Lc - 1);
    int ii1 = min(max(i + 1, 0), Lc - 1);
    int ii2 = min(max(i + 2, 0), Lc - 1);
    float p0 = g_psum[im1], p1 = g_psum[ii0], p2 = g_psum[ii1], p3 = g_psum[ii2];
    float t2 = t * t, t3 = t2 * t;
    g_qsca[n] = 0.5f * (2.f * p1 + (-p0 + p2) * t
              + (2.f * p0 - 5.f * p1 + 4.f * p2 - p3) * t2
              + (-p0 + 3.f * p1 - 3.f * p2 + p3) * t3);
}

// ---------------- split fp32 -> bf16 hi + lo ----------------
__global__ void split_kernel(const float* __restrict__ s,
                             __nv_bfloat16* __restrict__ h,
                             __nv_bfloat16* __restrict__ l) {
    int i = (blockIdx.x * blockDim.x + threadIdx.x) * 4;
    float4 v = *(const float4*)(s + i);
    float h0 = bf_hi(v.x), h1 = bf_hi(v.y), h2 = bf_hi(v.z), h3 = bf_hi(v.w);
    uint2 H = make_uint2(pack_bf16(h0, h1), pack_bf16(h2, h3));
    uint2 L = make_uint2(pack_bf16(v.x - h0, v.y - h1), pack_bf16(v.z - h2, v.w - h3));
    *(uint2*)(h + i) = H;
    *(uint2*)(l + i) = L;
}
__global__ void split_w_kernel(const float* __restrict__ WQ, const float* __restrict__ WK,
                               const float* __restrict__ WV, const float* __restrict__ WO) {
    const float* src = (blockIdx.y == 0) ? WQ : (blockIdx.y == 1) ? WK
                     : (blockIdx.y == 2) ? WV : WO;
    size_t off = (size_t)blockIdx.y << 20;
    int i = (blockIdx.x * blockDim.x + threadIdx.x) * 4;
    float4 v = *(const float4*)(src + i);
    float h0 = bf_hi(v.x), h1 = bf_hi(v.y), h2 = bf_hi(v.z), h3 = bf_hi(v.w);
    uint2 H = make_uint2(pack_bf16(h0, h1), pack_bf16(h2, h3));
    uint2 L = make_uint2(pack_bf16(v.x - h0, v.y - h1), pack_bf16(v.z - h2, v.w - h3));
    *(uint2*)(g_wh + off + i) = H;
    *(uint2*)(g_wl + off + i) = L;
}

// ================= mma.sync bf16x3 GEMM core (ldmatrix fragment loads) =================
#define KP 40
#define SB (128 * KP)
#define STG (4 * SB)
#define GEMM_SMEM_BYTES (2 * STG * 2)   // 81920

__device__ __forceinline__ void hmma(float c[4], uint32_t a0, uint32_t a1, uint32_t a2,
                                     uint32_t a3, uint32_t b0, uint32_t b1) {
    asm volatile(
        "mma.sync.aligned.m16n8k16.row.col.f32.bf16.bf16.f32 "
        "{%0,%1,%2,%3}, {%4,%5,%6,%7}, {%8,%9}, {%0,%1,%2,%3};"
        : "+f"(c[0]), "+f"(c[1]), "+f"(c[2]), "+f"(c[3])
        : "r"(a0), "r"(a1), "r"(a2), "r"(a3), "r"(b0), "r"(b1));
}

__device__ __forceinline__ void gemm_gissue(uint32_t st32,
                                            const __nv_bfloat16* Ah, const __nv_bfloat16* Al,
                                            const __nv_bfloat16* Bh, const __nv_bfloat16* Bl,
                                            int k0) {
    int tid = threadIdx.x;
#pragma unroll
    for (int i = 0; i < 4; i++) {
        int v = tid + i * 128;
        int row = v >> 2, seg = v & 3;
        size_t gs = (size_t)row * Dc + k0 + seg * 8;
        uint32_t so = (uint32_t)((row * KP + seg * 8) * 2);
        cp16(st32 + so,              Ah + gs);
        cp16(st32 + SB * 2 + so,     Al + gs);
        cp16(st32 + 2 * SB * 2 + so, Bh + gs);
        cp16(st32 + 3 * SB * 2 + so, Bl + gs);
    }
}

__device__ __forceinline__ void mma_core(const __nv_bfloat16* Ah, const __nv_bfloat16* Al,
                                         const __nv_bfloat16* Bh, const __nv_bfloat16* Bl,
                                         __nv_bfloat16* S, float c[4][8][4]) {
    int lane = threadIdx.x & 31, w = threadIdx.x >> 5;
    int wm = w >> 1, wn = w & 1;
    int quad = lane >> 3, lr = lane & 7;
    uint32_t s32 = smem_u32(S);

    // per-lane ldmatrix byte offsets within a buffer
    uint32_t aoff[4], boff[4];
#pragma unroll
    for (int mi = 0; mi < 4; mi++)
        aoff[mi] = (uint32_t)(((wm * 64 + mi * 16 + (quad & 1) * 8 + lr) * KP
                               + (quad >> 1) * 8) * 2);
#pragma unroll
    for (int p = 0; p < 4; p++)
        boff[p] = (uint32_t)(((wn * 64 + p * 16 + (quad >> 1) * 8 + lr) * KP
                              + (quad & 1) * 8) * 2);

    gemm_gissue(s32, Ah, Al, Bh, Bl, 0);
    CP_COMMIT();
    gemm_gissue(s32 + STG * 2, Ah, Al, Bh, Bl, 32);
    CP_COMMIT();
    const int NCH = Dc / 32;
    for (int ch = 0; ch < NCH; ch++) {
        CP_WAIT1();
        __syncthreads();
        uint32_t base = s32 + (ch & 1) * (STG * 2);
        uint32_t aAh = base, aAl = base + SB * 2;
        uint32_t aBh = base + 2 * SB * 2, aBl = base + 3 * SB * 2;
#pragma unroll
        for (int ks = 0; ks < 32; ks += 16) {
            uint32_t kb = (uint32_t)(ks * 2);
            uint32_t ah[4][4], al[4][4];
#pragma unroll
            for (int mi = 0; mi < 4; mi++) {
                ldsm4(ah[mi][0], ah[mi][1], ah[mi][2], ah[mi][3], aAh + aoff[mi] + kb);
                ldsm4(al[mi][0], al[mi][1], al[mi][2], al[mi][3], aAl + aoff[mi] + kb);
            }
            uint32_t bh[8][2], bl[8][2];
#pragma unroll
            for (int p = 0; p < 4; p++) {
                ldsm4(bh[2*p][0], bh[2*p][1], bh[2*p+1][0], bh[2*p+1][1], aBh + boff[p] + kb);
                ldsm4(bl[2*p][0], bl[2*p][1], bl[2*p+1][0], bl[2*p+1][1], aBl + boff[p] + kb);
            }
#pragma unroll
            for (int ni = 0; ni < 8; ni++)
#pragma unroll
                for (int mi = 0; mi < 4; mi++) {
                    hmma(c[mi][ni], ah[mi][0], ah[mi][1], ah[mi][2], ah[mi][3],
                         bh[ni][0], bh[ni][1]);
                    hmma(c[mi][ni], ah[mi][0], ah[mi][1], ah[mi][2], ah[mi][3],
                         bl[ni][0], bl[ni][1]);
                    hmma(c[mi][ni], al[mi][0], al[mi][1], al[mi][2], al[mi][3],
                         bh[ni][0], bh[ni][1]);
                }
        }
        __syncthreads();
        if (ch + 2 < NCH) {
            gemm_gissue(s32 + (ch & 1) * (STG * 2), Ah, Al, Bh, Bl, (ch + 2) * 32);
            CP_COMMIT();
        }
    }
}

// ---------------- kernel 2: QKV projection ----------------
__global__ void __launch_bounds__(128, 2) qkv_mma() {
    extern __shared__ __nv_bfloat16 Sdyn[];
    int z = blockIdx.z;
    int M0 = blockIdx.y * 128, N0 = blockIdx.x * 128;
    const __nv_bfloat16* Ah = g_xh + (size_t)M0 * Dc;
    const __nv_bfloat16* Al = g_xl + (size_t)M0 * Dc;
    const __nv_bfloat16* Bh = g_wh + ((size_t)z << 20) + (size_t)N0 * Dc;
    const __nv_bfloat16* Bl = g_wl + ((size_t)z << 20) + (size_t)N0 * Dc;
    float c[4][8][4] = {};
    mma_core(Ah, Al, Bh, Bl, Sdyn, c);

    int lane = threadIdx.x & 31, w = threadIdx.x >> 5;
    int wm = w >> 1, wn = w & 1;
    int g = lane >> 2, t2 = (lane & 3) * 2;
    if (z < 2) {
        __nv_bfloat16* dh = z ? g_kh : g_qh;
        __nv_bfloat16* dl = z ? g_kl : g_ql;
        float qs = z ? 1.0f : 0.125f;
#pragma unroll
        for (int mi = 0; mi < 4; mi++)
#pragma unroll
            for (int ni = 0; ni < 8; ni++) {
                int col = N0 + wn * 64 + ni * 8 + t2;
                int h = col >> 6, dd = col & 63;
#pragma unroll
                for (int rh = 0; rh < 2; rh++) {
                    int row = M0 + wm * 64 + mi * 16 + g + rh * 8;
                    int bb = row >> 10, l = row & (Lc - 1);
                    float v0 = c[mi][ni][rh * 2] * qs, v1 = c[mi][ni][rh * 2 + 1] * qs;
                    float h0 = bf_hi(v0), h1 = bf_hi(v1);
                    size_t idx = (((size_t)(bb * Hc + h)) * Lc + l) * dc + dd;
                    *(uint32_t*)(dh + idx) = pack_bf16(h0, h1);
                    *(uint32_t*)(dl + idx) = pack_bf16(v0 - h0, v1 - h1);
                }
            }
    } else {
        uint16_t* sT = (uint16_t*)Sdyn;
#pragma unroll
        for (int mi = 0; mi < 4; mi++)
#pragma unroll
            for (int ni = 0; ni < 8; ni++) {
                int col_l = wn * 64 + ni * 8 + t2;
#pragma unroll
                for (int rh = 0; rh < 2; rh++) {
                    int row_l = wm * 64 + mi * 16 + g + rh * 8;
#pragma unroll
                    for (int cc = 0; cc < 2; cc++) {
                        float v = c[mi][ni][rh * 2 + cc];
                        __nv_bfloat16 vh = __float2bfloat16(v);
                        __nv_bfloat16 vl = __float2bfloat16(v - __bfloat162float(vh));
                        sT[(col_l + cc) * 136 + row_l]             = *(uint16_t*)&vh;
                        sT[128 * 136 + (col_l + cc) * 136 + row_l] = *(uint16_t*)&vl;
                    }
                }
            }
        __syncthreads();
        int bb = M0 >> 10, l0 = M0 & (Lc - 1);
#pragma unroll
        for (int q = 0; q < 16; q++) {
            int v = threadIdx.x + q * 128;
            int d = v >> 4, seg = v & 15;
            int col = N0 + d;
            int h = col >> 6, dd = col & 63;
            size_t dst = (((size_t)(bb * Hc + h)) * dc + dd) * Lc + l0 + seg * 8;
            *(uint4*)(g_vth + dst) = *(const uint4*)(sT + d * 136 + seg * 8);
            *(uint4*)(g_vtl + dst) = *(const uint4*)(sT + 128 * 136 + d * 136 + seg * 8);
        }
    }
}

// ---------------- kernel 4: output projection + bias ----------------
__global__ void __launch_bounds__(128, 2) out_mma(const float* __restrict__ bO,
                                                  float* __restrict__ out) {
    extern __shared__ __nv_bfloat16 Sdyn[];
    int M0 = blockIdx.y * 128, N0 = blockIdx.x * 128;
    const __nv_bfloat16* Ah = g_oh + (size_t)M0 * Dc;
    const __nv_bfloat16* Al = g_ol + (size_t)M0 * Dc;
    const __nv_bfloat16* Bh = g_wh + ((size_t)3 << 20) + (size_t)N0 * Dc;
    const __nv_bfloat16* Bl = g_wl + ((size_t)3 << 20) + (size_t)N0 * Dc;
    float c[4][8][4] = {};
    mma_core(Ah, Al, Bh, Bl, Sdyn, c);

    int lane = threadIdx.x & 31, w = threadIdx.x >> 5;
    int wm = w >> 1, wn = w & 1;
    int g = lane >> 2, t2 = (lane & 3) * 2;
#pragma unroll
    for (int mi = 0; mi < 4; mi++)
#pragma unroll
        for (int ni = 0; ni < 8; ni++) {
            int col = N0 + wn * 64 + ni * 8 + t2;
            float2 bv = *(const float2*)(bO + col);
#pragma unroll
            for (int rh = 0; rh < 2; rh++) {
                int row = M0 + wm * 64 + mi * 16 + g + rh * 8;
                float2 v = make_float2(c[mi][ni][rh * 2] + bv.x,
                                       c[mi][ni][rh * 2 + 1] + bv.y);
                *(float2*)(out + (size_t)row * Dc + col) = v;
            }
        }
}

// ---------------- kernel 3: flash attention (ldmatrix j-side) ----------------
#define JROWB 128
#define JBUFB (64 * JROWB)
#define JSTGB (6 * JBUFB)
#define NSTG 4
#define ATTN_SMEM_BYTES (NSTG * JSTGB + (Lc + NSTG * 64 * 2) * 4)

__device__ __forceinline__ uint32_t jswz(int row, int byte_in_row) {
    return (uint32_t)(row * JROWB + (byte_in_row ^ ((row & 7) << 4)));
}

__global__ void __launch_bounds__(256, 1) attn_mma(const float* __restrict__ alpha,
                                                   const float* __restrict__ beta,
                                                   const float* __restrict__ gamma) {
    extern __shared__ __nv_bfloat16 smb[];
    __nv_bfloat16* jbase = smb;
    float* sR  = (float*)((char*)smb + NSTG * JSTGB);
    float* sCj = sR + Lc;
    float* sQj = sCj + NSTG * 64;

    uint32_t jb32 = smem_u32(jbase);

    int t = threadIdx.x;
    int w = t >> 5, lane = t & 31;
    int g = lane >> 2, t2 = (lane & 3) * 2;
    int quad = lane >> 3, lr = lane & 7;
    int bh = blockIdx.y;
    int b = bh >> 4, h = bh & 15;
    int i0 = blockIdx.x * 128;

    float a_h = alpha[h], b_h = beta[h], c_h = gamma[h];

    const size_t qoff = ((size_t)bh * Lc) * dc;
    const size_t xoff = ((size_t)b * Lc) * Dc + h * dc;
    const size_t voff = (size_t)bh * dc * Lc;

    for (int idx = t; idx < Lc; idx += 256) sR[idx] = g_rsum[idx];

    auto issue_stage = [&](int jt, int st) {
        uint32_t s32 = jb32 + (uint32_t)st * JSTGB;
        int j0 = jt * 64;
#pragma unroll
        for (int q = 0; q < 2; q++) {
            int v = t * 2 + q;
            int row = v >> 3, seg = v & 7;
            uint32_t boff = jswz(row, seg * 16);
            size_t gk = qoff + (size_t)(j0 + row) * dc + seg * 8;
            size_t gx = xoff + (size_t)(j0 + row) * Dc + seg * 8;
            size_t gv = voff + (size_t)row * Lc + j0 + seg * 8;
            cp16(s32 + 0 * JBUFB + boff, g_kh  + gk);
            cp16(s32 + 1 * JBUFB + boff, g_kl  + gk);
            cp16(s32 + 2 * JBUFB + boff, g_xh  + gx);
            cp16(s32 + 3 * JBUFB + boff, g_xl  + gx);
            cp16(s32 + 4 * JBUFB + boff, g_vth + gv);
            cp16(s32 + 5 * JBUFB + boff, g_vtl + gv);
        }
        CP_COMMIT();
        if (t < 64) {
            sCj[st * 64 + t] = g_coords[b * Lc + j0 + t];
            sQj[st * 64 + t] = a_h * g_qsca[b * Lc + j0 + t];
        }
    };
    issue_stage(0, 0);
    issue_stage(1, 1);
    issue_stage(2, 2);

    // ldmatrix per-lane offsets for j-buffers (B-pair pattern, swizzled)
    uint32_t jrow[4];
#pragma unroll
    for (int p = 0; p < 4; p++)
        jrow[p] = (uint32_t)((p * 16 + (quad >> 1) * 8 + lr) * JROWB);
    uint32_t jx16 = (uint32_t)((quad & 1) * 16);
    uint32_t xlr  = (uint32_t)(lr << 4);

    // i-side fragments direct from global (loop-invariant)
    uint32_t fqh[16], fql[16], fph[16], fpl[16];
    {
        int r0 = i0 + 16 * w + g;
#pragma unroll
        for (int ks4 = 0; ks4 < 4; ks4++) {
            int cc0 = ks4 * 16 + t2;
            size_t q0 = qoff + (size_t)r0 * dc + cc0;
            size_t q8 = qoff + (size_t)(r0 + 8) * dc + cc0;
            size_t x0 = xoff + (size_t)r0 * Dc + cc0;
            size_t x8 = xoff + (size_t)(r0 + 8) * Dc + cc0;
            fqh[ks4*4+0] = *(const uint32_t*)(g_qh + q0);
            fqh[ks4*4+1] = *(const uint32_t*)(g_qh + q8);
            fqh[ks4*4+2] = *(const uint32_t*)(g_qh + q0 + 8);
            fqh[ks4*4+3] = *(const uint32_t*)(g_qh + q8 + 8);
            fql[ks4*4+0] = *(const uint32_t*)(g_ql + q0);
            fql[ks4*4+1] = *(const uint32_t*)(g_ql + q8);
            fql[ks4*4+2] = *(const uint32_t*)(g_ql + q0 + 8);
            fql[ks4*4+3] = *(const uint32_t*)(g_ql + q8 + 8);
            fph[ks4*4+0] = *(const uint32_t*)(g_xh + x0);
            fph[ks4*4+1] = *(const uint32_t*)(g_xh + x8);
            fph[ks4*4+2] = *(const uint32_t*)(g_xh + x0 + 8);
            fph[ks4*4+3] = *(const uint32_t*)(g_xh + x8 + 8);
            fpl[ks4*4+0] = *(const uint32_t*)(g_xl + x0);
            fpl[ks4*4+1] = *(const uint32_t*)(g_xl + x8);
            fpl[ks4*4+2] = *(const uint32_t*)(g_xl + x0 + 8);
            fpl[ks4*4+3] = *(const uint32_t*)(g_xl + x8 + 8);
        }
    }
    float ci_r[2], qi_r[2];
    {
        int r0 = i0 + 16 * w + g;
        ci_r[0] = g_coords[b * Lc + r0];
        ci_r[1] = g_coords[b * Lc + r0 + 8];
        qi_r[0] = fmaf(a_h, g_qsca[b * Lc + r0], c_h);
        qi_r[1] = fmaf(a_h, g_qsca[b * Lc + r0 + 8], c_h);
    }

    float oacc[8][4] = {};
    float m_run[2] = {-INFINITY, -INFINITY}, l_run[2] = {0.f, 0.f};

    for (int jt = 0; jt < 16; jt++) {
        int st = jt & (NSTG - 1);
        if (jt <= 13) CP_WAIT2();
        else if (jt == 14) CP_WAIT1();
        else CP_WAIT0();
        __syncthreads();

        uint32_t stb = jb32 + (uint32_t)st * JSTGB;
        uint32_t aKh = stb, aKl = stb + JBUFB;
        uint32_t aJh = stb + 2 * JBUFB, aJl = stb + 3 * JBUFB;
        uint32_t aVh = stb + 4 * JBUFB, aVl = stb + 5 * JBUFB;
        const float* cjp = sCj + st * 64;
        const float* qjp = sQj + st * 64;

        // ---- QK^T and PP^T (ldmatrix B fragments) ----
        float cS[8][4] = {}, cP[8][4] = {};
#pragma unroll
        for (int ks4 = 0; ks4 < 4; ks4++) {
            uint32_t bb = (((uint32_t)(ks4 * 32) + jx16) ^ xlr);
#pragma unroll
            for (int p = 0; p < 4; p++) {
                uint32_t kh0, kh1, kh2, kh3, kl0, kl1, kl2, kl3;
                uint32_t jh0, jh1, jh2, jh3, jl0, jl1, jl2, jl3;
                ldsm4(kh0, kh1, kh2, kh3, aKh + jrow[p] + bb);
                ldsm4(kl0, kl1, kl2, kl3, aKl + jrow[p] + bb);
                ldsm4(jh0, jh1, jh2, jh3, aJh + jrow[p] + bb);
                ldsm4(jl0, jl1, jl2, jl3, aJl + jrow[p] + bb);
                hmma(cS[2*p],   fqh[ks4*4+0], fqh[ks4*4+1], fqh[ks4*4+2], fqh[ks4*4+3], kh0, kh1);
                hmma(cS[2*p],   fqh[ks4*4+0], fqh[ks4*4+1], fqh[ks4*4+2], fqh[ks4*4+3], kl0, kl1);
                hmma(cS[2*p],   fql[ks4*4+0], fql[ks4*4+1], fql[ks4*4+2], fql[ks4*4+3], kh0, kh1);
                hmma(cS[2*p+1], fqh[ks4*4+0], fqh[ks4*4+1], fqh[ks4*4+2], fqh[ks4*4+3], kh2, kh3);
                hmma(cS[2*p+1], fqh[ks4*4+0], fqh[ks4*4+1], fqh[ks4*4+2], fqh[ks4*4+3], kl2, kl3);
                hmma(cS[2*p+1], fql[ks4*4+0], fql[ks4*4+1], fql[ks4*4+2], fql[ks4*4+3], kh2, kh3);
                hmma(cP[2*p],   fph[ks4*4+0], fph[ks4*4+1], fph[ks4*4+2], fph[ks4*4+3], jh0, jh1);
                hmma(cP[2*p],   fph[ks4*4+0], fph[ks4*4+1], fph[ks4*4+2], fph[ks4*4+3], jl0, jl1);
                hmma(cP[2*p],   fpl[ks4*4+0], fpl[ks4*4+1], fpl[ks4*4+2], fpl[ks4*4+3], jh0, jh1);
                hmma(cP[2*p+1], fph[ks4*4+0], fph[ks4*4+1], fph[ks4*4+2], fph[ks4*4+3], jh2, jh3);
                hmma(cP[2*p+1], fph[ks4*4+0], fph[ks4*4+1], fph[ks4*4+2], fph[ks4*4+3], jl2, jl3);
                hmma(cP[2*p+1], fpl[ks4*4+0], fpl[ks4*4+1], fpl[ks4*4+2], fpl[ks4*4+3], jh2, jh3);
            }
        }

        // ---- bias + online softmax ----
        float scale[2];
#pragma unroll
        for (int rh = 0; rh < 2; rh++) {
            float ci = ci_r[rh], base_i = qi_r[rh];
            float rmax = -INFINITY;
#pragma unroll
            for (int ni = 0; ni < 8; ni++)
#pragma unroll
                for (int cc = 0; cc < 2; cc++) {
                    int col = ni * 8 + t2 + cc;
                    float delta = fabsf(ci - cjp[col]);
                    int   di = (int)delta;
                    float tt = delta - (float)di;
                    int d0 = min(di,     Lc - 1);
                    int d1 = min(di + 1, Lc - 1);
                    float r0 = sR[d0];
                    float r = fmaf(tt, sR[d1] - r0, r0);
                    float S = fmaf(b_h, r, base_i + qjp[col]);
                    float v = fmaf(S, cP[ni][rh * 2 + cc], cS[ni][rh * 2 + cc]);
                    cS[ni][rh * 2 + cc] = v;
                    rmax = fmaxf(rmax, v);
                }
            rmax = fmaxf(rmax, __shfl_xor_sync(0xffffffffu, rmax, 1));
            rmax = fmaxf(rmax, __shfl_xor_sync(0xffffffffu, rmax, 2));
            float mn = fmaxf(m_run[rh], rmax);
            float rsum = 0.f;
#pragma unroll
            for (int ni = 0; ni < 8; ni++)
#pragma unroll
                for (int cc = 0; cc < 2; cc++) {
                    float e = __expf(cS[ni][rh * 2 + cc] - mn);
                    cS[ni][rh * 2 + cc] = e;
                    rsum += e;
                }
            rsum += __shfl_xor_sync(0xffffffffu, rsum, 1);
            rsum += __shfl_xor_sync(0xffffffffu, rsum, 2);
            scale[rh] = __expf(m_run[rh] - mn);
            l_run[rh] = l_run[rh] * scale[rh] + rsum;
            m_run[rh] = mn;
        }
#pragma unroll
        for (int ni = 0; ni < 8; ni++) {
            oacc[ni][0] *= scale[0]; oacc[ni][1] *= scale[0];
            oacc[ni][2] *= scale[1]; oacc[ni][3] *= scale[1];
        }

        // ---- PV (C->A fragment identity), bf16x3, ldmatrix V ----
#pragma unroll
        for (int kc = 0; kc < 4; kc++) {
            float v00 = cS[2*kc][0],   v01 = cS[2*kc][1];
            float v10 = cS[2*kc][2],   v11 = cS[2*kc][3];
            float v20 = cS[2*kc+1][0], v21 = cS[2*kc+1][1];
            float v30 = cS[2*kc+1][2], v31 = cS[2*kc+1][3];
            float h00 = bf_hi(v00), h01 = bf_hi(v01), h10 = bf_hi(v10), h11 = bf_hi(v11);
            float h20 = bf_hi(v20), h21 = bf_hi(v21), h30 = bf_hi(v30), h31 = bf_hi(v31);
            uint32_t aph0 = pack_bf16(h00, h01), aph1 = pack_bf16(h10, h11);
            uint32_t aph2 = pack_bf16(h20, h21), aph3 = pack_bf16(h30, h31);
            uint32_t apl0 = pack_bf16(v00 - h00, v01 - h01), apl1 = pack_bf16(v10 - h10, v11 - h11);
            uint32_t apl2 = pack_bf16(v20 - h20, v21 - h21), apl3 = pack_bf16(v30 - h30, v31 - h31);
            uint32_t bb = (((uint32_t)(kc * 32) + jx16) ^ xlr);
#pragma unroll
            for (int p = 0; p < 4; p++) {
                uint32_t vh0, vh1, vh2, vh3, vl0, vl1, vl2, vl3;
                ldsm4(vh0, vh1, vh2, vh3, aVh + jrow[p] + bb);
                ldsm4(vl0, vl1, vl2, vl3, aVl + jrow[p] + bb);
                hmma(oacc[2*p],   aph0, aph1, aph2, aph3, vh0, vh1);
                hmma(oacc[2*p],   apl0, apl1, apl2, apl3, vh0, vh1);
                hmma(oacc[2*p],   aph0, aph1, aph2, aph3, vl0, vl1);
                hmma(oacc[2*p+1], aph0, aph1, aph2, aph3, vh2, vh3);
                hmma(oacc[2*p+1], apl0, apl1, apl2, apl3, vh2, vh3);
                hmma(oacc[2*p+1], aph0, aph1, aph2, aph3, vl2, vl3);
            }
        }

        __syncthreads();
        if (jt + 3 < 16) issue_stage(jt + 3, (jt + 3) & (NSTG - 1));
    }

    // ---- epilogue ----
    float inv0 = 1.f / l_run[0], inv1 = 1.f / l_run[1];
#pragma unroll
    for (int rh = 0; rh < 2; rh++) {
        int row = i0 + 16 * w + g + rh * 8;
        float inv = rh ? inv1 : inv0;
        size_t base = ((size_t)(b * Lc) + row) * Dc + h * dc;
#pragma unroll
        for (int ni = 0; ni < 8; ni++) {
            float v0 = oacc[ni][rh * 2]     * inv;
            float v1 = oacc[ni][rh * 2 + 1] * inv;
            float h0 = bf_hi(v0), h1 = bf_hi(v1);
            size_t idx = base + ni * 8 + t2;
            *(uint32_t*)(g_oh + idx) = pack_bf16(h0, h1);
            *(uint32_t*)(g_ol + idx) = pack_bf16(v0 - h0, v1 - h1);
        }
    }
}

// ---------------- launch ----------------
extern "C" void kernel_launch(void* const* d_in, const int* in_sizes, int n_in,
                              void* d_out, int out_size) {
    const float* x     = (const float*)d_in[0];
    const float* t_enc = (const float*)d_in[1];
    const float* WQ    = (const float*)d_in[2];
    const float* WK    = (const float*)d_in[3];
    const float* WV    = (const float*)d_in[4];
    const float* WO    = (const float*)d_in[5];
    const float* bO    = (const float*)d_in[6];
    const float* Wt    = (const float*)d_in[7];
    const float* bt    = (const float*)d_in[8];
    const float* p_mat = (const float*)d_in[9];
    const float* r_mat = (const float*)d_in[10];
    const float* alpha = (const float*)d_in[11];
    const float* beta  = (const float*)d_in[12];
    const float* gamma = (const float*)d_in[13];
    float* out = (float*)d_out;

    cudaFuncSetAttribute(attn_mma, cudaFuncAttributeMaxDynamicSharedMemorySize,
                         ATTN_SMEM_BYTES);
    cudaFuncSetAttribute(qkv_mma, cudaFuncAttributeMaxDynamicSharedMemorySize,
                         GEMM_SMEM_BYTES);
    cudaFuncSetAttribute(out_mma, cudaFuncAttributeMaxDynamicSharedMemorySize,
                         GEMM_SMEM_BYTES);

    __nv_bfloat16 *xh, *xl;
    cudaGetSymbolAddress((void**)&xh, g_xh);
    cudaGetSymbolAddress((void**)&xl, g_xl);

    colsum_kernel<<<dim3(Lc / 256, 2), 256>>>(p_mat, r_mat);
    coords_kernel<<<(Bc * Lc) / 128, 128>>>(t_enc, Wt, bt);
    split_kernel<<<(Bc * Lc * Dc) / (256 * 4), 256>>>(x, xh, xl);
    split_w_kernel<<<dim3((Dc * Dc) / (256 * 4), 4), 256>>>(WQ, WK, WV, WO);
    qkv_mma<<<dim3(Dc / 128, (Bc * Lc) / 128, 3), 128, GEMM_SMEM_BYTES>>>();
    attn_mma<<<dim3(Lc / 128, Bc * Hc), 256, ATTN_SMEM_BYTES>>>(alpha, beta, gamma);
    out_mma<<<dim3(Dc / 128, (Bc * Lc) / 128), 128, GEMM_SMEM_BYTES>>>(bO, out);
}

// round 12
// speedup vs baseline: 2.7893x; 1.0168x over previous
#include <cuda_runtime.h>
#include <cuda_bf16.h>
#include <math.h>
#include <stdint.h>

#define Bc 4
#define Lc 1024
#define Dc 1024
#define Hc 16
#define Tc 64
#define dc 64
#define BHLD (Bc*Hc*Lc*dc)   /* 4,194,304 */

// ---------------- scratch ----------------
__device__ float g_coords[Bc * Lc];
__device__ float g_qsca[Bc * Lc];
__device__ float g_psum[Lc];
__device__ float g_rsum[Lc];
__device__ __nv_bfloat16 g_xh[Bc*Lc*Dc], g_xl[Bc*Lc*Dc];     // x
__device__ __nv_bfloat16 g_wh[4*Dc*Dc],  g_wl[4*Dc*Dc];      // WQ|WK|WV|WO
__device__ __nv_bfloat16 g_qh[BHLD], g_ql[BHLD];             // Q*0.125 (b,h,l,d)
__device__ __nv_bfloat16 g_kh[BHLD], g_kl[BHLD];             // K (b,h,l,d)
__device__ __nv_bfloat16 g_vth[BHLD], g_vtl[BHLD];           // V^T (b,h,d,l)
__device__ __nv_bfloat16 g_oh[Bc*Lc*Dc], g_ol[Bc*Lc*Dc];     // attn out (b,l,D)

__device__ __forceinline__ uint32_t pack_bf16(float lo, float hi) {
    __nv_bfloat162 r = __floats2bfloat162_rn(lo, hi);
    return *(uint32_t*)&r;
}
__device__ __forceinline__ float bf_hi(float v) {
    return __bfloat162float(__float2bfloat16(v));
}
__device__ __forceinline__ uint32_t smem_u32(const void* p) {
    uint32_t a;
    asm("{ .reg .u64 t; cvta.to.shared.u64 t, %1; cvt.u32.u64 %0, t; }" : "=r"(a) : "l"(p));
    return a;
}
__device__ __forceinline__ void cp16(uint32_t dst, const void* src) {
    asm volatile("cp.async.cg.shared.global [%0], [%1], 16;" :: "r"(dst), "l"(src));
}
#define CP_COMMIT() asm volatile("cp.async.commit_group;" ::: "memory")
#define CP_WAIT0()  asm volatile("cp.async.wait_group 0;"  ::: "memory")
#define CP_WAIT1()  asm volatile("cp.async.wait_group 1;"  ::: "memory")
#define CP_WAIT2()  asm volatile("cp.async.wait_group 2;"  ::: "memory")

__device__ __forceinline__ void ldsm4(uint32_t& r0, uint32_t& r1, uint32_t& r2,
                                      uint32_t& r3, uint32_t addr) {
    asm volatile("ldmatrix.sync.aligned.m8n8.x4.shared.b16 {%0,%1,%2,%3}, [%4];"
                 : "=r"(r0), "=r"(r1), "=r"(r2), "=r"(r3) : "r"(addr));
}

// ---------------- kernel 0: column sums ----------------
__global__ void colsum_kernel(const float* __restrict__ p_mat,
                              const float* __restrict__ r_mat) {
    int l = blockIdx.x * blockDim.x + threadIdx.x;
    if (l >= Lc) return;
    const float* src = blockIdx.y ? r_mat : p_mat;
    float s = 0.f;
#pragma unroll 8
    for (int dd = 0; dd < Dc; dd++) s += src[dd * Lc + l];
    if (blockIdx.y) g_rsum[l] = s; else g_psum[l] = s;
}

// ---------------- kernel 1: coords + cubic q_sca ----------------
__global__ void coords_kernel(const float* __restrict__ t_enc,
                              const float* __restrict__ Wt,
                              const float* __restrict__ bt) {
    int n = blockIdx.x * blockDim.x + threadIdx.x;
    if (n >= Bc * Lc) return;
    float z = bt[0];
    const float* te = t_enc + (size_t)n * Tc;
#pragma unroll
    for (int k = 0; k < Tc; k++) z += te[k] * Wt[k];
    float tau = 1.f / (1.f + expf(-z));
    float c = tau * (float)(Lc - 1);
    g_coords[n] = c;
    int i = (int)floorf(c);
    float t = c - (float)i;
    int im1 = min(max(i - 1, 0), Lc - 1);
    int ii0 = min(max(i,     0), Lc - 1);
    int ii1 = min(max(i + 1, 0), Lc - 1);
    int ii2 = min(max(i + 2, 0), Lc - 1);
    float p0 = g_psum[im1], p1 = g_psum[ii0], p2 = g_psum[ii1], p3 = g_psum[ii2];
    float t2 = t * t, t3 = t2 * t;
    g_qsca[n] = 0.5f * (2.f * p1 + (-p0 + p2) * t
              + (2.f * p0 - 5.f * p1 + 4.f * p2 - p3) * t2
              + (-p0 + 3.f * p1 - 3.f * p2 + p3) * t3);
}

// ---------------- split fp32 -> bf16 hi + lo ----------------
__global__ void split_kernel(const float* __restrict__ s,
                             __nv_bfloat16* __restrict__ h,
                             __nv_bfloat16* __restrict__ l) {
    int i = (blockIdx.x * blockDim.x + threadIdx.x) * 4;
    float4 v = *(const float4*)(s + i);
    float h0 = bf_hi(v.x), h1 = bf_hi(v.y), h2 = bf_hi(v.z), h3 = bf_hi(v.w);
    uint2 H = make_uint2(pack_bf16(h0, h1), pack_bf16(h2, h3));
    uint2 L = make_uint2(pack_bf16(v.x - h0, v.y - h1), pack_bf16(v.z - h2, v.w - h3));
    *(uint2*)(h + i) = H;
    *(uint2*)(l + i) = L;
}
__global__ void split_w_kernel(const float* __restrict__ WQ, const float* __restrict__ WK,
                               const float* __restrict__ WV, const float* __restrict__ WO) {
    const float* src = (blockIdx.y == 0) ? WQ : (blockIdx.y == 1) ? WK
                     : (blockIdx.y == 2) ? WV : WO;
    size_t off = (size_t)blockIdx.y << 20;
    int i = (blockIdx.x * blockDim.x + threadIdx.x) * 4;
    float4 v = *(const float4*)(src + i);
    float h0 = bf_hi(v.x), h1 = bf_hi(v.y), h2 = bf_hi(v.z), h3 = bf_hi(v.w);
    uint2 H = make_uint2(pack_bf16(h0, h1), pack_bf16(h2, h3));
    uint2 L = make_uint2(pack_bf16(v.x - h0, v.y - h1), pack_bf16(v.z - h2, v.w - h3));
    *(uint2*)(g_wh + off + i) = H;
    *(uint2*)(g_wl + off + i) = L;
}

// ================= mma.sync bf16x3 GEMM core (term-major hmma ordering) =================
#define KP 40
#define SB (128 * KP)
#define STG (4 * SB)
#define GEMM_SMEM_BYTES (2 * STG * 2)   // 81920

__device__ __forceinline__ void hmma(float c[4], uint32_t a0, uint32_t a1, uint32_t a2,
                                     uint32_t a3, uint32_t b0, uint32_t b1) {
    asm volatile(
        "mma.sync.aligned.m16n8k16.row.col.f32.bf16.bf16.f32 "
        "{%0,%1,%2,%3}, {%4,%5,%6,%7}, {%8,%9}, {%0,%1,%2,%3};"
        : "+f"(c[0]), "+f"(c[1]), "+f"(c[2]), "+f"(c[3])
        : "r"(a0), "r"(a1), "r"(a2), "r"(a3), "r"(b0), "r"(b1));
}

__device__ __forceinline__ void gemm_gissue(uint32_t st32,
                                            const __nv_bfloat16* Ah, const __nv_bfloat16* Al,
                                            const __nv_bfloat16* Bh, const __nv_bfloat16* Bl,
                                            int k0) {
    int tid = threadIdx.x;
#pragma unroll
    for (int i = 0; i < 4; i++) {
        int v = tid + i * 128;
        int row = v >> 2, seg = v & 3;
        size_t gs = (size_t)row * Dc + k0 + seg * 8;
        uint32_t so = (uint32_t)((row * KP + seg * 8) * 2);
        cp16(st32 + so,              Ah + gs);
        cp16(st32 + SB * 2 + so,     Al + gs);
        cp16(st32 + 2 * SB * 2 + so, Bh + gs);
        cp16(st32 + 3 * SB * 2 + so, Bl + gs);
    }
}

__device__ __forceinline__ void mma_core(const __nv_bfloat16* Ah, const __nv_bfloat16* Al,
                                         const __nv_bfloat16* Bh, const __nv_bfloat16* Bl,
                                         __nv_bfloat16* S, float c[4][8][4]) {
    int lane = threadIdx.x & 31, w = threadIdx.x >> 5;
    int wm = w >> 1, wn = w & 1;
    int quad = lane >> 3, lr = lane & 7;
    uint32_t s32 = smem_u32(S);

    uint32_t aoff[4], boff[4];
#pragma unroll
    for (int mi = 0; mi < 4; mi++)
        aoff[mi] = (uint32_t)(((wm * 64 + mi * 16 + (quad & 1) * 8 + lr) * KP
                               + (quad >> 1) * 8) * 2);
#pragma unroll
    for (int p = 0; p < 4; p++)
        boff[p] = (uint32_t)(((wn * 64 + p * 16 + (quad >> 1) * 8 + lr) * KP
                              + (quad & 1) * 8) * 2);

    gemm_gissue(s32, Ah, Al, Bh, Bl, 0);
    CP_COMMIT();
    gemm_gissue(s32 + STG * 2, Ah, Al, Bh, Bl, 32);
    CP_COMMIT();
    const int NCH = Dc / 32;
    for (int ch = 0; ch < NCH; ch++) {
        CP_WAIT1();
        __syncthreads();
        uint32_t base = s32 + (ch & 1) * (STG * 2);
        uint32_t aAh = base, aAl = base + SB * 2;
        uint32_t aBh = base + 2 * SB * 2, aBl = base + 3 * SB * 2;
#pragma unroll
        for (int ks = 0; ks < 32; ks += 16) {
            uint32_t kb = (uint32_t)(ks * 2);
            uint32_t ah[4][4], al[4][4];
#pragma unroll
            for (int mi = 0; mi < 4; mi++) {
                ldsm4(ah[mi][0], ah[mi][1], ah[mi][2], ah[mi][3], aAh + aoff[mi] + kb);
                ldsm4(al[mi][0], al[mi][1], al[mi][2], al[mi][3], aAl + aoff[mi] + kb);
            }
            uint32_t bh[8][2], bl[8][2];
#pragma unroll
            for (int p = 0; p < 4; p++) {
                ldsm4(bh[2*p][0], bh[2*p][1], bh[2*p+1][0], bh[2*p+1][1], aBh + boff[p] + kb);
                ldsm4(bl[2*p][0], bl[2*p][1], bl[2*p+1][0], bl[2*p+1][1], aBl + boff[p] + kb);
            }
            // term-major: 32 independent accumulators between chain links
#pragma unroll
            for (int ni = 0; ni < 8; ni++)
#pragma unroll
                for (int mi = 0; mi < 4; mi++)
                    hmma(c[mi][ni], ah[mi][0], ah[mi][1], ah[mi][2], ah[mi][3],
                         bh[ni][0], bh[ni][1]);
#pragma unroll
            for (int ni = 0; ni < 8; ni++)
#pragma unroll
                for (int mi = 0; mi < 4; mi++)
                    hmma(c[mi][ni], ah[mi][0], ah[mi][1], ah[mi][2], ah[mi][3],
                         bl[ni][0], bl[ni][1]);
#pragma unroll
            for (int ni = 0; ni < 8; ni++)
#pragma unroll
                for (int mi = 0; mi < 4; mi++)
                    hmma(c[mi][ni], al[mi][0], al[mi][1], al[mi][2], al[mi][3],
                         bh[ni][0], bh[ni][1]);
        }
        __syncthreads();
        if (ch + 2 < NCH) {
            gemm_gissue(s32 + (ch & 1) * (STG * 2), Ah, Al, Bh, Bl, (ch + 2) * 32);
            CP_COMMIT();
        }
    }
}

// ---------------- kernel 2: QKV projection ----------------
__global__ void __launch_bounds__(128, 2) qkv_mma() {
    extern __shared__ __nv_bfloat16 Sdyn[];
    int z = blockIdx.z;
    int M0 = blockIdx.y * 128, N0 = blockIdx.x * 128;
    const __nv_bfloat16* Ah = g_xh + (size_t)M0 * Dc;
    const __nv_bfloat16* Al = g_xl + (size_t)M0 * Dc;
    const __nv_bfloat16* Bh = g_wh + ((size_t)z << 20) + (size_t)N0 * Dc;
    const __nv_bfloat16* Bl = g_wl + ((size_t)z << 20) + (size_t)N0 * Dc;
    float c[4][8][4] = {};
    mma_core(Ah, Al, Bh, Bl, Sdyn, c);

    int lane = threadIdx.x & 31, w = threadIdx.x >> 5;
    int wm = w >> 1, wn = w & 1;
    int g = lane >> 2, t2 = (lane & 3) * 2;
    if (z < 2) {
        __nv_bfloat16* dh = z ? g_kh : g_qh;
        __nv_bfloat16* dl = z ? g_kl : g_ql;
        float qs = z ? 1.0f : 0.125f;
#pragma unroll
        for (int mi = 0; mi < 4; mi++)
#pragma unroll
            for (int ni = 0; ni < 8; ni++) {
                int col = N0 + wn * 64 + ni * 8 + t2;
                int h = col >> 6, dd = col & 63;
#pragma unroll
                for (int rh = 0; rh < 2; rh++) {
                    int row = M0 + wm * 64 + mi * 16 + g + rh * 8;
                    int bb = row >> 10, l = row & (Lc - 1);
                    float v0 = c[mi][ni][rh * 2] * qs, v1 = c[mi][ni][rh * 2 + 1] * qs;
                    float h0 = bf_hi(v0), h1 = bf_hi(v1);
                    size_t idx = (((size_t)(bb * Hc + h)) * Lc + l) * dc + dd;
                    *(uint32_t*)(dh + idx) = pack_bf16(h0, h1);
                    *(uint32_t*)(dl + idx) = pack_bf16(v0 - h0, v1 - h1);
                }
            }
    } else {
        uint16_t* sT = (uint16_t*)Sdyn;
#pragma unroll
        for (int mi = 0; mi < 4; mi++)
#pragma unroll
            for (int ni = 0; ni < 8; ni++) {
                int col_l = wn * 64 + ni * 8 + t2;
#pragma unroll
                for (int rh = 0; rh < 2; rh++) {
                    int row_l = wm * 64 + mi * 16 + g + rh * 8;
#pragma unroll
                    for (int cc = 0; cc < 2; cc++) {
                        float v = c[mi][ni][rh * 2 + cc];
                        __nv_bfloat16 vh = __float2bfloat16(v);
                        __nv_bfloat16 vl = __float2bfloat16(v - __bfloat162float(vh));
                        sT[(col_l + cc) * 136 + row_l]             = *(uint16_t*)&vh;
                        sT[128 * 136 + (col_l + cc) * 136 + row_l] = *(uint16_t*)&vl;
                    }
                }
            }
        __syncthreads();
        int bb = M0 >> 10, l0 = M0 & (Lc - 1);
#pragma unroll
        for (int q = 0; q < 16; q++) {
            int v = threadIdx.x + q * 128;
            int d = v >> 4, seg = v & 15;
            int col = N0 + d;
            int h = col >> 6, dd = col & 63;
            size_t dst = (((size_t)(bb * Hc + h)) * dc + dd) * Lc + l0 + seg * 8;
            *(uint4*)(g_vth + dst) = *(const uint4*)(sT + d * 136 + seg * 8);
            *(uint4*)(g_vtl + dst) = *(const uint4*)(sT + 128 * 136 + d * 136 + seg * 8);
        }
    }
}

// ---------------- kernel 4: output projection + bias ----------------
__global__ void __launch_bounds__(128, 2) out_mma(const float* __restrict__ bO,
                                                  float* __restrict__ out) {
    extern __shared__ __nv_bfloat16 Sdyn[];
    int M0 = blockIdx.y * 128, N0 = blockIdx.x * 128;
    const __nv_bfloat16* Ah = g_oh + (size_t)M0 * Dc;
    const __nv_bfloat16* Al = g_ol + (size_t)M0 * Dc;
    const __nv_bfloat16* Bh = g_wh + ((size_t)3 << 20) + (size_t)N0 * Dc;
    const __nv_bfloat16* Bl = g_wl + ((size_t)3 << 20) + (size_t)N0 * Dc;
    float c[4][8][4] = {};
    mma_core(Ah, Al, Bh, Bl, Sdyn, c);

    int lane = threadIdx.x & 31, w = threadIdx.x >> 5;
    int wm = w >> 1, wn = w & 1;
    int g = lane >> 2, t2 = (lane & 3) * 2;
#pragma unroll
    for (int mi = 0; mi < 4; mi++)
#pragma unroll
        for (int ni = 0; ni < 8; ni++) {
            int col = N0 + wn * 64 + ni * 8 + t2;
            float2 bv = *(const float2*)(bO + col);
#pragma unroll
            for (int rh = 0; rh < 2; rh++) {
                int row = M0 + wm * 64 + mi * 16 + g + rh * 8;
                float2 v = make_float2(c[mi][ni][rh * 2] + bv.x,
                                       c[mi][ni][rh * 2 + 1] + bv.y);
                *(float2*)(out + (size_t)row * Dc + col) = v;
            }
        }
}

// ---------------- kernel 3: flash attention (term-grouped hmma) ----------------
#define JROWB 128
#define JBUFB (64 * JROWB)
#define JSTGB (6 * JBUFB)
#define NSTG 4
#define ATTN_SMEM_BYTES (NSTG * JSTGB + (Lc + NSTG * 64 * 2) * 4)

__device__ __forceinline__ uint32_t jswz(int row, int byte_in_row) {
    return (uint32_t)(row * JROWB + (byte_in_row ^ ((row & 7) << 4)));
}

__global__ void __launch_bounds__(256, 1) attn_mma(const float* __restrict__ alpha,
                                                   const float* __restrict__ beta,
                                                   const float* __restrict__ gamma) {
    extern __shared__ __nv_bfloat16 smb[];
    __nv_bfloat16* jbase = smb;
    float* sR  = (float*)((char*)smb + NSTG * JSTGB);
    float* sCj = sR + Lc;
    float* sQj = sCj + NSTG * 64;

    uint32_t jb32 = smem_u32(jbase);

    int t = threadIdx.x;
    int w = t >> 5, lane = t & 31;
    int g = lane >> 2, t2 = (lane & 3) * 2;
    int quad = lane >> 3, lr = lane & 7;
    int bh = blockIdx.y;
    int b = bh >> 4, h = bh & 15;
    int i0 = blockIdx.x * 128;

    float a_h = alpha[h], b_h = beta[h], c_h = gamma[h];

    const size_t qoff = ((size_t)bh * Lc) * dc;
    const size_t xoff = ((size_t)b * Lc) * Dc + h * dc;
    const size_t voff = (size_t)bh * dc * Lc;

    for (int idx = t; idx < Lc; idx += 256) sR[idx] = g_rsum[idx];

    auto issue_stage = [&](int jt, int st) {
        uint32_t s32 = jb32 + (uint32_t)st * JSTGB;
        int j0 = jt * 64;
#pragma unroll
        for (int q = 0; q < 2; q++) {
            int v = t * 2 + q;
            int row = v >> 3, seg = v & 7;
            uint32_t boff = jswz(row, seg * 16);
            size_t gk = qoff + (size_t)(j0 + row) * dc + seg * 8;
            size_t gx = xoff + (size_t)(j0 + row) * Dc + seg * 8;
            size_t gv = voff + (size_t)row * Lc + j0 + seg * 8;
            cp16(s32 + 0 * JBUFB + boff, g_kh  + gk);
            cp16(s32 + 1 * JBUFB + boff, g_kl  + gk);
            cp16(s32 + 2 * JBUFB + boff, g_xh  + gx);
            cp16(s32 + 3 * JBUFB + boff, g_xl  + gx);
            cp16(s32 + 4 * JBUFB + boff, g_vth + gv);
            cp16(s32 + 5 * JBUFB + boff, g_vtl + gv);
        }
        CP_COMMIT();
        if (t < 64) {
            sCj[st * 64 + t] = g_coords[b * Lc + j0 + t];
            sQj[st * 64 + t] = a_h * g_qsca[b * Lc + j0 + t];
        }
    };
    issue_stage(0, 0);
    issue_stage(1, 1);
    issue_stage(2, 2);

    uint32_t jrow[4];
#pragma unroll
    for (int p = 0; p < 4; p++)
        jrow[p] = (uint32_t)((p * 16 + (quad >> 1) * 8 + lr) * JROWB);
    uint32_t jx16 = (uint32_t)((quad & 1) * 16);
    uint32_t xlr  = (uint32_t)(lr << 4);

    uint32_t fqh[16], fql[16], fph[16], fpl[16];
    {
        int r0 = i0 + 16 * w + g;
#pragma unroll
        for (int ks4 = 0; ks4 < 4; ks4++) {
            int cc0 = ks4 * 16 + t2;
            size_t q0 = qoff + (size_t)r0 * dc + cc0;
            size_t q8 = qoff + (size_t)(r0 + 8) * dc + cc0;
            size_t x0 = xoff + (size_t)r0 * Dc + cc0;
            size_t x8 = xoff + (size_t)(r0 + 8) * Dc + cc0;
            fqh[ks4*4+0] = *(const uint32_t*)(g_qh + q0);
            fqh[ks4*4+1] = *(const uint32_t*)(g_qh + q8);
            fqh[ks4*4+2] = *(const uint32_t*)(g_qh + q0 + 8);
            fqh[ks4*4+3] = *(const uint32_t*)(g_qh + q8 + 8);
            fql[ks4*4+0] = *(const uint32_t*)(g_ql + q0);
            fql[ks4*4+1] = *(const uint32_t*)(g_ql + q8);
            fql[ks4*4+2] = *(const uint32_t*)(g_ql + q0 + 8);
            fql[ks4*4+3] = *(const uint32_t*)(g_ql + q8 + 8);
            fph[ks4*4+0] = *(const uint32_t*)(g_xh + x0);
            fph[ks4*4+1] = *(const uint32_t*)(g_xh + x8);
            fph[ks4*4+2] = *(const uint32_t*)(g_xh + x0 + 8);
            fph[ks4*4+3] = *(const uint32_t*)(g_xh + x8 + 8);
            fpl[ks4*4+0] = *(const uint32_t*)(g_xl + x0);
            fpl[ks4*4+1] = *(const uint32_t*)(g_xl + x8);
            fpl[ks4*4+2] = *(const uint32_t*)(g_xl + x0 + 8);
            fpl[ks4*4+3] = *(const uint32_t*)(g_xl + x8 + 8);
        }
    }
    float ci_r[2], qi_r[2];
    {
        int r0 = i0 + 16 * w + g;
        ci_r[0] = g_coords[b * Lc + r0];
        ci_r[1] = g_coords[b * Lc + r0 + 8];
        qi_r[0] = fmaf(a_h, g_qsca[b * Lc + r0], c_h);
        qi_r[1] = fmaf(a_h, g_qsca[b * Lc + r0 + 8], c_h);
    }

    float oacc[8][4] = {};
    float m_run[2] = {-INFINITY, -INFINITY}, l_run[2] = {0.f, 0.f};

    for (int jt = 0; jt < 16; jt++) {
        int st = jt & (NSTG - 1);
        if (jt <= 13) CP_WAIT2();
        else if (jt == 14) CP_WAIT1();
        else CP_WAIT0();
        __syncthreads();

        uint32_t stb = jb32 + (uint32_t)st * JSTGB;
        uint32_t aKh = stb, aKl = stb + JBUFB;
        uint32_t aJh = stb + 2 * JBUFB, aJl = stb + 3 * JBUFB;
        uint32_t aVh = stb + 4 * JBUFB, aVl = stb + 5 * JBUFB;
        const float* cjp = sCj + st * 64;
        const float* qjp = sQj + st * 64;

        // ---- QK^T and PP^T (term-grouped hmma per p) ----
        float cS[8][4] = {}, cP[8][4] = {};
#pragma unroll
        for (int ks4 = 0; ks4 < 4; ks4++) {
            uint32_t bb = (((uint32_t)(ks4 * 32) + jx16) ^ xlr);
            const uint32_t* Q = fqh + ks4 * 4;
            const uint32_t* Ql = fql + ks4 * 4;
            const uint32_t* P = fph + ks4 * 4;
            const uint32_t* Pl = fpl + ks4 * 4;
#pragma unroll
            for (int p = 0; p < 4; p++) {
                uint32_t kh0, kh1, kh2, kh3, kl0, kl1, kl2, kl3;
                uint32_t jh0, jh1, jh2, jh3, jl0, jl1, jl2, jl3;
                ldsm4(kh0, kh1, kh2, kh3, aKh + jrow[p] + bb);
                ldsm4(kl0, kl1, kl2, kl3, aKl + jrow[p] + bb);
                ldsm4(jh0, jh1, jh2, jh3, aJh + jrow[p] + bb);
                ldsm4(jl0, jl1, jl2, jl3, aJl + jrow[p] + bb);
                // hh terms (4 independent accumulators)
                hmma(cS[2*p],   Q[0], Q[1], Q[2], Q[3], kh0, kh1);
                hmma(cS[2*p+1], Q[0], Q[1], Q[2], Q[3], kh2, kh3);
                hmma(cP[2*p],   P[0], P[1], P[2], P[3], jh0, jh1);
                hmma(cP[2*p+1], P[0], P[1], P[2], P[3], jh2, jh3);
                // hl terms
                hmma(cS[2*p],   Q[0], Q[1], Q[2], Q[3], kl0, kl1);
                hmma(cS[2*p+1], Q[0], Q[1], Q[2], Q[3], kl2, kl3);
                hmma(cP[2*p],   P[0], P[1], P[2], P[3], jl0, jl1);
                hmma(cP[2*p+1], P[0], P[1], P[2], P[3], jl2, jl3);
                // lh terms
                hmma(cS[2*p],   Ql[0], Ql[1], Ql[2], Ql[3], kh0, kh1);
                hmma(cS[2*p+1], Ql[0], Ql[1], Ql[2], Ql[3], kh2, kh3);
                hmma(cP[2*p],   Pl[0], Pl[1], Pl[2], Pl[3], jh0, jh1);
                hmma(cP[2*p+1], Pl[0], Pl[1], Pl[2], Pl[3], jh2, jh3);
            }
        }

        // ---- bias + online softmax ----
        float scale[2];
#pragma unroll
        for (int rh = 0; rh < 2; rh++) {
            float ci = ci_r[rh], base_i = qi_r[rh];
            float rmax = -INFINITY;
#pragma unroll
            for (int ni = 0; ni < 8; ni++)
#pragma unroll
                for (int cc = 0; cc < 2; cc++) {
                    int col = ni * 8 + t2 + cc;
                    float delta = fabsf(ci - cjp[col]);
                    int   di = (int)delta;
                    float tt = delta - (float)di;
                    int d0 = min(di,     Lc - 1);
                    int d1 = min(di + 1, Lc - 1);
                    float r0 = sR[d0];
                    float r = fmaf(tt, sR[d1] - r0, r0);
                    float S = fmaf(b_h, r, base_i + qjp[col]);
                    float v = fmaf(S, cP[ni][rh * 2 + cc], cS[ni][rh * 2 + cc]);
                    cS[ni][rh * 2 + cc] = v;
                    rmax = fmaxf(rmax, v);
                }
            rmax = fmaxf(rmax, __shfl_xor_sync(0xffffffffu, rmax, 1));
            rmax = fmaxf(rmax, __shfl_xor_sync(0xffffffffu, rmax, 2));
            float mn = fmaxf(m_run[rh], rmax);
            float rsum = 0.f;
#pragma unroll
            for (int ni = 0; ni < 8; ni++)
#pragma unroll
                for (int cc = 0; cc < 2; cc++) {
                    float e = __expf(cS[ni][rh * 2 + cc] - mn);
                    cS[ni][rh * 2 + cc] = e;
                    rsum += e;
                }
            rsum += __shfl_xor_sync(0xffffffffu, rsum, 1);
            rsum += __shfl_xor_sync(0xffffffffu, rsum, 2);
            scale[rh] = __expf(m_run[rh] - mn);
            l_run[rh] = l_run[rh] * scale[rh] + rsum;
            m_run[rh] = mn;
        }
#pragma unroll
        for (int ni = 0; ni < 8; ni++) {
            oacc[ni][0] *= scale[0]; oacc[ni][1] *= scale[0];
            oacc[ni][2] *= scale[1]; oacc[ni][3] *= scale[1];
        }

        // ---- PV (C->A fragment identity), bf16x3, term-grouped ----
#pragma unroll
        for (int kc = 0; kc < 4; kc++) {
            float v00 = cS[2*kc][0],   v01 = cS[2*kc][1];
            float v10 = cS[2*kc][2],   v11 = cS[2*kc][3];
            float v20 = cS[2*kc+1][0], v21 = cS[2*kc+1][1];
            float v30 = cS[2*kc+1][2], v31 = cS[2*kc+1][3];
            float h00 = bf_hi(v00), h01 = bf_hi(v01), h10 = bf_hi(v10), h11 = bf_hi(v11);
            float h20 = bf_hi(v20), h21 = bf_hi(v21), h30 = bf_hi(v30), h31 = bf_hi(v31);
            uint32_t aph0 = pack_bf16(h00, h01), aph1 = pack_bf16(h10, h11);
            uint32_t aph2 = pack_bf16(h20, h21), aph3 = pack_bf16(h30, h31);
            uint32_t apl0 = pack_bf16(v00 - h00, v01 - h01), apl1 = pack_bf16(v10 - h10, v11 - h11);
            uint32_t apl2 = pack_bf16(v20 - h20, v21 - h21), apl3 = pack_bf16(v30 - h30, v31 - h31);
            uint32_t bb = (((uint32_t)(kc * 32) + jx16) ^ xlr);
#pragma unroll
            for (int p = 0; p < 4; p++) {
                uint32_t vh0, vh1, vh2, vh3, vl0, vl1, vl2, vl3;
                ldsm4(vh0, vh1, vh2, vh3, aVh + jrow[p] + bb);
                ldsm4(vl0, vl1, vl2, vl3, aVl + jrow[p] + bb);
                hmma(oacc[2*p],   aph0, aph1, aph2, aph3, vh0, vh1);
                hmma(oacc[2*p+1], aph0, aph1, aph2, aph3, vh2, vh3);
                hmma(oacc[2*p],   apl0, apl1, apl2, apl3, vh0, vh1);
                hmma(oacc[2*p+1], apl0, apl1, apl2, apl3, vh2, vh3);
                hmma(oacc[2*p],   aph0, aph1, aph2, aph3, vl0, vl1);
                hmma(oacc[2*p+1], aph0, aph1, aph2, aph3, vl2, vl3);
            }
        }

        __syncthreads();
        if (jt + 3 < 16) issue_stage(jt + 3, (jt + 3) & (NSTG - 1));
    }

    // ---- epilogue ----
    float inv0 = 1.f / l_run[0], inv1 = 1.f / l_run[1];
#pragma unroll
    for (int rh = 0; rh < 2; rh++) {
        int row = i0 + 16 * w + g + rh * 8;
        float inv = rh ? inv1 : inv0;
        size_t base = ((size_t)(b * Lc) + row) * Dc + h * dc;
#pragma unroll
        for (int ni = 0; ni < 8; ni++) {
            float v0 = oacc[ni][rh * 2]     * inv;
            float v1 = oacc[ni][rh * 2 + 1] * inv;
            float h0 = bf_hi(v0), h1 = bf_hi(v1);
            size_t idx = base + ni * 8 + t2;
            *(uint32_t*)(g_oh + idx) = pack_bf16(h0, h1);
            *(uint32_t*)(g_ol + idx) = pack_bf16(v0 - h0, v1 - h1);
        }
    }
}

// ---------------- launch ----------------
extern "C" void kernel_launch(void* const* d_in, const int* in_sizes, int n_in,
                              void* d_out, int out_size) {
    const float* x     = (const float*)d_in[0];
    const float* t_enc = (const float*)d_in[1];
    const float* WQ    = (const float*)d_in[2];
    const float* WK    = (const float*)d_in[3];
    const float* WV    = (const float*)d_in[4];
    const float* WO    = (const float*)d_in[5];
    const float* bO    = (const float*)d_in[6];
    const float* Wt    = (const float*)d_in[7];
    const float* bt    = (const float*)d_in[8];
    const float* p_mat = (const float*)d_in[9];
    const float* r_mat = (const float*)d_in[10];
    const float* alpha = (const float*)d_in[11];
    const float* beta  = (const float*)d_in[12];
    const float* gamma = (const float*)d_in[13];
    float* out = (float*)d_out;

    cudaFuncSetAttribute(attn_mma, cudaFuncAttributeMaxDynamicSharedMemorySize,
                         ATTN_SMEM_BYTES);
    cudaFuncSetAttribute(qkv_mma, cudaFuncAttributeMaxDynamicSharedMemorySize,
                         GEMM_SMEM_BYTES);
    cudaFuncSetAttribute(out_mma, cudaFuncAttributeMaxDynamicSharedMemorySize,
                         GEMM_SMEM_BYTES);

    __nv_bfloat16 *xh, *xl;
    cudaGetSymbolAddress((void**)&xh, g_xh);
    cudaGetSymbolAddress((void**)&xl, g_xl);

    colsum_kernel<<<dim3(Lc / 256, 2), 256>>>(p_mat, r_mat);
    coords_kernel<<<(Bc * Lc) / 128, 128>>>(t_enc, Wt, bt);
    split_kernel<<<(Bc * Lc * Dc) / (256 * 4), 256>>>(x, xh, xl);
    split_w_kernel<<<dim3((Dc * Dc) / (256 * 4), 4), 256>>>(WQ, WK, WV, WO);
    qkv_mma<<<dim3(Dc / 128, (Bc * Lc) / 128, 3), 128, GEMM_SMEM_BYTES>>>();
    attn_mma<<<dim3(Lc / 128, Bc * Hc), 256, ATTN_SMEM_BYTES>>>(alpha, beta, gamma);
    out_mma<<<dim3(Dc / 128, (Bc * Lc) / 128), 128, GEMM_SMEM_BYTES>>>(bO, out);
}

// round 13
// speedup vs baseline: 2.8734x; 1.0301x over previous
#include <cuda_runtime.h>
#include <cuda_bf16.h>
#include <cuda_fp16.h>
#include <math.h>
#include <stdint.h>

#define Bc 4
#define Lc 1024
#define Dc 1024
#define Hc 16
#define Tc 64
#define dc 64
#define BHLD (Bc*Hc*Lc*dc)   /* 4,194,304 */

// ---------------- scratch ----------------
__device__ float g_coords[Bc * Lc];
__device__ float g_qsca[Bc * Lc];
__device__ float g_psum[Lc];
__device__ float g_rsum[Lc];
__device__ __nv_bfloat16 g_xh[Bc*Lc*Dc], g_xl[Bc*Lc*Dc];     // x
__device__ __nv_bfloat16 g_wh[4*Dc*Dc],  g_wl[4*Dc*Dc];      // WQ|WK|WV|(WO unused)
__device__ __half        g_woh[Dc*Dc];                        // WO fp16 hi
__device__ __nv_bfloat16 g_qh[BHLD], g_ql[BHLD];             // Q*0.125 (b,h,l,d)
__device__ __nv_bfloat16 g_kh[BHLD], g_kl[BHLD];             // K (b,h,l,d)
__device__ __nv_bfloat16 g_vth[BHLD], g_vtl[BHLD];           // V^T (b,h,d,l)
__device__ __half g_ohh[Bc*Lc*Dc], g_ohl[Bc*Lc*Dc];          // attn out fp16 hi/lo

__device__ __forceinline__ uint32_t pack_bf16(float lo, float hi) {
    __nv_bfloat162 r = __floats2bfloat162_rn(lo, hi);
    return *(uint32_t*)&r;
}
__device__ __forceinline__ float bf_hi(float v) {
    return __bfloat162float(__float2bfloat16(v));
}
__device__ __forceinline__ uint32_t pack_f16(float lo, float hi) {
    __half2 r = __floats2half2_rn(lo, hi);
    return *(uint32_t*)&r;
}
__device__ __forceinline__ float f16_hi(float v) {
    return __half2float(__float2half_rn(v));
}
__device__ __forceinline__ uint32_t smem_u32(const void* p) {
    uint32_t a;
    asm("{ .reg .u64 t; cvta.to.shared.u64 t, %1; cvt.u32.u64 %0, t; }" : "=r"(a) : "l"(p));
    return a;
}
__device__ __forceinline__ void cp16(uint32_t dst, const void* src) {
    asm volatile("cp.async.cg.shared.global [%0], [%1], 16;" :: "r"(dst), "l"(src));
}
#define CP_COMMIT() asm volatile("cp.async.commit_group;" ::: "memory")
#define CP_WAIT0()  asm volatile("cp.async.wait_group 0;"  ::: "memory")
#define CP_WAIT1()  asm volatile("cp.async.wait_group 1;"  ::: "memory")
#define CP_WAIT2()  asm volatile("cp.async.wait_group 2;"  ::: "memory")

__device__ __forceinline__ void ldsm4(uint32_t& r0, uint32_t& r1, uint32_t& r2,
                                      uint32_t& r3, uint32_t addr) {
    asm volatile("ldmatrix.sync.aligned.m8n8.x4.shared.b16 {%0,%1,%2,%3}, [%4];"
                 : "=r"(r0), "=r"(r1), "=r"(r2), "=r"(r3) : "r"(addr));
}

// ---------------- kernel 0: column sums ----------------
__global__ void colsum_kernel(const float* __restrict__ p_mat,
                              const float* __restrict__ r_mat) {
    int l = blockIdx.x * blockDim.x + threadIdx.x;
    if (l >= Lc) return;
    const float* src = blockIdx.y ? r_mat : p_mat;
    float s = 0.f;
#pragma unroll 8
    for (int dd = 0; dd < Dc; dd++) s += src[dd * Lc + l];
    if (blockIdx.y) g_rsum[l] = s; else g_psum[l] = s;
}

// ---------------- kernel 1: coords + cubic q_sca ----------------
__global__ void coords_kernel(const float* __restrict__ t_enc,
                              const float* __restrict__ Wt,
                              const float* __restrict__ bt) {
    int n = blockIdx.x * blockDim.x + threadIdx.x;
    if (n >= Bc * Lc) return;
    float z = bt[0];
    const float* te = t_enc + (size_t)n * Tc;
#pragma unroll
    for (int k = 0; k < Tc; k++) z += te[k] * Wt[k];
    float tau = 1.f / (1.f + expf(-z));
    float c = tau * (float)(Lc - 1);
    g_coords[n] = c;
    int i = (int)floorf(c);
    float t = c - (float)i;
    int im1 = min(max(i - 1, 0), Lc - 1);
    int ii0 = min(max(i,     0), Lc - 1);
    int ii1 = min(max(i + 1, 0), Lc - 1);
    int ii2 = min(max(i + 2, 0), Lc - 1);
    float p0 = g_psum[im1], p1 = g_psum[ii0], p2 = g_psum[ii1], p3 = g_psum[ii2];
    float t2 = t * t, t3 = t2 * t;
    g_qsca[n] = 0.5f * (2.f * p1 + (-p0 + p2) * t
              + (2.f * p0 - 5.f * p1 + 4.f * p2 - p3) * t2
              + (-p0 + 3.f * p1 - 3.f * p2 + p3) * t3);
}

// ---------------- split fp32 -> bf16 hi + lo ----------------
__global__ void split_kernel(const float* __restrict__ s,
                             __nv_bfloat16* __restrict__ h,
                             __nv_bfloat16* __restrict__ l) {
    int i = (blockIdx.x * blockDim.x + threadIdx.x) * 4;
    float4 v = *(const float4*)(s + i);
    float h0 = bf_hi(v.x), h1 = bf_hi(v.y), h2 = bf_hi(v.z), h3 = bf_hi(v.w);
    uint2 H = make_uint2(pack_bf16(h0, h1), pack_bf16(h2, h3));
    uint2 L = make_uint2(pack_bf16(v.x - h0, v.y - h1), pack_bf16(v.z - h2, v.w - h3));
    *(uint2*)(h + i) = H;
    *(uint2*)(l + i) = L;
}
__global__ void split_w_kernel(const float* __restrict__ WQ, const float* __restrict__ WK,
                               const float* __restrict__ WV, const float* __restrict__ WO) {
    int i = (blockIdx.x * blockDim.x + threadIdx.x) * 4;
    if (blockIdx.y == 3) {   // WO: fp16 hi only
        float4 v = *(const float4*)(WO + i);
        uint2 H = make_uint2(pack_f16(v.x, v.y), pack_f16(v.z, v.w));
        *(uint2*)(g_woh + i) = H;
        return;
    }
    const float* src = (blockIdx.y == 0) ? WQ : (blockIdx.y == 1) ? WK : WV;
    size_t off = (size_t)blockIdx.y << 20;
    float4 v = *(const float4*)(src + i);
    float h0 = bf_hi(v.x), h1 = bf_hi(v.y), h2 = bf_hi(v.z), h3 = bf_hi(v.w);
    uint2 H = make_uint2(pack_bf16(h0, h1), pack_bf16(h2, h3));
    uint2 L = make_uint2(pack_bf16(v.x - h0, v.y - h1), pack_bf16(v.z - h2, v.w - h3));
    *(uint2*)(g_wh + off + i) = H;
    *(uint2*)(g_wl + off + i) = L;
}

// ================= mma.sync bf16x3 GEMM core (unchanged) =================
#define KP 40
#define SB (128 * KP)
#define STG (4 * SB)
#define GEMM_SMEM_BYTES (2 * STG * 2)   // 81920

__device__ __forceinline__ void hmma(float c[4], uint32_t a0, uint32_t a1, uint32_t a2,
                                     uint32_t a3, uint32_t b0, uint32_t b1) {
    asm volatile(
        "mma.sync.aligned.m16n8k16.row.col.f32.bf16.bf16.f32 "
        "{%0,%1,%2,%3}, {%4,%5,%6,%7}, {%8,%9}, {%0,%1,%2,%3};"
        : "+f"(c[0]), "+f"(c[1]), "+f"(c[2]), "+f"(c[3])
        : "r"(a0), "r"(a1), "r"(a2), "r"(a3), "r"(b0), "r"(b1));
}
__device__ __forceinline__ void hmma16(float c[4], uint32_t a0, uint32_t a1, uint32_t a2,
                                       uint32_t a3, uint32_t b0, uint32_t b1) {
    asm volatile(
        "mma.sync.aligned.m16n8k16.row.col.f32.f16.f16.f32 "
        "{%0,%1,%2,%3}, {%4,%5,%6,%7}, {%8,%9}, {%0,%1,%2,%3};"
        : "+f"(c[0]), "+f"(c[1]), "+f"(c[2]), "+f"(c[3])
        : "r"(a0), "r"(a1), "r"(a2), "r"(a3), "r"(b0), "r"(b1));
}

__device__ __forceinline__ void gemm_gissue(uint32_t st32,
                                            const __nv_bfloat16* Ah, const __nv_bfloat16* Al,
                                            const __nv_bfloat16* Bh, const __nv_bfloat16* Bl,
                                            int k0) {
    int tid = threadIdx.x;
#pragma unroll
    for (int i = 0; i < 4; i++) {
        int v = tid + i * 128;
        int row = v >> 2, seg = v & 3;
        size_t gs = (size_t)row * Dc + k0 + seg * 8;
        uint32_t so = (uint32_t)((row * KP + seg * 8) * 2);
        cp16(st32 + so,              Ah + gs);
        cp16(st32 + SB * 2 + so,     Al + gs);
        cp16(st32 + 2 * SB * 2 + so, Bh + gs);
        cp16(st32 + 3 * SB * 2 + so, Bl + gs);
    }
}

__device__ __forceinline__ void mma_core(const __nv_bfloat16* Ah, const __nv_bfloat16* Al,
                                         const __nv_bfloat16* Bh, const __nv_bfloat16* Bl,
                                         __nv_bfloat16* S, float c[4][8][4]) {
    int lane = threadIdx.x & 31, w = threadIdx.x >> 5;
    int wm = w >> 1, wn = w & 1;
    int quad = lane >> 3, lr = lane & 7;
    uint32_t s32 = smem_u32(S);

    uint32_t aoff[4], boff[4];
#pragma unroll
    for (int mi = 0; mi < 4; mi++)
        aoff[mi] = (uint32_t)(((wm * 64 + mi * 16 + (quad & 1) * 8 + lr) * KP
                               + (quad >> 1) * 8) * 2);
#pragma unroll
    for (int p = 0; p < 4; p++)
        boff[p] = (uint32_t)(((wn * 64 + p * 16 + (quad >> 1) * 8 + lr) * KP
                              + (quad & 1) * 8) * 2);

    gemm_gissue(s32, Ah, Al, Bh, Bl, 0);
    CP_COMMIT();
    gemm_gissue(s32 + STG * 2, Ah, Al, Bh, Bl, 32);
    CP_COMMIT();
    const int NCH = Dc / 32;
    for (int ch = 0; ch < NCH; ch++) {
        CP_WAIT1();
        __syncthreads();
        uint32_t base = s32 + (ch & 1) * (STG * 2);
        uint32_t aAh = base, aAl = base + SB * 2;
        uint32_t aBh = base + 2 * SB * 2, aBl = base + 3 * SB * 2;
#pragma unroll
        for (int ks = 0; ks < 32; ks += 16) {
            uint32_t kb = (uint32_t)(ks * 2);
            uint32_t ah[4][4], al[4][4];
#pragma unroll
            for (int mi = 0; mi < 4; mi++) {
                ldsm4(ah[mi][0], ah[mi][1], ah[mi][2], ah[mi][3], aAh + aoff[mi] + kb);
                ldsm4(al[mi][0], al[mi][1], al[mi][2], al[mi][3], aAl + aoff[mi] + kb);
            }
            uint32_t bh[8][2], bl[8][2];
#pragma unroll
            for (int p = 0; p < 4; p++) {
                ldsm4(bh[2*p][0], bh[2*p][1], bh[2*p+1][0], bh[2*p+1][1], aBh + boff[p] + kb);
                ldsm4(bl[2*p][0], bl[2*p][1], bl[2*p+1][0], bl[2*p+1][1], aBl + boff[p] + kb);
            }
#pragma unroll
            for (int ni = 0; ni < 8; ni++)
#pragma unroll
                for (int mi = 0; mi < 4; mi++)
                    hmma(c[mi][ni], ah[mi][0], ah[mi][1], ah[mi][2], ah[mi][3],
                         bh[ni][0], bh[ni][1]);
#pragma unroll
            for (int ni = 0; ni < 8; ni++)
#pragma unroll
                for (int mi = 0; mi < 4; mi++)
                    hmma(c[mi][ni], ah[mi][0], ah[mi][1], ah[mi][2], ah[mi][3],
                         bl[ni][0], bl[ni][1]);
#pragma unroll
            for (int ni = 0; ni < 8; ni++)
#pragma unroll
                for (int mi = 0; mi < 4; mi++)
                    hmma(c[mi][ni], al[mi][0], al[mi][1], al[mi][2], al[mi][3],
                         bh[ni][0], bh[ni][1]);
        }
        __syncthreads();
        if (ch + 2 < NCH) {
            gemm_gissue(s32 + (ch & 1) * (STG * 2), Ah, Al, Bh, Bl, (ch + 2) * 32);
            CP_COMMIT();
        }
    }
}

// ---------------- kernel 2: QKV projection (unchanged) ----------------
__global__ void __launch_bounds__(128, 2) qkv_mma() {
    extern __shared__ __nv_bfloat16 Sdyn[];
    int z = blockIdx.z;
    int M0 = blockIdx.y * 128, N0 = blockIdx.x * 128;
    const __nv_bfloat16* Ah = g_xh + (size_t)M0 * Dc;
    const __nv_bfloat16* Al = g_xl + (size_t)M0 * Dc;
    const __nv_bfloat16* Bh = g_wh + ((size_t)z << 20) + (size_t)N0 * Dc;
    const __nv_bfloat16* Bl = g_wl + ((size_t)z << 20) + (size_t)N0 * Dc;
    float c[4][8][4] = {};
    mma_core(Ah, Al, Bh, Bl, Sdyn, c);

    int lane = threadIdx.x & 31, w = threadIdx.x >> 5;
    int wm = w >> 1, wn = w & 1;
    int g = lane >> 2, t2 = (lane & 3) * 2;
    if (z < 2) {
        __nv_bfloat16* dh = z ? g_kh : g_qh;
        __nv_bfloat16* dl = z ? g_kl : g_ql;
        float qs = z ? 1.0f : 0.125f;
#pragma unroll
        for (int mi = 0; mi < 4; mi++)
#pragma unroll
            for (int ni = 0; ni < 8; ni++) {
                int col = N0 + wn * 64 + ni * 8 + t2;
                int h = col >> 6, dd = col & 63;
#pragma unroll
                for (int rh = 0; rh < 2; rh++) {
                    int row = M0 + wm * 64 + mi * 16 + g + rh * 8;
                    int bb = row >> 10, l = row & (Lc - 1);
                    float v0 = c[mi][ni][rh * 2] * qs, v1 = c[mi][ni][rh * 2 + 1] * qs;
                    float h0 = bf_hi(v0), h1 = bf_hi(v1);
                    size_t idx = (((size_t)(bb * Hc + h)) * Lc + l) * dc + dd;
                    *(uint32_t*)(dh + idx) = pack_bf16(h0, h1);
                    *(uint32_t*)(dl + idx) = pack_bf16(v0 - h0, v1 - h1);
                }
            }
    } else {
        uint16_t* sT = (uint16_t*)Sdyn;
#pragma unroll
        for (int mi = 0; mi < 4; mi++)
#pragma unroll
            for (int ni = 0; ni < 8; ni++) {
                int col_l = wn * 64 + ni * 8 + t2;
#pragma unroll
                for (int rh = 0; rh < 2; rh++) {
                    int row_l = wm * 64 + mi * 16 + g + rh * 8;
#pragma unroll
                    for (int cc = 0; cc < 2; cc++) {
                        float v = c[mi][ni][rh * 2 + cc];
                        __nv_bfloat16 vh = __float2bfloat16(v);
                        __nv_bfloat16 vl = __float2bfloat16(v - __bfloat162float(vh));
                        sT[(col_l + cc) * 136 + row_l]             = *(uint16_t*)&vh;
                        sT[128 * 136 + (col_l + cc) * 136 + row_l] = *(uint16_t*)&vl;
                    }
                }
            }
        __syncthreads();
        int bb = M0 >> 10, l0 = M0 & (Lc - 1);
#pragma unroll
        for (int q = 0; q < 16; q++) {
            int v = threadIdx.x + q * 128;
            int d = v >> 4, seg = v & 15;
            int col = N0 + d;
            int h = col >> 6, dd = col & 63;
            size_t dst = (((size_t)(bb * Hc + h)) * dc + dd) * Lc + l0 + seg * 8;
            *(uint4*)(g_vth + dst) = *(const uint4*)(sT + d * 136 + seg * 8);
            *(uint4*)(g_vtl + dst) = *(const uint4*)(sT + 128 * 136 + d * 136 + seg * 8);
        }
    }
}

// ---------------- kernel 4: output projection, fp16 2-term (Oh+Ol)·WOh ----------------
#define OSTG (3 * SB)
#define OUT_SMEM_BYTES (2 * OSTG * 2)   // 61440

__global__ void __launch_bounds__(128, 2) out_mma(const float* __restrict__ bO,
                                                  float* __restrict__ out) {
    extern __shared__ __half Sh[];
    int M0 = blockIdx.y * 128, N0 = blockIdx.x * 128;
    const __half* Ah = g_ohh + (size_t)M0 * Dc;
    const __half* Al = g_ohl + (size_t)M0 * Dc;
    const __half* Bh = g_woh + (size_t)N0 * Dc;

    int lane = threadIdx.x & 31, w = threadIdx.x >> 5;
    int wm = w >> 1, wn = w & 1;
    int quad = lane >> 3, lr = lane & 7;
    uint32_t s32 = smem_u32(Sh);

    uint32_t aoff[4], boff[4];
#pragma unroll
    for (int mi = 0; mi < 4; mi++)
        aoff[mi] = (uint32_t)(((wm * 64 + mi * 16 + (quad & 1) * 8 + lr) * KP
                               + (quad >> 1) * 8) * 2);
#pragma unroll
    for (int p = 0; p < 4; p++)
        boff[p] = (uint32_t)(((wn * 64 + p * 16 + (quad >> 1) * 8 + lr) * KP
                              + (quad & 1) * 8) * 2);

    auto issue = [&](uint32_t st32, int k0) {
        int tid = threadIdx.x;
#pragma unroll
        for (int i = 0; i < 4; i++) {
            int v = tid + i * 128;
            int row = v >> 2, seg = v & 3;
            size_t gs = (size_t)row * Dc + k0 + seg * 8;
            uint32_t so = (uint32_t)((row * KP + seg * 8) * 2);
            cp16(st32 + so,              Ah + gs);
            cp16(st32 + SB * 2 + so,     Al + gs);
            cp16(st32 + 2 * SB * 2 + so, Bh + gs);
        }
        CP_COMMIT();
    };

    float c[4][8][4] = {};
    issue(s32, 0);
    issue(s32 + OSTG * 2, 32);
    const int NCH = Dc / 32;
    for (int ch = 0; ch < NCH; ch++) {
        CP_WAIT1();
        __syncthreads();
        uint32_t base = s32 + (ch & 1) * (OSTG * 2);
        uint32_t aAh = base, aAl = base + SB * 2, aBh = base + 2 * SB * 2;
#pragma unroll
        for (int ks = 0; ks < 32; ks += 16) {
            uint32_t kb = (uint32_t)(ks * 2);
            uint32_t ah[4][4], al[4][4];
#pragma unroll
            for (int mi = 0; mi < 4; mi++) {
                ldsm4(ah[mi][0], ah[mi][1], ah[mi][2], ah[mi][3], aAh + aoff[mi] + kb);
                ldsm4(al[mi][0], al[mi][1], al[mi][2], al[mi][3], aAl + aoff[mi] + kb);
            }
            uint32_t bh[8][2];
#pragma unroll
            for (int p = 0; p < 4; p++)
                ldsm4(bh[2*p][0], bh[2*p][1], bh[2*p+1][0], bh[2*p+1][1], aBh + boff[p] + kb);
#pragma unroll
            for (int ni = 0; ni < 8; ni++)
#pragma unroll
                for (int mi = 0; mi < 4; mi++)
                    hmma16(c[mi][ni], ah[mi][0], ah[mi][1], ah[mi][2], ah[mi][3],
                           bh[ni][0], bh[ni][1]);
#pragma unroll
            for (int ni = 0; ni < 8; ni++)
#pragma unroll
                for (int mi = 0; mi < 4; mi++)
                    hmma16(c[mi][ni], al[mi][0], al[mi][1], al[mi][2], al[mi][3],
                           bh[ni][0], bh[ni][1]);
        }
        __syncthreads();
        if (ch + 2 < NCH) issue(s32 + (ch & 1) * (OSTG * 2), (ch + 2) * 32);
    }

    int g = lane >> 2, t2 = (lane & 3) * 2;
#pragma unroll
    for (int mi = 0; mi < 4; mi++)
#pragma unroll
        for (int ni = 0; ni < 8; ni++) {
            int col = N0 + wn * 64 + ni * 8 + t2;
            float2 bv = *(const float2*)(bO + col);
#pragma unroll
            for (int rh = 0; rh < 2; rh++) {
                int row = M0 + wm * 64 + mi * 16 + g + rh * 8;
                float2 v = make_float2(c[mi][ni][rh * 2] + bv.x,
                                       c[mi][ni][rh * 2 + 1] + bv.y);
                *(float2*)(out + (size_t)row * Dc + col) = v;
            }
        }
}

// ---------------- kernel 3: flash attention (unchanged except fp16 epilogue) ----------------
#define JROWB 128
#define JBUFB (64 * JROWB)
#define JSTGB (6 * JBUFB)
#define NSTG 4
#define ATTN_SMEM_BYTES (NSTG * JSTGB + (Lc + NSTG * 64 * 2) * 4)

__device__ __forceinline__ uint32_t jswz(int row, int byte_in_row) {
    return (uint32_t)(row * JROWB + (byte_in_row ^ ((row & 7) << 4)));
}

__global__ void __launch_bounds__(256, 1) attn_mma(const float* __restrict__ alpha,
                                                   const float* __restrict__ beta,
                                                   const float* __restrict__ gamma) {
    extern __shared__ __nv_bfloat16 smb[];
    __nv_bfloat16* jbase = smb;
    float* sR  = (float*)((char*)smb + NSTG * JSTGB);
    float* sCj = sR + Lc;
    float* sQj = sCj + NSTG * 64;

    uint32_t jb32 = smem_u32(jbase);

    int t = threadIdx.x;
    int w = t >> 5, lane = t & 31;
    int g = lane >> 2, t2 = (lane & 3) * 2;
    int quad = lane >> 3, lr = lane & 7;
    int bh = blockIdx.y;
    int b = bh >> 4, h = bh & 15;
    int i0 = blockIdx.x * 128;

    float a_h = alpha[h], b_h = beta[h], c_h = gamma[h];

    const size_t qoff = ((size_t)bh * Lc) * dc;
    const size_t xoff = ((size_t)b * Lc) * Dc + h * dc;
    const size_t voff = (size_t)bh * dc * Lc;

    for (int idx = t; idx < Lc; idx += 256) sR[idx] = g_rsum[idx];

    auto issue_stage = [&](int jt, int st) {
        uint32_t s32 = jb32 + (uint32_t)st * JSTGB;
        int j0 = jt * 64;
#pragma unroll
        for (int q = 0; q < 2; q++) {
            int v = t * 2 + q;
            int row = v >> 3, seg = v & 7;
            uint32_t boff = jswz(row, seg * 16);
            size_t gk = qoff + (size_t)(j0 + row) * dc + seg * 8;
            size_t gx = xoff + (size_t)(j0 + row) * Dc + seg * 8;
            size_t gv = voff + (size_t)row * Lc + j0 + seg * 8;
            cp16(s32 + 0 * JBUFB + boff, g_kh  + gk);
            cp16(s32 + 1 * JBUFB + boff, g_kl  + gk);
            cp16(s32 + 2 * JBUFB + boff, g_xh  + gx);
            cp16(s32 + 3 * JBUFB + boff, g_xl  + gx);
            cp16(s32 + 4 * JBUFB + boff, g_vth + gv);
            cp16(s32 + 5 * JBUFB + boff, g_vtl + gv);
        }
        CP_COMMIT();
        if (t < 64) {
            sCj[st * 64 + t] = g_coords[b * Lc + j0 + t];
            sQj[st * 64 + t] = a_h * g_qsca[b * Lc + j0 + t];
        }
    };
    issue_stage(0, 0);
    issue_stage(1, 1);
    issue_stage(2, 2);

    uint32_t jrow[4];
#pragma unroll
    for (int p = 0; p < 4; p++)
        jrow[p] = (uint32_t)((p * 16 + (quad >> 1) * 8 + lr) * JROWB);
    uint32_t jx16 = (uint32_t)((quad & 1) * 16);
    uint32_t xlr  = (uint32_t)(lr << 4);

    uint32_t fqh[16], fql[16], fph[16], fpl[16];
    {
        int r0 = i0 + 16 * w + g;
#pragma unroll
        for (int ks4 = 0; ks4 < 4; ks4++) {
            int cc0 = ks4 * 16 + t2;
            size_t q0 = qoff + (size_t)r0 * dc + cc0;
            size_t q8 = qoff + (size_t)(r0 + 8) * dc + cc0;
            size_t x0 = xoff + (size_t)r0 * Dc + cc0;
            size_t x8 = xoff + (size_t)(r0 + 8) * Dc + cc0;
            fqh[ks4*4+0] = *(const uint32_t*)(g_qh + q0);
            fqh[ks4*4+1] = *(const uint32_t*)(g_qh + q8);
            fqh[ks4*4+2] = *(const uint32_t*)(g_qh + q0 + 8);
            fqh[ks4*4+3] = *(const uint32_t*)(g_qh + q8 + 8);
            fql[ks4*4+0] = *(const uint32_t*)(g_ql + q0);
            fql[ks4*4+1] = *(const uint32_t*)(g_ql + q8);
            fql[ks4*4+2] = *(const uint32_t*)(g_ql + q0 + 8);
            fql[ks4*4+3] = *(const uint32_t*)(g_ql + q8 + 8);
            fph[ks4*4+0] = *(const uint32_t*)(g_xh + x0);
            fph[ks4*4+1] = *(const uint32_t*)(g_xh + x8);
            fph[ks4*4+2] = *(const uint32_t*)(g_xh + x0 + 8);
            fph[ks4*4+3] = *(const uint32_t*)(g_xh + x8 + 8);
            fpl[ks4*4+0] = *(const uint32_t*)(g_xl + x0);
            fpl[ks4*4+1] = *(const uint32_t*)(g_xl + x8);
            fpl[ks4*4+2] = *(const uint32_t*)(g_xl + x0 + 8);
            fpl[ks4*4+3] = *(const uint32_t*)(g_xl + x8 + 8);
        }
    }
    float ci_r[2], qi_r[2];
    {
        int r0 = i0 + 16 * w + g;
        ci_r[0] = g_coords[b * Lc + r0];
        ci_r[1] = g_coords[b * Lc + r0 + 8];
        qi_r[0] = fmaf(a_h, g_qsca[b * Lc + r0], c_h);
        qi_r[1] = fmaf(a_h, g_qsca[b * Lc + r0 + 8], c_h);
    }

    float oacc[8][4] = {};
    float m_run[2] = {-INFINITY, -INFINITY}, l_run[2] = {0.f, 0.f};

    for (int jt = 0; jt < 16; jt++) {
        int st = jt & (NSTG - 1);
        if (jt <= 13) CP_WAIT2();
        else if (jt == 14) CP_WAIT1();
        else CP_WAIT0();
        __syncthreads();

        uint32_t stb = jb32 + (uint32_t)st * JSTGB;
        uint32_t aKh = stb, aKl = stb + JBUFB;
        uint32_t aJh = stb + 2 * JBUFB, aJl = stb + 3 * JBUFB;
        uint32_t aVh = stb + 4 * JBUFB, aVl = stb + 5 * JBUFB;
        const float* cjp = sCj + st * 64;
        const float* qjp = sQj + st * 64;

        float cS[8][4] = {}, cP[8][4] = {};
#pragma unroll
        for (int ks4 = 0; ks4 < 4; ks4++) {
            uint32_t bb = (((uint32_t)(ks4 * 32) + jx16) ^ xlr);
            const uint32_t* Q = fqh + ks4 * 4;
            const uint32_t* Ql = fql + ks4 * 4;
            const uint32_t* P = fph + ks4 * 4;
            const uint32_t* Pl = fpl + ks4 * 4;
#pragma unroll
            for (int p = 0; p < 4; p++) {
                uint32_t kh0, kh1, kh2, kh3, kl0, kl1, kl2, kl3;
                uint32_t jh0, jh1, jh2, jh3, jl0, jl1, jl2, jl3;
                ldsm4(kh0, kh1, kh2, kh3, aKh + jrow[p] + bb);
                ldsm4(kl0, kl1, kl2, kl3, aKl + jrow[p] + bb);
                ldsm4(jh0, jh1, jh2, jh3, aJh + jrow[p] + bb);
                ldsm4(jl0, jl1, jl2, jl3, aJl + jrow[p] + bb);
                hmma(cS[2*p],   Q[0], Q[1], Q[2], Q[3], kh0, kh1);
                hmma(cS[2*p+1], Q[0], Q[1], Q[2], Q[3], kh2, kh3);
                hmma(cP[2*p],   P[0], P[1], P[2], P[3], jh0, jh1);
                hmma(cP[2*p+1], P[0], P[1], P[2], P[3], jh2, jh3);
                hmma(cS[2*p],   Q[0], Q[1], Q[2], Q[3], kl0, kl1);
                hmma(cS[2*p+1], Q[0], Q[1], Q[2], Q[3], kl2, kl3);
                hmma(cP[2*p],   P[0], P[1], P[2], P[3], jl0, jl1);
                hmma(cP[2*p+1], P[0], P[1], P[2], P[3], jl2, jl3);
                hmma(cS[2*p],   Ql[0], Ql[1], Ql[2], Ql[3], kh0, kh1);
                hmma(cS[2*p+1], Ql[0], Ql[1], Ql[2], Ql[3], kh2, kh3);
                hmma(cP[2*p],   Pl[0], Pl[1], Pl[2], Pl[3], jh0, jh1);
                hmma(cP[2*p+1], Pl[0], Pl[1], Pl[2], Pl[3], jh2, jh3);
            }
        }

        float scale[2];
#pragma unroll
        for (int rh = 0; rh < 2; rh++) {
            float ci = ci_r[rh], base_i = qi_r[rh];
            float rmax = -INFINITY;
#pragma unroll
            for (int ni = 0; ni < 8; ni++)
#pragma unroll
                for (int cc = 0; cc < 2; cc++) {
                    int col = ni * 8 + t2 + cc;
                    float delta = fabsf(ci - cjp[col]);
                    int   di = (int)delta;
                    float tt = delta - (float)di;
                    int d0 = min(di,     Lc - 1);
                    int d1 = min(di + 1, Lc - 1);
                    float r0 = sR[d0];
                    float r = fmaf(tt, sR[d1] - r0, r0);
                    float S = fmaf(b_h, r, base_i + qjp[col]);
                    float v = fmaf(S, cP[ni][rh * 2 + cc], cS[ni][rh * 2 + cc]);
                    cS[ni][rh * 2 + cc] = v;
                    rmax = fmaxf(rmax, v);
                }
            rmax = fmaxf(rmax, __shfl_xor_sync(0xffffffffu, rmax, 1));
            rmax = fmaxf(rmax, __shfl_xor_sync(0xffffffffu, rmax, 2));
            float mn = fmaxf(m_run[rh], rmax);
            float rsum = 0.f;
#pragma unroll
            for (int ni = 0; ni < 8; ni++)
#pragma unroll
                for (int cc = 0; cc < 2; cc++) {
                    float e = __expf(cS[ni][rh * 2 + cc] - mn);
                    cS[ni][rh * 2 + cc] = e;
                    rsum += e;
                }
            rsum += __shfl_xor_sync(0xffffffffu, rsum, 1);
            rsum += __shfl_xor_sync(0xffffffffu, rsum, 2);
            scale[rh] = __expf(m_run[rh] - mn);
            l_run[rh] = l_run[rh] * scale[rh] + rsum;
            m_run[rh] = mn;
        }
#pragma unroll
        for (int ni = 0; ni < 8; ni++) {
            oacc[ni][0] *= scale[0]; oacc[ni][1] *= scale[0];
            oacc[ni][2] *= scale[1]; oacc[ni][3] *= scale[1];
        }

#pragma unroll
        for (int kc = 0; kc < 4; kc++) {
            float v00 = cS[2*kc][0],   v01 = cS[2*kc][1];
            float v10 = cS[2*kc][2],   v11 = cS[2*kc][3];
            float v20 = cS[2*kc+1][0], v21 = cS[2*kc+1][1];
            float v30 = cS[2*kc+1][2], v31 = cS[2*kc+1][3];
            float h00 = bf_hi(v00), h01 = bf_hi(v01), h10 = bf_hi(v10), h11 = bf_hi(v11);
            float h20 = bf_hi(v20), h21 = bf_hi(v21), h30 = bf_hi(v30), h31 = bf_hi(v31);
            uint32_t aph0 = pack_bf16(h00, h01), aph1 = pack_bf16(h10, h11);
            uint32_t aph2 = pack_bf16(h20, h21), aph3 = pack_bf16(h30, h31);
            uint32_t apl0 = pack_bf16(v00 - h00, v01 - h01), apl1 = pack_bf16(v10 - h10, v11 - h11);
            uint32_t apl2 = pack_bf16(v20 - h20, v21 - h21), apl3 = pack_bf16(v30 - h30, v31 - h31);
            uint32_t bb = (((uint32_t)(kc * 32) + jx16) ^ xlr);
#pragma unroll
            for (int p = 0; p < 4; p++) {
                uint32_t vh0, vh1, vh2, vh3, vl0, vl1, vl2, vl3;
                ldsm4(vh0, vh1, vh2, vh3, aVh + jrow[p] + bb);
                ldsm4(vl0, vl1, vl2, vl3, aVl + jrow[p] + bb);
                hmma(oacc[2*p],   aph0, aph1, aph2, aph3, vh0, vh1);
                hmma(oacc[2*p+1], aph0, aph1, aph2, aph3, vh2, vh3);
                hmma(oacc[2*p],   apl0, apl1, apl2, apl3, vh0, vh1);
                hmma(oacc[2*p+1], apl0, apl1, apl2, apl3, vh2, vh3);
                hmma(oacc[2*p],   aph0, aph1, aph2, aph3, vl0, vl1);
                hmma(oacc[2*p+1], aph0, aph1, aph2, aph3, vl2, vl3);
            }
        }

        __syncthreads();
        if (jt + 3 < 16) issue_stage(jt + 3, (jt + 3) & (NSTG - 1));
    }

    // ---- epilogue: fp16 hi/lo for the out projection ----
    float inv0 = 1.f / l_run[0], inv1 = 1.f / l_run[1];
#pragma unroll
    for (int rh = 0; rh < 2; rh++) {
        int row = i0 + 16 * w + g + rh * 8;
        float inv = rh ? inv1 : inv0;
        size_t base = ((size_t)(b * Lc) + row) * Dc + h * dc;
#pragma unroll
        for (int ni = 0; ni < 8; ni++) {
            float v0 = oacc[ni][rh * 2]     * inv;
            float v1 = oacc[ni][rh * 2 + 1] * inv;
            float h0 = f16_hi(v0), h1 = f16_hi(v1);
            size_t idx = base + ni * 8 + t2;
            *(uint32_t*)(g_ohh + idx) = pack_f16(h0, h1);
            *(uint32_t*)(g_ohl + idx) = pack_f16(v0 - h0, v1 - h1);
        }
    }
}

// ---------------- launch ----------------
extern "C" void kernel_launch(void* const* d_in, const int* in_sizes, int n_in,
                              void* d_out, int out_size) {
    const float* x     = (const float*)d_in[0];
    const float* t_enc = (const float*)d_in[1];
    const float* WQ    = (const float*)d_in[2];
    const float* WK    = (const float*)d_in[3];
    const float* WV    = (const float*)d_in[4];
    const float* WO    = (const float*)d_in[5];
    const float* bO    = (const float*)d_in[6];
    const float* Wt    = (const float*)d_in[7];
    const float* bt    = (const float*)d_in[8];
    const float* p_mat = (const float*)d_in[9];
    const float* r_mat = (const float*)d_in[10];
    const float* alpha = (const float*)d_in[11];
    const float* beta  = (const float*)d_in[12];
    const float* gamma = (const float*)d_in[13];
    float* out = (float*)d_out;

    cudaFuncSetAttribute(attn_mma, cudaFuncAttributeMaxDynamicSharedMemorySize,
                         ATTN_SMEM_BYTES);
    cudaFuncSetAttribute(qkv_mma, cudaFuncAttributeMaxDynamicSharedMemorySize,
                         GEMM_SMEM_BYTES);
    cudaFuncSetAttribute(out_mma, cudaFuncAttributeMaxDynamicSharedMemorySize,
                         OUT_SMEM_BYTES);

    __nv_bfloat16 *xh, *xl;
    cudaGetSymbolAddress((void**)&xh, g_xh);
    cudaGetSymbolAddress((void**)&xl, g_xl);

    colsum_kernel<<<dim3(Lc / 256, 2), 256>>>(p_mat, r_mat);
    coords_kernel<<<(Bc * Lc) / 128, 128>>>(t_enc, Wt, bt);
    split_kernel<<<(Bc * Lc * Dc) / (256 * 4), 256>>>(x, xh, xl);
    split_w_kernel<<<dim3((Dc * Dc) / (256 * 4), 4), 256>>>(WQ, WK, WV, WO);
    qkv_mma<<<dim3(Dc / 128, (Bc * Lc) / 128, 3), 128, GEMM_SMEM_BYTES>>>();
    attn_mma<<<dim3(Lc / 128, Bc * Hc), 256, ATTN_SMEM_BYTES>>>(alpha, beta, gamma);
    out_mma<<<dim3(Dc / 128, (Bc * Lc) / 128), 128, OUT_SMEM_BYTES>>>(bO, out);
}

// round 15
// speedup vs baseline: 3.0121x; 1.0483x over previous
#include <cuda_runtime.h>
#include <cuda_bf16.h>
#include <cuda_fp16.h>
#include <math.h>
#include <stdint.h>

#define Bc 4
#define Lc 1024
#define Dc 1024
#define Hc 16
#define Tc 64
#define dc 64
#define BHLD (Bc*Hc*Lc*dc)   /* 4,194,304 */

// ---------------- scratch ----------------
__device__ float g_coords[Bc * Lc];
__device__ float g_qsca[Bc * Lc];
__device__ float g_psum[Lc];
__device__ float g_rsum[Lc];
__device__ __nv_bfloat16 g_xh[Bc*Lc*Dc], g_xl[Bc*Lc*Dc];     // x bf16 (score path)
__device__ __half        g_xfh[Bc*Lc*Dc], g_xfl[Bc*Lc*Dc];   // x fp16 (V projection)
__device__ __nv_bfloat16 g_wh[2*Dc*Dc],  g_wl[2*Dc*Dc];      // WQ|WK bf16
__device__ __half        g_wvh[Dc*Dc];                        // WV fp16 hi
__device__ __half        g_woh[Dc*Dc];                        // WO fp16 hi
__device__ __nv_bfloat16 g_qh[BHLD], g_ql[BHLD];             // Q*0.125 (b,h,l,d)
__device__ __nv_bfloat16 g_kh[BHLD], g_kl[BHLD];             // K (b,h,l,d)
__device__ __half        g_vth[BHLD];                         // V^T fp16 hi (b,h,d,l)
__device__ __half g_ohh[Bc*Lc*Dc], g_ohl[Bc*Lc*Dc];          // attn out fp16 hi/lo

__device__ __forceinline__ uint32_t pack_bf16(float lo, float hi) {
    __nv_bfloat162 r = __floats2bfloat162_rn(lo, hi);
    return *(uint32_t*)&r;
}
__device__ __forceinline__ float bf_hi(float v) {
    return __bfloat162float(__float2bfloat16(v));
}
__device__ __forceinline__ uint32_t pack_f16(float lo, float hi) {
    __half2 r = __floats2half2_rn(lo, hi);
    return *(uint32_t*)&r;
}
__device__ __forceinline__ float f16_hi(float v) {
    return __half2float(__float2half_rn(v));
}
__device__ __forceinline__ uint32_t smem_u32(const void* p) {
    uint32_t a;
    asm("{ .reg .u64 t; cvta.to.shared.u64 t, %1; cvt.u32.u64 %0, t; }" : "=r"(a) : "l"(p));
    return a;
}
__device__ __forceinline__ void cp16(uint32_t dst, const void* src) {
    asm volatile("cp.async.cg.shared.global [%0], [%1], 16;" :: "r"(dst), "l"(src));
}
#define CP_COMMIT() asm volatile("cp.async.commit_group;" ::: "memory")
#define CP_WAIT0()  asm volatile("cp.async.wait_group 0;"  ::: "memory")
#define CP_WAIT1()  asm volatile("cp.async.wait_group 1;"  ::: "memory")
#define CP_WAIT2()  asm volatile("cp.async.wait_group 2;"  ::: "memory")

__device__ __forceinline__ void ldsm4(uint32_t& r0, uint32_t& r1, uint32_t& r2,
                                      uint32_t& r3, uint32_t addr) {
    asm volatile("ldmatrix.sync.aligned.m8n8.x4.shared.b16 {%0,%1,%2,%3}, [%4];"
                 : "=r"(r0), "=r"(r1), "=r"(r2), "=r"(r3) : "r"(addr));
}

// ---------------- kernel 0: column sums ----------------
__global__ void colsum_kernel(const float* __restrict__ p_mat,
                              const float* __restrict__ r_mat) {
    int l = blockIdx.x * blockDim.x + threadIdx.x;
    if (l >= Lc) return;
    const float* src = blockIdx.y ? r_mat : p_mat;
    float s = 0.f;
#pragma unroll 8
    for (int dd = 0; dd < Dc; dd++) s += src[dd * Lc + l];
    if (blockIdx.y) g_rsum[l] = s; else g_psum[l] = s;
}

// ---------------- kernel 1: coords + cubic q_sca ----------------
__global__ void coords_kernel(const float* __restrict__ t_enc,
                              const float* __restrict__ Wt,
                              const float* __restrict__ bt) {
    int n = blockIdx.x * blockDim.x + threadIdx.x;
    if (n >= Bc * Lc) return;
    float z = bt[0];
    const float* te = t_enc + (size_t)n * Tc;
#pragma unroll
    for (int k = 0; k < Tc; k++) z += te[k] * Wt[k];
    float tau = 1.f / (1.f + expf(-z));
    float c = tau * (float)(Lc - 1);
    g_coords[n] = c;
    int i = (int)floorf(c);
    float t = c - (float)i;
    int im1 = min(max(i - 1, 0), Lc - 1);
    int ii0 = min(max(i,     0), Lc - 1);
    int ii1 = min(max(i + 1, 0), Lc - 1);
    int ii2 = min(max(i + 2, 0), Lc - 1);
    float p0 = g_psum[im1], p1 = g_psum[ii0], p2 = g_psum[ii1], p3 = g_psum[ii2];
    float t2 = t * t, t3 = t2 * t;
    g_qsca[n] = 0.5f * (2.f * p1 + (-p0 + p2) * t
              + (2.f * p0 - 5.f * p1 + 4.f * p2 - p3) * t2
              + (-p0 + 3.f * p1 - 3.f * p2 + p3) * t3);
}

// ---------------- split x: bf16 hi/lo + fp16 hi/lo ----------------
__global__ void split_x_kernel(const float* __restrict__ s) {
    int i = (blockIdx.x * blockDim.x + threadIdx.x) * 4;
    float4 v = *(const float4*)(s + i);
    float h0 = bf_hi(v.x), h1 = bf_hi(v.y), h2 = bf_hi(v.z), h3 = bf_hi(v.w);
    *(uint2*)(g_xh + i) = make_uint2(pack_bf16(h0, h1), pack_bf16(h2, h3));
    *(uint2*)(g_xl + i) = make_uint2(pack_bf16(v.x - h0, v.y - h1), pack_bf16(v.z - h2, v.w - h3));
    float f0 = f16_hi(v.x), f1 = f16_hi(v.y), f2 = f16_hi(v.z), f3 = f16_hi(v.w);
    *(uint2*)(g_xfh + i) = make_uint2(pack_f16(f0, f1), pack_f16(f2, f3));
    *(uint2*)(g_xfl + i) = make_uint2(pack_f16(v.x - f0, v.y - f1), pack_f16(v.z - f2, v.w - f3));
}
__global__ void split_w_kernel(const float* __restrict__ WQ, const float* __restrict__ WK,
                               const float* __restrict__ WV, const float* __restrict__ WO) {
    int i = (blockIdx.x * blockDim.x + threadIdx.x) * 4;
    if (blockIdx.y >= 2) {   // WV / WO: fp16 hi only
        const float* src = (blockIdx.y == 2) ? WV : WO;
        __half* dst = (blockIdx.y == 2) ? g_wvh : g_woh;
        float4 v = *(const float4*)(src + i);
        *(uint2*)(dst + i) = make_uint2(pack_f16(v.x, v.y), pack_f16(v.z, v.w));
        return;
    }
    const float* src = (blockIdx.y == 0) ? WQ : WK;
    size_t off = (size_t)blockIdx.y << 20;
    float4 v = *(const float4*)(src + i);
    float h0 = bf_hi(v.x), h1 = bf_hi(v.y), h2 = bf_hi(v.z), h3 = bf_hi(v.w);
    *(uint2*)(g_wh + off + i) = make_uint2(pack_bf16(h0, h1), pack_bf16(h2, h3));
    *(uint2*)(g_wl + off + i) = make_uint2(pack_bf16(v.x - h0, v.y - h1), pack_bf16(v.z - h2, v.w - h3));
}

// ================= shared mma machinery =================
#define KP 40
#define SB (128 * KP)
#define STG (4 * SB)
#define GEMM_SMEM_BYTES (2 * STG * 2)   // 81920
#define OSTG (3 * SB)
#define OUT_SMEM_BYTES (2 * OSTG * 2)   // 61440

__device__ __forceinline__ void hmma(float c[4], uint32_t a0, uint32_t a1, uint32_t a2,
                                     uint32_t a3, uint32_t b0, uint32_t b1) {
    asm volatile(
        "mma.sync.aligned.m16n8k16.row.col.f32.bf16.bf16.f32 "
        "{%0,%1,%2,%3}, {%4,%5,%6,%7}, {%8,%9}, {%0,%1,%2,%3};"
        : "+f"(c[0]), "+f"(c[1]), "+f"(c[2]), "+f"(c[3])
        : "r"(a0), "r"(a1), "r"(a2), "r"(a3), "r"(b0), "r"(b1));
}
__device__ __forceinline__ void hmma16(float c[4], uint32_t a0, uint32_t a1, uint32_t a2,
                                       uint32_t a3, uint32_t b0, uint32_t b1) {
    asm volatile(
        "mma.sync.aligned.m16n8k16.row.col.f32.f16.f16.f32 "
        "{%0,%1,%2,%3}, {%4,%5,%6,%7}, {%8,%9}, {%0,%1,%2,%3};"
        : "+f"(c[0]), "+f"(c[1]), "+f"(c[2]), "+f"(c[3])
        : "r"(a0), "r"(a1), "r"(a2), "r"(a3), "r"(b0), "r"(b1));
}

__device__ __forceinline__ void frag_offsets(uint32_t aoff[4], uint32_t boff[4]) {
    int lane = threadIdx.x & 31, w = threadIdx.x >> 5;
    int wm = w >> 1, wn = w & 1;
    int quad = lane >> 3, lr = lane & 7;
#pragma unroll
    for (int mi = 0; mi < 4; mi++)
        aoff[mi] = (uint32_t)(((wm * 64 + mi * 16 + (quad & 1) * 8 + lr) * KP
                               + (quad >> 1) * 8) * 2);
#pragma unroll
    for (int p = 0; p < 4; p++)
        boff[p] = (uint32_t)(((wn * 64 + p * 16 + (quad >> 1) * 8 + lr) * KP
                              + (quad & 1) * 8) * 2);
}

// ---------------- bf16x3 core (Q/K projections) ----------------
__device__ __forceinline__ void gemm_gissue(uint32_t st32,
                                            const __nv_bfloat16* Ah, const __nv_bfloat16* Al,
                                            const __nv_bfloat16* Bh, const __nv_bfloat16* Bl,
                                            int k0) {
    int tid = threadIdx.x;
#pragma unroll
    for (int i = 0; i < 4; i++) {
        int v = tid + i * 128;
        int row = v >> 2, seg = v & 3;
        size_t gs = (size_t)row * Dc + k0 + seg * 8;
        uint32_t so = (uint32_t)((row * KP + seg * 8) * 2);
        cp16(st32 + so,              Ah + gs);
        cp16(st32 + SB * 2 + so,     Al + gs);
        cp16(st32 + 2 * SB * 2 + so, Bh + gs);
        cp16(st32 + 3 * SB * 2 + so, Bl + gs);
    }
}

__device__ __forceinline__ void mma_core(const __nv_bfloat16* Ah, const __nv_bfloat16* Al,
                                         const __nv_bfloat16* Bh, const __nv_bfloat16* Bl,
                                         __nv_bfloat16* S, float c[4][8][4]) {
    uint32_t aoff[4], boff[4];
    frag_offsets(aoff, boff);
    uint32_t s32 = smem_u32(S);
    gemm_gissue(s32, Ah, Al, Bh, Bl, 0);
    CP_COMMIT();
    gemm_gissue(s32 + STG * 2, Ah, Al, Bh, Bl, 32);
    CP_COMMIT();
    const int NCH = Dc / 32;
    for (int ch = 0; ch < NCH; ch++) {
        CP_WAIT1();
        __syncthreads();
        uint32_t base = s32 + (ch & 1) * (STG * 2);
        uint32_t aAh = base, aAl = base + SB * 2;
        uint32_t aBh = base + 2 * SB * 2, aBl = base + 3 * SB * 2;
#pragma unroll
        for (int ks = 0; ks < 32; ks += 16) {
            uint32_t kb = (uint32_t)(ks * 2);
            uint32_t ah[4][4], al[4][4];
#pragma unroll
            for (int mi = 0; mi < 4; mi++) {
                ldsm4(ah[mi][0], ah[mi][1], ah[mi][2], ah[mi][3], aAh + aoff[mi] + kb);
                ldsm4(al[mi][0], al[mi][1], al[mi][2], al[mi][3], aAl + aoff[mi] + kb);
            }
            uint32_t bh[8][2], bl[8][2];
#pragma unroll
            for (int p = 0; p < 4; p++) {
                ldsm4(bh[2*p][0], bh[2*p][1], bh[2*p+1][0], bh[2*p+1][1], aBh + boff[p] + kb);
                ldsm4(bl[2*p][0], bl[2*p][1], bl[2*p+1][0], bl[2*p+1][1], aBl + boff[p] + kb);
            }
#pragma unroll
            for (int ni = 0; ni < 8; ni++)
#pragma unroll
                for (int mi = 0; mi < 4; mi++)
                    hmma(c[mi][ni], ah[mi][0], ah[mi][1], ah[mi][2], ah[mi][3],
                         bh[ni][0], bh[ni][1]);
#pragma unroll
            for (int ni = 0; ni < 8; ni++)
#pragma unroll
                for (int mi = 0; mi < 4; mi++)
                    hmma(c[mi][ni], ah[mi][0], ah[mi][1], ah[mi][2], ah[mi][3],
                         bl[ni][0], bl[ni][1]);
#pragma unroll
            for (int ni = 0; ni < 8; ni++)
#pragma unroll
                for (int mi = 0; mi < 4; mi++)
                    hmma(c[mi][ni], al[mi][0], al[mi][1], al[mi][2], al[mi][3],
                         bh[ni][0], bh[ni][1]);
        }
        __syncthreads();
        if (ch + 2 < NCH) {
            gemm_gissue(s32 + (ch & 1) * (STG * 2), Ah, Al, Bh, Bl, (ch + 2) * 32);
            CP_COMMIT();
        }
    }
}

// ---------------- fp16 2-term core: C = (Ah+Al)*Bh ----------------
__device__ __forceinline__ void mma_core_f16(const __half* Ah, const __half* Al,
                                             const __half* Bh,
                                             __half* S, float c[4][8][4]) {
    uint32_t aoff[4], boff[4];
    frag_offsets(aoff, boff);
    uint32_t s32 = smem_u32(S);
    auto issue = [&](uint32_t st32, int k0) {
        int tid = threadIdx.x;
#pragma unroll
        for (int i = 0; i < 4; i++) {
            int v = tid + i * 128;
            int row = v >> 2, seg = v & 3;
            size_t gs = (size_t)row * Dc + k0 + seg * 8;
            uint32_t so = (uint32_t)((row * KP + seg * 8) * 2);
            cp16(st32 + so,              Ah + gs);
            cp16(st32 + SB * 2 + so,     Al + gs);
            cp16(st32 + 2 * SB * 2 + so, Bh + gs);
        }
        CP_COMMIT();
    };
    issue(s32, 0);
    issue(s32 + OSTG * 2, 32);
    const int NCH = Dc / 32;
    for (int ch = 0; ch < NCH; ch++) {
        CP_WAIT1();
        __syncthreads();
        uint32_t base = s32 + (ch & 1) * (OSTG * 2);
        uint32_t aAh = base, aAl = base + SB * 2, aBh = base + 2 * SB * 2;
#pragma unroll
        for (int ks = 0; ks < 32; ks += 16) {
            uint32_t kb = (uint32_t)(ks * 2);
            uint32_t ah[4][4], al[4][4];
#pragma unroll
            for (int mi = 0; mi < 4; mi++) {
                ldsm4(ah[mi][0], ah[mi][1], ah[mi][2], ah[mi][3], aAh + aoff[mi] + kb);
                ldsm4(al[mi][0], al[mi][1], al[mi][2], al[mi][3], aAl + aoff[mi] + kb);
            }
            uint32_t bh[8][2];
#pragma unroll
            for (int p = 0; p < 4; p++)
                ldsm4(bh[2*p][0], bh[2*p][1], bh[2*p+1][0], bh[2*p+1][1], aBh + boff[p] + kb);
#pragma unroll
            for (int ni = 0; ni < 8; ni++)
#pragma unroll
                for (int mi = 0; mi < 4; mi++)
                    hmma16(c[mi][ni], ah[mi][0], ah[mi][1], ah[mi][2], ah[mi][3],
                           bh[ni][0], bh[ni][1]);
#pragma unroll
            for (int ni = 0; ni < 8; ni++)
#pragma unroll
                for (int mi = 0; mi < 4; mi++)
                    hmma16(c[mi][ni], al[mi][0], al[mi][1], al[mi][2], al[mi][3],
                           bh[ni][0], bh[ni][1]);
        }
        __syncthreads();
        if (ch + 2 < NCH) issue(s32 + (ch & 1) * (OSTG * 2), (ch + 2) * 32);
    }
}

// ---------------- kernel 2a: Q/K projection (bf16x3) ----------------
__global__ void __launch_bounds__(128, 2) qk_mma() {
    extern __shared__ __nv_bfloat16 Sdyn[];
    int z = blockIdx.z;
    int M0 = blockIdx.y * 128, N0 = blockIdx.x * 128;
    const __nv_bfloat16* Ah = g_xh + (size_t)M0 * Dc;
    const __nv_bfloat16* Al = g_xl + (size_t)M0 * Dc;
    const __nv_bfloat16* Bh = g_wh + ((size_t)z << 20) + (size_t)N0 * Dc;
    const __nv_bfloat16* Bl = g_wl + ((size_t)z << 20) + (size_t)N0 * Dc;
    float c[4][8][4] = {};
    mma_core(Ah, Al, Bh, Bl, Sdyn, c);

    int lane = threadIdx.x & 31, w = threadIdx.x >> 5;
    int wm = w >> 1, wn = w & 1;
    int g = lane >> 2, t2 = (lane & 3) * 2;
    __nv_bfloat16* dh = z ? g_kh : g_qh;
    __nv_bfloat16* dl = z ? g_kl : g_ql;
    float qs = z ? 1.0f : 0.125f;
#pragma unroll
    for (int mi = 0; mi < 4; mi++)
#pragma unroll
        for (int ni = 0; ni < 8; ni++) {
            int col = N0 + wn * 64 + ni * 8 + t2;
            int h = col >> 6, dd = col & 63;
#pragma unroll
            for (int rh = 0; rh < 2; rh++) {
                int row = M0 + wm * 64 + mi * 16 + g + rh * 8;
                int bb = row >> 10, l = row & (Lc - 1);
                float v0 = c[mi][ni][rh * 2] * qs, v1 = c[mi][ni][rh * 2 + 1] * qs;
                float h0 = bf_hi(v0), h1 = bf_hi(v1);
                size_t idx = (((size_t)(bb * Hc + h)) * Lc + l) * dc + dd;
                *(uint32_t*)(dh + idx) = pack_bf16(h0, h1);
                *(uint32_t*)(dl + idx) = pack_bf16(v0 - h0, v1 - h1);
            }
        }
}

// ---------------- kernel 2b: V projection (fp16 2-term) -> V^T fp16 hi ----------------
__global__ void __launch_bounds__(128, 2) v_mma() {
    extern __shared__ __half Sh[];
    int M0 = blockIdx.y * 128, N0 = blockIdx.x * 128;
    const __half* Ah = g_xfh + (size_t)M0 * Dc;
    const __half* Al = g_xfl + (size_t)M0 * Dc;
    const __half* Bh = g_wvh + (size_t)N0 * Dc;
    float c[4][8][4] = {};
    mma_core_f16(Ah, Al, Bh, Sh, c);

    int lane = threadIdx.x & 31, w = threadIdx.x >> 5;
    int wm = w >> 1, wn = w & 1;
    int g = lane >> 2, t2 = (lane & 3) * 2;
    // transpose via smem: [col][row] pitch 136, fp16 hi only
    uint16_t* sT = (uint16_t*)Sh;
#pragma unroll
    for (int mi = 0; mi < 4; mi++)
#pragma unroll
        for (int ni = 0; ni < 8; ni++) {
            int col_l = wn * 64 + ni * 8 + t2;
#pragma unroll
            for (int rh = 0; rh < 2; rh++) {
                int row_l = wm * 64 + mi * 16 + g + rh * 8;
#pragma unroll
                for (int cc = 0; cc < 2; cc++) {
                    __half vh = __float2half_rn(c[mi][ni][rh * 2 + cc]);
                    sT[(col_l + cc) * 136 + row_l] = *(uint16_t*)&vh;
                }
            }
        }
    __syncthreads();
    int bb = M0 >> 10, l0 = M0 & (Lc - 1);
    // FIXED: full 128-row coverage (16 segments of 8 halves per column)
#pragma unroll
    for (int q = 0; q < 16; q++) {
        int v = threadIdx.x + q * 128;
        int d = v >> 4, seg = v & 15;
        int col = N0 + d;
        int h = col >> 6, dd = col & 63;
        size_t dst = (((size_t)(bb * Hc + h)) * dc + dd) * Lc + l0 + seg * 8;
        *(uint4*)(g_vth + dst) = *(const uint4*)(sT + d * 136 + seg * 8);
    }
}

// ---------------- kernel 4: output projection (fp16 2-term) ----------------
__global__ void __launch_bounds__(128, 2) out_mma(const float* __restrict__ bO,
                                                  float* __restrict__ out) {
    extern __shared__ __half Sh[];
    int M0 = blockIdx.y * 128, N0 = blockIdx.x * 128;
    const __half* Ah = g_ohh + (size_t)M0 * Dc;
    const __half* Al = g_ohl + (size_t)M0 * Dc;
    const __half* Bh = g_woh + (size_t)N0 * Dc;
    float c[4][8][4] = {};
    mma_core_f16(Ah, Al, Bh, Sh, c);

    int lane = threadIdx.x & 31, w = threadIdx.x >> 5;
    int wm = w >> 1, wn = w & 1;
    int g = lane >> 2, t2 = (lane & 3) * 2;
#pragma unroll
    for (int mi = 0; mi < 4; mi++)
#pragma unroll
        for (int ni = 0; ni < 8; ni++) {
            int col = N0 + wn * 64 + ni * 8 + t2;
            float2 bv = *(const float2*)(bO + col);
#pragma unroll
            for (int rh = 0; rh < 2; rh++) {
                int row = M0 + wm * 64 + mi * 16 + g + rh * 8;
                float2 v = make_float2(c[mi][ni][rh * 2] + bv.x,
                                       c[mi][ni][rh * 2 + 1] + bv.y);
                *(float2*)(out + (size_t)row * Dc + col) = v;
            }
        }
}

// ---------------- kernel 3: flash attention (PV fp16 2-term, 5-buffer stages) ----------------
#define JROWB 128
#define JBUFB (64 * JROWB)
#define JSTGB (5 * JBUFB)
#define NSTG 4
#define ATTN_SMEM_BYTES (NSTG * JSTGB + (Lc + NSTG * 64 * 2) * 4)

__device__ __forceinline__ uint32_t jswz(int row, int byte_in_row) {
    return (uint32_t)(row * JROWB + (byte_in_row ^ ((row & 7) << 4)));
}

__global__ void __launch_bounds__(256, 1) attn_mma(const float* __restrict__ alpha,
                                                   const float* __restrict__ beta,
                                                   const float* __restrict__ gamma) {
    extern __shared__ __nv_bfloat16 smb[];
    __nv_bfloat16* jbase = smb;
    float* sR  = (float*)((char*)smb + NSTG * JSTGB);
    float* sCj = sR + Lc;
    float* sQj = sCj + NSTG * 64;

    uint32_t jb32 = smem_u32(jbase);

    int t = threadIdx.x;
    int w = t >> 5, lane = t & 31;
    int g = lane >> 2, t2 = (lane & 3) * 2;
    int quad = lane >> 3, lr = lane & 7;
    int bh = blockIdx.y;
    int b = bh >> 4, h = bh & 15;
    int i0 = blockIdx.x * 128;

    float a_h = alpha[h], b_h = beta[h], c_h = gamma[h];

    const size_t qoff = ((size_t)bh * Lc) * dc;
    const size_t xoff = ((size_t)b * Lc) * Dc + h * dc;
    const size_t voff = (size_t)bh * dc * Lc;

    for (int idx = t; idx < Lc; idx += 256) sR[idx] = g_rsum[idx];

    auto issue_stage = [&](int jt, int st) {
        uint32_t s32 = jb32 + (uint32_t)st * JSTGB;
        int j0 = jt * 64;
#pragma unroll
        for (int q = 0; q < 2; q++) {
            int v = t * 2 + q;
            int row = v >> 3, seg = v & 7;
            uint32_t boff = jswz(row, seg * 16);
            size_t gk = qoff + (size_t)(j0 + row) * dc + seg * 8;
            size_t gx = xoff + (size_t)(j0 + row) * Dc + seg * 8;
            size_t gv = voff + (size_t)row * Lc + j0 + seg * 8;
            cp16(s32 + 0 * JBUFB + boff, g_kh  + gk);
            cp16(s32 + 1 * JBUFB + boff, g_kl  + gk);
            cp16(s32 + 2 * JBUFB + boff, g_xh  + gx);
            cp16(s32 + 3 * JBUFB + boff, g_xl  + gx);
            cp16(s32 + 4 * JBUFB + boff, g_vth + gv);
        }
        CP_COMMIT();
        if (t < 64) {
            sCj[st * 64 + t] = g_coords[b * Lc + j0 + t];
            sQj[st * 64 + t] = a_h * g_qsca[b * Lc + j0 + t];
        }
    };
    issue_stage(0, 0);
    issue_stage(1, 1);
    issue_stage(2, 2);

    uint32_t jrow[4];
#pragma unroll
    for (int p = 0; p < 4; p++)
        jrow[p] = (uint32_t)((p * 16 + (quad >> 1) * 8 + lr) * JROWB);
    uint32_t jx16 = (uint32_t)((quad & 1) * 16);
    uint32_t xlr  = (uint32_t)(lr << 4);

    uint32_t fqh[16], fql[16], fph[16], fpl[16];
    {
        int r0 = i0 + 16 * w + g;
#pragma unroll
        for (int ks4 = 0; ks4 < 4; ks4++) {
            int cc0 = ks4 * 16 + t2;
            size_t q0 = qoff + (size_t)r0 * dc + cc0;
            size_t q8 = qoff + (size_t)(r0 + 8) * dc + cc0;
            size_t x0 = xoff + (size_t)r0 * Dc + cc0;
            size_t x8 = xoff + (size_t)(r0 + 8) * Dc + cc0;
            fqh[ks4*4+0] = *(const uint32_t*)(g_qh + q0);
            fqh[ks4*4+1] = *(const uint32_t*)(g_qh + q8);
            fqh[ks4*4+2] = *(const uint32_t*)(g_qh + q0 + 8);
            fqh[ks4*4+3] = *(const uint32_t*)(g_qh + q8 + 8);
            fql[ks4*4+0] = *(const uint32_t*)(g_ql + q0);
            fql[ks4*4+1] = *(const uint32_t*)(g_ql + q8);
            fql[ks4*4+2] = *(const uint32_t*)(g_ql + q0 + 8);
            fql[ks4*4+3] = *(const uint32_t*)(g_ql + q8 + 8);
            fph[ks4*4+0] = *(const uint32_t*)(g_xh + x0);
            fph[ks4*4+1] = *(const uint32_t*)(g_xh + x8);
            fph[ks4*4+2] = *(const uint32_t*)(g_xh + x0 + 8);
            fph[ks4*4+3] = *(const uint32_t*)(g_xh + x8 + 8);
            fpl[ks4*4+0] = *(const uint32_t*)(g_xl + x0);
            fpl[ks4*4+1] = *(const uint32_t*)(g_xl + x8);
            fpl[ks4*4+2] = *(const uint32_t*)(g_xl + x0 + 8);
            fpl[ks4*4+3] = *(const uint32_t*)(g_xl + x8 + 8);
        }
    }
    float ci_r[2], qi_r[2];
    {
        int r0 = i0 + 16 * w + g;
        ci_r[0] = g_coords[b * Lc + r0];
        ci_r[1] = g_coords[b * Lc + r0 + 8];
        qi_r[0] = fmaf(a_h, g_qsca[b * Lc + r0], c_h);
        qi_r[1] = fmaf(a_h, g_qsca[b * Lc + r0 + 8], c_h);
    }

    float oacc[8][4] = {};
    float m_run[2] = {-INFINITY, -INFINITY}, l_run[2] = {0.f, 0.f};

    for (int jt = 0; jt < 16; jt++) {
        int st = jt & (NSTG - 1);
        if (jt <= 13) CP_WAIT2();
        else if (jt == 14) CP_WAIT1();
        else CP_WAIT0();
        __syncthreads();

        uint32_t stb = jb32 + (uint32_t)st * JSTGB;
        uint32_t aKh = stb, aKl = stb + JBUFB;
        uint32_t aJh = stb + 2 * JBUFB, aJl = stb + 3 * JBUFB;
        uint32_t aVh = stb + 4 * JBUFB;
        const float* cjp = sCj + st * 64;
        const float* qjp = sQj + st * 64;

        float cS[8][4] = {}, cP[8][4] = {};
#pragma unroll
        for (int ks4 = 0; ks4 < 4; ks4++) {
            uint32_t bb = (((uint32_t)(ks4 * 32) + jx16) ^ xlr);
            const uint32_t* Q = fqh + ks4 * 4;
            const uint32_t* Ql = fql + ks4 * 4;
            const uint32_t* P = fph + ks4 * 4;
            const uint32_t* Pl = fpl + ks4 * 4;
#pragma unroll
            for (int p = 0; p < 4; p++) {
                uint32_t kh0, kh1, kh2, kh3, kl0, kl1, kl2, kl3;
                uint32_t jh0, jh1, jh2, jh3, jl0, jl1, jl2, jl3;
                ldsm4(kh0, kh1, kh2, kh3, aKh + jrow[p] + bb);
                ldsm4(kl0, kl1, kl2, kl3, aKl + jrow[p] + bb);
                ldsm4(jh0, jh1, jh2, jh3, aJh + jrow[p] + bb);
                ldsm4(jl0, jl1, jl2, jl3, aJl + jrow[p] + bb);
                hmma(cS[2*p],   Q[0], Q[1], Q[2], Q[3], kh0, kh1);
                hmma(cS[2*p+1], Q[0], Q[1], Q[2], Q[3], kh2, kh3);
                hmma(cP[2*p],   P[0], P[1], P[2], P[3], jh0, jh1);
                hmma(cP[2*p+1], P[0], P[1], P[2], P[3], jh2, jh3);
                hmma(cS[2*p],   Q[0], Q[1], Q[2], Q[3], kl0, kl1);
                hmma(cS[2*p+1], Q[0], Q[1], Q[2], Q[3], kl2, kl3);
                hmma(cP[2*p],   P[0], P[1], P[2], P[3], jl0, jl1);
                hmma(cP[2*p+1], P[0], P[1], P[2], P[3], jl2, jl3);
                hmma(cS[2*p],   Ql[0], Ql[1], Ql[2], Ql[3], kh0, kh1);
                hmma(cS[2*p+1], Ql[0], Ql[1], Ql[2], Ql[3], kh2, kh3);
                hmma(cP[2*p],   Pl[0], Pl[1], Pl[2], Pl[3], jh0, jh1);
                hmma(cP[2*p+1], Pl[0], Pl[1], Pl[2], Pl[3], jh2, jh3);
            }
        }

        float scale[2];
#pragma unroll
        for (int rh = 0; rh < 2; rh++) {
            float ci = ci_r[rh], base_i = qi_r[rh];
            float rmax = -INFINITY;
#pragma unroll
            for (int ni = 0; ni < 8; ni++)
#pragma unroll
                for (int cc = 0; cc < 2; cc++) {
                    int col = ni * 8 + t2 + cc;
                    float delta = fabsf(ci - cjp[col]);
                    int   di = (int)delta;
                    float tt = delta - (float)di;
                    int d0 = min(di,     Lc - 1);
                    int d1 = min(di + 1, Lc - 1);
                    float r0 = sR[d0];
                    float r = fmaf(tt, sR[d1] - r0, r0);
                    float S = fmaf(b_h, r, base_i + qjp[col]);
                    float v = fmaf(S, cP[ni][rh * 2 + cc], cS[ni][rh * 2 + cc]);
                    cS[ni][rh * 2 + cc] = v;
                    rmax = fmaxf(rmax, v);
                }
            rmax = fmaxf(rmax, __shfl_xor_sync(0xffffffffu, rmax, 1));
            rmax = fmaxf(rmax, __shfl_xor_sync(0xffffffffu, rmax, 2));
            float mn = fmaxf(m_run[rh], rmax);
            float rsum = 0.f;
#pragma unroll
            for (int ni = 0; ni < 8; ni++)
#pragma unroll
                for (int cc = 0; cc < 2; cc++) {
                    float e = __expf(cS[ni][rh * 2 + cc] - mn);
                    cS[ni][rh * 2 + cc] = e;
                    rsum += e;
                }
            rsum += __shfl_xor_sync(0xffffffffu, rsum, 1);
            rsum += __shfl_xor_sync(0xffffffffu, rsum, 2);
            scale[rh] = __expf(m_run[rh] - mn);
            l_run[rh] = l_run[rh] * scale[rh] + rsum;
            m_run[rh] = mn;
        }
#pragma unroll
        for (int ni = 0; ni < 8; ni++) {
            oacc[ni][0] *= scale[0]; oacc[ni][1] *= scale[0];
            oacc[ni][2] *= scale[1]; oacc[ni][3] *= scale[1];
        }

        // ---- PV: fp16 2-term (P hi/lo x V hi) ----
#pragma unroll
        for (int kc = 0; kc < 4; kc++) {
            float v00 = cS[2*kc][0],   v01 = cS[2*kc][1];
            float v10 = cS[2*kc][2],   v11 = cS[2*kc][3];
            float v20 = cS[2*kc+1][0], v21 = cS[2*kc+1][1];
            float v30 = cS[2*kc+1][2], v31 = cS[2*kc+1][3];
            float h00 = f16_hi(v00), h01 = f16_hi(v01), h10 = f16_hi(v10), h11 = f16_hi(v11);
            float h20 = f16_hi(v20), h21 = f16_hi(v21), h30 = f16_hi(v30), h31 = f16_hi(v31);
            uint32_t aph0 = pack_f16(h00, h01), aph1 = pack_f16(h10, h11);
            uint32_t aph2 = pack_f16(h20, h21), aph3 = pack_f16(h30, h31);
            uint32_t apl0 = pack_f16(v00 - h00, v01 - h01), apl1 = pack_f16(v10 - h10, v11 - h11);
            uint32_t apl2 = pack_f16(v20 - h20, v21 - h21), apl3 = pack_f16(v30 - h30, v31 - h31);
            uint32_t bb = (((uint32_t)(kc * 32) + jx16) ^ xlr);
#pragma unroll
            for (int p = 0; p < 4; p++) {
                uint32_t vh0, vh1, vh2, vh3;
                ldsm4(vh0, vh1, vh2, vh3, aVh + jrow[p] + bb);
                hmma16(oacc[2*p],   aph0, aph1, aph2, aph3, vh0, vh1);
                hmma16(oacc[2*p+1], aph0, aph1, aph2, aph3, vh2, vh3);
                hmma16(oacc[2*p],   apl0, apl1, apl2, apl3, vh0, vh1);
                hmma16(oacc[2*p+1], apl0, apl1, apl2, apl3, vh2, vh3);
            }
        }

        __syncthreads();
        if (jt + 3 < 16) issue_stage(jt + 3, (jt + 3) & (NSTG - 1));
    }

    // ---- epilogue: fp16 hi/lo for the out projection ----
    float inv0 = 1.f / l_run[0], inv1 = 1.f / l_run[1];
#pragma unroll
    for (int rh = 0; rh < 2; rh++) {
        int row = i0 + 16 * w + g + rh * 8;
        float inv = rh ? inv1 : inv0;
        size_t base = ((size_t)(b * Lc) + row) * Dc + h * dc;
#pragma unroll
        for (int ni = 0; ni < 8; ni++) {
            float v0 = oacc[ni][rh * 2]     * inv;
            float v1 = oacc[ni][rh * 2 + 1] * inv;
            float h0 = f16_hi(v0), h1 = f16_hi(v1);
            size_t idx = base + ni * 8 + t2;
            *(uint32_t*)(g_ohh + idx) = pack_f16(h0, h1);
            *(uint32_t*)(g_ohl + idx) = pack_f16(v0 - h0, v1 - h1);
        }
    }
}

// ---------------- launch ----------------
extern "C" void kernel_launch(void* const* d_in, const int* in_sizes, int n_in,
                              void* d_out, int out_size) {
    const float* x     = (const float*)d_in[0];
    const float* t_enc = (const float*)d_in[1];
    const float* WQ    = (const float*)d_in[2];
    const float* WK    = (const float*)d_in[3];
    const float* WV    = (const float*)d_in[4];
    const float* WO    = (const float*)d_in[5];
    const float* bO    = (const float*)d_in[6];
    const float* Wt    = (const float*)d_in[7];
    const float* bt    = (const float*)d_in[8];
    const float* p_mat = (const float*)d_in[9];
    const float* r_mat = (const float*)d_in[10];
    const float* alpha = (const float*)d_in[11];
    const float* beta  = (const float*)d_in[12];
    const float* gamma = (const float*)d_in[13];
    float* out = (float*)d_out;

    cudaFuncSetAttribute(attn_mma, cudaFuncAttributeMaxDynamicSharedMemorySize,
                         ATTN_SMEM_BYTES);
    cudaFuncSetAttribute(qk_mma, cudaFuncAttributeMaxDynamicSharedMemorySize,
                         GEMM_SMEM_BYTES);
    cudaFuncSetAttribute(v_mma, cudaFuncAttributeMaxDynamicSharedMemorySize,
                         OUT_SMEM_BYTES);
    cudaFuncSetAttribute(out_mma, cudaFuncAttributeMaxDynamicSharedMemorySize,
                         OUT_SMEM_BYTES);

    colsum_kernel<<<dim3(Lc / 256, 2), 256>>>(p_mat, r_mat);
    coords_kernel<<<(Bc * Lc) / 128, 128>>>(t_enc, Wt, bt);
    split_x_kernel<<<(Bc * Lc * Dc) / (256 * 4), 256>>>(x);
    split_w_kernel<<<dim3((Dc * Dc) / (256 * 4), 4), 256>>>(WQ, WK, WV, WO);
    qk_mma<<<dim3(Dc / 128, (Bc * Lc) / 128, 2), 128, GEMM_SMEM_BYTES>>>();
    v_mma<<<dim3(Dc / 128, (Bc * Lc) / 128), 128, OUT_SMEM_BYTES>>>();
    attn_mma<<<dim3(Lc / 128, Bc * Hc), 256, ATTN_SMEM_BYTES>>>(alpha, beta, gamma);
    out_mma<<<dim3(Dc / 128, (Bc * Lc) / 128), 128, OUT_SMEM_BYTES>>>(bO, out);
}

// round 16
// speedup vs baseline: 3.1193x; 1.0356x over previous
#include <cuda_runtime.h>
#include <cuda_fp16.h>
#include <math.h>
#include <stdint.h>

#define Bc 4
#define Lc 1024
#define Dc 1024
#define Hc 16
#define Tc 64
#define dc 64
#define BHLD (Bc*Hc*Lc*dc)   /* 4,194,304 */

// ---------------- scratch (all fp16 now) ----------------
__device__ float g_coords[Bc * Lc];
__device__ float g_qsca[Bc * Lc];
__device__ float g_psum[Lc];
__device__ float g_rsum[Lc];
__device__ __half g_xfh[Bc*Lc*Dc], g_xfl[Bc*Lc*Dc];   // x fp16 hi/lo
__device__ __half g_wh[2*Dc*Dc],  g_wl[2*Dc*Dc];      // WQ|WK fp16 hi/lo
__device__ __half g_wvh[Dc*Dc];                        // WV fp16 hi
__device__ __half g_woh[Dc*Dc];                        // WO fp16 hi
__device__ __half g_qh[BHLD], g_ql[BHLD];             // Q*0.125 (b,h,l,d)
__device__ __half g_kh[BHLD], g_kl[BHLD];             // K (b,h,l,d)
__device__ __half g_vth[BHLD];                         // V^T fp16 hi (b,h,d,l)
__device__ __half g_ohh[Bc*Lc*Dc], g_ohl[Bc*Lc*Dc];   // attn out fp16 hi/lo

__device__ __forceinline__ uint32_t pack_f16(float lo, float hi) {
    __half2 r = __floats2half2_rn(lo, hi);
    return *(uint32_t*)&r;
}
__device__ __forceinline__ float f16_hi(float v) {
    return __half2float(__float2half_rn(v));
}
__device__ __forceinline__ uint32_t smem_u32(const void* p) {
    uint32_t a;
    asm("{ .reg .u64 t; cvta.to.shared.u64 t, %1; cvt.u32.u64 %0, t; }" : "=r"(a) : "l"(p));
    return a;
}
__device__ __forceinline__ void cp16(uint32_t dst, const void* src) {
    asm volatile("cp.async.cg.shared.global [%0], [%1], 16;" :: "r"(dst), "l"(src));
}
#define CP_COMMIT() asm volatile("cp.async.commit_group;" ::: "memory")
#define CP_WAIT0()  asm volatile("cp.async.wait_group 0;"  ::: "memory")
#define CP_WAIT1()  asm volatile("cp.async.wait_group 1;"  ::: "memory")
#define CP_WAIT2()  asm volatile("cp.async.wait_group 2;"  ::: "memory")

__device__ __forceinline__ void ldsm4(uint32_t& r0, uint32_t& r1, uint32_t& r2,
                                      uint32_t& r3, uint32_t addr) {
    asm volatile("ldmatrix.sync.aligned.m8n8.x4.shared.b16 {%0,%1,%2,%3}, [%4];"
                 : "=r"(r0), "=r"(r1), "=r"(r2), "=r"(r3) : "r"(addr));
}
__device__ __forceinline__ void hmma16(float c[4], uint32_t a0, uint32_t a1, uint32_t a2,
                                       uint32_t a3, uint32_t b0, uint32_t b1) {
    asm volatile(
        "mma.sync.aligned.m16n8k16.row.col.f32.f16.f16.f32 "
        "{%0,%1,%2,%3}, {%4,%5,%6,%7}, {%8,%9}, {%0,%1,%2,%3};"
        : "+f"(c[0]), "+f"(c[1]), "+f"(c[2]), "+f"(c[3])
        : "r"(a0), "r"(a1), "r"(a2), "r"(a3), "r"(b0), "r"(b1));
}

// ---------------- kernel 0: column sums ----------------
__global__ void colsum_kernel(const float* __restrict__ p_mat,
                              const float* __restrict__ r_mat) {
    int l = blockIdx.x * blockDim.x + threadIdx.x;
    if (l >= Lc) return;
    const float* src = blockIdx.y ? r_mat : p_mat;
    float s = 0.f;
#pragma unroll 8
    for (int dd = 0; dd < Dc; dd++) s += src[dd * Lc + l];
    if (blockIdx.y) g_rsum[l] = s; else g_psum[l] = s;
}

// ---------------- kernel 1: coords + cubic q_sca ----------------
__global__ void coords_kernel(const float* __restrict__ t_enc,
                              const float* __restrict__ Wt,
                              const float* __restrict__ bt) {
    int n = blockIdx.x * blockDim.x + threadIdx.x;
    if (n >= Bc * Lc) return;
    float z = bt[0];
    const float* te = t_enc + (size_t)n * Tc;
#pragma unroll
    for (int k = 0; k < Tc; k++) z += te[k] * Wt[k];
    float tau = 1.f / (1.f + expf(-z));
    float c = tau * (float)(Lc - 1);
    g_coords[n] = c;
    int i = (int)floorf(c);
    float t = c - (float)i;
    int im1 = min(max(i - 1, 0), Lc - 1);
    int ii0 = min(max(i,     0), Lc - 1);
    int ii1 = min(max(i + 1, 0), Lc - 1);
    int ii2 = min(max(i + 2, 0), Lc - 1);
    float p0 = g_psum[im1], p1 = g_psum[ii0], p2 = g_psum[ii1], p3 = g_psum[ii2];
    float t2 = t * t, t3 = t2 * t;
    g_qsca[n] = 0.5f * (2.f * p1 + (-p0 + p2) * t
              + (2.f * p0 - 5.f * p1 + 4.f * p2 - p3) * t2
              + (-p0 + 3.f * p1 - 3.f * p2 + p3) * t3);
}

// ---------------- splits (all fp16) ----------------
__global__ void split_x_kernel(const float* __restrict__ s) {
    int i = (blockIdx.x * blockDim.x + threadIdx.x) * 4;
    float4 v = *(const float4*)(s + i);
    float f0 = f16_hi(v.x), f1 = f16_hi(v.y), f2 = f16_hi(v.z), f3 = f16_hi(v.w);
    *(uint2*)(g_xfh + i) = make_uint2(pack_f16(f0, f1), pack_f16(f2, f3));
    *(uint2*)(g_xfl + i) = make_uint2(pack_f16(v.x - f0, v.y - f1), pack_f16(v.z - f2, v.w - f3));
}
__global__ void split_w_kernel(const float* __restrict__ WQ, const float* __restrict__ WK,
                               const float* __restrict__ WV, const float* __restrict__ WO) {
    int i = (blockIdx.x * blockDim.x + threadIdx.x) * 4;
    if (blockIdx.y >= 2) {   // WV / WO: fp16 hi only
        const float* src = (blockIdx.y == 2) ? WV : WO;
        __half* dst = (blockIdx.y == 2) ? g_wvh : g_woh;
        float4 v = *(const float4*)(src + i);
        *(uint2*)(dst + i) = make_uint2(pack_f16(v.x, v.y), pack_f16(v.z, v.w));
        return;
    }
    const float* src = (blockIdx.y == 0) ? WQ : WK;
    size_t off = (size_t)blockIdx.y << 20;
    float4 v = *(const float4*)(src + i);
    float f0 = f16_hi(v.x), f1 = f16_hi(v.y), f2 = f16_hi(v.z), f3 = f16_hi(v.w);
    *(uint2*)(g_wh + off + i) = make_uint2(pack_f16(f0, f1), pack_f16(f2, f3));
    *(uint2*)(g_wl + off + i) = make_uint2(pack_f16(v.x - f0, v.y - f1), pack_f16(v.z - f2, v.w - f3));
}

// ================= shared mma machinery =================
#define KP 40
#define SB (128 * KP)
#define STG (4 * SB)
#define GEMM_SMEM_BYTES (2 * STG * 2)   // 81920
#define OSTG (3 * SB)
#define OUT_SMEM_BYTES (2 * OSTG * 2)   // 61440

__device__ __forceinline__ void frag_offsets(uint32_t aoff[4], uint32_t boff[4]) {
    int lane = threadIdx.x & 31, w = threadIdx.x >> 5;
    int wm = w >> 1, wn = w & 1;
    int quad = lane >> 3, lr = lane & 7;
#pragma unroll
    for (int mi = 0; mi < 4; mi++)
        aoff[mi] = (uint32_t)(((wm * 64 + mi * 16 + (quad & 1) * 8 + lr) * KP
                               + (quad >> 1) * 8) * 2);
#pragma unroll
    for (int p = 0; p < 4; p++)
        boff[p] = (uint32_t)(((wn * 64 + p * 16 + (quad >> 1) * 8 + lr) * KP
                              + (quad & 1) * 8) * 2);
}

// ---------------- fp16x3 core (Q/K projections) ----------------
__device__ __forceinline__ void gemm_gissue(uint32_t st32,
                                            const __half* Ah, const __half* Al,
                                            const __half* Bh, const __half* Bl,
                                            int k0) {
    int tid = threadIdx.x;
#pragma unroll
    for (int i = 0; i < 4; i++) {
        int v = tid + i * 128;
        int row = v >> 2, seg = v & 3;
        size_t gs = (size_t)row * Dc + k0 + seg * 8;
        uint32_t so = (uint32_t)((row * KP + seg * 8) * 2);
        cp16(st32 + so,              Ah + gs);
        cp16(st32 + SB * 2 + so,     Al + gs);
        cp16(st32 + 2 * SB * 2 + so, Bh + gs);
        cp16(st32 + 3 * SB * 2 + so, Bl + gs);
    }
}

__device__ __forceinline__ void mma_core3(const __half* Ah, const __half* Al,
                                          const __half* Bh, const __half* Bl,
                                          __half* S, float c[4][8][4]) {
    uint32_t aoff[4], boff[4];
    frag_offsets(aoff, boff);
    uint32_t s32 = smem_u32(S);
    gemm_gissue(s32, Ah, Al, Bh, Bl, 0);
    CP_COMMIT();
    gemm_gissue(s32 + STG * 2, Ah, Al, Bh, Bl, 32);
    CP_COMMIT();
    const int NCH = Dc / 32;
    for (int ch = 0; ch < NCH; ch++) {
        CP_WAIT1();
        __syncthreads();
        uint32_t base = s32 + (ch & 1) * (STG * 2);
        uint32_t aAh = base, aAl = base + SB * 2;
        uint32_t aBh = base + 2 * SB * 2, aBl = base + 3 * SB * 2;
#pragma unroll
        for (int ks = 0; ks < 32; ks += 16) {
            uint32_t kb = (uint32_t)(ks * 2);
            uint32_t ah[4][4], al[4][4];
#pragma unroll
            for (int mi = 0; mi < 4; mi++) {
                ldsm4(ah[mi][0], ah[mi][1], ah[mi][2], ah[mi][3], aAh + aoff[mi] + kb);
                ldsm4(al[mi][0], al[mi][1], al[mi][2], al[mi][3], aAl + aoff[mi] + kb);
            }
            uint32_t bh[8][2], bl[8][2];
#pragma unroll
            for (int p = 0; p < 4; p++) {
                ldsm4(bh[2*p][0], bh[2*p][1], bh[2*p+1][0], bh[2*p+1][1], aBh + boff[p] + kb);
                ldsm4(bl[2*p][0], bl[2*p][1], bl[2*p+1][0], bl[2*p+1][1], aBl + boff[p] + kb);
            }
#pragma unroll
            for (int ni = 0; ni < 8; ni++)
#pragma unroll
                for (int mi = 0; mi < 4; mi++)
                    hmma16(c[mi][ni], ah[mi][0], ah[mi][1], ah[mi][2], ah[mi][3],
                           bh[ni][0], bh[ni][1]);
#pragma unroll
            for (int ni = 0; ni < 8; ni++)
#pragma unroll
                for (int mi = 0; mi < 4; mi++)
                    hmma16(c[mi][ni], ah[mi][0], ah[mi][1], ah[mi][2], ah[mi][3],
                           bl[ni][0], bl[ni][1]);
#pragma unroll
            for (int ni = 0; ni < 8; ni++)
#pragma unroll
                for (int mi = 0; mi < 4; mi++)
                    hmma16(c[mi][ni], al[mi][0], al[mi][1], al[mi][2], al[mi][3],
                           bh[ni][0], bh[ni][1]);
        }
        __syncthreads();
        if (ch + 2 < NCH) {
            gemm_gissue(s32 + (ch & 1) * (STG * 2), Ah, Al, Bh, Bl, (ch + 2) * 32);
            CP_COMMIT();
        }
    }
}

// ---------------- fp16 2-term core: C = (Ah+Al)*Bh ----------------
__device__ __forceinline__ void mma_core_f16(const __half* Ah, const __half* Al,
                                             const __half* Bh,
                                             __half* S, float c[4][8][4]) {
    uint32_t aoff[4], boff[4];
    frag_offsets(aoff, boff);
    uint32_t s32 = smem_u32(S);
    auto issue = [&](uint32_t st32, int k0) {
        int tid = threadIdx.x;
#pragma unroll
        for (int i = 0; i < 4; i++) {
            int v = tid + i * 128;
            int row = v >> 2, seg = v & 3;
            size_t gs = (size_t)row * Dc + k0 + seg * 8;
            uint32_t so = (uint32_t)((row * KP + seg * 8) * 2);
            cp16(st32 + so,              Ah + gs);
            cp16(st32 + SB * 2 + so,     Al + gs);
            cp16(st32 + 2 * SB * 2 + so, Bh + gs);
        }
        CP_COMMIT();
    };
    issue(s32, 0);
    issue(s32 + OSTG * 2, 32);
    const int NCH = Dc / 32;
    for (int ch = 0; ch < NCH; ch++) {
        CP_WAIT1();
        __syncthreads();
        uint32_t base = s32 + (ch & 1) * (OSTG * 2);
        uint32_t aAh = base, aAl = base + SB * 2, aBh = base + 2 * SB * 2;
#pragma unroll
        for (int ks = 0; ks < 32; ks += 16) {
            uint32_t kb = (uint32_t)(ks * 2);
            uint32_t ah[4][4], al[4][4];
#pragma unroll
            for (int mi = 0; mi < 4; mi++) {
                ldsm4(ah[mi][0], ah[mi][1], ah[mi][2], ah[mi][3], aAh + aoff[mi] + kb);
                ldsm4(al[mi][0], al[mi][1], al[mi][2], al[mi][3], aAl + aoff[mi] + kb);
            }
            uint32_t bh[8][2];
#pragma unroll
            for (int p = 0; p < 4; p++)
                ldsm4(bh[2*p][0], bh[2*p][1], bh[2*p+1][0], bh[2*p+1][1], aBh + boff[p] + kb);
#pragma unroll
            for (int ni = 0; ni < 8; ni++)
#pragma unroll
                for (int mi = 0; mi < 4; mi++)
                    hmma16(c[mi][ni], ah[mi][0], ah[mi][1], ah[mi][2], ah[mi][3],
                           bh[ni][0], bh[ni][1]);
#pragma unroll
            for (int ni = 0; ni < 8; ni++)
#pragma unroll
                for (int mi = 0; mi < 4; mi++)
                    hmma16(c[mi][ni], al[mi][0], al[mi][1], al[mi][2], al[mi][3],
                           bh[ni][0], bh[ni][1]);
        }
        __syncthreads();
        if (ch + 2 < NCH) issue(s32 + (ch & 1) * (OSTG * 2), (ch + 2) * 32);
    }
}

// ---------------- kernel 2a: Q/K projection (fp16x3) ----------------
__global__ void __launch_bounds__(128, 2) qk_mma() {
    extern __shared__ __half Sh[];
    int z = blockIdx.z;
    int M0 = blockIdx.y * 128, N0 = blockIdx.x * 128;
    const __half* Ah = g_xfh + (size_t)M0 * Dc;
    const __half* Al = g_xfl + (size_t)M0 * Dc;
    const __half* Bh = g_wh + ((size_t)z << 20) + (size_t)N0 * Dc;
    const __half* Bl = g_wl + ((size_t)z << 20) + (size_t)N0 * Dc;
    float c[4][8][4] = {};
    mma_core3(Ah, Al, Bh, Bl, Sh, c);

    int lane = threadIdx.x & 31, w = threadIdx.x >> 5;
    int wm = w >> 1, wn = w & 1;
    int g = lane >> 2, t2 = (lane & 3) * 2;
    __half* dh = z ? g_kh : g_qh;
    __half* dl = z ? g_kl : g_ql;
    float qs = z ? 1.0f : 0.125f;
#pragma unroll
    for (int mi = 0; mi < 4; mi++)
#pragma unroll
        for (int ni = 0; ni < 8; ni++) {
            int col = N0 + wn * 64 + ni * 8 + t2;
            int h = col >> 6, dd = col & 63;
#pragma unroll
            for (int rh = 0; rh < 2; rh++) {
                int row = M0 + wm * 64 + mi * 16 + g + rh * 8;
                int bb = row >> 10, l = row & (Lc - 1);
                float v0 = c[mi][ni][rh * 2] * qs, v1 = c[mi][ni][rh * 2 + 1] * qs;
                float h0 = f16_hi(v0), h1 = f16_hi(v1);
                size_t idx = (((size_t)(bb * Hc + h)) * Lc + l) * dc + dd;
                *(uint32_t*)(dh + idx) = pack_f16(h0, h1);
                *(uint32_t*)(dl + idx) = pack_f16(v0 - h0, v1 - h1);
            }
        }
}

// ---------------- kernel 2b: V projection (fp16 2-term) -> V^T fp16 hi ----------------
__global__ void __launch_bounds__(128, 2) v_mma() {
    extern __shared__ __half Sh[];
    int M0 = blockIdx.y * 128, N0 = blockIdx.x * 128;
    const __half* Ah = g_xfh + (size_t)M0 * Dc;
    const __half* Al = g_xfl + (size_t)M0 * Dc;
    const __half* Bh = g_wvh + (size_t)N0 * Dc;
    float c[4][8][4] = {};
    mma_core_f16(Ah, Al, Bh, Sh, c);

    int lane = threadIdx.x & 31, w = threadIdx.x >> 5;
    int wm = w >> 1, wn = w & 1;
    int g = lane >> 2, t2 = (lane & 3) * 2;
    uint16_t* sT = (uint16_t*)Sh;
#pragma unroll
    for (int mi = 0; mi < 4; mi++)
#pragma unroll
        for (int ni = 0; ni < 8; ni++) {
            int col_l = wn * 64 + ni * 8 + t2;
#pragma unroll
            for (int rh = 0; rh < 2; rh++) {
                int row_l = wm * 64 + mi * 16 + g + rh * 8;
#pragma unroll
                for (int cc = 0; cc < 2; cc++) {
                    __half vh = __float2half_rn(c[mi][ni][rh * 2 + cc]);
                    sT[(col_l + cc) * 136 + row_l] = *(uint16_t*)&vh;
                }
            }
        }
    __syncthreads();
    int bb = M0 >> 10, l0 = M0 & (Lc - 1);
#pragma unroll
    for (int q = 0; q < 16; q++) {
        int v = threadIdx.x + q * 128;
        int d = v >> 4, seg = v & 15;
        int col = N0 + d;
        int h = col >> 6, dd = col & 63;
        size_t dst = (((size_t)(bb * Hc + h)) * dc + dd) * Lc + l0 + seg * 8;
        *(uint4*)(g_vth + dst) = *(const uint4*)(sT + d * 136 + seg * 8);
    }
}

// ---------------- kernel 4: output projection (fp16 2-term) ----------------
__global__ void __launch_bounds__(128, 2) out_mma(const float* __restrict__ bO,
                                                  float* __restrict__ out) {
    extern __shared__ __half Sh[];
    int M0 = blockIdx.y * 128, N0 = blockIdx.x * 128;
    const __half* Ah = g_ohh + (size_t)M0 * Dc;
    const __half* Al = g_ohl + (size_t)M0 * Dc;
    const __half* Bh = g_woh + (size_t)N0 * Dc;
    float c[4][8][4] = {};
    mma_core_f16(Ah, Al, Bh, Sh, c);

    int lane = threadIdx.x & 31, w = threadIdx.x >> 5;
    int wm = w >> 1, wn = w & 1;
    int g = lane >> 2, t2 = (lane & 3) * 2;
#pragma unroll
    for (int mi = 0; mi < 4; mi++)
#pragma unroll
        for (int ni = 0; ni < 8; ni++) {
            int col = N0 + wn * 64 + ni * 8 + t2;
            float2 bv = *(const float2*)(bO + col);
#pragma unroll
            for (int rh = 0; rh < 2; rh++) {
                int row = M0 + wm * 64 + mi * 16 + g + rh * 8;
                float2 v = make_float2(c[mi][ni][rh * 2] + bv.x,
                                       c[mi][ni][rh * 2 + 1] + bv.y);
                *(float2*)(out + (size_t)row * Dc + col) = v;
            }
        }
}

// ---------------- kernel 3: flash attention (fp16x3 scores, 1-term PV) ----------------
#define JROWB 128
#define JBUFB (64 * JROWB)
#define JSTGB (5 * JBUFB)
#define NSTG 4
#define ATTN_SMEM_BYTES (NSTG * JSTGB + (Lc + NSTG * 64 * 2) * 4)

__device__ __forceinline__ uint32_t jswz(int row, int byte_in_row) {
    return (uint32_t)(row * JROWB + (byte_in_row ^ ((row & 7) << 4)));
}

__global__ void __launch_bounds__(256, 1) attn_mma(const float* __restrict__ alpha,
                                                   const float* __restrict__ beta,
                                                   const float* __restrict__ gamma) {
    extern __shared__ __half smb[];
    __half* jbase = smb;
    float* sR  = (float*)((char*)smb + NSTG * JSTGB);
    float* sCj = sR + Lc;
    float* sQj = sCj + NSTG * 64;

    uint32_t jb32 = smem_u32(jbase);

    int t = threadIdx.x;
    int w = t >> 5, lane = t & 31;
    int g = lane >> 2, t2 = (lane & 3) * 2;
    int quad = lane >> 3, lr = lane & 7;
    int bh = blockIdx.y;
    int b = bh >> 4, h = bh & 15;
    int i0 = blockIdx.x * 128;

    float a_h = alpha[h], b_h = beta[h], c_h = gamma[h];

    const size_t qoff = ((size_t)bh * Lc) * dc;
    const size_t xoff = ((size_t)b * Lc) * Dc + h * dc;
    const size_t voff = (size_t)bh * dc * Lc;

    for (int idx = t; idx < Lc; idx += 256) sR[idx] = g_rsum[idx];

    auto issue_stage = [&](int jt, int st) {
        uint32_t s32 = jb32 + (uint32_t)st * JSTGB;
        int j0 = jt * 64;
#pragma unroll
        for (int q = 0; q < 2; q++) {
            int v = t * 2 + q;
            int row = v >> 3, seg = v & 7;
            uint32_t boff = jswz(row, seg * 16);
            size_t gk = qoff + (size_t)(j0 + row) * dc + seg * 8;
            size_t gx = xoff + (size_t)(j0 + row) * Dc + seg * 8;
            size_t gv = voff + (size_t)row * Lc + j0 + seg * 8;
            cp16(s32 + 0 * JBUFB + boff, g_kh  + gk);
            cp16(s32 + 1 * JBUFB + boff, g_kl  + gk);
            cp16(s32 + 2 * JBUFB + boff, g_xfh + gx);
            cp16(s32 + 3 * JBUFB + boff, g_xfl + gx);
            cp16(s32 + 4 * JBUFB + boff, g_vth + gv);
        }
        CP_COMMIT();
        if (t < 64) {
            sCj[st * 64 + t] = g_coords[b * Lc + j0 + t];
            sQj[st * 64 + t] = a_h * g_qsca[b * Lc + j0 + t];
        }
    };
    issue_stage(0, 0);
    issue_stage(1, 1);
    issue_stage(2, 2);

    uint32_t jrow[4];
#pragma unroll
    for (int p = 0; p < 4; p++)
        jrow[p] = (uint32_t)((p * 16 + (quad >> 1) * 8 + lr) * JROWB);
    uint32_t jx16 = (uint32_t)((quad & 1) * 16);
    uint32_t xlr  = (uint32_t)(lr << 4);

    uint32_t fqh[16], fql[16], fph[16], fpl[16];
    {
        int r0 = i0 + 16 * w + g;
#pragma unroll
        for (int ks4 = 0; ks4 < 4; ks4++) {
            int cc0 = ks4 * 16 + t2;
            size_t q0 = qoff + (size_t)r0 * dc + cc0;
            size_t q8 = qoff + (size_t)(r0 + 8) * dc + cc0;
            size_t x0 = xoff + (size_t)r0 * Dc + cc0;
            size_t x8 = xoff + (size_t)(r0 + 8) * Dc + cc0;
            fqh[ks4*4+0] = *(const uint32_t*)(g_qh + q0);
            fqh[ks4*4+1] = *(const uint32_t*)(g_qh + q8);
            fqh[ks4*4+2] = *(const uint32_t*)(g_qh + q0 + 8);
            fqh[ks4*4+3] = *(const uint32_t*)(g_qh + q8 + 8);
            fql[ks4*4+0] = *(const uint32_t*)(g_ql + q0);
            fql[ks4*4+1] = *(const uint32_t*)(g_ql + q8);
            fql[ks4*4+2] = *(const uint32_t*)(g_ql + q0 + 8);
            fql[ks4*4+3] = *(const uint32_t*)(g_ql + q8 + 8);
            fph[ks4*4+0] = *(const uint32_t*)(g_xfh + x0);
            fph[ks4*4+1] = *(const uint32_t*)(g_xfh + x8);
            fph[ks4*4+2] = *(const uint32_t*)(g_xfh + x0 + 8);
            fph[ks4*4+3] = *(const uint32_t*)(g_xfh + x8 + 8);
            fpl[ks4*4+0] = *(const uint32_t*)(g_xfl + x0);
            fpl[ks4*4+1] = *(const uint32_t*)(g_xfl + x8);
            fpl[ks4*4+2] = *(const uint32_t*)(g_xfl + x0 + 8);
            fpl[ks4*4+3] = *(const uint32_t*)(g_xfl + x8 + 8);
        }
    }
    float ci_r[2], qi_r[2];
    {
        int r0 = i0 + 16 * w + g;
        ci_r[0] = g_coords[b * Lc + r0];
        ci_r[1] = g_coords[b * Lc + r0 + 8];
        qi_r[0] = fmaf(a_h, g_qsca[b * Lc + r0], c_h);
        qi_r[1] = fmaf(a_h, g_qsca[b * Lc + r0 + 8], c_h);
    }

    float oacc[8][4] = {};
    float m_run[2] = {-INFINITY, -INFINITY}, l_run[2] = {0.f, 0.f};

    for (int jt = 0; jt < 16; jt++) {
        int st = jt & (NSTG - 1);
        if (jt <= 13) CP_WAIT2();
        else if (jt == 14) CP_WAIT1();
        else CP_WAIT0();
        __syncthreads();

        uint32_t stb = jb32 + (uint32_t)st * JSTGB;
        uint32_t aKh = stb, aKl = stb + JBUFB;
        uint32_t aJh = stb + 2 * JBUFB, aJl = stb + 3 * JBUFB;
        uint32_t aVh = stb + 4 * JBUFB;
        const float* cjp = sCj + st * 64;
        const float* qjp = sQj + st * 64;

        float cS[8][4] = {}, cP[8][4] = {};
#pragma unroll
        for (int ks4 = 0; ks4 < 4; ks4++) {
            uint32_t bb = (((uint32_t)(ks4 * 32) + jx16) ^ xlr);
            const uint32_t* Q = fqh + ks4 * 4;
            const uint32_t* Ql = fql + ks4 * 4;
            const uint32_t* P = fph + ks4 * 4;
            const uint32_t* Pl = fpl + ks4 * 4;
#pragma unroll
            for (int p = 0; p < 4; p++) {
                uint32_t kh0, kh1, kh2, kh3, kl0, kl1, kl2, kl3;
                uint32_t jh0, jh1, jh2, jh3, jl0, jl1, jl2, jl3;
                ldsm4(kh0, kh1, kh2, kh3, aKh + jrow[p] + bb);
                ldsm4(kl0, kl1, kl2, kl3, aKl + jrow[p] + bb);
                ldsm4(jh0, jh1, jh2, jh3, aJh + jrow[p] + bb);
                ldsm4(jl0, jl1, jl2, jl3, aJl + jrow[p] + bb);
                hmma16(cS[2*p],   Q[0], Q[1], Q[2], Q[3], kh0, kh1);
                hmma16(cS[2*p+1], Q[0], Q[1], Q[2], Q[3], kh2, kh3);
                hmma16(cP[2*p],   P[0], P[1], P[2], P[3], jh0, jh1);
                hmma16(cP[2*p+1], P[0], P[1], P[2], P[3], jh2, jh3);
                hmma16(cS[2*p],   Q[0], Q[1], Q[2], Q[3], kl0, kl1);
                hmma16(cS[2*p+1], Q[0], Q[1], Q[2], Q[3], kl2, kl3);
                hmma16(cP[2*p],   P[0], P[1], P[2], P[3], jl0, jl1);
                hmma16(cP[2*p+1], P[0], P[1], P[2], P[3], jl2, jl3);
                hmma16(cS[2*p],   Ql[0], Ql[1], Ql[2], Ql[3], kh0, kh1);
                hmma16(cS[2*p+1], Ql[0], Ql[1], Ql[2], Ql[3], kh2, kh3);
                hmma16(cP[2*p],   Pl[0], Pl[1], Pl[2], Pl[3], jh0, jh1);
                hmma16(cP[2*p+1], Pl[0], Pl[1], Pl[2], Pl[3], jh2, jh3);
            }
        }

        float scale[2];
#pragma unroll
        for (int rh = 0; rh < 2; rh++) {
            float ci = ci_r[rh], base_i = qi_r[rh];
            float rmax = -INFINITY;
#pragma unroll
            for (int ni = 0; ni < 8; ni++)
#pragma unroll
                for (int cc = 0; cc < 2; cc++) {
                    int col = ni * 8 + t2 + cc;
                    float delta = fabsf(ci - cjp[col]);
                    int   di = (int)delta;
                    float tt = delta - (float)di;
                    int d0 = min(di,     Lc - 1);
                    int d1 = min(di + 1, Lc - 1);
                    float r0 = sR[d0];
                    float r = fmaf(tt, sR[d1] - r0, r0);
                    float S = fmaf(b_h, r, base_i + qjp[col]);
                    float v = fmaf(S, cP[ni][rh * 2 + cc], cS[ni][rh * 2 + cc]);
                    cS[ni][rh * 2 + cc] = v;
                    rmax = fmaxf(rmax, v);
                }
            rmax = fmaxf(rmax, __shfl_xor_sync(0xffffffffu, rmax, 1));
            rmax = fmaxf(rmax, __shfl_xor_sync(0xffffffffu, rmax, 2));
            float mn = fmaxf(m_run[rh], rmax);
            float rsum = 0.f;
#pragma unroll
            for (int ni = 0; ni < 8; ni++)
#pragma unroll
                for (int cc = 0; cc < 2; cc++) {
                    float e = __expf(cS[ni][rh * 2 + cc] - mn);
                    cS[ni][rh * 2 + cc] = e;
                    rsum += e;
                }
            rsum += __shfl_xor_sync(0xffffffffu, rsum, 1);
            rsum += __shfl_xor_sync(0xffffffffu, rsum, 2);
            scale[rh] = __expf(m_run[rh] - mn);
            l_run[rh] = l_run[rh] * scale[rh] + rsum;
            m_run[rh] = mn;
        }
#pragma unroll
        for (int ni = 0; ni < 8; ni++) {
            oacc[ni][0] *= scale[0]; oacc[ni][1] *= scale[0];
            oacc[ni][2] *= scale[1]; oacc[ni][3] *= scale[1];
        }

        // ---- PV: 1-term (P fp16-hi x V-hi) ----
#pragma unroll
        for (int kc = 0; kc < 4; kc++) {
            uint32_t ap0 = pack_f16(cS[2*kc][0],   cS[2*kc][1]);
            uint32_t ap1 = pack_f16(cS[2*kc][2],   cS[2*kc][3]);
            uint32_t ap2 = pack_f16(cS[2*kc+1][0], cS[2*kc+1][1]);
            uint32_t ap3 = pack_f16(cS[2*kc+1][2], cS[2*kc+1][3]);
            uint32_t bb = (((uint32_t)(kc * 32) + jx16) ^ xlr);
#pragma unroll
            for (int p = 0; p < 4; p++) {
                uint32_t vh0, vh1, vh2, vh3;
                ldsm4(vh0, vh1, vh2, vh3, aVh + jrow[p] + bb);
                hmma16(oacc[2*p],   ap0, ap1, ap2, ap3, vh0, vh1);
                hmma16(oacc[2*p+1], ap0, ap1, ap2, ap3, vh2, vh3);
            }
        }

        __syncthreads();
        if (jt + 3 < 16) issue_stage(jt + 3, (jt + 3) & (NSTG - 1));
    }

    // ---- epilogue: fp16 hi/lo for the out projection ----
    float inv0 = 1.f / l_run[0], inv1 = 1.f / l_run[1];
#pragma unroll
    for (int rh = 0; rh < 2; rh++) {
        int row = i0 + 16 * w + g + rh * 8;
        float inv = rh ? inv1 : inv0;
        size_t base = ((size_t)(b * Lc) + row) * Dc + h * dc;
#pragma unroll
        for (int ni = 0; ni < 8; ni++) {
            float v0 = oacc[ni][rh * 2]     * inv;
            float v1 = oacc[ni][rh * 2 + 1] * inv;
            float h0 = f16_hi(v0), h1 = f16_hi(v1);
            size_t idx = base + ni * 8 + t2;
            *(uint32_t*)(g_ohh + idx) = pack_f16(h0, h1);
            *(uint32_t*)(g_ohl + idx) = pack_f16(v0 - h0, v1 - h1);
        }
    }
}

// ---------------- launch ----------------
extern "C" void kernel_launch(void* const* d_in, const int* in_sizes, int n_in,
                              void* d_out, int out_size) {
    const float* x     = (const float*)d_in[0];
    const float* t_enc = (const float*)d_in[1];
    const float* WQ    = (const float*)d_in[2];
    const float* WK    = (const float*)d_in[3];
    const float* WV    = (const float*)d_in[4];
    const float* WO    = (const float*)d_in[5];
    const float* bO    = (const float*)d_in[6];
    const float* Wt    = (const float*)d_in[7];
    const float* bt    = (const float*)d_in[8];
    const float* p_mat = (const float*)d_in[9];
    const float* r_mat = (const float*)d_in[10];
    const float* alpha = (const float*)d_in[11];
    const float* beta  = (const float*)d_in[12];
    const float* gamma = (const float*)d_in[13];
    float* out = (float*)d_out;

    cudaFuncSetAttribute(attn_mma, cudaFuncAttributeMaxDynamicSharedMemorySize,
                         ATTN_SMEM_BYTES);
    cudaFuncSetAttribute(qk_mma, cudaFuncAttributeMaxDynamicSharedMemorySize,
                         GEMM_SMEM_BYTES);
    cudaFuncSetAttribute(v_mma, cudaFuncAttributeMaxDynamicSharedMemorySize,
                         OUT_SMEM_BYTES);
    cudaFuncSetAttribute(out_mma, cudaFuncAttributeMaxDynamicSharedMemorySize,
                         OUT_SMEM_BYTES);

    colsum_kernel<<<dim3(Lc / 256, 2), 256>>>(p_mat, r_mat);
    coords_kernel<<<(Bc * Lc) / 128, 128>>>(t_enc, Wt, bt);
    split_x_kernel<<<(Bc * Lc * Dc) / (256 * 4), 256>>>(x);
    split_w_kernel<<<dim3((Dc * Dc) / (256 * 4), 4), 256>>>(WQ, WK, WV, WO);
    qk_mma<<<dim3(Dc / 128, (Bc * Lc) / 128, 2), 128, GEMM_SMEM_BYTES>>>();
    v_mma<<<dim3(Dc / 128, (Bc * Lc) / 128), 128, OUT_SMEM_BYTES>>>();
    attn_mma<<<dim3(Lc / 128, Bc * Hc), 256, ATTN_SMEM_BYTES>>>(alpha, beta, gamma);
    out_mma<<<dim3(Dc / 128, (Bc * Lc) / 128), 128, OUT_SMEM_BYTES>>>(bO, out);
}

// round 17
// speedup vs baseline: 3.1210x; 1.0006x over previous
#include <cuda_runtime.h>
#include <cuda_fp16.h>
#include <math.h>
#include <stdint.h>

#define Bc 4
#define Lc 1024
#define Dc 1024
#define Hc 16
#define Tc 64
#define dc 64
#define BHLD (Bc*Hc*Lc*dc)   /* 4,194,304 */

// ---------------- scratch (all fp16 now) ----------------
__device__ float g_coords[Bc * Lc];
__device__ float g_qsca[Bc * Lc];
__device__ float g_psum[Lc];
__device__ float g_rsum[Lc];
__device__ __half g_xfh[Bc*Lc*Dc], g_xfl[Bc*Lc*Dc];   // x fp16 hi/lo
__device__ __half g_wh[2*Dc*Dc],  g_wl[2*Dc*Dc];      // WQ|WK fp16 hi/lo
__device__ __half g_wvh[Dc*Dc];                        // WV fp16 hi
__device__ __half g_woh[Dc*Dc];                        // WO fp16 hi
__device__ __half g_qh[BHLD], g_ql[BHLD];             // Q*0.125 (b,h,l,d)
__device__ __half g_kh[BHLD], g_kl[BHLD];             // K (b,h,l,d)
__device__ __half g_vth[BHLD];                         // V^T fp16 hi (b,h,d,l)
__device__ __half g_ohh[Bc*Lc*Dc], g_ohl[Bc*Lc*Dc];   // attn out fp16 hi/lo

__device__ __forceinline__ uint32_t pack_f16(float lo, float hi) {
    __half2 r = __floats2half2_rn(lo, hi);
    return *(uint32_t*)&r;
}
__device__ __forceinline__ float f16_hi(float v) {
    return __half2float(__float2half_rn(v));
}
__device__ __forceinline__ uint32_t smem_u32(const void* p) {
    uint32_t a;
    asm("{ .reg .u64 t; cvta.to.shared.u64 t, %1; cvt.u32.u64 %0, t; }" : "=r"(a) : "l"(p));
    return a;
}
__device__ __forceinline__ void cp16(uint32_t dst, const void* src) {
    asm volatile("cp.async.cg.shared.global [%0], [%1], 16;" :: "r"(dst), "l"(src));
}
#define CP_COMMIT() asm volatile("cp.async.commit_group;" ::: "memory")
#define CP_WAIT0()  asm volatile("cp.async.wait_group 0;"  ::: "memory")
#define CP_WAIT1()  asm volatile("cp.async.wait_group 1;"  ::: "memory")
#define CP_WAIT2()  asm volatile("cp.async.wait_group 2;"  ::: "memory")

__device__ __forceinline__ void ldsm4(uint32_t& r0, uint32_t& r1, uint32_t& r2,
                                      uint32_t& r3, uint32_t addr) {
    asm volatile("ldmatrix.sync.aligned.m8n8.x4.shared.b16 {%0,%1,%2,%3}, [%4];"
                 : "=r"(r0), "=r"(r1), "=r"(r2), "=r"(r3) : "r"(addr));
}
__device__ __forceinline__ void hmma16(float c[4], uint32_t a0, uint32_t a1, uint32_t a2,
                                       uint32_t a3, uint32_t b0, uint32_t b1) {
    asm volatile(
        "mma.sync.aligned.m16n8k16.row.col.f32.f16.f16.f32 "
        "{%0,%1,%2,%3}, {%4,%5,%6,%7}, {%8,%9}, {%0,%1,%2,%3};"
        : "+f"(c[0]), "+f"(c[1]), "+f"(c[2]), "+f"(c[3])
        : "r"(a0), "r"(a1), "r"(a2), "r"(a3), "r"(b0), "r"(b1));
}

// ---------------- kernel 0: column sums ----------------
__global__ void colsum_kernel(const float* __restrict__ p_mat,
                              const float* __restrict__ r_mat) {
    int l = blockIdx.x * blockDim.x + threadIdx.x;
    if (l >= Lc) return;
    const float* src = blockIdx.y ? r_mat : p_mat;
    float s = 0.f;
#pragma unroll 8
    for (int dd = 0; dd < Dc; dd++) s += src[dd * Lc + l];
    if (blockIdx.y) g_rsum[l] = s; else g_psum[l] = s;
}

// ---------------- kernel 1: coords + cubic q_sca ----------------
__global__ void coords_kernel(const float* __restrict__ t_enc,
                              const float* __restrict__ Wt,
                              const float* __restrict__ bt) {
    int n = blockIdx.x * blockDim.x + threadIdx.x;
    if (n >= Bc * Lc) return;
    float z = bt[0];
    const float* te = t_enc + (size_t)n * Tc;
#pragma unroll
    for (int k = 0; k < Tc; k++) z += te[k] * Wt[k];
    float tau = 1.f / (1.f + expf(-z));
    float c = tau * (float)(Lc - 1);
    g_coords[n] = c;
    int i = (int)floorf(c);
    float t = c - (float)i;
    int im1 = min(max(i - 1, 0), Lc - 1);
    int ii0 = min(max(i,     0), Lc - 1);
    int ii1 = min(max(i + 1, 0), Lc - 1);
    int ii2 = min(max(i + 2, 0), Lc - 1);
    float p0 = g_psum[im1], p1 = g_psum[ii0], p2 = g_psum[ii1], p3 = g_psum[ii2];
    float t2 = t * t, t3 = t2 * t;
    g_qsca[n] = 0.5f * (2.f * p1 + (-p0 + p2) * t
              + (2.f * p0 - 5.f * p1 + 4.f * p2 - p3) * t2
              + (-p0 + 3.f * p1 - 3.f * p2 + p3) * t3);
}

// ---------------- splits (all fp16) ----------------
__global__ void split_x_kernel(const float* __restrict__ s) {
    int i = (blockIdx.x * blockDim.x + threadIdx.x) * 4;
    float4 v = *(const float4*)(s + i);
    float f0 = f16_hi(v.x), f1 = f16_hi(v.y), f2 = f16_hi(v.z), f3 = f16_hi(v.w);
    *(uint2*)(g_xfh + i) = make_uint2(pack_f16(f0, f1), pack_f16(f2, f3));
    *(uint2*)(g_xfl + i) = make_uint2(pack_f16(v.x - f0, v.y - f1), pack_f16(v.z - f2, v.w - f3));
}
__global__ void split_w_kernel(const float* __restrict__ WQ, const float* __restrict__ WK,
                               const float* __restrict__ WV, const float* __restrict__ WO) {
    int i = (blockIdx.x * blockDim.x + threadIdx.x) * 4;
    if (blockIdx.y >= 2) {   // WV / WO: fp16 hi only
        const float* src = (blockIdx.y == 2) ? WV : WO;
        __half* dst = (blockIdx.y == 2) ? g_wvh : g_woh;
        float4 v = *(const float4*)(src + i);
        *(uint2*)(dst + i) = make_uint2(pack_f16(v.x, v.y), pack_f16(v.z, v.w));
        return;
    }
    const float* src = (blockIdx.y == 0) ? WQ : WK;
    size_t off = (size_t)blockIdx.y << 20;
    float4 v = *(const float4*)(src + i);
    float f0 = f16_hi(v.x), f1 = f16_hi(v.y), f2 = f16_hi(v.z), f3 = f16_hi(v.w);
    *(uint2*)(g_wh + off + i) = make_uint2(pack_f16(f0, f1), pack_f16(f2, f3));
    *(uint2*)(g_wl + off + i) = make_uint2(pack_f16(v.x - f0, v.y - f1), pack_f16(v.z - f2, v.w - f3));
}

// ================= shared mma machinery =================
#define KP 40
#define SB (128 * KP)
#define STG (4 * SB)
#define GEMM_SMEM_BYTES (2 * STG * 2)   // 81920
#define OSTG (3 * SB)
#define OUT_SMEM_BYTES (2 * OSTG * 2)   // 61440

__device__ __forceinline__ void frag_offsets(uint32_t aoff[4], uint32_t boff[4]) {
    int lane = threadIdx.x & 31, w = threadIdx.x >> 5;
    int wm = w >> 1, wn = w & 1;
    int quad = lane >> 3, lr = lane & 7;
#pragma unroll
    for (int mi = 0; mi < 4; mi++)
        aoff[mi] = (uint32_t)(((wm * 64 + mi * 16 + (quad & 1) * 8 + lr) * KP
                               + (quad >> 1) * 8) * 2);
#pragma unroll
    for (int p = 0; p < 4; p++)
        boff[p] = (uint32_t)(((wn * 64 + p * 16 + (quad >> 1) * 8 + lr) * KP
                              + (quad & 1) * 8) * 2);
}

// ---------------- fp16x3 core (Q/K projections) ----------------
__device__ __forceinline__ void gemm_gissue(uint32_t st32,
                                            const __half* Ah, const __half* Al,
                                            const __half* Bh, const __half* Bl,
                                            int k0) {
    int tid = threadIdx.x;
#pragma unroll
    for (int i = 0; i < 4; i++) {
        int v = tid + i * 128;
        int row = v >> 2, seg = v & 3;
        size_t gs = (size_t)row * Dc + k0 + seg * 8;
        uint32_t so = (uint32_t)((row * KP + seg * 8) * 2);
        cp16(st32 + so,              Ah + gs);
        cp16(st32 + SB * 2 + so,     Al + gs);
        cp16(st32 + 2 * SB * 2 + so, Bh + gs);
        cp16(st32 + 3 * SB * 2 + so, Bl + gs);
    }
}

__device__ __forceinline__ void mma_core3(const __half* Ah, const __half* Al,
                                          const __half* Bh, const __half* Bl,
                                          __half* S, float c[4][8][4]) {
    uint32_t aoff[4], boff[4];
    frag_offsets(aoff, boff);
    uint32_t s32 = smem_u32(S);
    gemm_gissue(s32, Ah, Al, Bh, Bl, 0);
    CP_COMMIT();
    gemm_gissue(s32 + STG * 2, Ah, Al, Bh, Bl, 32);
    CP_COMMIT();
    const int NCH = Dc / 32;
    for (int ch = 0; ch < NCH; ch++) {
        CP_WAIT1();
        __syncthreads();
        uint32_t base = s32 + (ch & 1) * (STG * 2);
        uint32_t aAh = base, aAl = base + SB * 2;
        uint32_t aBh = base + 2 * SB * 2, aBl = base + 3 * SB * 2;
#pragma unroll
        for (int ks = 0; ks < 32; ks += 16) {
            uint32_t kb = (uint32_t)(ks * 2);
            uint32_t ah[4][4], al[4][4];
#pragma unroll
            for (int mi = 0; mi < 4; mi++) {
                ldsm4(ah[mi][0], ah[mi][1], ah[mi][2], ah[mi][3], aAh + aoff[mi] + kb);
                ldsm4(al[mi][0], al[mi][1], al[mi][2], al[mi][3], aAl + aoff[mi] + kb);
            }
            uint32_t bh[8][2], bl[8][2];
#pragma unroll
            for (int p = 0; p < 4; p++) {
                ldsm4(bh[2*p][0], bh[2*p][1], bh[2*p+1][0], bh[2*p+1][1], aBh + boff[p] + kb);
                ldsm4(bl[2*p][0], bl[2*p][1], bl[2*p+1][0], bl[2*p+1][1], aBl + boff[p] + kb);
            }
#pragma unroll
            for (int ni = 0; ni < 8; ni++)
#pragma unroll
                for (int mi = 0; mi < 4; mi++)
                    hmma16(c[mi][ni], ah[mi][0], ah[mi][1], ah[mi][2], ah[mi][3],
                           bh[ni][0], bh[ni][1]);
#pragma unroll
            for (int ni = 0; ni < 8; ni++)
#pragma unroll
                for (int mi = 0; mi < 4; mi++)
                    hmma16(c[mi][ni], ah[mi][0], ah[mi][1], ah[mi][2], ah[mi][3],
                           bl[ni][0], bl[ni][1]);
#pragma unroll
            for (int ni = 0; ni < 8; ni++)
#pragma unroll
                for (int mi = 0; mi < 4; mi++)
                    hmma16(c[mi][ni], al[mi][0], al[mi][1], al[mi][2], al[mi][3],
                           bh[ni][0], bh[ni][1]);
        }
        __syncthreads();
        if (ch + 2 < NCH) {
            gemm_gissue(s32 + (ch & 1) * (STG * 2), Ah, Al, Bh, Bl, (ch + 2) * 32);
            CP_COMMIT();
        }
    }
}

// ---------------- fp16 2-term core: C = (Ah+Al)*Bh ----------------
__device__ __forceinline__ void mma_core_f16(const __half* Ah, const __half* Al,
                                             const __half* Bh,
                                             __half* S, float c[4][8][4]) {
    uint32_t aoff[4], boff[4];
    frag_offsets(aoff, boff);
    uint32_t s32 = smem_u32(S);
    auto issue = [&](uint32_t st32, int k0) {
        int tid = threadIdx.x;
#pragma unroll
        for (int i = 0; i < 4; i++) {
            int v = tid + i * 128;
            int row = v >> 2, seg = v & 3;
            size_t gs = (size_t)row * Dc + k0 + seg * 8;
            uint32_t so = (uint32_t)((row * KP + seg * 8) * 2);
            cp16(st32 + so,              Ah + gs);
            cp16(st32 + SB * 2 + so,     Al + gs);
            cp16(st32 + 2 * SB * 2 + so, Bh + gs);
        }
        CP_COMMIT();
    };
    issue(s32, 0);
    issue(s32 + OSTG * 2, 32);
    const int NCH = Dc / 32;
    for (int ch = 0; ch < NCH; ch++) {
        CP_WAIT1();
        __syncthreads();
        uint32_t base = s32 + (ch & 1) * (OSTG * 2);
        uint32_t aAh = base, aAl = base + SB * 2, aBh = base + 2 * SB * 2;
#pragma unroll
        for (int ks = 0; ks < 32; ks += 16) {
            uint32_t kb = (uint32_t)(ks * 2);
            uint32_t ah[4][4], al[4][4];
#pragma unroll
            for (int mi = 0; mi < 4; mi++) {
                ldsm4(ah[mi][0], ah[mi][1], ah[mi][2], ah[mi][3], aAh + aoff[mi] + kb);
                ldsm4(al[mi][0], al[mi][1], al[mi][2], al[mi][3], aAl + aoff[mi] + kb);
            }
            uint32_t bh[8][2];
#pragma unroll
            for (int p = 0; p < 4; p++)
                ldsm4(bh[2*p][0], bh[2*p][1], bh[2*p+1][0], bh[2*p+1][1], aBh + boff[p] + kb);
#pragma unroll
            for (int ni = 0; ni < 8; ni++)
#pragma unroll
                for (int mi = 0; mi < 4; mi++)
                    hmma16(c[mi][ni], ah[mi][0], ah[mi][1], ah[mi][2], ah[mi][3],
                           bh[ni][0], bh[ni][1]);
#pragma unroll
            for (int ni = 0; ni < 8; ni++)
#pragma unroll
                for (int mi = 0; mi < 4; mi++)
                    hmma16(c[mi][ni], al[mi][0], al[mi][1], al[mi][2], al[mi][3],
                           bh[ni][0], bh[ni][1]);
        }
        __syncthreads();
        if (ch + 2 < NCH) issue(s32 + (ch & 1) * (OSTG * 2), (ch + 2) * 32);
    }
}

// ---------------- kernel 2a: Q/K projection (fp16x3) ----------------
__global__ void __launch_bounds__(128, 2) qk_mma() {
    extern __shared__ __half Sh[];
    int z = blockIdx.z;
    int M0 = blockIdx.y * 128, N0 = blockIdx.x * 128;
    const __half* Ah = g_xfh + (size_t)M0 * Dc;
    const __half* Al = g_xfl + (size_t)M0 * Dc;
    const __half* Bh = g_wh + ((size_t)z << 20) + (size_t)N0 * Dc;
    const __half* Bl = g_wl + ((size_t)z << 20) + (size_t)N0 * Dc;
    float c[4][8][4] = {};
    mma_core3(Ah, Al, Bh, Bl, Sh, c);

    int lane = threadIdx.x & 31, w = threadIdx.x >> 5;
    int wm = w >> 1, wn = w & 1;
    int g = lane >> 2, t2 = (lane & 3) * 2;
    __half* dh = z ? g_kh : g_qh;
    __half* dl = z ? g_kl : g_ql;
    float qs = z ? 1.0f : 0.125f;
#pragma unroll
    for (int mi = 0; mi < 4; mi++)
#pragma unroll
        for (int ni = 0; ni < 8; ni++) {
            int col = N0 + wn * 64 + ni * 8 + t2;
            int h = col >> 6, dd = col & 63;
#pragma unroll
            for (int rh = 0; rh < 2; rh++) {
                int row = M0 + wm * 64 + mi * 16 + g + rh * 8;
                int bb = row >> 10, l = row & (Lc - 1);
                float v0 = c[mi][ni][rh * 2] * qs, v1 = c[mi][ni][rh * 2 + 1] * qs;
                float h0 = f16_hi(v0), h1 = f16_hi(v1);
                size_t idx = (((size_t)(bb * Hc + h)) * Lc + l) * dc + dd;
                *(uint32_t*)(dh + idx) = pack_f16(h0, h1);
                *(uint32_t*)(dl + idx) = pack_f16(v0 - h0, v1 - h1);
            }
        }
}

// ---------------- kernel 2b: V projection (fp16 2-term) -> V^T fp16 hi ----------------
__global__ void __launch_bounds__(128, 2) v_mma() {
    extern __shared__ __half Sh[];
    int M0 = blockIdx.y * 128, N0 = blockIdx.x * 128;
    const __half* Ah = g_xfh + (size_t)M0 * Dc;
    const __half* Al = g_xfl + (size_t)M0 * Dc;
    const __half* Bh = g_wvh + (size_t)N0 * Dc;
    float c[4][8][4] = {};
    mma_core_f16(Ah, Al, Bh, Sh, c);

    int lane = threadIdx.x & 31, w = threadIdx.x >> 5;
    int wm = w >> 1, wn = w & 1;
    int g = lane >> 2, t2 = (lane & 3) * 2;
    uint16_t* sT = (uint16_t*)Sh;
#pragma unroll
    for (int mi = 0; mi < 4; mi++)
#pragma unroll
        for (int ni = 0; ni < 8; ni++) {
            int col_l = wn * 64 + ni * 8 + t2;
#pragma unroll
            for (int rh = 0; rh < 2; rh++) {
                int row_l = wm * 64 + mi * 16 + g + rh * 8;
#pragma unroll
                for (int cc = 0; cc < 2; cc++) {
                    __half vh = __float2half_rn(c[mi][ni][rh * 2 + cc]);
                    sT[(col_l + cc) * 136 + row_l] = *(uint16_t*)&vh;
                }
            }
        }
    __syncthreads();
    int bb = M0 >> 10, l0 = M0 & (Lc - 1);
#pragma unroll
    for (int q = 0; q < 16; q++) {
        int v = threadIdx.x + q * 128;
        int d = v >> 4, seg = v & 15;
        int col = N0 + d;
        int h = col >> 6, dd = col & 63;
        size_t dst = (((size_t)(bb * Hc + h)) * dc + dd) * Lc + l0 + seg * 8;
        *(uint4*)(g_vth + dst) = *(const uint4*)(sT + d * 136 + seg * 8);
    }
}

// ---------------- kernel 4: output projection (fp16 2-term) ----------------
__global__ void __launch_bounds__(128, 2) out_mma(const float* __restrict__ bO,
                                                  float* __restrict__ out) {
    extern __shared__ __half Sh[];
    int M0 = blockIdx.y * 128, N0 = blockIdx.x * 128;
    const __half* Ah = g_ohh + (size_t)M0 * Dc;
    const __half* Al = g_ohl + (size_t)M0 * Dc;
    const __half* Bh = g_woh + (size_t)N0 * Dc;
    float c[4][8][4] = {};
    mma_core_f16(Ah, Al, Bh, Sh, c);

    int lane = threadIdx.x & 31, w = threadIdx.x >> 5;
    int wm = w >> 1, wn = w & 1;
    int g = lane >> 2, t2 = (lane & 3) * 2;
#pragma unroll
    for (int mi = 0; mi < 4; mi++)
#pragma unroll
        for (int ni = 0; ni < 8; ni++) {
            int col = N0 + wn * 64 + ni * 8 + t2;
            float2 bv = *(const float2*)(bO + col);
#pragma unroll
            for (int rh = 0; rh < 2; rh++) {
                int row = M0 + wm * 64 + mi * 16 + g + rh * 8;
                float2 v = make_float2(c[mi][ni][rh * 2] + bv.x,
                                       c[mi][ni][rh * 2 + 1] + bv.y);
                *(float2*)(out + (size_t)row * Dc + col) = v;
            }
        }
}

// ---------------- kernel 3: flash attention (fp16x3 scores, 1-term PV) ----------------
#define JROWB 128
#define JBUFB (64 * JROWB)
#define JSTGB (5 * JBUFB)
#define NSTG 4
#define ATTN_SMEM_BYTES (NSTG * JSTGB + (Lc + NSTG * 64 * 2) * 4)

__device__ __forceinline__ uint32_t jswz(int row, int byte_in_row) {
    return (uint32_t)(row * JROWB + (byte_in_row ^ ((row & 7) << 4)));
}

__global__ void __launch_bounds__(256, 1) attn_mma(const float* __restrict__ alpha,
                                                   const float* __restrict__ beta,
                                                   const float* __restrict__ gamma) {
    extern __shared__ __half smb[];
    __half* jbase = smb;
    float* sR  = (float*)((char*)smb + NSTG * JSTGB);
    float* sCj = sR + Lc;
    float* sQj = sCj + NSTG * 64;

    uint32_t jb32 = smem_u32(jbase);

    int t = threadIdx.x;
    int w = t >> 5, lane = t & 31;
    int g = lane >> 2, t2 = (lane & 3) * 2;
    int quad = lane >> 3, lr = lane & 7;
    int bh = blockIdx.y;
    int b = bh >> 4, h = bh & 15;
    int i0 = blockIdx.x * 128;

    float a_h = alpha[h], b_h = beta[h], c_h = gamma[h];

    const size_t qoff = ((size_t)bh * Lc) * dc;
    const size_t xoff = ((size_t)b * Lc) * Dc + h * dc;
    const size_t voff = (size_t)bh * dc * Lc;

    for (int idx = t; idx < Lc; idx += 256) sR[idx] = g_rsum[idx];

    auto issue_stage = [&](int jt, int st) {
        uint32_t s32 = jb32 + (uint32_t)st * JSTGB;
        int j0 = jt * 64;
#pragma unroll
        for (int q = 0; q < 2; q++) {
            int v = t * 2 + q;
            int row = v >> 3, seg = v & 7;
            uint32_t boff = jswz(row, seg * 16);
            size_t gk = qoff + (size_t)(j0 + row) * dc + seg * 8;
            size_t gx = xoff + (size_t)(j0 + row) * Dc + seg * 8;
            size_t gv = voff + (size_t)row * Lc + j0 + seg * 8;
            cp16(s32 + 0 * JBUFB + boff, g_kh  + gk);
            cp16(s32 + 1 * JBUFB + boff, g_kl  + gk);
            cp16(s32 + 2 * JBUFB + boff, g_xfh + gx);
            cp16(s32 + 3 * JBUFB + boff, g_xfl + gx);
            cp16(s32 + 4 * JBUFB + boff, g_vth + gv);
        }
        CP_COMMIT();
        if (t < 64) {
            sCj[st * 64 + t] = g_coords[b * Lc + j0 + t];
            sQj[st * 64 + t] = a_h * g_qsca[b * Lc + j0 + t];
        }
    };
    issue_stage(0, 0);
    issue_stage(1, 1);
    issue_stage(2, 2);

    uint32_t jrow[4];
#pragma unroll
    for (int p = 0; p < 4; p++)
        jrow[p] = (uint32_t)((p * 16 + (quad >> 1) * 8 + lr) * JROWB);
    uint32_t jx16 = (uint32_t)((quad & 1) * 16);
    uint32_t xlr  = (uint32_t)(lr << 4);

    uint32_t fqh[16], fql[16], fph[16], fpl[16];
    {
        int r0 = i0 + 16 * w + g;
#pragma unroll
        for (int ks4 = 0; ks4 < 4; ks4++) {
            int cc0 = ks4 * 16 + t2;
            size_t q0 = qoff + (size_t)r0 * dc + cc0;
            size_t q8 = qoff + (size_t)(r0 + 8) * dc + cc0;
            size_t x0 = xoff + (size_t)r0 * Dc + cc0;
            size_t x8 = xoff + (size_t)(r0 + 8) * Dc + cc0;
            fqh[ks4*4+0] = *(const uint32_t*)(g_qh + q0);
            fqh[ks4*4+1] = *(const uint32_t*)(g_qh + q8);
            fqh[ks4*4+2] = *(const uint32_t*)(g_qh + q0 + 8);
            fqh[ks4*4+3] = *(const uint32_t*)(g_qh + q8 + 8);
            fql[ks4*4+0] = *(const uint32_t*)(g_ql + q0);
            fql[ks4*4+1] = *(const uint32_t*)(g_ql + q8);
            fql[ks4*4+2] = *(const uint32_t*)(g_ql + q0 + 8);
            fql[ks4*4+3] = *(const uint32_t*)(g_ql + q8 + 8);
            fph[ks4*4+0] = *(const uint32_t*)(g_xfh + x0);
            fph[ks4*4+1] = *(const uint32_t*)(g_xfh + x8);
            fph[ks4*4+2] = *(const uint32_t*)(g_xfh + x0 + 8);
            fph[ks4*4+3] = *(const uint32_t*)(g_xfh + x8 + 8);
            fpl[ks4*4+0] = *(const uint32_t*)(g_xfl + x0);
            fpl[ks4*4+1] = *(const uint32_t*)(g_xfl + x8);
            fpl[ks4*4+2] = *(const uint32_t*)(g_xfl + x0 + 8);
            fpl[ks4*4+3] = *(const uint32_t*)(g_xfl + x8 + 8);
        }
    }
    float ci_r[2], qi_r[2];
    {
        int r0 = i0 + 16 * w + g;
        ci_r[0] = g_coords[b * Lc + r0];
        ci_r[1] = g_coords[b * Lc + r0 + 8];
        qi_r[0] = fmaf(a_h, g_qsca[b * Lc + r0], c_h);
        qi_r[1] = fmaf(a_h, g_qsca[b * Lc + r0 + 8], c_h);
    }

    float oacc[8][4] = {};
    float m_run[2] = {-INFINITY, -INFINITY}, l_run[2] = {0.f, 0.f};

    for (int jt = 0; jt < 16; jt++) {
        int st = jt & (NSTG - 1);
        if (jt <= 13) CP_WAIT2();
        else if (jt == 14) CP_WAIT1();
        else CP_WAIT0();
        __syncthreads();

        uint32_t stb = jb32 + (uint32_t)st * JSTGB;
        uint32_t aKh = stb, aKl = stb + JBUFB;
        uint32_t aJh = stb + 2 * JBUFB, aJl = stb + 3 * JBUFB;
        uint32_t aVh = stb + 4 * JBUFB;
        const float* cjp = sCj + st * 64;
        const float* qjp = sQj + st * 64;

        float cS[8][4] = {}, cP[8][4] = {};
#pragma unroll
        for (int ks4 = 0; ks4 < 4; ks4++) {
            uint32_t bb = (((uint32_t)(ks4 * 32) + jx16) ^ xlr);
            const uint32_t* Q = fqh + ks4 * 4;
            const uint32_t* Ql = fql + ks4 * 4;
            const uint32_t* P = fph + ks4 * 4;
            const uint32_t* Pl = fpl + ks4 * 4;
#pragma unroll
            for (int p = 0; p < 4; p++) {
                uint32_t kh0, kh1, kh2, kh3, kl0, kl1, kl2, kl3;
                uint32_t jh0, jh1, jh2, jh3, jl0, jl1, jl2, jl3;
                ldsm4(kh0, kh1, kh2, kh3, aKh + jrow[p] + bb);
                ldsm4(kl0, kl1, kl2, kl3, aKl + jrow[p] + bb);
                ldsm4(jh0, jh1, jh2, jh3, aJh + jrow[p] + bb);
                ldsm4(jl0, jl1, jl2, jl3, aJl + jrow[p] + bb);
                hmma16(cS[2*p],   Q[0], Q[1], Q[2], Q[3], kh0, kh1);
                hmma16(cS[2*p+1], Q[0], Q[1], Q[2], Q[3], kh2, kh3);
                hmma16(cP[2*p],   P[0], P[1], P[2], P[3], jh0, jh1);
                hmma16(cP[2*p+1], P[0], P[1], P[2], P[3], jh2, jh3);
                hmma16(cS[2*p],   Q[0], Q[1], Q[2], Q[3], kl0, kl1);
                hmma16(cS[2*p+1], Q[0], Q[1], Q[2], Q[3], kl2, kl3);
                hmma16(cP[2*p],   P[0], P[1], P[2], P[3], jl0, jl1);
                hmma16(cP[2*p+1], P[0], P[1], P[2], P[3], jl2, jl3);
                hmma16(cS[2*p],   Ql[0], Ql[1], Ql[2], Ql[3], kh0, kh1);
                hmma16(cS[2*p+1], Ql[0], Ql[1], Ql[2], Ql[3], kh2, kh3);
                hmma16(cP[2*p],   Pl[0], Pl[1], Pl[2], Pl[3], jh0, jh1);
                hmma16(cP[2*p+1], Pl[0], Pl[1], Pl[2], Pl[3], jh2, jh3);
            }
        }

        float scale[2];
#pragma unroll
        for (int rh = 0; rh < 2; rh++) {
            float ci = ci_r[rh], base_i = qi_r[rh];
            float rmax = -INFINITY;
#pragma unroll
            for (int ni = 0; ni < 8; ni++)
#pragma unroll
                for (int cc = 0; cc < 2; cc++) {
                    int col = ni * 8 + t2 + cc;
                    float delta = fabsf(ci - cjp[col]);
                    int   di = (int)delta;
                    float tt = delta - (float)di;
                    int d0 = min(di,     Lc - 1);
                    int d1 = min(di + 1, Lc - 1);
                    float r0 = sR[d0];
                    float r = fmaf(tt, sR[d1] - r0, r0);
                    float S = fmaf(b_h, r, base_i + qjp[col]);
                    float v = fmaf(S, cP[ni][rh * 2 + cc], cS[ni][rh * 2 + cc]);
                    cS[ni][rh * 2 + cc] = v;
                    rmax = fmaxf(rmax, v);
                }
            rmax = fmaxf(rmax, __shfl_xor_sync(0xffffffffu, rmax, 1));
            rmax = fmaxf(rmax, __shfl_xor_sync(0xffffffffu, rmax, 2));
            float mn = fmaxf(m_run[rh], rmax);
            float rsum = 0.f;
#pragma unroll
            for (int ni = 0; ni < 8; ni++)
#pragma unroll
                for (int cc = 0; cc < 2; cc++) {
                    float e = __expf(cS[ni][rh * 2 + cc] - mn);
                    cS[ni][rh * 2 + cc] = e;
                    rsum += e;
                }
            rsum += __shfl_xor_sync(0xffffffffu, rsum, 1);
            rsum += __shfl_xor_sync(0xffffffffu, rsum, 2);
            scale[rh] = __expf(m_run[rh] - mn);
            l_run[rh] = l_run[rh] * scale[rh] + rsum;
            m_run[rh] = mn;
        }
#pragma unroll
        for (int ni = 0; ni < 8; ni++) {
            oacc[ni][0] *= scale[0]; oacc[ni][1] *= scale[0];
            oacc[ni][2] *= scale[1]; oacc[ni][3] *= scale[1];
        }

        // ---- PV: 1-term (P fp16-hi x V-hi) ----
#pragma unroll
        for (int kc = 0; kc < 4; kc++) {
            uint32_t ap0 = pack_f16(cS[2*kc][0],   cS[2*kc][1]);
            uint32_t ap1 = pack_f16(cS[2*kc][2],   cS[2*kc][3]);
            uint32_t ap2 = pack_f16(cS[2*kc+1][0], cS[2*kc+1][1]);
            uint32_t ap3 = pack_f16(cS[2*kc+1][2], cS[2*kc+1][3]);
            uint32_t bb = (((uint32_t)(kc * 32) + jx16) ^ xlr);
#pragma unroll
            for (int p = 0; p < 4; p++) {
                uint32_t vh0, vh1, vh2, vh3;
                ldsm4(vh0, vh1, vh2, vh3, aVh + jrow[p] + bb);
                hmma16(oacc[2*p],   ap0, ap1, ap2, ap3, vh0, vh1);
                hmma16(oacc[2*p+1], ap0, ap1, ap2, ap3, vh2, vh3);
            }
        }

        __syncthreads();
        if (jt + 3 < 16) issue_stage(jt + 3, (jt + 3) & (NSTG - 1));
    }

    // ---- epilogue: fp16 hi/lo for the out projection ----
    float inv0 = 1.f / l_run[0], inv1 = 1.f / l_run[1];
#pragma unroll
    for (int rh = 0; rh < 2; rh++) {
        int row = i0 + 16 * w + g + rh * 8;
        float inv = rh ? inv1 : inv0;
        size_t base = ((size_t)(b * Lc) + row) * Dc + h * dc;
#pragma unroll
        for (int ni = 0; ni < 8; ni++) {
            float v0 = oacc[ni][rh * 2]     * inv;
            float v1 = oacc[ni][rh * 2 + 1] * inv;
            float h0 = f16_hi(v0), h1 = f16_hi(v1);
            size_t idx = base + ni * 8 + t2;
            *(uint32_t*)(g_ohh + idx) = pack_f16(h0, h1);
            *(uint32_t*)(g_ohl + idx) = pack_f16(v0 - h0, v1 - h1);
        }
    }
}

// ---------------- launch ----------------
extern "C" void kernel_launch(void* const* d_in, const int* in_sizes, int n_in,
                              void* d_out, int out_size) {
    const float* x     = (const float*)d_in[0];
    const float* t_enc = (const float*)d_in[1];
    const float* WQ    = (const float*)d_in[2];
    const float* WK    = (const float*)d_in[3];
    const float* WV    = (const float*)d_in[4];
    const float* WO    = (const float*)d_in[5];
    const float* bO    = (const float*)d_in[6];
    const float* Wt    = (const float*)d_in[7];
    const float* bt    = (const float*)d_in[8];
    const float* p_mat = (const float*)d_in[9];
    const float* r_mat = (const float*)d_in[10];
    const float* alpha = (const float*)d_in[11];
    const float* beta  = (const float*)d_in[12];
    const float* gamma = (const float*)d_in[13];
    float* out = (float*)d_out;

    cudaFuncSetAttribute(attn_mma, cudaFuncAttributeMaxDynamicSharedMemorySize,
                         ATTN_SMEM_BYTES);
    cudaFuncSetAttribute(qk_mma, cudaFuncAttributeMaxDynamicSharedMemorySize,
                         GEMM_SMEM_BYTES);
    cudaFuncSetAttribute(v_mma, cudaFuncAttributeMaxDynamicSharedMemorySize,
                         OUT_SMEM_BYTES);
    cudaFuncSetAttribute(out_mma, cudaFuncAttributeMaxDynamicSharedMemorySize,
                         OUT_SMEM_BYTES);

    colsum_kernel<<<dim3(Lc / 256, 2), 256>>>(p_mat, r_mat);
    coords_kernel<<<(Bc * Lc) / 128, 128>>>(t_enc, Wt, bt);
    split_x_kernel<<<(Bc * Lc * Dc) / (256 * 4), 256>>>(x);
    split_w_kernel<<<dim3((Dc * Dc) / (256 * 4), 4), 256>>>(WQ, WK, WV, WO);
    qk_mma<<<dim3(Dc / 128, (Bc * Lc) / 128, 2), 128, GEMM_SMEM_BYTES>>>();
    v_mma<<<dim3(Dc / 128, (Bc * Lc) / 128), 128, OUT_SMEM_BYTES>>>();
    attn_mma<<<dim3(Lc / 128, Bc * Hc), 256, ATTN_SMEM_BYTES>>>(alpha, beta, gamma);
    out_mma<<<dim3(Dc / 128, (Bc * Lc) / 128), 128, OUT_SMEM_BYTES>>>(bO, out);
}